// round 4
// baseline (speedup 1.0000x reference)
#include <cuda_runtime.h>

// ---------------- problem constants ----------------
#define PB 2
#define PL 2048
#define PD 1024
#define PH 16
#define PDH 64
#define PU 1228          // int(0.6 * 2048)
#define PBH (PB * PH)    // 32

// ---------------- device scratch (no allocation allowed) ----------------
__device__ float g_q[(size_t)PBH * PL * PDH];     // [b,h,l,dh]
__device__ float g_k[(size_t)PBH * PL * PDH];
__device__ float g_v[(size_t)PBH * PL * PDH];
__device__ float g_spars[(size_t)PBH * PL];
__device__ int   g_topidx[(size_t)PBH * PU];
__device__ float g_attn[(size_t)PB * PL * PD];    // pre-output-proj, [b,l,d]

// ============================================================
// SGEMM: C[M,N] = A[M,K] @ Bm[K,N] + bias[N]
// MODE 0: plain row-major write to C
// MODE 1: write into head layout [b,h,l,dh] (for Q/K/V projections)
// Tiles: 128x128x8, 256 threads, 8x8 per-thread micro-tile.
// Requires M%128==0, N%128==0, K%8==0 (true here: 4096,1024,1024).
// ============================================================
template<int MODE>
__global__ __launch_bounds__(256) void sgemm128(
    const float* __restrict__ A, const float* __restrict__ Bm,
    const float* __restrict__ bias, float* __restrict__ C,
    int M, int N, int K) {
  __shared__ float As[8][132];   // transposed A tile, padded vs bank conflicts
  __shared__ float Bs[8][128];

  const int tid = threadIdx.x;
  const int tx = tid & 15, ty = tid >> 4;
  const int arow = tid >> 1;            // 0..127
  const int acol = (tid & 1) << 2;      // 0 or 4
  const int brow = tid >> 5;            // 0..7
  const int bcol = (tid & 31) << 2;     // 0..124

  const float* Ap = A + (size_t)(blockIdx.y * 128 + arow) * K + acol;
  const float* Bp = Bm + (size_t)brow * N + blockIdx.x * 128 + bcol;

  float acc[8][8];
#pragma unroll
  for (int i = 0; i < 8; i++)
#pragma unroll
    for (int j = 0; j < 8; j++) acc[i][j] = 0.f;

  for (int k0 = 0; k0 < K; k0 += 8) {
    float4 av = *(const float4*)(Ap + k0);
    float4 bv = *(const float4*)(Bp + (size_t)k0 * N);
    __syncthreads();
    As[acol + 0][arow] = av.x;
    As[acol + 1][arow] = av.y;
    As[acol + 2][arow] = av.z;
    As[acol + 3][arow] = av.w;
    *(float4*)&Bs[brow][bcol] = bv;
    __syncthreads();
#pragma unroll
    for (int kk = 0; kk < 8; kk++) {
      float a[8], b[8];
      *(float4*)(a)     = *(const float4*)&As[kk][ty * 8];
      *(float4*)(a + 4) = *(const float4*)&As[kk][ty * 8 + 4];
      *(float4*)(b)     = *(const float4*)&Bs[kk][tx * 8];
      *(float4*)(b + 4) = *(const float4*)&Bs[kk][tx * 8 + 4];
#pragma unroll
      for (int i = 0; i < 8; i++)
#pragma unroll
        for (int j = 0; j < 8; j++) acc[i][j] += a[i] * b[j];
    }
  }

#pragma unroll
  for (int i = 0; i < 8; i++) {
    const int m = blockIdx.y * 128 + ty * 8 + i;
#pragma unroll
    for (int j = 0; j < 8; j++) {
      const int n = blockIdx.x * 128 + tx * 8 + j;
      const float val = acc[i][j] + bias[n];
      if (MODE == 0) {
        C[(size_t)m * N + n] = val;
      } else {
        const int b = m >> 11;        // / PL
        const int l = m & (PL - 1);
        const int h = n >> 6;         // / PDH
        const int dh = n & (PDH - 1);
        C[(((size_t)b * PH + h) * PL + l) * PDH + dh] = val;
      }
    }
  }
}

// ============================================================
// Sparsity: per (b,h,row): scale*max_k(q.k) - scale*mean_k(q.k)
// Block = (64 q rows) x (one bh), streams K in 64-tiles.
// Q/K tiles stored dh-transposed in smem: T[d][row], pad 68.
// ============================================================
__global__ __launch_bounds__(256) void sparsity_kernel() {
  __shared__ float Qts[64 * 68];
  __shared__ float Kts[64 * 68];
  const int bh = blockIdx.y;
  const int q0 = blockIdx.x * 64;
  const int tid = threadIdx.x;
  const int tx = tid & 15, ty = tid >> 4;

  {
    const int r = tid >> 2;
    const int c0 = (tid & 3) << 4;
    const float* qrow = g_q + ((size_t)bh * PL + q0 + r) * PDH + c0;
#pragma unroll
    for (int c = 0; c < 16; c += 4) {
      float4 v = *(const float4*)(qrow + c);
      Qts[(c0 + c + 0) * 68 + r] = v.x;
      Qts[(c0 + c + 1) * 68 + r] = v.y;
      Qts[(c0 + c + 2) * 68 + r] = v.z;
      Qts[(c0 + c + 3) * 68 + r] = v.w;
    }
  }

  float rmax[4] = {-1e30f, -1e30f, -1e30f, -1e30f};
  float rsum[4] = {0.f, 0.f, 0.f, 0.f};

  for (int kt = 0; kt < PL / 64; kt++) {
    __syncthreads();
    {
      const int r = tid >> 2;
      const int c0 = (tid & 3) << 4;
      const float* krow = g_k + ((size_t)bh * PL + kt * 64 + r) * PDH + c0;
#pragma unroll
      for (int c = 0; c < 16; c += 4) {
        float4 v = *(const float4*)(krow + c);
        Kts[(c0 + c + 0) * 68 + r] = v.x;
        Kts[(c0 + c + 1) * 68 + r] = v.y;
        Kts[(c0 + c + 2) * 68 + r] = v.z;
        Kts[(c0 + c + 3) * 68 + r] = v.w;
      }
    }
    __syncthreads();

    float s[4][4];
#pragma unroll
    for (int i = 0; i < 4; i++)
#pragma unroll
      for (int j = 0; j < 4; j++) s[i][j] = 0.f;

#pragma unroll 4
    for (int d = 0; d < 64; d++) {
      float a[4], b[4];
      *(float4*)a = *(const float4*)&Qts[d * 68 + ty * 4];
      *(float4*)b = *(const float4*)&Kts[d * 68 + tx * 4];
#pragma unroll
      for (int i = 0; i < 4; i++)
#pragma unroll
        for (int j = 0; j < 4; j++) s[i][j] += a[i] * b[j];
    }
#pragma unroll
    for (int i = 0; i < 4; i++) {
      float m = fmaxf(fmaxf(s[i][0], s[i][1]), fmaxf(s[i][2], s[i][3]));
      rmax[i] = fmaxf(rmax[i], m);
      rsum[i] += (s[i][0] + s[i][1]) + (s[i][2] + s[i][3]);
    }
  }

  const float scale = 0.125f;  // 1/sqrt(64)
#pragma unroll
  for (int i = 0; i < 4; i++) {
    float mx = rmax[i], sm = rsum[i];
#pragma unroll
    for (int o = 8; o; o >>= 1) {
      mx = fmaxf(mx, __shfl_xor_sync(0xffffffffu, mx, o));
      sm += __shfl_xor_sync(0xffffffffu, sm, o);
    }
    if (tx == 0)
      g_spars[(size_t)bh * PL + q0 + ty * 4 + i] =
          scale * mx - scale * sm * (1.0f / PL);
  }
}

// ============================================================
// Top-k: bitonic sort of 2048 (val, idx) pairs per (b,h).
// Order: value descending, tie -> lower index first (matches lax.top_k).
// ============================================================
__global__ __launch_bounds__(1024) void topk_kernel() {
  __shared__ float sv[2048];
  __shared__ int si[2048];
  const int bh = blockIdx.x;
  const int tid = threadIdx.x;

  for (int t = tid; t < 2048; t += 1024) {
    sv[t] = g_spars[(size_t)bh * PL + t];
    si[t] = t;
  }
  __syncthreads();

  for (int k = 2; k <= 2048; k <<= 1) {
    for (int j = k >> 1; j > 0; j >>= 1) {
      for (int t = tid; t < 2048; t += 1024) {
        const int p = t ^ j;
        if (p > t) {
          const bool up = ((t & k) == 0);
          const float va = sv[t], vb = sv[p];
          const int ia = si[t], ib = si[p];
          const bool bfirst = (vb > va) || (vb == va && ib < ia);
          if (bfirst == up) {
            sv[t] = vb; sv[p] = va;
            si[t] = ib; si[p] = ia;
          }
        }
      }
      __syncthreads();
    }
  }
  for (int t = tid; t < PU; t += 1024) g_topidx[(size_t)bh * PU + t] = si[t];
}

// ============================================================
// Zero the scatter buffer (non-selected rows stay 0 pre-Wo).
// ============================================================
__global__ void zero_attn_kernel() {
  const size_t i = (size_t)blockIdx.x * blockDim.x + threadIdx.x;
  float4 z = {0.f, 0.f, 0.f, 0.f};
  ((float4*)g_attn)[i] = z;
}

// ============================================================
// Flash attention on the selected query rows only.
// Block = 64 selected queries x one (b,h); stream K/V in 64-tiles,
// online softmax, scatter result into g_attn[b, l_idx, h*64 + d].
// Dynamic smem: Qts/Kts (dh-transposed) + Vs + Ssm + row stats.
// ============================================================
#define FLASH_SMEM ((4 * 64 * 68 + 3 * 64) * (int)sizeof(float))

__global__ __launch_bounds__(256) void flash_sel_kernel() {
  extern __shared__ float smemf[];
  float* Qts  = smemf;               // [64][68] Qts[d][r]
  float* Kts  = Qts + 64 * 68;       // [64][68] Kts[d][c]
  float* Vs   = Kts + 64 * 68;       // [64][68] Vs[k][d] row-major
  float* Ssm  = Vs + 64 * 68;        // [64][68] scores / probs
  float* mrow = Ssm + 64 * 68;       // [64]
  float* lrow = mrow + 64;           // [64]
  float* arow = lrow + 64;           // [64]
  __shared__ int qidx[64];

  const int bh = blockIdx.y;
  const int qt = blockIdx.x;
  const int tid = threadIdx.x;
  const int tx = tid & 15, ty = tid >> 4;
  const float scale = 0.125f;

  if (tid < 64) {
    const int u = qt * 64 + tid;
    qidx[tid] = (u < PU) ? g_topidx[(size_t)bh * PU + u] : -1;
    mrow[tid] = -1e30f;
    lrow[tid] = 0.f;
  }
  __syncthreads();

  {  // gather + transpose Q
    const int r = tid >> 2;
    const int c0 = (tid & 3) << 4;
    const int src = (qidx[r] < 0) ? 0 : qidx[r];
    const float* qrow = g_q + ((size_t)bh * PL + src) * PDH + c0;
#pragma unroll
    for (int c = 0; c < 16; c += 4) {
      float4 v = *(const float4*)(qrow + c);
      Qts[(c0 + c + 0) * 68 + r] = v.x;
      Qts[(c0 + c + 1) * 68 + r] = v.y;
      Qts[(c0 + c + 2) * 68 + r] = v.z;
      Qts[(c0 + c + 3) * 68 + r] = v.w;
    }
  }

  float acc[4][4];
#pragma unroll
  for (int i = 0; i < 4; i++)
#pragma unroll
    for (int j = 0; j < 4; j++) acc[i][j] = 0.f;

  for (int kt = 0; kt < PL / 64; kt++) {
    __syncthreads();  // prior iter finished with Kts/Vs/Ssm; Q store done (it 0)
    {
      const int r = tid >> 2;
      const int c0 = (tid & 3) << 4;
      const float* krow = g_k + ((size_t)bh * PL + kt * 64 + r) * PDH + c0;
      const float* vrow = g_v + ((size_t)bh * PL + kt * 64 + r) * PDH + c0;
#pragma unroll
      for (int c = 0; c < 16; c += 4) {
        float4 kv = *(const float4*)(krow + c);
        Kts[(c0 + c + 0) * 68 + r] = kv.x;
        Kts[(c0 + c + 1) * 68 + r] = kv.y;
        Kts[(c0 + c + 2) * 68 + r] = kv.z;
        Kts[(c0 + c + 3) * 68 + r] = kv.w;
        *(float4*)&Vs[r * 68 + c0 + c] = *(const float4*)(vrow + c);
      }
    }
    __syncthreads();

    // S = scale * (Qsel . K^T)
    float s[4][4];
#pragma unroll
    for (int i = 0; i < 4; i++)
#pragma unroll
      for (int j = 0; j < 4; j++) s[i][j] = 0.f;
#pragma unroll 4
    for (int d = 0; d < 64; d++) {
      float a[4], b[4];
      *(float4*)a = *(const float4*)&Qts[d * 68 + ty * 4];
      *(float4*)b = *(const float4*)&Kts[d * 68 + tx * 4];
#pragma unroll
      for (int i = 0; i < 4; i++)
#pragma unroll
        for (int j = 0; j < 4; j++) s[i][j] += a[i] * b[j];
    }
#pragma unroll
    for (int i = 0; i < 4; i++)
#pragma unroll
      for (int j = 0; j < 4; j++)
        Ssm[(ty * 4 + i) * 68 + tx * 4 + j] = s[i][j] * scale;
    __syncthreads();

    // online-softmax row stats: 4 threads per row
    {
      const int r = tid >> 2;
      const int part = tid & 3;
      float* row = &Ssm[r * 68];
      float tmax = -1e30f;
#pragma unroll
      for (int c = 0; c < 16; c++) tmax = fmaxf(tmax, row[part * 16 + c]);
      tmax = fmaxf(tmax, __shfl_xor_sync(0xffffffffu, tmax, 1));
      tmax = fmaxf(tmax, __shfl_xor_sync(0xffffffffu, tmax, 2));
      const float m_old = mrow[r];
      const float m_new = fmaxf(m_old, tmax);
      float tsum = 0.f;
#pragma unroll
      for (int c = 0; c < 16; c++) {
        const float p = __expf(row[part * 16 + c] - m_new);
        row[part * 16 + c] = p;
        tsum += p;
      }
      tsum += __shfl_xor_sync(0xffffffffu, tsum, 1);
      tsum += __shfl_xor_sync(0xffffffffu, tsum, 2);
      if (part == 0) {
        const float alpha = __expf(m_old - m_new);
        mrow[r] = m_new;
        arow[r] = alpha;
        lrow[r] = lrow[r] * alpha + tsum;
      }
    }
    __syncthreads();

    // acc = acc*alpha + P @ V
#pragma unroll
    for (int i = 0; i < 4; i++) {
      const float al = arow[ty * 4 + i];
#pragma unroll
      for (int j = 0; j < 4; j++) acc[i][j] *= al;
    }
#pragma unroll 4
    for (int k = 0; k < 64; k++) {
      float v4[4];
      *(float4*)v4 = *(const float4*)&Vs[k * 68 + tx * 4];
#pragma unroll
      for (int i = 0; i < 4; i++) {
        const float p = Ssm[(ty * 4 + i) * 68 + k];
#pragma unroll
        for (int j = 0; j < 4; j++) acc[i][j] += p * v4[j];
      }
    }
  }

  // write out: attn[b, l_idx, h*64 + d] = acc / l
  const int b = bh / PH, h = bh % PH;
#pragma unroll
  for (int i = 0; i < 4; i++) {
    const int r = ty * 4 + i;
    const int src = qidx[r];
    if (src >= 0) {
      const float inv = 1.0f / lrow[r];
      float4 o;
      o.x = acc[i][0] * inv;
      o.y = acc[i][1] * inv;
      o.z = acc[i][2] * inv;
      o.w = acc[i][3] * inv;
      *(float4*)&g_attn[((size_t)b * PL + src) * PD + h * PDH + tx * 4] = o;
    }
  }
}

// ============================================================
// host launcher
// ============================================================
extern "C" void kernel_launch(void* const* d_in, const int* in_sizes, int n_in,
                              void* d_out, int out_size) {
  (void)in_sizes; (void)n_in; (void)out_size;
  const float* x  = (const float*)d_in[0];
  const float* Wq = (const float*)d_in[1];
  const float* bq = (const float*)d_in[2];
  const float* Wk = (const float*)d_in[3];
  const float* bk = (const float*)d_in[4];
  const float* Wv = (const float*)d_in[5];
  const float* bv = (const float*)d_in[6];
  const float* Wo = (const float*)d_in[7];
  const float* bo = (const float*)d_in[8];
  float* out = (float*)d_out;

  float *pq, *pk, *pv, *pattn;
  cudaGetSymbolAddress((void**)&pq, g_q);
  cudaGetSymbolAddress((void**)&pk, g_k);
  cudaGetSymbolAddress((void**)&pv, g_v);
  cudaGetSymbolAddress((void**)&pattn, g_attn);

  cudaFuncSetAttribute(flash_sel_kernel,
                       cudaFuncAttributeMaxDynamicSharedMemorySize, FLASH_SMEM);

  const dim3 gGemm(PD / 128, (PB * PL) / 128);  // (8, 32)

  // Q/K/V projections into head layout
  sgemm128<1><<<gGemm, 256>>>(x, Wq, bq, pq, PB * PL, PD, PD);
  sgemm128<1><<<gGemm, 256>>>(x, Wk, bk, pk, PB * PL, PD, PD);
  sgemm128<1><<<gGemm, 256>>>(x, Wv, bv, pv, PB * PL, PD, PD);

  // sparsity heuristic over full scores
  sparsity_kernel<<<dim3(PL / 64, PBH), 256>>>();

  // per-(b,h) top-U selection
  topk_kernel<<<PBH, 1024>>>();

  // zero scatter buffer, then attention on selected rows
  zero_attn_kernel<<<(PB * PL * PD / 4) / 256, 256>>>();
  flash_sel_kernel<<<dim3((PU + 63) / 64, PBH), 256, FLASH_SMEM>>>();

  // output projection
  sgemm128<0><<<gGemm, 256>>>(pattn, Wo, bo, out, PB * PL, PD, PD);
}

// round 5
// speedup vs baseline: 1.2313x; 1.2313x over previous
#include <cuda_runtime.h>

// ---------------- problem constants ----------------
#define PB 2
#define PL 2048
#define PD 1024
#define PH 16
#define PDH 64
#define PU 1228          // int(0.6 * 2048)
#define PBH (PB * PH)    // 32

// ---------------- device scratch (no allocation allowed) ----------------
__device__ float g_q[(size_t)PBH * PL * PDH];     // [b,h,l,dh]
__device__ float g_k[(size_t)PBH * PL * PDH];
__device__ float g_v[(size_t)PBH * PL * PDH];
__device__ float g_spars[(size_t)PBH * PL];
__device__ int   g_topidx[(size_t)PBH * PU];
__device__ float g_attn[(size_t)PB * PL * PD];    // pre-output-proj, [b,l,d]

// ============================================================
// SGEMM v2: C[M,N] = A[M,K] @ Bm[K,N] + bias[N]
// 128x128x16 tiles, 256 threads, 8x8 micro-tile (split 4+4 fragments),
// double-buffered smem, one __syncthreads per K-panel.
// MODE 0: row-major C.  MODE 1: write into [b,h,l,dh] head layout.
// ============================================================
template<int MODE>
__global__ __launch_bounds__(256) void sgemm_v2(
    const float* __restrict__ A, const float* __restrict__ Bm,
    const float* __restrict__ bias, float* __restrict__ C,
    int M, int N, int K) {
  __shared__ float As[2][16][132];   // transposed A panel
  __shared__ float Bs[2][16][128];

  const int tid = threadIdx.x;
  const int tx = tid & 15, ty = tid >> 4;

  const int a_row = tid >> 1;          // 0..127
  const int a_c   = (tid & 1) * 8;     // 0 or 8
  const int b_row = tid >> 4;          // 0..15
  const int b_c   = (tid & 15) * 8;    // 0..120

  const float* Ap = A + (size_t)(blockIdx.y * 128 + a_row) * K + a_c;
  const float* Bp = Bm + (size_t)b_row * N + blockIdx.x * 128 + b_c;

  float acc[8][8];
#pragma unroll
  for (int i = 0; i < 8; i++)
#pragma unroll
    for (int j = 0; j < 8; j++) acc[i][j] = 0.f;

  const int NP = K >> 4;

  float4 a0 = *(const float4*)(Ap);
  float4 a1 = *(const float4*)(Ap + 4);
  float4 b0 = *(const float4*)(Bp);
  float4 b1 = *(const float4*)(Bp + 4);

  // store panel 0
  As[0][a_c + 0][a_row] = a0.x; As[0][a_c + 1][a_row] = a0.y;
  As[0][a_c + 2][a_row] = a0.z; As[0][a_c + 3][a_row] = a0.w;
  As[0][a_c + 4][a_row] = a1.x; As[0][a_c + 5][a_row] = a1.y;
  As[0][a_c + 6][a_row] = a1.z; As[0][a_c + 7][a_row] = a1.w;
  *(float4*)&Bs[0][b_row][b_c] = b0;
  *(float4*)&Bs[0][b_row][b_c + 4] = b1;
  __syncthreads();

#pragma unroll 1
  for (int p = 0; p < NP; p++) {
    const int buf = p & 1;
    if (p + 1 < NP) {
      const float* Ap2 = Ap + (p + 1) * 16;
      const float* Bp2 = Bp + (size_t)(p + 1) * 16 * N;
      a0 = *(const float4*)(Ap2);
      a1 = *(const float4*)(Ap2 + 4);
      b0 = *(const float4*)(Bp2);
      b1 = *(const float4*)(Bp2 + 4);
    }
#pragma unroll
    for (int kk = 0; kk < 16; kk++) {
      float av[8], bv[8];
      *(float4*)(av)     = *(const float4*)&As[buf][kk][ty * 4];
      *(float4*)(av + 4) = *(const float4*)&As[buf][kk][64 + ty * 4];
      *(float4*)(bv)     = *(const float4*)&Bs[buf][kk][tx * 4];
      *(float4*)(bv + 4) = *(const float4*)&Bs[buf][kk][64 + tx * 4];
#pragma unroll
      for (int i = 0; i < 8; i++)
#pragma unroll
        for (int j = 0; j < 8; j++) acc[i][j] += av[i] * bv[j];
    }
    if (p + 1 < NP) {
      const int nb = buf ^ 1;
      As[nb][a_c + 0][a_row] = a0.x; As[nb][a_c + 1][a_row] = a0.y;
      As[nb][a_c + 2][a_row] = a0.z; As[nb][a_c + 3][a_row] = a0.w;
      As[nb][a_c + 4][a_row] = a1.x; As[nb][a_c + 5][a_row] = a1.y;
      As[nb][a_c + 6][a_row] = a1.z; As[nb][a_c + 7][a_row] = a1.w;
      *(float4*)&Bs[nb][b_row][b_c] = b0;
      *(float4*)&Bs[nb][b_row][b_c + 4] = b1;
      __syncthreads();
    }
  }

  // epilogue (vectorized, fragment cols are 4-consecutive within a 64-half)
#pragma unroll
  for (int i = 0; i < 8; i++) {
    const int m = blockIdx.y * 128 + ty * 4 + (i & 3) + ((i >> 2) << 6);
#pragma unroll
    for (int jh = 0; jh < 2; jh++) {
      const int n = blockIdx.x * 128 + tx * 4 + (jh << 6);
      float4 bb = *(const float4*)&bias[n];
      float4 v;
      v.x = acc[i][jh * 4 + 0] + bb.x;
      v.y = acc[i][jh * 4 + 1] + bb.y;
      v.z = acc[i][jh * 4 + 2] + bb.z;
      v.w = acc[i][jh * 4 + 3] + bb.w;
      if (MODE == 0) {
        *(float4*)&C[(size_t)m * N + n] = v;
      } else {
        const int b = m >> 11;
        const int l = m & (PL - 1);
        const int h = n >> 6;
        const int dh = n & (PDH - 1);
        *(float4*)&C[(((size_t)b * PH + h) * PL + l) * PDH + dh] = v;
      }
    }
  }
}

// ============================================================
// Sparsity v2: per (b,h,row): scale*max_k(q.k) - scale*mean_k(q.k)
// 128 q-rows x 128 k-cols tiles, 8x8 micro-tile, dh=64 resident.
// Dynamic smem: Qts[64][132] + Kts[64][132].
// ============================================================
#define SPARS_SMEM (2 * 64 * 132 * (int)sizeof(float))

__global__ __launch_bounds__(256) void sparsity_v2() {
  extern __shared__ float smem_sp[];
  float* Qts = smem_sp;              // Qts[d][q] stride 132
  float* Kts = smem_sp + 64 * 132;   // Kts[d][k] stride 132

  const int bh = blockIdx.y;
  const int q0 = blockIdx.x * 128;
  const int tid = threadIdx.x;
  const int tx = tid & 15, ty = tid >> 4;

  {  // load + transpose Q tile (128 rows x 64)
    const int r = tid >> 1;
    const int c0 = (tid & 1) * 32;
    const float* qrow = g_q + ((size_t)bh * PL + q0 + r) * PDH + c0;
#pragma unroll
    for (int c = 0; c < 32; c += 4) {
      float4 v = *(const float4*)(qrow + c);
      Qts[(c0 + c + 0) * 132 + r] = v.x;
      Qts[(c0 + c + 1) * 132 + r] = v.y;
      Qts[(c0 + c + 2) * 132 + r] = v.z;
      Qts[(c0 + c + 3) * 132 + r] = v.w;
    }
  }

  float rmax[8], rsum[8];
#pragma unroll
  for (int i = 0; i < 8; i++) { rmax[i] = -1e30f; rsum[i] = 0.f; }

  for (int kt = 0; kt < PL / 128; kt++) {
    __syncthreads();
    {
      const int r = tid >> 1;
      const int c0 = (tid & 1) * 32;
      const float* krow = g_k + ((size_t)bh * PL + kt * 128 + r) * PDH + c0;
#pragma unroll
      for (int c = 0; c < 32; c += 4) {
        float4 v = *(const float4*)(krow + c);
        Kts[(c0 + c + 0) * 132 + r] = v.x;
        Kts[(c0 + c + 1) * 132 + r] = v.y;
        Kts[(c0 + c + 2) * 132 + r] = v.z;
        Kts[(c0 + c + 3) * 132 + r] = v.w;
      }
    }
    __syncthreads();

    float s[8][8];
#pragma unroll
    for (int i = 0; i < 8; i++)
#pragma unroll
      for (int j = 0; j < 8; j++) s[i][j] = 0.f;

#pragma unroll 16
    for (int d = 0; d < 64; d++) {
      float av[8], bv[8];
      *(float4*)(av)     = *(const float4*)&Qts[d * 132 + ty * 4];
      *(float4*)(av + 4) = *(const float4*)&Qts[d * 132 + 64 + ty * 4];
      *(float4*)(bv)     = *(const float4*)&Kts[d * 132 + tx * 4];
      *(float4*)(bv + 4) = *(const float4*)&Kts[d * 132 + 64 + tx * 4];
#pragma unroll
      for (int i = 0; i < 8; i++)
#pragma unroll
        for (int j = 0; j < 8; j++) s[i][j] += av[i] * bv[j];
    }
#pragma unroll
    for (int i = 0; i < 8; i++) {
      float m0 = fmaxf(fmaxf(s[i][0], s[i][1]), fmaxf(s[i][2], s[i][3]));
      float m1 = fmaxf(fmaxf(s[i][4], s[i][5]), fmaxf(s[i][6], s[i][7]));
      rmax[i] = fmaxf(rmax[i], fmaxf(m0, m1));
      rsum[i] += ((s[i][0] + s[i][1]) + (s[i][2] + s[i][3])) +
                 ((s[i][4] + s[i][5]) + (s[i][6] + s[i][7]));
    }
  }

  const float scale = 0.125f;  // 1/sqrt(64)
#pragma unroll
  for (int i = 0; i < 8; i++) {
    float mx = rmax[i], sm = rsum[i];
#pragma unroll
    for (int o = 8; o; o >>= 1) {
      mx = fmaxf(mx, __shfl_xor_sync(0xffffffffu, mx, o));
      sm += __shfl_xor_sync(0xffffffffu, sm, o);
    }
    if (tx == 0) {
      const int r = ty * 4 + (i & 3) + ((i >> 2) << 6);
      g_spars[(size_t)bh * PL + q0 + r] = scale * mx - scale * sm * (1.0f / PL);
    }
  }
}

// ============================================================
// Top-k: bitonic sort of 2048 (val, idx) pairs per (b,h).
// Order: value descending, tie -> lower index first (matches lax.top_k).
// ============================================================
__global__ __launch_bounds__(1024) void topk_kernel() {
  __shared__ float sv[2048];
  __shared__ int si[2048];
  const int bh = blockIdx.x;
  const int tid = threadIdx.x;

  for (int t = tid; t < 2048; t += 1024) {
    sv[t] = g_spars[(size_t)bh * PL + t];
    si[t] = t;
  }
  __syncthreads();

  for (int k = 2; k <= 2048; k <<= 1) {
    for (int j = k >> 1; j > 0; j >>= 1) {
      for (int t = tid; t < 2048; t += 1024) {
        const int p = t ^ j;
        if (p > t) {
          const bool up = ((t & k) == 0);
          const float va = sv[t], vb = sv[p];
          const int ia = si[t], ib = si[p];
          const bool bfirst = (vb > va) || (vb == va && ib < ia);
          if (bfirst == up) {
            sv[t] = vb; sv[p] = va;
            si[t] = ib; si[p] = ia;
          }
        }
      }
      __syncthreads();
    }
  }
  for (int t = tid; t < PU; t += 1024) g_topidx[(size_t)bh * PU + t] = si[t];
}

// ============================================================
// Zero the scatter buffer (non-selected rows stay 0 pre-Wo).
// ============================================================
__global__ void zero_attn_kernel() {
  const size_t i = (size_t)blockIdx.x * blockDim.x + threadIdx.x;
  float4 z = {0.f, 0.f, 0.f, 0.f};
  ((float4*)g_attn)[i] = z;
}

// ============================================================
// Flash v2: attention on selected query rows.
// 128 selected q x 128 k tiles, 8x8 micro-tile, register-resident
// online softmax (shfl over 16-lane row groups), P staged row-major
// in smem for a float4 PV pass.
// Dynamic smem: Qts[64][132] + Kts[64][132] + Vs[128][68] + Ps[128][132].
// ============================================================
#define FL_KOFF (64 * 132)
#define FL_VOFF (2 * 64 * 132)
#define FL_POFF (2 * 64 * 132 + 128 * 68)
#define FLASH_SMEM ((2 * 64 * 132 + 128 * 68 + 128 * 132) * (int)sizeof(float))

__global__ __launch_bounds__(256) void flash_v2() {
  extern __shared__ float smem_fl[];
  float* Qts = smem_fl;             // [64][132]  Q^T (gathered)
  float* Kts = smem_fl + FL_KOFF;   // [64][132]  K^T
  float* Vs  = smem_fl + FL_VOFF;   // [128][68]  V row-major
  float* Ps  = smem_fl + FL_POFF;   // [128][132] probabilities
  __shared__ int qidx[128];

  const int bh = blockIdx.y;
  const int qt = blockIdx.x;
  const int tid = threadIdx.x;
  const int tx = tid & 15, ty = tid >> 4;
  const float scale = 0.125f;

  if (tid < 128) {
    const int u = qt * 128 + tid;
    qidx[tid] = (u < PU) ? g_topidx[(size_t)bh * PU + u] : -1;
  }
  __syncthreads();

  {  // gather + transpose Q
    const int r = tid >> 1;
    const int c0 = (tid & 1) * 32;
    int src = qidx[r];
    if (src < 0) src = 0;
    const float* qrow = g_q + ((size_t)bh * PL + src) * PDH + c0;
#pragma unroll
    for (int c = 0; c < 32; c += 4) {
      float4 v = *(const float4*)(qrow + c);
      Qts[(c0 + c + 0) * 132 + r] = v.x;
      Qts[(c0 + c + 1) * 132 + r] = v.y;
      Qts[(c0 + c + 2) * 132 + r] = v.z;
      Qts[(c0 + c + 3) * 132 + r] = v.w;
    }
  }

  float m_run[8], l_run[8], o[8][4];
#pragma unroll
  for (int i = 0; i < 8; i++) {
    m_run[i] = -1e30f; l_run[i] = 0.f;
#pragma unroll
    for (int j = 0; j < 4; j++) o[i][j] = 0.f;
  }

  for (int kt = 0; kt < PL / 128; kt++) {
    __syncthreads();  // Kts/Vs/Ps free (prev iter done); Qts store done (iter 0)
    {
      const int r = tid >> 1;
      const int c0 = (tid & 1) * 32;
      const float* krow = g_k + ((size_t)bh * PL + kt * 128 + r) * PDH + c0;
      const float* vrow = g_v + ((size_t)bh * PL + kt * 128 + r) * PDH + c0;
#pragma unroll
      for (int c = 0; c < 32; c += 4) {
        float4 kv = *(const float4*)(krow + c);
        Kts[(c0 + c + 0) * 132 + r] = kv.x;
        Kts[(c0 + c + 1) * 132 + r] = kv.y;
        Kts[(c0 + c + 2) * 132 + r] = kv.z;
        Kts[(c0 + c + 3) * 132 + r] = kv.w;
        *(float4*)&Vs[r * 68 + c0 + c] = *(const float4*)(vrow + c);
      }
    }
    __syncthreads();

    // S = scale * (Q_sel . K^T), 8x8 in registers
    float s[8][8];
#pragma unroll
    for (int i = 0; i < 8; i++)
#pragma unroll
      for (int j = 0; j < 8; j++) s[i][j] = 0.f;
#pragma unroll 16
    for (int d = 0; d < 64; d++) {
      float av[8], bv[8];
      *(float4*)(av)     = *(const float4*)&Qts[d * 132 + ty * 4];
      *(float4*)(av + 4) = *(const float4*)&Qts[d * 132 + 64 + ty * 4];
      *(float4*)(bv)     = *(const float4*)&Kts[d * 132 + tx * 4];
      *(float4*)(bv + 4) = *(const float4*)&Kts[d * 132 + 64 + tx * 4];
#pragma unroll
      for (int i = 0; i < 8; i++)
#pragma unroll
        for (int j = 0; j < 8; j++) s[i][j] += av[i] * bv[j];
    }

    // register online softmax; row r owned by the 16 lanes of one ty group
#pragma unroll
    for (int i = 0; i < 8; i++) {
      float tm = s[i][0] * scale;
#pragma unroll
      for (int j = 1; j < 8; j++) tm = fmaxf(tm, s[i][j] * scale);
#pragma unroll
      for (int off = 8; off; off >>= 1)
        tm = fmaxf(tm, __shfl_xor_sync(0xffffffffu, tm, off));
      const float mn = fmaxf(m_run[i], tm);
      const float alpha = __expf(m_run[i] - mn);
      m_run[i] = mn;
      float ts = 0.f;
#pragma unroll
      for (int j = 0; j < 8; j++) {
        const float pv = __expf(s[i][j] * scale - mn);
        s[i][j] = pv;
        ts += pv;
      }
#pragma unroll
      for (int off = 8; off; off >>= 1)
        ts += __shfl_xor_sync(0xffffffffu, ts, off);
      l_run[i] = l_run[i] * alpha + ts;
#pragma unroll
      for (int j = 0; j < 4; j++) o[i][j] *= alpha;
    }

    // stage P row-major
#pragma unroll
    for (int i = 0; i < 8; i++) {
      const int ri = ty * 4 + (i & 3) + ((i >> 2) << 6);
      float4 p0 = {s[i][0], s[i][1], s[i][2], s[i][3]};
      float4 p1 = {s[i][4], s[i][5], s[i][6], s[i][7]};
      *(float4*)&Ps[ri * 132 + tx * 4] = p0;
      *(float4*)&Ps[ri * 132 + 64 + tx * 4] = p1;
    }
    __syncthreads();

    // O += P @ V  (thread owns d-cols tx*4..tx*4+3)
#pragma unroll 4
    for (int k = 0; k < 128; k += 4) {
      float4 vv0 = *(const float4*)&Vs[(k + 0) * 68 + tx * 4];
      float4 vv1 = *(const float4*)&Vs[(k + 1) * 68 + tx * 4];
      float4 vv2 = *(const float4*)&Vs[(k + 2) * 68 + tx * 4];
      float4 vv3 = *(const float4*)&Vs[(k + 3) * 68 + tx * 4];
#pragma unroll
      for (int i = 0; i < 8; i++) {
        const int ri = ty * 4 + (i & 3) + ((i >> 2) << 6);
        float4 pk = *(const float4*)&Ps[ri * 132 + k];
        o[i][0] += pk.x * vv0.x + pk.y * vv1.x + pk.z * vv2.x + pk.w * vv3.x;
        o[i][1] += pk.x * vv0.y + pk.y * vv1.y + pk.z * vv2.y + pk.w * vv3.y;
        o[i][2] += pk.x * vv0.z + pk.y * vv1.z + pk.z * vv2.z + pk.w * vv3.z;
        o[i][3] += pk.x * vv0.w + pk.y * vv1.w + pk.z * vv2.w + pk.w * vv3.w;
      }
    }
  }

  // scatter: attn[b, l_idx, h*64 + d] = o / l
  const int b = bh >> 4, h = bh & 15;
#pragma unroll
  for (int i = 0; i < 8; i++) {
    const int ri = ty * 4 + (i & 3) + ((i >> 2) << 6);
    const int src = qidx[ri];
    if (src >= 0) {
      const float inv = 1.0f / l_run[i];
      float4 ov = {o[i][0] * inv, o[i][1] * inv, o[i][2] * inv, o[i][3] * inv};
      *(float4*)&g_attn[((size_t)b * PL + src) * PD + h * PDH + tx * 4] = ov;
    }
  }
}

// ============================================================
// host launcher
// ============================================================
extern "C" void kernel_launch(void* const* d_in, const int* in_sizes, int n_in,
                              void* d_out, int out_size) {
  (void)in_sizes; (void)n_in; (void)out_size;
  const float* x  = (const float*)d_in[0];
  const float* Wq = (const float*)d_in[1];
  const float* bq = (const float*)d_in[2];
  const float* Wk = (const float*)d_in[3];
  const float* bk = (const float*)d_in[4];
  const float* Wv = (const float*)d_in[5];
  const float* bv = (const float*)d_in[6];
  const float* Wo = (const float*)d_in[7];
  const float* bo = (const float*)d_in[8];
  float* out = (float*)d_out;

  float *pq, *pk, *pv, *pattn;
  cudaGetSymbolAddress((void**)&pq, g_q);
  cudaGetSymbolAddress((void**)&pk, g_k);
  cudaGetSymbolAddress((void**)&pv, g_v);
  cudaGetSymbolAddress((void**)&pattn, g_attn);

  cudaFuncSetAttribute(sparsity_v2,
                       cudaFuncAttributeMaxDynamicSharedMemorySize, SPARS_SMEM);
  cudaFuncSetAttribute(flash_v2,
                       cudaFuncAttributeMaxDynamicSharedMemorySize, FLASH_SMEM);

  const dim3 gGemm(PD / 128, (PB * PL) / 128);  // (8, 32)

  // Q/K/V projections into head layout
  sgemm_v2<1><<<gGemm, 256>>>(x, Wq, bq, pq, PB * PL, PD, PD);
  sgemm_v2<1><<<gGemm, 256>>>(x, Wk, bk, pk, PB * PL, PD, PD);
  sgemm_v2<1><<<gGemm, 256>>>(x, Wv, bv, pv, PB * PL, PD, PD);

  // sparsity heuristic over full scores
  sparsity_v2<<<dim3(PL / 128, PBH), 256, SPARS_SMEM>>>();

  // per-(b,h) top-U selection
  topk_kernel<<<PBH, 1024>>>();

  // zero scatter buffer, then attention on selected rows
  zero_attn_kernel<<<(PB * PL * PD / 4) / 256, 256>>>();
  flash_v2<<<dim3((PU + 127) / 128, PBH), 256, FLASH_SMEM>>>();

  // output projection
  sgemm_v2<0><<<gGemm, 256>>>(pattn, Wo, bo, out, PB * PL, PD, PD);
}

// round 6
// speedup vs baseline: 1.2796x; 1.0393x over previous
#include <cuda_runtime.h>
#include <cstdint>

// ---------------- problem constants ----------------
#define PB 2
#define PL 2048
#define PD 1024
#define PH 16
#define PDH 64
#define PU 1228          // int(0.6 * 2048)
#define PBH (PB * PH)    // 32

// ---------------- device scratch (no allocation allowed) ----------------
__device__ float g_q [(size_t)PBH * PL * PDH];   // [b,h,l,dh]
__device__ float g_k [(size_t)PBH * PL * PDH];   // [b,h,l,dh]
__device__ float g_v [(size_t)PBH * PL * PDH];   // [b,h,l,dh]
__device__ float g_qt[(size_t)PBH * PDH * PL];   // [b,h,dh,l]
__device__ float g_kt[(size_t)PBH * PDH * PL];   // [b,h,dh,l]
__device__ float g_spars[(size_t)PBH * PL];
__device__ int   g_topidx[(size_t)PBH * PU];
__device__ float g_attn[(size_t)PB * PL * PD];   // pre-output-proj, [b,l,d]

// ---------------- cp.async helpers ----------------
#define CP16(dst_u32, src_ptr) \
  asm volatile("cp.async.cg.shared.global [%0], [%1], 16;\n" :: "r"(dst_u32), "l"(src_ptr))
#define CP_COMMIT() asm volatile("cp.async.commit_group;\n" ::)
#define CP_WAIT0()  asm volatile("cp.async.wait_group 0;\n" ::)
#define CP_WAIT1()  asm volatile("cp.async.wait_group 1;\n" ::)

static __device__ __forceinline__ uint32_t sptr(const void* p) {
  return (uint32_t)__cvta_generic_to_shared(p);
}

// ============================================================
// SGEMM v2 (unchanged from R4): 128x128x16, double-buffered.
// MODE 0: row-major C.  MODE 1: [b,h,l,dh] head layout.
// ============================================================
template<int MODE>
__global__ __launch_bounds__(256) void sgemm_v2(
    const float* __restrict__ A, const float* __restrict__ Bm,
    const float* __restrict__ bias, float* __restrict__ C,
    int M, int N, int K) {
  __shared__ float As[2][16][132];
  __shared__ float Bs[2][16][128];

  const int tid = threadIdx.x;
  const int tx = tid & 15, ty = tid >> 4;

  const int a_row = tid >> 1;
  const int a_c   = (tid & 1) * 8;
  const int b_row = tid >> 4;
  const int b_c   = (tid & 15) * 8;

  const float* Ap = A + (size_t)(blockIdx.y * 128 + a_row) * K + a_c;
  const float* Bp = Bm + (size_t)b_row * N + blockIdx.x * 128 + b_c;

  float acc[8][8];
#pragma unroll
  for (int i = 0; i < 8; i++)
#pragma unroll
    for (int j = 0; j < 8; j++) acc[i][j] = 0.f;

  const int NP = K >> 4;

  float4 a0 = *(const float4*)(Ap);
  float4 a1 = *(const float4*)(Ap + 4);
  float4 b0 = *(const float4*)(Bp);
  float4 b1 = *(const float4*)(Bp + 4);

  As[0][a_c + 0][a_row] = a0.x; As[0][a_c + 1][a_row] = a0.y;
  As[0][a_c + 2][a_row] = a0.z; As[0][a_c + 3][a_row] = a0.w;
  As[0][a_c + 4][a_row] = a1.x; As[0][a_c + 5][a_row] = a1.y;
  As[0][a_c + 6][a_row] = a1.z; As[0][a_c + 7][a_row] = a1.w;
  *(float4*)&Bs[0][b_row][b_c] = b0;
  *(float4*)&Bs[0][b_row][b_c + 4] = b1;
  __syncthreads();

#pragma unroll 1
  for (int p = 0; p < NP; p++) {
    const int buf = p & 1;
    if (p + 1 < NP) {
      const float* Ap2 = Ap + (p + 1) * 16;
      const float* Bp2 = Bp + (size_t)(p + 1) * 16 * N;
      a0 = *(const float4*)(Ap2);
      a1 = *(const float4*)(Ap2 + 4);
      b0 = *(const float4*)(Bp2);
      b1 = *(const float4*)(Bp2 + 4);
    }
#pragma unroll
    for (int kk = 0; kk < 16; kk++) {
      float av[8], bv[8];
      *(float4*)(av)     = *(const float4*)&As[buf][kk][ty * 4];
      *(float4*)(av + 4) = *(const float4*)&As[buf][kk][64 + ty * 4];
      *(float4*)(bv)     = *(const float4*)&Bs[buf][kk][tx * 4];
      *(float4*)(bv + 4) = *(const float4*)&Bs[buf][kk][64 + tx * 4];
#pragma unroll
      for (int i = 0; i < 8; i++)
#pragma unroll
        for (int j = 0; j < 8; j++) acc[i][j] += av[i] * bv[j];
    }
    if (p + 1 < NP) {
      const int nb = buf ^ 1;
      As[nb][a_c + 0][a_row] = a0.x; As[nb][a_c + 1][a_row] = a0.y;
      As[nb][a_c + 2][a_row] = a0.z; As[nb][a_c + 3][a_row] = a0.w;
      As[nb][a_c + 4][a_row] = a1.x; As[nb][a_c + 5][a_row] = a1.y;
      As[nb][a_c + 6][a_row] = a1.z; As[nb][a_c + 7][a_row] = a1.w;
      *(float4*)&Bs[nb][b_row][b_c] = b0;
      *(float4*)&Bs[nb][b_row][b_c + 4] = b1;
      __syncthreads();
    }
  }

#pragma unroll
  for (int i = 0; i < 8; i++) {
    const int m = blockIdx.y * 128 + ty * 4 + (i & 3) + ((i >> 2) << 6);
#pragma unroll
    for (int jh = 0; jh < 2; jh++) {
      const int n = blockIdx.x * 128 + tx * 4 + (jh << 6);
      float4 bb = *(const float4*)&bias[n];
      float4 v;
      v.x = acc[i][jh * 4 + 0] + bb.x;
      v.y = acc[i][jh * 4 + 1] + bb.y;
      v.z = acc[i][jh * 4 + 2] + bb.z;
      v.w = acc[i][jh * 4 + 3] + bb.w;
      if (MODE == 0) {
        *(float4*)&C[(size_t)m * N + n] = v;
      } else {
        const int b = m >> 11;
        const int l = m & (PL - 1);
        const int h = n >> 6;
        const int dh = n & (PDH - 1);
        *(float4*)&C[(((size_t)b * PH + h) * PL + l) * PDH + dh] = v;
      }
    }
  }
}

// ============================================================
// Head-layout transpose: [bh][l][dh] -> [bh][dh][l], 32x32 tiles.
// grid (PL/32, PDH/32, PBH), block 256 (=32x8).
// ============================================================
__global__ __launch_bounds__(256) void transpose_head(
    const float* __restrict__ in, float* __restrict__ out) {
  __shared__ float t[32][33];
  const int bh = blockIdx.z;
  const int l0 = blockIdx.x * 32, d0 = blockIdx.y * 32;
  const int x = threadIdx.x & 31, y = threadIdx.x >> 5;
  const float* ip = in + (size_t)bh * PL * PDH;
#pragma unroll
  for (int k = 0; k < 4; k++)
    t[y + 8 * k][x] = ip[(size_t)(l0 + y + 8 * k) * PDH + d0 + x];
  __syncthreads();
  float* op = out + (size_t)bh * PDH * PL;
#pragma unroll
  for (int k = 0; k < 4; k++)
    op[(size_t)(d0 + y + 8 * k) * PL + l0 + x] = t[x][y + 8 * k];
}

// ============================================================
// Sparsity v3: 128q x 128k tiles, 8x8 micro-tile, cp.async
// double-buffered K ring, no in-kernel transposes (uses g_qt/g_kt).
// smem: Qs[64][132] + Ks[2][64][132] = 99KB -> 2 CTAs/SM.
// ============================================================
#define SP_SMEM (3 * 64 * 132 * (int)sizeof(float))

__global__ __launch_bounds__(256, 2) void sparsity_v3() {
  extern __shared__ float sm_sp[];
  float* Qs = sm_sp;                  // [64][132]
  float* Ks = sm_sp + 64 * 132;       // [2][64][132]

  const int bh = blockIdx.y;
  const int q0 = blockIdx.x * 128;
  const int tid = threadIdx.x;
  const int tx = tid & 15, ty = tid >> 4;
  const int rr = tid >> 2;            // 0..63 (d row)
  const int seg = (tid & 3) * 32;     // 0,32,64,96

  {  // Q tile + K tile 0 via cp.async (group 0)
    const float* qsrc = g_qt + ((size_t)bh * PDH + rr) * PL + q0 + seg;
    const float* ksrc = g_kt + ((size_t)bh * PDH + rr) * PL + seg;
    const uint32_t qdst = sptr(&Qs[rr * 132 + seg]);
    const uint32_t kdst = sptr(&Ks[rr * 132 + seg]);
#pragma unroll
    for (int j = 0; j < 8; j++) CP16(qdst + j * 16, qsrc + j * 4);
#pragma unroll
    for (int j = 0; j < 8; j++) CP16(kdst + j * 16, ksrc + j * 4);
    CP_COMMIT();
  }

  float rmax[8], rsum[8];
#pragma unroll
  for (int i = 0; i < 8; i++) { rmax[i] = -1e30f; rsum[i] = 0.f; }

#pragma unroll 1
  for (int kt = 0; kt < 16; kt++) {
    if (kt + 1 < 16) {  // prefetch next K tile into the other buffer
      const float* ksrc =
          g_kt + ((size_t)bh * PDH + rr) * PL + (kt + 1) * 128 + seg;
      const uint32_t kdst =
          sptr(&Ks[((kt + 1) & 1) * 64 * 132 + rr * 132 + seg]);
#pragma unroll
      for (int j = 0; j < 8; j++) CP16(kdst + j * 16, ksrc + j * 4);
      CP_COMMIT();
      CP_WAIT1();
    } else {
      CP_WAIT0();
    }
    __syncthreads();

    const float* Kb = Ks + (kt & 1) * 64 * 132;
    float s[8][8];
#pragma unroll
    for (int i = 0; i < 8; i++)
#pragma unroll
      for (int j = 0; j < 8; j++) s[i][j] = 0.f;

#pragma unroll 16
    for (int d = 0; d < 64; d++) {
      float av[8], bv[8];
      *(float4*)(av)     = *(const float4*)&Qs[d * 132 + ty * 4];
      *(float4*)(av + 4) = *(const float4*)&Qs[d * 132 + 64 + ty * 4];
      *(float4*)(bv)     = *(const float4*)&Kb[d * 132 + tx * 4];
      *(float4*)(bv + 4) = *(const float4*)&Kb[d * 132 + 64 + tx * 4];
#pragma unroll
      for (int i = 0; i < 8; i++)
#pragma unroll
        for (int j = 0; j < 8; j++) s[i][j] += av[i] * bv[j];
    }
#pragma unroll
    for (int i = 0; i < 8; i++) {
      float m0 = fmaxf(fmaxf(s[i][0], s[i][1]), fmaxf(s[i][2], s[i][3]));
      float m1 = fmaxf(fmaxf(s[i][4], s[i][5]), fmaxf(s[i][6], s[i][7]));
      rmax[i] = fmaxf(rmax[i], fmaxf(m0, m1));
      rsum[i] += ((s[i][0] + s[i][1]) + (s[i][2] + s[i][3])) +
                 ((s[i][4] + s[i][5]) + (s[i][6] + s[i][7]));
    }
    __syncthreads();   // compute done before ring buffer reuse
  }

  const float scale = 0.125f;  // 1/sqrt(64)
#pragma unroll
  for (int i = 0; i < 8; i++) {
    float mx = rmax[i], smv = rsum[i];
#pragma unroll
    for (int o = 8; o; o >>= 1) {
      mx = fmaxf(mx, __shfl_xor_sync(0xffffffffu, mx, o));
      smv += __shfl_xor_sync(0xffffffffu, smv, o);
    }
    if (tx == 0) {
      const int r = ty * 4 + (i & 3) + ((i >> 2) << 6);
      g_spars[(size_t)bh * PL + q0 + r] = scale * mx - scale * smv * (1.0f / PL);
    }
  }
}

// ============================================================
// Exact top-U via radix select on sortable uint32 keys.
// Selects {u > T} plus the lowest-index (U - count_gt) elements == T,
// which is bit-identical to lax.top_k's selected SET (order is
// irrelevant downstream: scatter is per-row).
// One block of 256 threads per (b,h).
// ============================================================
__global__ __launch_bounds__(256) void topk_radix() {
  __shared__ unsigned su[2048];
  __shared__ int hist[256];
  __shared__ unsigned s_pref;
  __shared__ int s_rem;
  __shared__ unsigned eqm[64];
  __shared__ int wpfx[64];
  __shared__ int outcnt;

  const int bh = blockIdx.x;
  const int tid = threadIdx.x;

  for (int t = tid; t < 2048; t += 256) {
    unsigned b = __float_as_uint(g_spars[(size_t)bh * PL + t]);
    su[t] = (b & 0x80000000u) ? ~b : (b | 0x80000000u);
  }
  if (tid == 0) { s_pref = 0u; s_rem = PU; outcnt = 0; }
  if (tid < 64) eqm[tid] = 0u;
  __syncthreads();

  for (int shift = 24; shift >= 0; shift -= 8) {
    hist[tid & 255] = 0;  // 256 threads, one bin each
    __syncthreads();
    const unsigned pref = s_pref;
    for (int t = tid; t < 2048; t += 256) {
      const unsigned u = su[t];
      if (shift == 24 || (u >> (shift + 8)) == pref)
        atomicAdd(&hist[(u >> shift) & 255], 1);
    }
    __syncthreads();
    if (tid == 0) {
      int rem = s_rem, acc = 0;
      for (int b = 255; b >= 0; b--) {
        if (acc + hist[b] >= rem) {
          s_rem = rem - acc;
          s_pref = (s_pref << 8) | (unsigned)b;
          break;
        }
        acc += hist[b];
      }
    }
    __syncthreads();
  }

  const unsigned T = s_pref;
  const int e = s_rem;  // how many ==T to take (lowest indices)

  for (int t = tid; t < 2048; t += 256)
    if (su[t] == T) atomicOr(&eqm[t >> 5], 1u << (t & 31));
  __syncthreads();
  if (tid == 0) {
    int a = 0;
    for (int w = 0; w < 64; w++) { wpfx[w] = a; a += __popc(eqm[w]); }
  }
  __syncthreads();

  for (int t = tid; t < 2048; t += 256) {
    const unsigned u = su[t];
    bool sel = (u > T);
    if (u == T) {
      const int rank = wpfx[t >> 5] + __popc(eqm[t >> 5] & ((1u << (t & 31)) - 1u));
      sel = (rank < e);
    }
    if (sel) {
      const int slot = atomicAdd(&outcnt, 1);
      g_topidx[(size_t)bh * PU + slot] = t;
    }
  }
}

// ============================================================
// Zero the scatter buffer.
// ============================================================
__global__ void zero_attn_kernel() {
  const size_t i = (size_t)blockIdx.x * blockDim.x + threadIdx.x;
  float4 z = {0.f, 0.f, 0.f, 0.f};
  ((float4*)g_attn)[i] = z;
}

// ============================================================
// Flash v3: 128 selected q x 64 k tiles, 8x4 micro-tile, cp.async
// K/V loads (K^T from g_kt, no transpose), register online softmax,
// P staged in a 16B-aligned [128][68] buffer.
// smem: Qs[64][132] + Ks[64][68] + Vs[64][68] + Ps[128][68]
//     = 101KB -> 2 CTAs/SM.
// ============================================================
#define FL_KOFF (64 * 132)
#define FL_VOFF (64 * 132 + 64 * 68)
#define FL_POFF (64 * 132 + 2 * 64 * 68)
#define FLv3_SMEM ((64 * 132 + 2 * 64 * 68 + 128 * 68) * (int)sizeof(float))

__global__ __launch_bounds__(256, 2) void flash_v3() {
  extern __shared__ float sm_fl[];
  float* Qs = sm_fl;             // [64][132]  Q^T (gathered)
  float* Ks = sm_fl + FL_KOFF;   // [64][68]   K^T tile
  float* Vs = sm_fl + FL_VOFF;   // [64][68]   V tile row-major
  float* Ps = sm_fl + FL_POFF;   // [128][68]  probabilities
  __shared__ int qidx[128];

  const int bh = blockIdx.y;
  const int qt = blockIdx.x;
  const int tid = threadIdx.x;
  const int tx = tid & 15, ty = tid >> 4;
  const float scale = 0.125f;

  if (tid < 128) {
    const int u = qt * 128 + tid;
    qidx[tid] = (u < PU) ? g_topidx[(size_t)bh * PU + u] : -1;
  }
  __syncthreads();

  {  // gather + transpose Q (once per CTA)
    const int r = tid >> 1, c0 = (tid & 1) * 32;
    int src = qidx[r];
    if (src < 0) src = 0;
    const float* qrow = g_q + ((size_t)bh * PL + src) * PDH + c0;
#pragma unroll
    for (int c = 0; c < 32; c += 4) {
      float4 v = *(const float4*)(qrow + c);
      Qs[(c0 + c + 0) * 132 + r] = v.x;
      Qs[(c0 + c + 1) * 132 + r] = v.y;
      Qs[(c0 + c + 2) * 132 + r] = v.z;
      Qs[(c0 + c + 3) * 132 + r] = v.w;
    }
  }

  float m_run[8], l_run[8], o[8][4];
#pragma unroll
  for (int i = 0; i < 8; i++) {
    m_run[i] = -1e30f; l_run[i] = 0.f;
#pragma unroll
    for (int j = 0; j < 4; j++) o[i][j] = 0.f;
  }

  const int rr = tid >> 2;            // 0..63
  const int sg = (tid & 3) * 16;      // 0,16,32,48

#pragma unroll 1
  for (int kt = 0; kt < PL / 64; kt++) {
    __syncthreads();  // prev tile fully consumed (PV done); Qs ready (iter 0)
    {
      const float* ksrc = g_kt + ((size_t)bh * PDH + rr) * PL + kt * 64 + sg;
      const float* vsrc = g_v + ((size_t)bh * PL + kt * 64 + rr) * PDH + sg;
      const uint32_t kdst = sptr(&Ks[rr * 68 + sg]);
      const uint32_t vdst = sptr(&Vs[rr * 68 + sg]);
#pragma unroll
      for (int j = 0; j < 4; j++) CP16(kdst + j * 16, ksrc + j * 4);
#pragma unroll
      for (int j = 0; j < 4; j++) CP16(vdst + j * 16, vsrc + j * 4);
      CP_COMMIT();
      CP_WAIT0();
    }
    __syncthreads();

    // S = scale * (Q_sel . K^T), 8x4 in registers
    float s[8][4];
#pragma unroll
    for (int i = 0; i < 8; i++)
#pragma unroll
      for (int j = 0; j < 4; j++) s[i][j] = 0.f;
#pragma unroll 8
    for (int d = 0; d < 64; d++) {
      float av[8], bv[4];
      *(float4*)(av)     = *(const float4*)&Qs[d * 132 + ty * 4];
      *(float4*)(av + 4) = *(const float4*)&Qs[d * 132 + 64 + ty * 4];
      *(float4*)(bv)     = *(const float4*)&Ks[d * 68 + tx * 4];
#pragma unroll
      for (int i = 0; i < 8; i++)
#pragma unroll
        for (int j = 0; j < 4; j++) s[i][j] += av[i] * bv[j];
    }

    // register online softmax (row spans 16 lanes x 4 cols)
#pragma unroll
    for (int i = 0; i < 8; i++) {
      float tm = fmaxf(fmaxf(s[i][0], s[i][1]), fmaxf(s[i][2], s[i][3])) * scale;
#pragma unroll
      for (int off = 8; off; off >>= 1)
        tm = fmaxf(tm, __shfl_xor_sync(0xffffffffu, tm, off));
      const float mn = fmaxf(m_run[i], tm);
      const float alpha = __expf(m_run[i] - mn);
      m_run[i] = mn;
      float ts = 0.f;
#pragma unroll
      for (int j = 0; j < 4; j++) {
        const float pv = __expf(s[i][j] * scale - mn);
        s[i][j] = pv;
        ts += pv;
      }
#pragma unroll
      for (int off = 8; off; off >>= 1)
        ts += __shfl_xor_sync(0xffffffffu, ts, off);
      l_run[i] = l_run[i] * alpha + ts;
#pragma unroll
      for (int j = 0; j < 4; j++) o[i][j] *= alpha;
    }

    // stage P
#pragma unroll
    for (int i = 0; i < 8; i++) {
      const int ri = ty * 4 + (i & 3) + ((i >> 2) << 6);
      float4 pv = {s[i][0], s[i][1], s[i][2], s[i][3]};
      *(float4*)&Ps[ri * 68 + tx * 4] = pv;
    }
    __syncthreads();

    // O += P @ V (thread owns d-cols tx*4..+3)
#pragma unroll 4
    for (int k4 = 0; k4 < 64; k4 += 4) {
      float4 vv0 = *(const float4*)&Vs[(k4 + 0) * 68 + tx * 4];
      float4 vv1 = *(const float4*)&Vs[(k4 + 1) * 68 + tx * 4];
      float4 vv2 = *(const float4*)&Vs[(k4 + 2) * 68 + tx * 4];
      float4 vv3 = *(const float4*)&Vs[(k4 + 3) * 68 + tx * 4];
#pragma unroll
      for (int i = 0; i < 8; i++) {
        const int ri = ty * 4 + (i & 3) + ((i >> 2) << 6);
        float4 pk = *(const float4*)&Ps[ri * 68 + k4];
        o[i][0] += pk.x * vv0.x + pk.y * vv1.x + pk.z * vv2.x + pk.w * vv3.x;
        o[i][1] += pk.x * vv0.y + pk.y * vv1.y + pk.z * vv2.y + pk.w * vv3.y;
        o[i][2] += pk.x * vv0.z + pk.y * vv1.z + pk.z * vv2.z + pk.w * vv3.z;
        o[i][3] += pk.x * vv0.w + pk.y * vv1.w + pk.z * vv2.w + pk.w * vv3.w;
      }
    }
  }

  // scatter: attn[b, l_idx, h*64 + d] = o / l
  const int b = bh >> 4, h = bh & 15;
#pragma unroll
  for (int i = 0; i < 8; i++) {
    const int ri = ty * 4 + (i & 3) + ((i >> 2) << 6);
    const int src = qidx[ri];
    if (src >= 0) {
      const float inv = 1.0f / l_run[i];
      float4 ov = {o[i][0] * inv, o[i][1] * inv, o[i][2] * inv, o[i][3] * inv};
      *(float4*)&g_attn[((size_t)b * PL + src) * PD + h * PDH + tx * 4] = ov;
    }
  }
}

// ============================================================
// host launcher
// ============================================================
extern "C" void kernel_launch(void* const* d_in, const int* in_sizes, int n_in,
                              void* d_out, int out_size) {
  (void)in_sizes; (void)n_in; (void)out_size;
  const float* x  = (const float*)d_in[0];
  const float* Wq = (const float*)d_in[1];
  const float* bq = (const float*)d_in[2];
  const float* Wk = (const float*)d_in[3];
  const float* bk = (const float*)d_in[4];
  const float* Wv = (const float*)d_in[5];
  const float* bv = (const float*)d_in[6];
  const float* Wo = (const float*)d_in[7];
  const float* bo = (const float*)d_in[8];
  float* out = (float*)d_out;

  float *pq, *pk, *pv, *pqt, *pkt, *pattn;
  cudaGetSymbolAddress((void**)&pq, g_q);
  cudaGetSymbolAddress((void**)&pk, g_k);
  cudaGetSymbolAddress((void**)&pv, g_v);
  cudaGetSymbolAddress((void**)&pqt, g_qt);
  cudaGetSymbolAddress((void**)&pkt, g_kt);
  cudaGetSymbolAddress((void**)&pattn, g_attn);

  cudaFuncSetAttribute(sparsity_v3,
                       cudaFuncAttributeMaxDynamicSharedMemorySize, SP_SMEM);
  cudaFuncSetAttribute(flash_v3,
                       cudaFuncAttributeMaxDynamicSharedMemorySize, FLv3_SMEM);

  const dim3 gGemm(PD / 128, (PB * PL) / 128);  // (8, 32)

  // Q/K/V projections into head layout
  sgemm_v2<1><<<gGemm, 256>>>(x, Wq, bq, pq, PB * PL, PD, PD);
  sgemm_v2<1><<<gGemm, 256>>>(x, Wk, bk, pk, PB * PL, PD, PD);
  sgemm_v2<1><<<gGemm, 256>>>(x, Wv, bv, pv, PB * PL, PD, PD);

  // one-time head transposes for streaming kernels
  const dim3 gT(PL / 32, PDH / 32, PBH);
  transpose_head<<<gT, 256>>>(pq, pqt);
  transpose_head<<<gT, 256>>>(pk, pkt);

  // sparsity heuristic over full scores
  sparsity_v3<<<dim3(PL / 128, PBH), 256, SP_SMEM>>>();

  // exact per-(b,h) top-U selection
  topk_radix<<<PBH, 256>>>();

  // zero scatter buffer, then attention on selected rows
  zero_attn_kernel<<<(PB * PL * PD / 4) / 256, 256>>>();
  flash_v3<<<dim3((PU + 127) / 128, PBH), 256, FLv3_SMEM>>>();

  // output projection
  sgemm_v2<0><<<gGemm, 256>>>(pattn, Wo, bo, out, PB * PL, PD, PD);
}

// round 7
// speedup vs baseline: 1.3911x; 1.0871x over previous
#include <cuda_runtime.h>
#include <cstdint>

// ---------------- problem constants ----------------
#define PB 2
#define PL 2048
#define PD 1024
#define PH 16
#define PDH 64
#define PU 1228          // int(0.6 * 2048)
#define PBH (PB * PH)    // 32

// ---------------- device scratch (no allocation allowed) ----------------
__device__ float g_q [(size_t)PBH * PL * PDH];   // [b,h,l,dh]
__device__ float g_k [(size_t)PBH * PL * PDH];   // [b,h,l,dh]
__device__ float g_v [(size_t)PBH * PL * PDH];   // [b,h,l,dh]
__device__ float g_kt[(size_t)PBH * PDH * PL];   // [b,h,dh,l]
__device__ float g_spars[(size_t)PBH * PL];
__device__ int   g_topidx[(size_t)PBH * PU];
__device__ float g_attn[(size_t)PB * PL * PD];   // pre-output-proj, [b,l,d]

// ---------------- cp.async helpers ----------------
#define CP16(dst_u32, src_ptr) \
  asm volatile("cp.async.cg.shared.global [%0], [%1], 16;\n" :: "r"(dst_u32), "l"(src_ptr))
#define CP_COMMIT() asm volatile("cp.async.commit_group;\n" ::)
#define CP_WAIT0()  asm volatile("cp.async.wait_group 0;\n" ::)
#define CP_WAIT1()  asm volatile("cp.async.wait_group 1;\n" ::)

static __device__ __forceinline__ uint32_t sptr(const void* p) {
  return (uint32_t)__cvta_generic_to_shared(p);
}

// ---------------- tf32 mma helpers ----------------
static __device__ __forceinline__ void split_tf32(float x, uint32_t& hi, uint32_t& lo) {
  uint32_t h;
  asm("cvt.rna.tf32.f32 %0, %1;" : "=r"(h) : "f"(x));
  float r = x - __uint_as_float(h);
  uint32_t l;
  asm("cvt.rna.tf32.f32 %0, %1;" : "=r"(l) : "f"(r));
  hi = h; lo = l;
}

static __device__ __forceinline__ void mma_tf32(
    float* c, uint32_t a0, uint32_t a1, uint32_t a2, uint32_t a3,
    uint32_t b0, uint32_t b1) {
  asm volatile(
      "mma.sync.aligned.m16n8k8.row.col.f32.tf32.tf32.f32 "
      "{%0,%1,%2,%3}, {%4,%5,%6,%7}, {%8,%9}, {%0,%1,%2,%3};"
      : "+f"(c[0]), "+f"(c[1]), "+f"(c[2]), "+f"(c[3])
      : "r"(a0), "r"(a1), "r"(a2), "r"(a3), "r"(b0), "r"(b1));
}

// ============================================================
// tf32x3 GEMM: C[M,N] = A[M,K] @ Bm[K,N] + bias[N]
// 128x128x16 tiles, 8 warps (4x2), mma.m16n8k8, 3xTF32 split.
// cp.async double-buffered panels. Requires M%128==0,N%128==0,K%16==0.
// MODE 0: row-major C.  MODE 1: [b,h,l,dh] head layout.
// ============================================================
#define GM_AS 20    // A smem row stride (floats)
#define GM_BS 136   // B smem row stride (floats)

template<int MODE>
__global__ __launch_bounds__(256) void gemm_tf32x3(
    const float* __restrict__ A, const float* __restrict__ Bm,
    const float* __restrict__ bias, float* __restrict__ C,
    int M, int N, int K) {
  __shared__ float As[2][128 * GM_AS];
  __shared__ float Bs[2][16 * GM_BS];

  const int tid = threadIdx.x;
  const int warp = tid >> 5, lane = tid & 31;
  const int gid = lane >> 2, tig = lane & 3;
  const int wm = warp >> 1, wn = warp & 1;   // 4x2 warp grid
  const int bm = blockIdx.y * 128, bn = blockIdx.x * 128;

  // cp.async assignments
  const int ar = tid >> 1, ak = (tid & 1) * 8;   // A: 2 thr/row, 8 floats each
  const int br = tid >> 4, bc = (tid & 15) * 8;  // B: 16 thr/row, 8 floats each

  const float* Agp = A + (size_t)(bm + ar) * K + ak;
  const float* Bgp = Bm + (size_t)br * N + bn + bc;

  float c[2][8][4];
#pragma unroll
  for (int mb = 0; mb < 2; mb++)
#pragma unroll
    for (int nb = 0; nb < 8; nb++)
#pragma unroll
      for (int j = 0; j < 4; j++) c[mb][nb][j] = 0.f;

  const int NP = K >> 4;

  {  // panel 0
    const uint32_t ad = sptr(&As[0][ar * GM_AS + ak]);
    CP16(ad, Agp); CP16(ad + 16, Agp + 4);
    const uint32_t bd = sptr(&Bs[0][br * GM_BS + bc]);
    CP16(bd, Bgp); CP16(bd + 16, Bgp + 4);
    CP_COMMIT();
  }

#pragma unroll 1
  for (int p = 0; p < NP; p++) {
    const int buf = p & 1;
    if (p + 1 < NP) {
      const float* a2 = Agp + (p + 1) * 16;
      const float* b2 = Bgp + (size_t)(p + 1) * 16 * N;
      const uint32_t ad = sptr(&As[buf ^ 1][ar * GM_AS + ak]);
      CP16(ad, a2); CP16(ad + 16, a2 + 4);
      const uint32_t bd = sptr(&Bs[buf ^ 1][br * GM_BS + bc]);
      CP16(bd, b2); CP16(bd + 16, b2 + 4);
      CP_COMMIT();
      CP_WAIT1();
    } else {
      CP_WAIT0();
    }
    __syncthreads();

    const float* Ab = As[buf];
    const float* Bb = Bs[buf];
#pragma unroll
    for (int ks = 0; ks < 2; ks++) {
      const int k0 = ks * 8;
      uint32_t ahi[2][4], alo[2][4];
#pragma unroll
      for (int mb = 0; mb < 2; mb++) {
        const int r = wm * 32 + mb * 16;
        split_tf32(Ab[(r + gid)     * GM_AS + k0 + tig],     ahi[mb][0], alo[mb][0]);
        split_tf32(Ab[(r + gid + 8) * GM_AS + k0 + tig],     ahi[mb][1], alo[mb][1]);
        split_tf32(Ab[(r + gid)     * GM_AS + k0 + tig + 4], ahi[mb][2], alo[mb][2]);
        split_tf32(Ab[(r + gid + 8) * GM_AS + k0 + tig + 4], ahi[mb][3], alo[mb][3]);
      }
#pragma unroll
      for (int nb = 0; nb < 8; nb++) {
        const int n = wn * 64 + nb * 8 + gid;
        uint32_t bh0, bl0, bh1, bl1;
        split_tf32(Bb[(k0 + tig)     * GM_BS + n], bh0, bl0);
        split_tf32(Bb[(k0 + tig + 4) * GM_BS + n], bh1, bl1);
#pragma unroll
        for (int mb = 0; mb < 2; mb++) {
          mma_tf32(c[mb][nb], ahi[mb][0], ahi[mb][1], ahi[mb][2], ahi[mb][3], bh0, bh1);
          mma_tf32(c[mb][nb], ahi[mb][0], ahi[mb][1], ahi[mb][2], ahi[mb][3], bl0, bl1);
          mma_tf32(c[mb][nb], alo[mb][0], alo[mb][1], alo[mb][2], alo[mb][3], bh0, bh1);
        }
      }
    }
    __syncthreads();
  }

  // epilogue: each (mb,nb) fragment -> rows (gid, gid+8), cols (2tig, 2tig+1)
#pragma unroll
  for (int mb = 0; mb < 2; mb++) {
#pragma unroll
    for (int nb = 0; nb < 8; nb++) {
      const int m0 = bm + wm * 32 + mb * 16 + gid;
      const int n0 = bn + wn * 64 + nb * 8 + tig * 2;
      const float bx = bias[n0], by = bias[n0 + 1];
      float2 v0 = {c[mb][nb][0] + bx, c[mb][nb][1] + by};
      float2 v1 = {c[mb][nb][2] + bx, c[mb][nb][3] + by};
      if (MODE == 0) {
        *(float2*)&C[(size_t)m0 * N + n0] = v0;
        *(float2*)&C[(size_t)(m0 + 8) * N + n0] = v1;
      } else {
        const int h = n0 >> 6, dh = n0 & 63;
        const int b0i = m0 >> 11, l0 = m0 & (PL - 1);
        const int b1i = (m0 + 8) >> 11, l1 = (m0 + 8) & (PL - 1);
        *(float2*)&g_attn[0] = *(float2*)&g_attn[0];  // no-op guard (never taken path removed)
        *(float2*)&C[(((size_t)b0i * PH + h) * PL + l0) * PDH + dh] = v0;
        *(float2*)&C[(((size_t)b1i * PH + h) * PL + l1) * PDH + dh] = v1;
      }
    }
  }
}

// ============================================================
// Head-layout transpose: [bh][l][dh] -> [bh][dh][l], 32x32 tiles.
// ============================================================
__global__ __launch_bounds__(256) void transpose_head(
    const float* __restrict__ in, float* __restrict__ out) {
  __shared__ float t[32][33];
  const int bh = blockIdx.z;
  const int l0 = blockIdx.x * 32, d0 = blockIdx.y * 32;
  const int x = threadIdx.x & 31, y = threadIdx.x >> 5;
  const float* ip = in + (size_t)bh * PL * PDH;
#pragma unroll
  for (int k = 0; k < 4; k++)
    t[y + 8 * k][x] = ip[(size_t)(l0 + y + 8 * k) * PDH + d0 + x];
  __syncthreads();
  float* op = out + (size_t)bh * PDH * PL;
#pragma unroll
  for (int k = 0; k < 4; k++)
    op[(size_t)(d0 + y + 8 * k) * PL + l0 + x] = t[x][y + 8 * k];
}

// ============================================================
// Sparsity v4 (tensor cores, tf32x3):
// per (b,h,row): scale*max_k(q.k) - scale*mean_k(q.k)
// CTA = 128 q-rows x one bh; 8 warps, each warp 16 rows x 128 keys.
// A = Q rows (row-major from g_q), B = K^T (from g_kt), streamed in
// 128-key tiles, cp.async double-buffered. C frags reduced per tile.
// ============================================================
#define SPQ_S 68
#define SPK_S 136
#define SP_SMEM ((128 * SPQ_S + 2 * 64 * SPK_S) * (int)sizeof(float))

__global__ __launch_bounds__(256, 2) void sparsity_v4() {
  extern __shared__ float sm[];
  float* Qs = sm;                    // [128][68]
  float* Ks = sm + 128 * SPQ_S;      // [2][64][136]

  const int bh = blockIdx.y;
  const int q0 = blockIdx.x * 128;
  const int tid = threadIdx.x;
  const int warp = tid >> 5, lane = tid & 31;
  const int gid = lane >> 2, tig = lane & 3;

  // cp.async assignments
  const int qr = tid >> 1, qc = (tid & 1) * 32;   // Q: 2 thr/row, 32 floats
  const int kr = tid >> 2, kc = (tid & 3) * 32;   // K^T: 4 thr/row, 32 floats

  {  // Q tile + K tile 0
    const float* qsrc = g_q + ((size_t)bh * PL + q0 + qr) * PDH + qc;
    const uint32_t qd = sptr(&Qs[qr * SPQ_S + qc]);
#pragma unroll
    for (int j = 0; j < 8; j++) CP16(qd + j * 16, qsrc + j * 4);
    const float* ksrc = g_kt + ((size_t)bh * PDH + kr) * PL + kc;
    const uint32_t kd = sptr(&Ks[kr * SPK_S + kc]);
#pragma unroll
    for (int j = 0; j < 8; j++) CP16(kd + j * 16, ksrc + j * 4);
    CP_COMMIT();
  }

  float c[16][4];
#pragma unroll
  for (int nb = 0; nb < 16; nb++)
#pragma unroll
    for (int j = 0; j < 4; j++) c[nb][j] = 0.f;

  float rmax0 = -1e30f, rsum0 = 0.f, rmax1 = -1e30f, rsum1 = 0.f;

#pragma unroll 1
  for (int kt = 0; kt < PL / 128; kt++) {
    if (kt + 1 < PL / 128) {
      const float* ksrc = g_kt + ((size_t)bh * PDH + kr) * PL + (kt + 1) * 128 + kc;
      const uint32_t kd = sptr(&Ks[((kt + 1) & 1) * 64 * SPK_S + kr * SPK_S + kc]);
#pragma unroll
      for (int j = 0; j < 8; j++) CP16(kd + j * 16, ksrc + j * 4);
      CP_COMMIT();
      CP_WAIT1();
    } else {
      CP_WAIT0();
    }
    __syncthreads();

    const float* Kb = Ks + (kt & 1) * 64 * SPK_S;
    const int rbase = warp * 16;

#pragma unroll
    for (int ks = 0; ks < 8; ks++) {
      const int k0 = ks * 8;
      uint32_t ahi[4], alo[4];
      split_tf32(Qs[(rbase + gid)     * SPQ_S + k0 + tig],     ahi[0], alo[0]);
      split_tf32(Qs[(rbase + gid + 8) * SPQ_S + k0 + tig],     ahi[1], alo[1]);
      split_tf32(Qs[(rbase + gid)     * SPQ_S + k0 + tig + 4], ahi[2], alo[2]);
      split_tf32(Qs[(rbase + gid + 8) * SPQ_S + k0 + tig + 4], ahi[3], alo[3]);
#pragma unroll
      for (int nb = 0; nb < 16; nb++) {
        const int n = nb * 8 + gid;
        uint32_t bh0, bl0, bh1, bl1;
        split_tf32(Kb[(k0 + tig)     * SPK_S + n], bh0, bl0);
        split_tf32(Kb[(k0 + tig + 4) * SPK_S + n], bh1, bl1);
        mma_tf32(c[nb], ahi[0], ahi[1], ahi[2], ahi[3], bh0, bh1);
        mma_tf32(c[nb], ahi[0], ahi[1], ahi[2], ahi[3], bl0, bl1);
        mma_tf32(c[nb], alo[0], alo[1], alo[2], alo[3], bh0, bh1);
      }
    }

    // reduce this tile's 128 columns into running row stats, zero C
    float mx0 = -1e30f, sm0 = 0.f, mx1 = -1e30f, sm1 = 0.f;
#pragma unroll
    for (int nb = 0; nb < 16; nb++) {
      mx0 = fmaxf(mx0, fmaxf(c[nb][0], c[nb][1]));
      sm0 += c[nb][0] + c[nb][1];
      mx1 = fmaxf(mx1, fmaxf(c[nb][2], c[nb][3]));
      sm1 += c[nb][2] + c[nb][3];
#pragma unroll
      for (int j = 0; j < 4; j++) c[nb][j] = 0.f;
    }
#pragma unroll
    for (int off = 1; off <= 2; off <<= 1) {
      mx0 = fmaxf(mx0, __shfl_xor_sync(0xffffffffu, mx0, off));
      sm0 += __shfl_xor_sync(0xffffffffu, sm0, off);
      mx1 = fmaxf(mx1, __shfl_xor_sync(0xffffffffu, mx1, off));
      sm1 += __shfl_xor_sync(0xffffffffu, sm1, off);
    }
    rmax0 = fmaxf(rmax0, mx0); rsum0 += sm0;
    rmax1 = fmaxf(rmax1, mx1); rsum1 += sm1;
    __syncthreads();
  }

  const float scale = 0.125f;  // 1/sqrt(64)
  if (tig == 0) {
    const int r0 = q0 + warp * 16 + gid;
    g_spars[(size_t)bh * PL + r0]     = scale * rmax0 - scale * rsum0 * (1.0f / PL);
    g_spars[(size_t)bh * PL + r0 + 8] = scale * rmax1 - scale * rsum1 * (1.0f / PL);
  }
}

// ============================================================
// Exact top-U via radix select (unchanged from R5).
// ============================================================
__global__ __launch_bounds__(256) void topk_radix() {
  __shared__ unsigned su[2048];
  __shared__ int hist[256];
  __shared__ unsigned s_pref;
  __shared__ int s_rem;
  __shared__ unsigned eqm[64];
  __shared__ int wpfx[64];
  __shared__ int outcnt;

  const int bh = blockIdx.x;
  const int tid = threadIdx.x;

  for (int t = tid; t < 2048; t += 256) {
    unsigned b = __float_as_uint(g_spars[(size_t)bh * PL + t]);
    su[t] = (b & 0x80000000u) ? ~b : (b | 0x80000000u);
  }
  if (tid == 0) { s_pref = 0u; s_rem = PU; outcnt = 0; }
  if (tid < 64) eqm[tid] = 0u;
  __syncthreads();

  for (int shift = 24; shift >= 0; shift -= 8) {
    hist[tid & 255] = 0;
    __syncthreads();
    const unsigned pref = s_pref;
    for (int t = tid; t < 2048; t += 256) {
      const unsigned u = su[t];
      if (shift == 24 || (u >> (shift + 8)) == pref)
        atomicAdd(&hist[(u >> shift) & 255], 1);
    }
    __syncthreads();
    if (tid == 0) {
      int rem = s_rem, acc = 0;
      for (int b = 255; b >= 0; b--) {
        if (acc + hist[b] >= rem) {
          s_rem = rem - acc;
          s_pref = (s_pref << 8) | (unsigned)b;
          break;
        }
        acc += hist[b];
      }
    }
    __syncthreads();
  }

  const unsigned T = s_pref;
  const int e = s_rem;

  for (int t = tid; t < 2048; t += 256)
    if (su[t] == T) atomicOr(&eqm[t >> 5], 1u << (t & 31));
  __syncthreads();
  if (tid == 0) {
    int a = 0;
    for (int w = 0; w < 64; w++) { wpfx[w] = a; a += __popc(eqm[w]); }
  }
  __syncthreads();

  for (int t = tid; t < 2048; t += 256) {
    const unsigned u = su[t];
    bool sel = (u > T);
    if (u == T) {
      const int rank = wpfx[t >> 5] + __popc(eqm[t >> 5] & ((1u << (t & 31)) - 1u));
      sel = (rank < e);
    }
    if (sel) {
      const int slot = atomicAdd(&outcnt, 1);
      g_topidx[(size_t)bh * PU + slot] = t;
    }
  }
}

// ============================================================
// Zero the scatter buffer.
// ============================================================
__global__ void zero_attn_kernel() {
  const size_t i = (size_t)blockIdx.x * blockDim.x + threadIdx.x;
  float4 z = {0.f, 0.f, 0.f, 0.f};
  ((float4*)g_attn)[i] = z;
}

// ============================================================
// Flash v3 (unchanged from R5): 128 sel q x 64 k tiles, fp32.
// ============================================================
#define FL_KOFF (64 * 132)
#define FL_VOFF (64 * 132 + 64 * 68)
#define FL_POFF (64 * 132 + 2 * 64 * 68)
#define FLv3_SMEM ((64 * 132 + 2 * 64 * 68 + 128 * 68) * (int)sizeof(float))

__global__ __launch_bounds__(256, 2) void flash_v3() {
  extern __shared__ float sm_fl[];
  float* Qs = sm_fl;
  float* Ks = sm_fl + FL_KOFF;
  float* Vs = sm_fl + FL_VOFF;
  float* Ps = sm_fl + FL_POFF;
  __shared__ int qidx[128];

  const int bh = blockIdx.y;
  const int qt = blockIdx.x;
  const int tid = threadIdx.x;
  const int tx = tid & 15, ty = tid >> 4;
  const float scale = 0.125f;

  if (tid < 128) {
    const int u = qt * 128 + tid;
    qidx[tid] = (u < PU) ? g_topidx[(size_t)bh * PU + u] : -1;
  }
  __syncthreads();

  {
    const int r = tid >> 1, c0 = (tid & 1) * 32;
    int src = qidx[r];
    if (src < 0) src = 0;
    const float* qrow = g_q + ((size_t)bh * PL + src) * PDH + c0;
#pragma unroll
    for (int c = 0; c < 32; c += 4) {
      float4 v = *(const float4*)(qrow + c);
      Qs[(c0 + c + 0) * 132 + r] = v.x;
      Qs[(c0 + c + 1) * 132 + r] = v.y;
      Qs[(c0 + c + 2) * 132 + r] = v.z;
      Qs[(c0 + c + 3) * 132 + r] = v.w;
    }
  }

  float m_run[8], l_run[8], o[8][4];
#pragma unroll
  for (int i = 0; i < 8; i++) {
    m_run[i] = -1e30f; l_run[i] = 0.f;
#pragma unroll
    for (int j = 0; j < 4; j++) o[i][j] = 0.f;
  }

  const int rr = tid >> 2;
  const int sg = (tid & 3) * 16;

#pragma unroll 1
  for (int kt = 0; kt < PL / 64; kt++) {
    __syncthreads();
    {
      const float* ksrc = g_kt + ((size_t)bh * PDH + rr) * PL + kt * 64 + sg;
      const float* vsrc = g_v + ((size_t)bh * PL + kt * 64 + rr) * PDH + sg;
      const uint32_t kdst = sptr(&Ks[rr * 68 + sg]);
      const uint32_t vdst = sptr(&Vs[rr * 68 + sg]);
#pragma unroll
      for (int j = 0; j < 4; j++) CP16(kdst + j * 16, ksrc + j * 4);
#pragma unroll
      for (int j = 0; j < 4; j++) CP16(vdst + j * 16, vsrc + j * 4);
      CP_COMMIT();
      CP_WAIT0();
    }
    __syncthreads();

    float s[8][4];
#pragma unroll
    for (int i = 0; i < 8; i++)
#pragma unroll
      for (int j = 0; j < 4; j++) s[i][j] = 0.f;
#pragma unroll 8
    for (int d = 0; d < 64; d++) {
      float av[8], bv[4];
      *(float4*)(av)     = *(const float4*)&Qs[d * 132 + ty * 4];
      *(float4*)(av + 4) = *(const float4*)&Qs[d * 132 + 64 + ty * 4];
      *(float4*)(bv)     = *(const float4*)&Ks[d * 68 + tx * 4];
#pragma unroll
      for (int i = 0; i < 8; i++)
#pragma unroll
        for (int j = 0; j < 4; j++) s[i][j] += av[i] * bv[j];
    }

#pragma unroll
    for (int i = 0; i < 8; i++) {
      float tm = fmaxf(fmaxf(s[i][0], s[i][1]), fmaxf(s[i][2], s[i][3])) * scale;
#pragma unroll
      for (int off = 8; off; off >>= 1)
        tm = fmaxf(tm, __shfl_xor_sync(0xffffffffu, tm, off));
      const float mn = fmaxf(m_run[i], tm);
      const float alpha = __expf(m_run[i] - mn);
      m_run[i] = mn;
      float ts = 0.f;
#pragma unroll
      for (int j = 0; j < 4; j++) {
        const float pv = __expf(s[i][j] * scale - mn);
        s[i][j] = pv;
        ts += pv;
      }
#pragma unroll
      for (int off = 8; off; off >>= 1)
        ts += __shfl_xor_sync(0xffffffffu, ts, off);
      l_run[i] = l_run[i] * alpha + ts;
#pragma unroll
      for (int j = 0; j < 4; j++) o[i][j] *= alpha;
    }

#pragma unroll
    for (int i = 0; i < 8; i++) {
      const int ri = ty * 4 + (i & 3) + ((i >> 2) << 6);
      float4 pv = {s[i][0], s[i][1], s[i][2], s[i][3]};
      *(float4*)&Ps[ri * 68 + tx * 4] = pv;
    }
    __syncthreads();

#pragma unroll 4
    for (int k4 = 0; k4 < 64; k4 += 4) {
      float4 vv0 = *(const float4*)&Vs[(k4 + 0) * 68 + tx * 4];
      float4 vv1 = *(const float4*)&Vs[(k4 + 1) * 68 + tx * 4];
      float4 vv2 = *(const float4*)&Vs[(k4 + 2) * 68 + tx * 4];
      float4 vv3 = *(const float4*)&Vs[(k4 + 3) * 68 + tx * 4];
#pragma unroll
      for (int i = 0; i < 8; i++) {
        const int ri = ty * 4 + (i & 3) + ((i >> 2) << 6);
        float4 pk = *(const float4*)&Ps[ri * 68 + k4];
        o[i][0] += pk.x * vv0.x + pk.y * vv1.x + pk.z * vv2.x + pk.w * vv3.x;
        o[i][1] += pk.x * vv0.y + pk.y * vv1.y + pk.z * vv2.y + pk.w * vv3.y;
        o[i][2] += pk.x * vv0.z + pk.y * vv1.z + pk.z * vv2.z + pk.w * vv3.z;
        o[i][3] += pk.x * vv0.w + pk.y * vv1.w + pk.z * vv2.w + pk.w * vv3.w;
      }
    }
  }

  const int b = bh >> 4, h = bh & 15;
#pragma unroll
  for (int i = 0; i < 8; i++) {
    const int ri = ty * 4 + (i & 3) + ((i >> 2) << 6);
    const int src = qidx[ri];
    if (src >= 0) {
      const float inv = 1.0f / l_run[i];
      float4 ov = {o[i][0] * inv, o[i][1] * inv, o[i][2] * inv, o[i][3] * inv};
      *(float4*)&g_attn[((size_t)b * PL + src) * PD + h * PDH + tx * 4] = ov;
    }
  }
}

// ============================================================
// host launcher
// ============================================================
extern "C" void kernel_launch(void* const* d_in, const int* in_sizes, int n_in,
                              void* d_out, int out_size) {
  (void)in_sizes; (void)n_in; (void)out_size;
  const float* x  = (const float*)d_in[0];
  const float* Wq = (const float*)d_in[1];
  const float* bq = (const float*)d_in[2];
  const float* Wk = (const float*)d_in[3];
  const float* bk = (const float*)d_in[4];
  const float* Wv = (const float*)d_in[5];
  const float* bv = (const float*)d_in[6];
  const float* Wo = (const float*)d_in[7];
  const float* bo = (const float*)d_in[8];
  float* out = (float*)d_out;

  float *pq, *pk, *pv, *pkt, *pattn;
  cudaGetSymbolAddress((void**)&pq, g_q);
  cudaGetSymbolAddress((void**)&pk, g_k);
  cudaGetSymbolAddress((void**)&pv, g_v);
  cudaGetSymbolAddress((void**)&pkt, g_kt);
  cudaGetSymbolAddress((void**)&pattn, g_attn);

  cudaFuncSetAttribute(sparsity_v4,
                       cudaFuncAttributeMaxDynamicSharedMemorySize, SP_SMEM);
  cudaFuncSetAttribute(flash_v3,
                       cudaFuncAttributeMaxDynamicSharedMemorySize, FLv3_SMEM);

  const dim3 gGemm(PD / 128, (PB * PL) / 128);  // (8, 32)

  // Q/K/V projections into head layout (tensor cores, tf32x3)
  gemm_tf32x3<1><<<gGemm, 256>>>(x, Wq, bq, pq, PB * PL, PD, PD);
  gemm_tf32x3<1><<<gGemm, 256>>>(x, Wk, bk, pk, PB * PL, PD, PD);
  gemm_tf32x3<1><<<gGemm, 256>>>(x, Wv, bv, pv, PB * PL, PD, PD);

  // one-time K transpose for sparsity/flash streaming
  const dim3 gT(PL / 32, PDH / 32, PBH);
  transpose_head<<<gT, 256>>>(pk, pkt);

  // sparsity heuristic over full scores (tensor cores, tf32x3)
  sparsity_v4<<<dim3(PL / 128, PBH), 256, SP_SMEM>>>();

  // exact per-(b,h) top-U selection
  topk_radix<<<PBH, 256>>>();

  // zero scatter buffer, then attention on selected rows
  zero_attn_kernel<<<(PB * PL * PD / 4) / 256, 256>>>();
  flash_v3<<<dim3((PU + 127) / 128, PBH), 256, FLv3_SMEM>>>();

  // output projection (tensor cores, tf32x3)
  gemm_tf32x3<0><<<gGemm, 256>>>(pattn, Wo, bo, out, PB * PL, PD, PD);
}

// round 8
// speedup vs baseline: 1.3969x; 1.0042x over previous
#include <cuda_runtime.h>
#include <cstdint>

// ---------------- problem constants ----------------
#define PB 2
#define PL 2048
#define PD 1024
#define PH 16
#define PDH 64
#define PU 1228          // int(0.6 * 2048)
#define PBH (PB * PH)    // 32

// ---------------- device scratch (no allocation allowed) ----------------
__device__ float g_q [(size_t)PBH * PL * PDH];   // [b,h,l,dh]
__device__ float g_k [(size_t)PBH * PL * PDH];   // [b,h,l,dh]
__device__ float g_v [(size_t)PBH * PL * PDH];   // [b,h,l,dh]
__device__ float g_kt[(size_t)PBH * PDH * PL];   // [b,h,dh,l] fp32 (flash)
__device__ uint32_t g_kthi[(size_t)PBH * PDH * PL];  // tf32 hi
__device__ uint32_t g_ktlo[(size_t)PBH * PDH * PL];  // tf32 lo
__device__ uint32_t g_whi[(size_t)4 * PD * PD];  // Wq,Wk,Wv,Wo pre-split hi
__device__ uint32_t g_wlo[(size_t)4 * PD * PD];  // pre-split lo
__device__ float g_spars[(size_t)PBH * PL];
__device__ int   g_topidx[(size_t)PBH * PU];
__device__ float g_attn[(size_t)PB * PL * PD];   // pre-output-proj, [b,l,d]

// ---------------- cp.async helpers ----------------
#define CP16(dst_u32, src_ptr) \
  asm volatile("cp.async.cg.shared.global [%0], [%1], 16;\n" :: "r"(dst_u32), "l"(src_ptr))
#define CP_COMMIT() asm volatile("cp.async.commit_group;\n" ::)
#define CP_WAIT0()  asm volatile("cp.async.wait_group 0;\n" ::)
#define CP_WAIT1()  asm volatile("cp.async.wait_group 1;\n" ::)

static __device__ __forceinline__ uint32_t sptr(const void* p) {
  return (uint32_t)__cvta_generic_to_shared(p);
}

// ---------------- tf32 helpers ----------------
static __device__ __forceinline__ void split_tf32(float x, uint32_t& hi, uint32_t& lo) {
  uint32_t h;
  asm("cvt.rna.tf32.f32 %0, %1;" : "=r"(h) : "f"(x));
  float r = x - __uint_as_float(h);
  uint32_t l;
  asm("cvt.rna.tf32.f32 %0, %1;" : "=r"(l) : "f"(r));
  hi = h; lo = l;
}

static __device__ __forceinline__ void mma_tf32(
    float* c, uint32_t a0, uint32_t a1, uint32_t a2, uint32_t a3,
    uint32_t b0, uint32_t b1) {
  asm volatile(
      "mma.sync.aligned.m16n8k8.row.col.f32.tf32.tf32.f32 "
      "{%0,%1,%2,%3}, {%4,%5,%6,%7}, {%8,%9}, {%0,%1,%2,%3};"
      : "+f"(c[0]), "+f"(c[1]), "+f"(c[2]), "+f"(c[3])
      : "r"(a0), "r"(a1), "r"(a2), "r"(a3), "r"(b0), "r"(b1));
}

// ============================================================
// Pre-split a float array into tf32 hi/lo u32 arrays.
// ============================================================
__global__ __launch_bounds__(256) void split_kernel(
    const float* __restrict__ in, uint32_t* __restrict__ hi,
    uint32_t* __restrict__ lo, int n4) {
  const int i = blockIdx.x * 256 + threadIdx.x;
  if (i >= n4) return;
  float4 v = ((const float4*)in)[i];
  uint4 h, l;
  split_tf32(v.x, h.x, l.x);
  split_tf32(v.y, h.y, l.y);
  split_tf32(v.z, h.z, l.z);
  split_tf32(v.w, h.w, l.w);
  ((uint4*)hi)[i] = h;
  ((uint4*)lo)[i] = l;
}

// ============================================================
// tf32x3 GEMM v2: C[M,N] = A[M,K] @ W[K,N] + bias[N]
// W pre-split into hi/lo (u32). A split in-kernel.
// 128x128x16 tiles, 8 warps (4x2), cp.async double-buffered.
// MODE 0: row-major C.  MODE 1: [b,h,l,dh] head layout.
// ============================================================
#define GM_AS 20    // A smem row stride (floats)
#define GM_BS 136   // B smem row stride (u32)
#define GEMM_SMEM ((2 * 128 * GM_AS + 2 * 2 * 16 * GM_BS) * 4)

template<int MODE>
__global__ __launch_bounds__(256, 2) void gemm_tf32x3(
    const float* __restrict__ A, const uint32_t* __restrict__ Whi,
    const uint32_t* __restrict__ Wlo, const float* __restrict__ bias,
    float* __restrict__ C, int M, int N, int K) {
  extern __shared__ float smg[];
  float* As = smg;                                        // [2][128*20]
  uint32_t* Bh = (uint32_t*)(smg + 2 * 128 * GM_AS);      // [2][16*136]
  uint32_t* Bl = Bh + 2 * 16 * GM_BS;                     // [2][16*136]

  const int tid = threadIdx.x;
  const int warp = tid >> 5, lane = tid & 31;
  const int gid = lane >> 2, tig = lane & 3;
  const int wm = warp >> 1, wn = warp & 1;   // 4x2 warp grid
  const int bm = blockIdx.y * 128, bn = blockIdx.x * 128;

  const int ar = tid >> 1, ak = (tid & 1) * 8;   // A: 2 thr/row
  const int br = tid >> 4, bc = (tid & 15) * 8;  // B: 16 thr/row

  const float* Agp = A + (size_t)(bm + ar) * K + ak;
  const uint32_t* Bhp = Whi + (size_t)br * N + bn + bc;
  const uint32_t* Blp = Wlo + (size_t)br * N + bn + bc;

  float c[2][8][4];
#pragma unroll
  for (int mb = 0; mb < 2; mb++)
#pragma unroll
    for (int nb = 0; nb < 8; nb++)
#pragma unroll
      for (int j = 0; j < 4; j++) c[mb][nb][j] = 0.f;

  const int NP = K >> 4;

  {  // panel 0
    const uint32_t ad = sptr(&As[ar * GM_AS + ak]);
    CP16(ad, Agp); CP16(ad + 16, Agp + 4);
    const uint32_t bhd = sptr(&Bh[br * GM_BS + bc]);
    CP16(bhd, Bhp); CP16(bhd + 16, Bhp + 4);
    const uint32_t bld = sptr(&Bl[br * GM_BS + bc]);
    CP16(bld, Blp); CP16(bld + 16, Blp + 4);
    CP_COMMIT();
  }

#pragma unroll 1
  for (int p = 0; p < NP; p++) {
    const int buf = p & 1;
    if (p + 1 < NP) {
      const int nb2 = (buf ^ 1);
      const float* a2 = Agp + (p + 1) * 16;
      const uint32_t ad = sptr(&As[nb2 * 128 * GM_AS + ar * GM_AS + ak]);
      CP16(ad, a2); CP16(ad + 16, a2 + 4);
      const uint32_t* bh2 = Bhp + (size_t)(p + 1) * 16 * N;
      const uint32_t* bl2 = Blp + (size_t)(p + 1) * 16 * N;
      const uint32_t bhd = sptr(&Bh[nb2 * 16 * GM_BS + br * GM_BS + bc]);
      CP16(bhd, bh2); CP16(bhd + 16, bh2 + 4);
      const uint32_t bld = sptr(&Bl[nb2 * 16 * GM_BS + br * GM_BS + bc]);
      CP16(bld, bl2); CP16(bld + 16, bl2 + 4);
      CP_COMMIT();
      CP_WAIT1();
    } else {
      CP_WAIT0();
    }
    __syncthreads();

    const float* Ab = As + buf * 128 * GM_AS;
    const uint32_t* Bhb = Bh + buf * 16 * GM_BS;
    const uint32_t* Blb = Bl + buf * 16 * GM_BS;
#pragma unroll
    for (int ks = 0; ks < 2; ks++) {
      const int k0 = ks * 8;
      uint32_t ahi[2][4], alo[2][4];
#pragma unroll
      for (int mb = 0; mb < 2; mb++) {
        const int r = wm * 32 + mb * 16;
        split_tf32(Ab[(r + gid)     * GM_AS + k0 + tig],     ahi[mb][0], alo[mb][0]);
        split_tf32(Ab[(r + gid + 8) * GM_AS + k0 + tig],     ahi[mb][1], alo[mb][1]);
        split_tf32(Ab[(r + gid)     * GM_AS + k0 + tig + 4], ahi[mb][2], alo[mb][2]);
        split_tf32(Ab[(r + gid + 8) * GM_AS + k0 + tig + 4], ahi[mb][3], alo[mb][3]);
      }
#pragma unroll
      for (int nb = 0; nb < 8; nb++) {
        const int n = wn * 64 + nb * 8 + gid;
        const uint32_t bh0 = Bhb[(k0 + tig)     * GM_BS + n];
        const uint32_t bh1 = Bhb[(k0 + tig + 4) * GM_BS + n];
        const uint32_t bl0 = Blb[(k0 + tig)     * GM_BS + n];
        const uint32_t bl1 = Blb[(k0 + tig + 4) * GM_BS + n];
#pragma unroll
        for (int mb = 0; mb < 2; mb++) {
          mma_tf32(c[mb][nb], ahi[mb][0], ahi[mb][1], ahi[mb][2], ahi[mb][3], bh0, bh1);
          mma_tf32(c[mb][nb], ahi[mb][0], ahi[mb][1], ahi[mb][2], ahi[mb][3], bl0, bl1);
          mma_tf32(c[mb][nb], alo[mb][0], alo[mb][1], alo[mb][2], alo[mb][3], bh0, bh1);
        }
      }
    }
    __syncthreads();
  }

#pragma unroll
  for (int mb = 0; mb < 2; mb++) {
#pragma unroll
    for (int nb = 0; nb < 8; nb++) {
      const int m0 = bm + wm * 32 + mb * 16 + gid;
      const int n0 = bn + wn * 64 + nb * 8 + tig * 2;
      const float bx = bias[n0], by = bias[n0 + 1];
      float2 v0 = {c[mb][nb][0] + bx, c[mb][nb][1] + by};
      float2 v1 = {c[mb][nb][2] + bx, c[mb][nb][3] + by};
      if (MODE == 0) {
        *(float2*)&C[(size_t)m0 * N + n0] = v0;
        *(float2*)&C[(size_t)(m0 + 8) * N + n0] = v1;
      } else {
        const int h = n0 >> 6, dh = n0 & 63;
        const int b0i = m0 >> 11, l0 = m0 & (PL - 1);
        const int b1i = (m0 + 8) >> 11, l1 = (m0 + 8) & (PL - 1);
        *(float2*)&C[(((size_t)b0i * PH + h) * PL + l0) * PDH + dh] = v0;
        *(float2*)&C[(((size_t)b1i * PH + h) * PL + l1) * PDH + dh] = v1;
      }
    }
  }
}

// ============================================================
// Head transpose + tf32 split: [bh][l][dh] -> [bh][dh][l]
// Emits fp32 (for flash) plus tf32 hi/lo (for sparsity).
// ============================================================
__global__ __launch_bounds__(256) void transpose_head_split(
    const float* __restrict__ in, float* __restrict__ out,
    uint32_t* __restrict__ ohi, uint32_t* __restrict__ olo) {
  __shared__ float t[32][33];
  const int bh = blockIdx.z;
  const int l0 = blockIdx.x * 32, d0 = blockIdx.y * 32;
  const int x = threadIdx.x & 31, y = threadIdx.x >> 5;
  const float* ip = in + (size_t)bh * PL * PDH;
#pragma unroll
  for (int k = 0; k < 4; k++)
    t[y + 8 * k][x] = ip[(size_t)(l0 + y + 8 * k) * PDH + d0 + x];
  __syncthreads();
  const size_t base = (size_t)bh * PDH * PL;
#pragma unroll
  for (int k = 0; k < 4; k++) {
    const float v = t[x][y + 8 * k];
    const size_t idx = base + (size_t)(d0 + y + 8 * k) * PL + l0 + x;
    out[idx] = v;
    uint32_t h, l;
    split_tf32(v, h, l);
    ohi[idx] = h;
    olo[idx] = l;
  }
}

// ============================================================
// Sparsity v5 (tensor cores, pre-split K^T):
// CTA = 128 q-rows x one bh; warp = 16 rows x 128 keys.
// K^T hi/lo tiles cp.async'd from g_kthi/g_ktlo (no in-loop split);
// Q split in-kernel (cheap). Single-buffered K tile.
// smem: Qs[128][68] f32 + Kh[64][136] + Kl[64][136] u32 = 102KB.
// ============================================================
#define SPQ_S 68
#define SPK_S 136
#define SP_SMEM ((128 * SPQ_S + 2 * 64 * SPK_S) * 4)

__global__ __launch_bounds__(256, 2) void sparsity_v5() {
  extern __shared__ float sm[];
  float* Qs = sm;                                  // [128][68]
  uint32_t* Kh = (uint32_t*)(sm + 128 * SPQ_S);    // [64][136]
  uint32_t* Kl = Kh + 64 * SPK_S;                  // [64][136]

  const int bh = blockIdx.y;
  const int q0 = blockIdx.x * 128;
  const int tid = threadIdx.x;
  const int warp = tid >> 5, lane = tid & 31;
  const int gid = lane >> 2, tig = lane & 3;

  const int qr = tid >> 1, qc = (tid & 1) * 32;   // Q: 2 thr/row
  const int kr = tid >> 2, kc = (tid & 3) * 32;   // K^T: 4 thr/row

  {  // Q tile (stays for whole kernel)
    const float* qsrc = g_q + ((size_t)bh * PL + q0 + qr) * PDH + qc;
    const uint32_t qd = sptr(&Qs[qr * SPQ_S + qc]);
#pragma unroll
    for (int j = 0; j < 8; j++) CP16(qd + j * 16, qsrc + j * 4);
    CP_COMMIT();
  }

  float rmax0 = -1e30f, rsum0 = 0.f, rmax1 = -1e30f, rsum1 = 0.f;

#pragma unroll 1
  for (int kt = 0; kt < PL / 128; kt++) {
    __syncthreads();  // previous tile fully consumed
    {
      const size_t off = ((size_t)bh * PDH + kr) * PL + kt * 128 + kc;
      const uint32_t hd = sptr(&Kh[kr * SPK_S + kc]);
      const uint32_t ld = sptr(&Kl[kr * SPK_S + kc]);
      const uint32_t* hsrc = g_kthi + off;
      const uint32_t* lsrc = g_ktlo + off;
#pragma unroll
      for (int j = 0; j < 8; j++) CP16(hd + j * 16, hsrc + j * 4);
#pragma unroll
      for (int j = 0; j < 8; j++) CP16(ld + j * 16, lsrc + j * 4);
      CP_COMMIT();
      CP_WAIT0();
    }
    __syncthreads();

    float c[16][4];
#pragma unroll
    for (int nb = 0; nb < 16; nb++)
#pragma unroll
      for (int j = 0; j < 4; j++) c[nb][j] = 0.f;

    const int rbase = warp * 16;
#pragma unroll
    for (int ks = 0; ks < 8; ks++) {
      const int k0 = ks * 8;
      uint32_t ahi[4], alo[4];
      split_tf32(Qs[(rbase + gid)     * SPQ_S + k0 + tig],     ahi[0], alo[0]);
      split_tf32(Qs[(rbase + gid + 8) * SPQ_S + k0 + tig],     ahi[1], alo[1]);
      split_tf32(Qs[(rbase + gid)     * SPQ_S + k0 + tig + 4], ahi[2], alo[2]);
      split_tf32(Qs[(rbase + gid + 8) * SPQ_S + k0 + tig + 4], ahi[3], alo[3]);
#pragma unroll
      for (int nb = 0; nb < 16; nb++) {
        const int n = nb * 8 + gid;
        const uint32_t bh0 = Kh[(k0 + tig)     * SPK_S + n];
        const uint32_t bh1 = Kh[(k0 + tig + 4) * SPK_S + n];
        const uint32_t bl0 = Kl[(k0 + tig)     * SPK_S + n];
        const uint32_t bl1 = Kl[(k0 + tig + 4) * SPK_S + n];
        mma_tf32(c[nb], ahi[0], ahi[1], ahi[2], ahi[3], bh0, bh1);
        mma_tf32(c[nb], ahi[0], ahi[1], ahi[2], ahi[3], bl0, bl1);
        mma_tf32(c[nb], alo[0], alo[1], alo[2], alo[3], bh0, bh1);
      }
    }

    float mx0 = -1e30f, sm0 = 0.f, mx1 = -1e30f, sm1 = 0.f;
#pragma unroll
    for (int nb = 0; nb < 16; nb++) {
      mx0 = fmaxf(mx0, fmaxf(c[nb][0], c[nb][1]));
      sm0 += c[nb][0] + c[nb][1];
      mx1 = fmaxf(mx1, fmaxf(c[nb][2], c[nb][3]));
      sm1 += c[nb][2] + c[nb][3];
    }
#pragma unroll
    for (int off = 1; off <= 2; off <<= 1) {
      mx0 = fmaxf(mx0, __shfl_xor_sync(0xffffffffu, mx0, off));
      sm0 += __shfl_xor_sync(0xffffffffu, sm0, off);
      mx1 = fmaxf(mx1, __shfl_xor_sync(0xffffffffu, mx1, off));
      sm1 += __shfl_xor_sync(0xffffffffu, sm1, off);
    }
    rmax0 = fmaxf(rmax0, mx0); rsum0 += sm0;
    rmax1 = fmaxf(rmax1, mx1); rsum1 += sm1;
  }

  const float scale = 0.125f;  // 1/sqrt(64)
  if (tig == 0) {
    const int r0 = q0 + warp * 16 + gid;
    g_spars[(size_t)bh * PL + r0]     = scale * rmax0 - scale * rsum0 * (1.0f / PL);
    g_spars[(size_t)bh * PL + r0 + 8] = scale * rmax1 - scale * rsum1 * (1.0f / PL);
  }
}

// ============================================================
// Exact top-U via radix select (unchanged).
// ============================================================
__global__ __launch_bounds__(256) void topk_radix() {
  __shared__ unsigned su[2048];
  __shared__ int hist[256];
  __shared__ unsigned s_pref;
  __shared__ int s_rem;
  __shared__ unsigned eqm[64];
  __shared__ int wpfx[64];
  __shared__ int outcnt;

  const int bh = blockIdx.x;
  const int tid = threadIdx.x;

  for (int t = tid; t < 2048; t += 256) {
    unsigned b = __float_as_uint(g_spars[(size_t)bh * PL + t]);
    su[t] = (b & 0x80000000u) ? ~b : (b | 0x80000000u);
  }
  if (tid == 0) { s_pref = 0u; s_rem = PU; outcnt = 0; }
  if (tid < 64) eqm[tid] = 0u;
  __syncthreads();

  for (int shift = 24; shift >= 0; shift -= 8) {
    hist[tid & 255] = 0;
    __syncthreads();
    const unsigned pref = s_pref;
    for (int t = tid; t < 2048; t += 256) {
      const unsigned u = su[t];
      if (shift == 24 || (u >> (shift + 8)) == pref)
        atomicAdd(&hist[(u >> shift) & 255], 1);
    }
    __syncthreads();
    if (tid == 0) {
      int rem = s_rem, acc = 0;
      for (int b = 255; b >= 0; b--) {
        if (acc + hist[b] >= rem) {
          s_rem = rem - acc;
          s_pref = (s_pref << 8) | (unsigned)b;
          break;
        }
        acc += hist[b];
      }
    }
    __syncthreads();
  }

  const unsigned T = s_pref;
  const int e = s_rem;

  for (int t = tid; t < 2048; t += 256)
    if (su[t] == T) atomicOr(&eqm[t >> 5], 1u << (t & 31));
  __syncthreads();
  if (tid == 0) {
    int a = 0;
    for (int w = 0; w < 64; w++) { wpfx[w] = a; a += __popc(eqm[w]); }
  }
  __syncthreads();

  for (int t = tid; t < 2048; t += 256) {
    const unsigned u = su[t];
    bool sel = (u > T);
    if (u == T) {
      const int rank = wpfx[t >> 5] + __popc(eqm[t >> 5] & ((1u << (t & 31)) - 1u));
      sel = (rank < e);
    }
    if (sel) {
      const int slot = atomicAdd(&outcnt, 1);
      g_topidx[(size_t)bh * PU + slot] = t;
    }
  }
}

// ============================================================
// Zero the scatter buffer.
// ============================================================
__global__ void zero_attn_kernel() {
  const size_t i = (size_t)blockIdx.x * blockDim.x + threadIdx.x;
  float4 z = {0.f, 0.f, 0.f, 0.f};
  ((float4*)g_attn)[i] = z;
}

// ============================================================
// Flash v3 (unchanged): 128 sel q x 64 k tiles, fp32.
// ============================================================
#define FL_KOFF (64 * 132)
#define FL_VOFF (64 * 132 + 64 * 68)
#define FL_POFF (64 * 132 + 2 * 64 * 68)
#define FLv3_SMEM ((64 * 132 + 2 * 64 * 68 + 128 * 68) * (int)sizeof(float))

__global__ __launch_bounds__(256, 2) void flash_v3() {
  extern __shared__ float sm_fl[];
  float* Qs = sm_fl;
  float* Ks = sm_fl + FL_KOFF;
  float* Vs = sm_fl + FL_VOFF;
  float* Ps = sm_fl + FL_POFF;
  __shared__ int qidx[128];

  const int bh = blockIdx.y;
  const int qt = blockIdx.x;
  const int tid = threadIdx.x;
  const int tx = tid & 15, ty = tid >> 4;
  const float scale = 0.125f;

  if (tid < 128) {
    const int u = qt * 128 + tid;
    qidx[tid] = (u < PU) ? g_topidx[(size_t)bh * PU + u] : -1;
  }
  __syncthreads();

  {
    const int r = tid >> 1, c0 = (tid & 1) * 32;
    int src = qidx[r];
    if (src < 0) src = 0;
    const float* qrow = g_q + ((size_t)bh * PL + src) * PDH + c0;
#pragma unroll
    for (int c = 0; c < 32; c += 4) {
      float4 v = *(const float4*)(qrow + c);
      Qs[(c0 + c + 0) * 132 + r] = v.x;
      Qs[(c0 + c + 1) * 132 + r] = v.y;
      Qs[(c0 + c + 2) * 132 + r] = v.z;
      Qs[(c0 + c + 3) * 132 + r] = v.w;
    }
  }

  float m_run[8], l_run[8], o[8][4];
#pragma unroll
  for (int i = 0; i < 8; i++) {
    m_run[i] = -1e30f; l_run[i] = 0.f;
#pragma unroll
    for (int j = 0; j < 4; j++) o[i][j] = 0.f;
  }

  const int rr = tid >> 2;
  const int sg = (tid & 3) * 16;

#pragma unroll 1
  for (int kt = 0; kt < PL / 64; kt++) {
    __syncthreads();
    {
      const float* ksrc = g_kt + ((size_t)bh * PDH + rr) * PL + kt * 64 + sg;
      const float* vsrc = g_v + ((size_t)bh * PL + kt * 64 + rr) * PDH + sg;
      const uint32_t kdst = sptr(&Ks[rr * 68 + sg]);
      const uint32_t vdst = sptr(&Vs[rr * 68 + sg]);
#pragma unroll
      for (int j = 0; j < 4; j++) CP16(kdst + j * 16, ksrc + j * 4);
#pragma unroll
      for (int j = 0; j < 4; j++) CP16(vdst + j * 16, vsrc + j * 4);
      CP_COMMIT();
      CP_WAIT0();
    }
    __syncthreads();

    float s[8][4];
#pragma unroll
    for (int i = 0; i < 8; i++)
#pragma unroll
      for (int j = 0; j < 4; j++) s[i][j] = 0.f;
#pragma unroll 8
    for (int d = 0; d < 64; d++) {
      float av[8], bv[4];
      *(float4*)(av)     = *(const float4*)&Qs[d * 132 + ty * 4];
      *(float4*)(av + 4) = *(const float4*)&Qs[d * 132 + 64 + ty * 4];
      *(float4*)(bv)     = *(const float4*)&Ks[d * 68 + tx * 4];
#pragma unroll
      for (int i = 0; i < 8; i++)
#pragma unroll
        for (int j = 0; j < 4; j++) s[i][j] += av[i] * bv[j];
    }

#pragma unroll
    for (int i = 0; i < 8; i++) {
      float tm = fmaxf(fmaxf(s[i][0], s[i][1]), fmaxf(s[i][2], s[i][3])) * scale;
#pragma unroll
      for (int off = 8; off; off >>= 1)
        tm = fmaxf(tm, __shfl_xor_sync(0xffffffffu, tm, off));
      const float mn = fmaxf(m_run[i], tm);
      const float alpha = __expf(m_run[i] - mn);
      m_run[i] = mn;
      float ts = 0.f;
#pragma unroll
      for (int j = 0; j < 4; j++) {
        const float pv = __expf(s[i][j] * scale - mn);
        s[i][j] = pv;
        ts += pv;
      }
#pragma unroll
      for (int off = 8; off; off >>= 1)
        ts += __shfl_xor_sync(0xffffffffu, ts, off);
      l_run[i] = l_run[i] * alpha + ts;
#pragma unroll
      for (int j = 0; j < 4; j++) o[i][j] *= alpha;
    }

#pragma unroll
    for (int i = 0; i < 8; i++) {
      const int ri = ty * 4 + (i & 3) + ((i >> 2) << 6);
      float4 pv = {s[i][0], s[i][1], s[i][2], s[i][3]};
      *(float4*)&Ps[ri * 68 + tx * 4] = pv;
    }
    __syncthreads();

#pragma unroll 4
    for (int k4 = 0; k4 < 64; k4 += 4) {
      float4 vv0 = *(const float4*)&Vs[(k4 + 0) * 68 + tx * 4];
      float4 vv1 = *(const float4*)&Vs[(k4 + 1) * 68 + tx * 4];
      float4 vv2 = *(const float4*)&Vs[(k4 + 2) * 68 + tx * 4];
      float4 vv3 = *(const float4*)&Vs[(k4 + 3) * 68 + tx * 4];
#pragma unroll
      for (int i = 0; i < 8; i++) {
        const int ri = ty * 4 + (i & 3) + ((i >> 2) << 6);
        float4 pk = *(const float4*)&Ps[ri * 68 + k4];
        o[i][0] += pk.x * vv0.x + pk.y * vv1.x + pk.z * vv2.x + pk.w * vv3.x;
        o[i][1] += pk.x * vv0.y + pk.y * vv1.y + pk.z * vv2.y + pk.w * vv3.y;
        o[i][2] += pk.x * vv0.z + pk.y * vv1.z + pk.z * vv2.z + pk.w * vv3.z;
        o[i][3] += pk.x * vv0.w + pk.y * vv1.w + pk.z * vv2.w + pk.w * vv3.w;
      }
    }
  }

  const int b = bh >> 4, h = bh & 15;
#pragma unroll
  for (int i = 0; i < 8; i++) {
    const int ri = ty * 4 + (i & 3) + ((i >> 2) << 6);
    const int src = qidx[ri];
    if (src >= 0) {
      const float inv = 1.0f / l_run[i];
      float4 ov = {o[i][0] * inv, o[i][1] * inv, o[i][2] * inv, o[i][3] * inv};
      *(float4*)&g_attn[((size_t)b * PL + src) * PD + h * PDH + tx * 4] = ov;
    }
  }
}

// ============================================================
// host launcher
// ============================================================
extern "C" void kernel_launch(void* const* d_in, const int* in_sizes, int n_in,
                              void* d_out, int out_size) {
  (void)in_sizes; (void)n_in; (void)out_size;
  const float* x  = (const float*)d_in[0];
  const float* Wq = (const float*)d_in[1];
  const float* bq = (const float*)d_in[2];
  const float* Wk = (const float*)d_in[3];
  const float* bk = (const float*)d_in[4];
  const float* Wv = (const float*)d_in[5];
  const float* bv = (const float*)d_in[6];
  const float* Wo = (const float*)d_in[7];
  const float* bo = (const float*)d_in[8];
  float* out = (float*)d_out;

  float *pq, *pk, *pv, *pkt, *pattn;
  uint32_t *pkthi, *pktlo, *pwhi, *pwlo;
  cudaGetSymbolAddress((void**)&pq, g_q);
  cudaGetSymbolAddress((void**)&pk, g_k);
  cudaGetSymbolAddress((void**)&pv, g_v);
  cudaGetSymbolAddress((void**)&pkt, g_kt);
  cudaGetSymbolAddress((void**)&pkthi, g_kthi);
  cudaGetSymbolAddress((void**)&pktlo, g_ktlo);
  cudaGetSymbolAddress((void**)&pwhi, g_whi);
  cudaGetSymbolAddress((void**)&pwlo, g_wlo);
  cudaGetSymbolAddress((void**)&pattn, g_attn);

  cudaFuncSetAttribute(gemm_tf32x3<0>,
                       cudaFuncAttributeMaxDynamicSharedMemorySize, GEMM_SMEM);
  cudaFuncSetAttribute(gemm_tf32x3<1>,
                       cudaFuncAttributeMaxDynamicSharedMemorySize, GEMM_SMEM);
  cudaFuncSetAttribute(sparsity_v5,
                       cudaFuncAttributeMaxDynamicSharedMemorySize, SP_SMEM);
  cudaFuncSetAttribute(flash_v3,
                       cudaFuncAttributeMaxDynamicSharedMemorySize, FLv3_SMEM);

  // pre-split all weight matrices into tf32 hi/lo
  const size_t WN = (size_t)PD * PD;
  const int n4 = (int)(WN / 4);
  split_kernel<<<(n4 + 255) / 256, 256>>>(Wq, pwhi + 0 * WN, pwlo + 0 * WN, n4);
  split_kernel<<<(n4 + 255) / 256, 256>>>(Wk, pwhi + 1 * WN, pwlo + 1 * WN, n4);
  split_kernel<<<(n4 + 255) / 256, 256>>>(Wv, pwhi + 2 * WN, pwlo + 2 * WN, n4);
  split_kernel<<<(n4 + 255) / 256, 256>>>(Wo, pwhi + 3 * WN, pwlo + 3 * WN, n4);

  const dim3 gGemm(PD / 128, (PB * PL) / 128);  // (8, 32)

  // Q/K/V projections into head layout (tensor cores, pre-split W)
  gemm_tf32x3<1><<<gGemm, 256, GEMM_SMEM>>>(x, pwhi + 0 * WN, pwlo + 0 * WN, bq, pq, PB * PL, PD, PD);
  gemm_tf32x3<1><<<gGemm, 256, GEMM_SMEM>>>(x, pwhi + 1 * WN, pwlo + 1 * WN, bk, pk, PB * PL, PD, PD);
  gemm_tf32x3<1><<<gGemm, 256, GEMM_SMEM>>>(x, pwhi + 2 * WN, pwlo + 2 * WN, bv, pv, PB * PL, PD, PD);

  // K transpose + tf32 pre-split
  const dim3 gT(PL / 32, PDH / 32, PBH);
  transpose_head_split<<<gT, 256>>>(pk, pkt, pkthi, pktlo);

  // sparsity heuristic over full scores
  sparsity_v5<<<dim3(PL / 128, PBH), 256, SP_SMEM>>>();

  // exact per-(b,h) top-U selection
  topk_radix<<<PBH, 256>>>();

  // zero scatter buffer, then attention on selected rows
  zero_attn_kernel<<<(PB * PL * PD / 4) / 256, 256>>>();
  flash_v3<<<dim3((PU + 127) / 128, PBH), 256, FLv3_SMEM>>>();

  // output projection
  gemm_tf32x3<0><<<gGemm, 256, GEMM_SMEM>>>(pattn, pwhi + 3 * WN, pwlo + 3 * WN, bo, out, PB * PL, PD, PD);
}

// round 9
// speedup vs baseline: 1.4401x; 1.0309x over previous
#include <cuda_runtime.h>
#include <cstdint>

// ---------------- problem constants ----------------
#define PB 2
#define PL 2048
#define PD 1024
#define PH 16
#define PDH 64
#define PU 1228          // int(0.6 * 2048)
#define PBH (PB * PH)    // 32
#define PM (PB * PL)     // 4096 rows

// ---------------- device scratch (no allocation allowed) ----------------
__device__ float g_q [(size_t)PBH * PL * PDH];   // [b,h,l,dh]
__device__ float g_k [(size_t)PBH * PL * PDH];
__device__ float g_v [(size_t)PBH * PL * PDH];
__device__ float g_kt[(size_t)PBH * PDH * PL];   // [b,h,dh,l] fp32 (flash)
__device__ float g_qtf[(size_t)PBH * PDH * PL];  // scratch fp32 (unused data)
__device__ uint32_t g_kthi[(size_t)PBH * PDH * PL];
__device__ uint32_t g_ktlo[(size_t)PBH * PDH * PL];
__device__ uint32_t g_qthi[(size_t)PBH * PDH * PL];
__device__ uint32_t g_qtlo[(size_t)PBH * PDH * PL];
__device__ uint32_t g_whi[(size_t)4 * PD * PD];  // Wq,Wk,Wv,Wo pre-split
__device__ uint32_t g_wlo[(size_t)4 * PD * PD];
__device__ uint32_t g_xthi[(size_t)PD * PM];     // x^T  K-major hi
__device__ uint32_t g_xtlo[(size_t)PD * PM];
__device__ uint32_t g_athi[(size_t)PD * PM];     // attn^T K-major hi
__device__ uint32_t g_atlo[(size_t)PD * PM];
__device__ float g_spars[(size_t)PBH * PL];
__device__ int   g_topidx[(size_t)PBH * PU];
__device__ float g_attn[(size_t)PB * PL * PD];   // pre-output-proj, [b,l,d]

// ---------------- cp.async helpers ----------------
#define CP16(dst_u32, src_ptr) \
  asm volatile("cp.async.cg.shared.global [%0], [%1], 16;\n" :: "r"(dst_u32), "l"(src_ptr))
#define CP_COMMIT() asm volatile("cp.async.commit_group;\n" ::)
#define CP_WAIT0()  asm volatile("cp.async.wait_group 0;\n" ::)
#define CP_WAIT1()  asm volatile("cp.async.wait_group 1;\n" ::)

static __device__ __forceinline__ uint32_t sptr(const void* p) {
  return (uint32_t)__cvta_generic_to_shared(p);
}

// ---------------- tf32 / f32x2 helpers ----------------
static __device__ __forceinline__ void split_tf32(float x, uint32_t& hi, uint32_t& lo) {
  uint32_t h;
  asm("cvt.rna.tf32.f32 %0, %1;" : "=r"(h) : "f"(x));
  float r = x - __uint_as_float(h);
  uint32_t l;
  asm("cvt.rna.tf32.f32 %0, %1;" : "=r"(l) : "f"(r));
  hi = h; lo = l;
}

static __device__ __forceinline__ void mma_tf32(
    float* c, uint32_t a0, uint32_t a1, uint32_t a2, uint32_t a3,
    uint32_t b0, uint32_t b1) {
  asm volatile(
      "mma.sync.aligned.m16n8k8.row.col.f32.tf32.tf32.f32 "
      "{%0,%1,%2,%3}, {%4,%5,%6,%7}, {%8,%9}, {%0,%1,%2,%3};"
      : "+f"(c[0]), "+f"(c[1]), "+f"(c[2]), "+f"(c[3])
      : "r"(a0), "r"(a1), "r"(a2), "r"(a3), "r"(b0), "r"(b1));
}

static __device__ __forceinline__ unsigned long long pk2(float lo, float hi) {
  unsigned long long r;
  asm("mov.b64 %0, {%1, %2};" : "=l"(r) : "f"(lo), "f"(hi));
  return r;
}
static __device__ __forceinline__ void upk2(unsigned long long v, float& lo, float& hi) {
  asm("mov.b64 {%0, %1}, %2;" : "=f"(lo), "=f"(hi) : "l"(v));
}
static __device__ __forceinline__ unsigned long long fma2(
    unsigned long long a, unsigned long long b, unsigned long long c) {
  unsigned long long d;
  asm("fma.rn.f32x2 %0, %1, %2, %3;" : "=l"(d) : "l"(a), "l"(b), "l"(c));
  return d;
}
static __device__ __forceinline__ unsigned long long mul2(
    unsigned long long a, unsigned long long b) {
  unsigned long long d;
  asm("mul.rn.f32x2 %0, %1, %2;" : "=l"(d) : "l"(a), "l"(b));
  return d;
}

// ============================================================
// Pre-split a float array into tf32 hi/lo u32 arrays (no transpose).
// ============================================================
__global__ __launch_bounds__(256) void split_kernel(
    const float* __restrict__ in, uint32_t* __restrict__ hi,
    uint32_t* __restrict__ lo, int n4) {
  const int i = blockIdx.x * 256 + threadIdx.x;
  if (i >= n4) return;
  float4 v = ((const float4*)in)[i];
  uint4 h, l;
  split_tf32(v.x, h.x, l.x);
  split_tf32(v.y, h.y, l.y);
  split_tf32(v.z, h.z, l.z);
  split_tf32(v.w, h.w, l.w);
  ((uint4*)hi)[i] = h;
  ((uint4*)lo)[i] = l;
}

// ============================================================
// Transpose + split: in[M][N] fp32 -> outhi/outlo [N][M] tf32.
// 32x32 tiles; grid (M/32, N/32), 256 threads.
// ============================================================
__global__ __launch_bounds__(256) void transpose_split(
    const float* __restrict__ in, uint32_t* __restrict__ ohi,
    uint32_t* __restrict__ olo, int M, int N) {
  __shared__ float t[32][33];
  const int m0 = blockIdx.x * 32, n0 = blockIdx.y * 32;
  const int x = threadIdx.x & 31, y = threadIdx.x >> 5;
#pragma unroll
  for (int k = 0; k < 4; k++)
    t[y + 8 * k][x] = in[(size_t)(m0 + y + 8 * k) * N + n0 + x];
  __syncthreads();
#pragma unroll
  for (int k = 0; k < 4; k++) {
    const float v = t[x][y + 8 * k];
    uint32_t h, l;
    split_tf32(v, h, l);
    const size_t idx = (size_t)(n0 + y + 8 * k) * M + m0 + x;
    ohi[idx] = h;
    olo[idx] = l;
  }
}

// ============================================================
// Head transpose + split: [bh][l][dh] -> [bh][dh][l].
// Emits fp32 plus tf32 hi/lo.
// ============================================================
__global__ __launch_bounds__(256) void transpose_head_split(
    const float* __restrict__ in, float* __restrict__ out,
    uint32_t* __restrict__ ohi, uint32_t* __restrict__ olo) {
  __shared__ float t[32][33];
  const int bh = blockIdx.z;
  const int l0 = blockIdx.x * 32, d0 = blockIdx.y * 32;
  const int x = threadIdx.x & 31, y = threadIdx.x >> 5;
  const float* ip = in + (size_t)bh * PL * PDH;
#pragma unroll
  for (int k = 0; k < 4; k++)
    t[y + 8 * k][x] = ip[(size_t)(l0 + y + 8 * k) * PDH + d0 + x];
  __syncthreads();
  const size_t base = (size_t)bh * PDH * PL;
#pragma unroll
  for (int k = 0; k < 4; k++) {
    const float v = t[x][y + 8 * k];
    const size_t idx = base + (size_t)(d0 + y + 8 * k) * PL + l0 + x;
    out[idx] = v;
    uint32_t h, l;
    split_tf32(v, h, l);
    ohi[idx] = h;
    olo[idx] = l;
  }
}

// ============================================================
// tf32x3 GEMM v3: C = A @ W + bias, BOTH operands pre-split.
// A given K-major ([K][M] hi/lo), W row-major ([K][N] hi/lo).
// 128x128x16 tiles, 8 warps (4x2), cp.async double-buffered,
// pure LDS+MMA mainloop. smem 68KB -> 2 CTAs/SM.
// MODE 0: row-major C.  MODE 1: [b,h,l,dh] head layout.
// ============================================================
#define GS 136   // smem row stride (u32), %32==8 -> conflict-free frags
#define GEMM_SMEM (4 * 2 * 16 * GS * 4)

template<int MODE>
__global__ __launch_bounds__(256, 2) void gemm_v3(
    const uint32_t* __restrict__ Ahi, const uint32_t* __restrict__ Alo,
    const uint32_t* __restrict__ Whi, const uint32_t* __restrict__ Wlo,
    const float* __restrict__ bias, float* __restrict__ C,
    int M, int N, int K) {
  extern __shared__ uint32_t smg[];
  uint32_t* Ah = smg;                   // [2][16][GS]
  uint32_t* Al = Ah + 2 * 16 * GS;
  uint32_t* Bh = Al + 2 * 16 * GS;
  uint32_t* Bl = Bh + 2 * 16 * GS;

  const int tid = threadIdx.x;
  const int warp = tid >> 5, lane = tid & 31;
  const int gid = lane >> 2, tig = lane & 3;
  const int wm = warp >> 1, wn = warp & 1;
  const int bm = blockIdx.y * 128, bn = blockIdx.x * 128;

  const int lr = tid >> 4;              // 0..15 (k row)
  const int lc = (tid & 15) * 8;        // 0..120

  float c[2][8][4];
#pragma unroll
  for (int mb = 0; mb < 2; mb++)
#pragma unroll
    for (int nb = 0; nb < 8; nb++)
#pragma unroll
      for (int j = 0; j < 4; j++) c[mb][nb][j] = 0.f;

  const int NP = K >> 4;

  // issue panel p into buffer bf
  auto issue = [&](int p, int bf) {
    const size_t arow = (size_t)(p * 16 + lr) * M + bm + lc;
    const size_t brow = (size_t)(p * 16 + lr) * N + bn + lc;
    const uint32_t so = bf * 16 * GS + lr * GS + lc;
    CP16(sptr(&Ah[so]), Ahi + arow); CP16(sptr(&Ah[so]) + 16, Ahi + arow + 4);
    CP16(sptr(&Al[so]), Alo + arow); CP16(sptr(&Al[so]) + 16, Alo + arow + 4);
    CP16(sptr(&Bh[so]), Whi + brow); CP16(sptr(&Bh[so]) + 16, Whi + brow + 4);
    CP16(sptr(&Bl[so]), Wlo + brow); CP16(sptr(&Bl[so]) + 16, Wlo + brow + 4);
    CP_COMMIT();
  };

  issue(0, 0);

#pragma unroll 1
  for (int p = 0; p < NP; p++) {
    const int buf = p & 1;
    if (p + 1 < NP) { issue(p + 1, buf ^ 1); CP_WAIT1(); }
    else            { CP_WAIT0(); }
    __syncthreads();

    const uint32_t* ah = Ah + buf * 16 * GS;
    const uint32_t* al = Al + buf * 16 * GS;
    const uint32_t* bhp = Bh + buf * 16 * GS;
    const uint32_t* blp = Bl + buf * 16 * GS;

#pragma unroll
    for (int ks = 0; ks < 2; ks++) {
      const int k0 = ks * 8;
      uint32_t ahi[2][4], alo[2][4];
#pragma unroll
      for (int mb = 0; mb < 2; mb++) {
        const int r = wm * 32 + mb * 16;
        ahi[mb][0] = ah[(k0 + tig)     * GS + r + gid];
        ahi[mb][1] = ah[(k0 + tig)     * GS + r + gid + 8];
        ahi[mb][2] = ah[(k0 + tig + 4) * GS + r + gid];
        ahi[mb][3] = ah[(k0 + tig + 4) * GS + r + gid + 8];
        alo[mb][0] = al[(k0 + tig)     * GS + r + gid];
        alo[mb][1] = al[(k0 + tig)     * GS + r + gid + 8];
        alo[mb][2] = al[(k0 + tig + 4) * GS + r + gid];
        alo[mb][3] = al[(k0 + tig + 4) * GS + r + gid + 8];
      }
#pragma unroll
      for (int nb = 0; nb < 8; nb++) {
        const int n = wn * 64 + nb * 8 + gid;
        const uint32_t bh0 = bhp[(k0 + tig)     * GS + n];
        const uint32_t bh1 = bhp[(k0 + tig + 4) * GS + n];
        const uint32_t bl0 = blp[(k0 + tig)     * GS + n];
        const uint32_t bl1 = blp[(k0 + tig + 4) * GS + n];
#pragma unroll
        for (int mb = 0; mb < 2; mb++) {
          mma_tf32(c[mb][nb], ahi[mb][0], ahi[mb][1], ahi[mb][2], ahi[mb][3], bh0, bh1);
          mma_tf32(c[mb][nb], ahi[mb][0], ahi[mb][1], ahi[mb][2], ahi[mb][3], bl0, bl1);
          mma_tf32(c[mb][nb], alo[mb][0], alo[mb][1], alo[mb][2], alo[mb][3], bh0, bh1);
        }
      }
    }
    __syncthreads();
  }

#pragma unroll
  for (int mb = 0; mb < 2; mb++) {
#pragma unroll
    for (int nb = 0; nb < 8; nb++) {
      const int m0 = bm + wm * 32 + mb * 16 + gid;
      const int n0 = bn + wn * 64 + nb * 8 + tig * 2;
      const float bx = bias[n0], by = bias[n0 + 1];
      float2 v0 = {c[mb][nb][0] + bx, c[mb][nb][1] + by};
      float2 v1 = {c[mb][nb][2] + bx, c[mb][nb][3] + by};
      if (MODE == 0) {
        *(float2*)&C[(size_t)m0 * N + n0] = v0;
        *(float2*)&C[(size_t)(m0 + 8) * N + n0] = v1;
      } else {
        const int h = n0 >> 6, dh = n0 & 63;
        const int b0i = m0 >> 11, l0 = m0 & (PL - 1);
        const int b1i = (m0 + 8) >> 11, l1 = (m0 + 8) & (PL - 1);
        *(float2*)&C[(((size_t)b0i * PH + h) * PL + l0) * PDH + dh] = v0;
        *(float2*)&C[(((size_t)b1i * PH + h) * PL + l1) * PDH + dh] = v1;
      }
    }
  }
}

// ============================================================
// Sparsity v6: per (b,h,row): scale*max - scale*mean of q.k
// CTA = 128 q-rows; A = Q^T hi/lo resident [64][136]; B = K^T
// hi/lo in 32-key double-buffered tiles [64][40]x2. Pure LDS+MMA.
// smem = 110,592B -> 2 CTAs/SM.
// ============================================================
#define SPA_S 136
#define SPK_S 40
#define SP_SMEM ((2 * 64 * SPA_S + 2 * 2 * 64 * SPK_S) * 4)

__global__ __launch_bounds__(256, 2) void sparsity_v6() {
  extern __shared__ uint32_t sm[];
  uint32_t* Qh = sm;                         // [64][136]
  uint32_t* Ql = Qh + 64 * SPA_S;
  uint32_t* Kh = Ql + 64 * SPA_S;            // [2][64][40]
  uint32_t* Kl = Kh + 2 * 64 * SPK_S;

  const int bh = blockIdx.y;
  const int q0 = blockIdx.x * 128;
  const int tid = threadIdx.x;
  const int warp = tid >> 5, lane = tid & 31;
  const int gid = lane >> 2, tig = lane & 3;

  const int dr = tid >> 2;                   // 0..63 (dh row)

  {  // resident Q^T tile: 64 x 128 u32 hi/lo
    const int qc = (tid & 3) * 32;
    const size_t off = ((size_t)bh * PDH + dr) * PL + q0 + qc;
    const uint32_t hd = sptr(&Qh[dr * SPA_S + qc]);
    const uint32_t ld = sptr(&Ql[dr * SPA_S + qc]);
#pragma unroll
    for (int j = 0; j < 8; j++) CP16(hd + j * 16, g_qthi + off + j * 4);
#pragma unroll
    for (int j = 0; j < 8; j++) CP16(ld + j * 16, g_qtlo + off + j * 4);
  }
  const int kc = (tid & 3) * 8;
  auto issueK = [&](int kt, int bf) {
    const size_t off = ((size_t)bh * PDH + dr) * PL + kt * 32 + kc;
    const uint32_t so = bf * 64 * SPK_S + dr * SPK_S + kc;
    CP16(sptr(&Kh[so]), g_kthi + off); CP16(sptr(&Kh[so]) + 16, g_kthi + off + 4);
    CP16(sptr(&Kl[so]), g_ktlo + off); CP16(sptr(&Kl[so]) + 16, g_ktlo + off + 4);
    CP_COMMIT();
  };
  issueK(0, 0);

  float rmax0 = -1e30f, rsum0 = 0.f, rmax1 = -1e30f, rsum1 = 0.f;
  const int rbase = warp * 16;

#pragma unroll 1
  for (int kt = 0; kt < PL / 32; kt++) {
    const int buf = kt & 1;
    if (kt + 1 < PL / 32) { issueK(kt + 1, buf ^ 1); CP_WAIT1(); }
    else                  { CP_WAIT0(); }
    __syncthreads();

    const uint32_t* kh = Kh + buf * 64 * SPK_S;
    const uint32_t* kl = Kl + buf * 64 * SPK_S;

    float c[4][4];
#pragma unroll
    for (int nb = 0; nb < 4; nb++)
#pragma unroll
      for (int j = 0; j < 4; j++) c[nb][j] = 0.f;

#pragma unroll
    for (int ks = 0; ks < 8; ks++) {
      const int k0 = ks * 8;
      uint32_t ahi[4], alo[4];
      ahi[0] = Qh[(k0 + tig)     * SPA_S + rbase + gid];
      ahi[1] = Qh[(k0 + tig)     * SPA_S + rbase + gid + 8];
      ahi[2] = Qh[(k0 + tig + 4) * SPA_S + rbase + gid];
      ahi[3] = Qh[(k0 + tig + 4) * SPA_S + rbase + gid + 8];
      alo[0] = Ql[(k0 + tig)     * SPA_S + rbase + gid];
      alo[1] = Ql[(k0 + tig)     * SPA_S + rbase + gid + 8];
      alo[2] = Ql[(k0 + tig + 4) * SPA_S + rbase + gid];
      alo[3] = Ql[(k0 + tig + 4) * SPA_S + rbase + gid + 8];
#pragma unroll
      for (int nb = 0; nb < 4; nb++) {
        const int n = nb * 8 + gid;
        const uint32_t bh0 = kh[(k0 + tig)     * SPK_S + n];
        const uint32_t bh1 = kh[(k0 + tig + 4) * SPK_S + n];
        const uint32_t bl0 = kl[(k0 + tig)     * SPK_S + n];
        const uint32_t bl1 = kl[(k0 + tig + 4) * SPK_S + n];
        mma_tf32(c[nb], ahi[0], ahi[1], ahi[2], ahi[3], bh0, bh1);
        mma_tf32(c[nb], ahi[0], ahi[1], ahi[2], ahi[3], bl0, bl1);
        mma_tf32(c[nb], alo[0], alo[1], alo[2], alo[3], bh0, bh1);
      }
    }

    float mx0 = -1e30f, sm0 = 0.f, mx1 = -1e30f, sm1 = 0.f;
#pragma unroll
    for (int nb = 0; nb < 4; nb++) {
      mx0 = fmaxf(mx0, fmaxf(c[nb][0], c[nb][1]));
      sm0 += c[nb][0] + c[nb][1];
      mx1 = fmaxf(mx1, fmaxf(c[nb][2], c[nb][3]));
      sm1 += c[nb][2] + c[nb][3];
    }
    rmax0 = fmaxf(rmax0, mx0); rsum0 += sm0;
    rmax1 = fmaxf(rmax1, mx1); rsum1 += sm1;
    __syncthreads();
  }

#pragma unroll
  for (int off = 1; off <= 2; off <<= 1) {
    rmax0 = fmaxf(rmax0, __shfl_xor_sync(0xffffffffu, rmax0, off));
    rsum0 += __shfl_xor_sync(0xffffffffu, rsum0, off);
    rmax1 = fmaxf(rmax1, __shfl_xor_sync(0xffffffffu, rmax1, off));
    rsum1 += __shfl_xor_sync(0xffffffffu, rsum1, off);
  }
  const float scale = 0.125f;
  if (tig == 0) {
    const int r0 = q0 + warp * 16 + gid;
    g_spars[(size_t)bh * PL + r0]     = scale * rmax0 - scale * rsum0 * (1.0f / PL);
    g_spars[(size_t)bh * PL + r0 + 8] = scale * rmax1 - scale * rsum1 * (1.0f / PL);
  }
}

// ============================================================
// Exact top-U via radix select (unchanged).
// ============================================================
__global__ __launch_bounds__(256) void topk_radix() {
  __shared__ unsigned su[2048];
  __shared__ int hist[256];
  __shared__ unsigned s_pref;
  __shared__ int s_rem;
  __shared__ unsigned eqm[64];
  __shared__ int wpfx[64];
  __shared__ int outcnt;

  const int bh = blockIdx.x;
  const int tid = threadIdx.x;

  for (int t = tid; t < 2048; t += 256) {
    unsigned b = __float_as_uint(g_spars[(size_t)bh * PL + t]);
    su[t] = (b & 0x80000000u) ? ~b : (b | 0x80000000u);
  }
  if (tid == 0) { s_pref = 0u; s_rem = PU; outcnt = 0; }
  if (tid < 64) eqm[tid] = 0u;
  __syncthreads();

  for (int shift = 24; shift >= 0; shift -= 8) {
    hist[tid & 255] = 0;
    __syncthreads();
    const unsigned pref = s_pref;
    for (int t = tid; t < 2048; t += 256) {
      const unsigned u = su[t];
      if (shift == 24 || (u >> (shift + 8)) == pref)
        atomicAdd(&hist[(u >> shift) & 255], 1);
    }
    __syncthreads();
    if (tid == 0) {
      int rem = s_rem, acc = 0;
      for (int b = 255; b >= 0; b--) {
        if (acc + hist[b] >= rem) {
          s_rem = rem - acc;
          s_pref = (s_pref << 8) | (unsigned)b;
          break;
        }
        acc += hist[b];
      }
    }
    __syncthreads();
  }

  const unsigned T = s_pref;
  const int e = s_rem;

  for (int t = tid; t < 2048; t += 256)
    if (su[t] == T) atomicOr(&eqm[t >> 5], 1u << (t & 31));
  __syncthreads();
  if (tid == 0) {
    int a = 0;
    for (int w = 0; w < 64; w++) { wpfx[w] = a; a += __popc(eqm[w]); }
  }
  __syncthreads();

  for (int t = tid; t < 2048; t += 256) {
    const unsigned u = su[t];
    bool sel = (u > T);
    if (u == T) {
      const int rank = wpfx[t >> 5] + __popc(eqm[t >> 5] & ((1u << (t & 31)) - 1u));
      sel = (rank < e);
    }
    if (sel) {
      const int slot = atomicAdd(&outcnt, 1);
      g_topidx[(size_t)bh * PU + slot] = t;
    }
  }
}

// ============================================================
// Zero the scatter buffer.
// ============================================================
__global__ void zero_attn_kernel() {
  const size_t i = (size_t)blockIdx.x * blockDim.x + threadIdx.x;
  float4 z = {0.f, 0.f, 0.f, 0.f};
  ((float4*)g_attn)[i] = z;
}

// ============================================================
// Flash v4: f32x2-packed FFMA. Same tiling/accumulation order as
// v3 (bit-identical output), ~27% fewer issue slots.
// ============================================================
#define FL_KOFF (64 * 132)
#define FL_VOFF (64 * 132 + 64 * 68)
#define FL_POFF (64 * 132 + 2 * 64 * 68)
#define FL_SMEM ((64 * 132 + 2 * 64 * 68 + 128 * 68) * (int)sizeof(float))

__global__ __launch_bounds__(256, 2) void flash_v4() {
  extern __shared__ float sm_fl[];
  float* Qs = sm_fl;             // [64][132] Q^T gathered
  float* Ks = sm_fl + FL_KOFF;   // [64][68]  K^T tile
  float* Vs = sm_fl + FL_VOFF;   // [64][68]  V tile
  float* Ps = sm_fl + FL_POFF;   // [128][68] probabilities
  __shared__ int qidx[128];

  const int bh = blockIdx.y;
  const int qt = blockIdx.x;
  const int tid = threadIdx.x;
  const int tx = tid & 15, ty = tid >> 4;
  const float scale = 0.125f;

  if (tid < 128) {
    const int u = qt * 128 + tid;
    qidx[tid] = (u < PU) ? g_topidx[(size_t)bh * PU + u] : -1;
  }
  __syncthreads();

  {  // gather + transpose Q
    const int r = tid >> 1, c0 = (tid & 1) * 32;
    int src = qidx[r];
    if (src < 0) src = 0;
    const float* qrow = g_q + ((size_t)bh * PL + src) * PDH + c0;
#pragma unroll
    for (int c = 0; c < 32; c += 4) {
      float4 v = *(const float4*)(qrow + c);
      Qs[(c0 + c + 0) * 132 + r] = v.x;
      Qs[(c0 + c + 1) * 132 + r] = v.y;
      Qs[(c0 + c + 2) * 132 + r] = v.z;
      Qs[(c0 + c + 3) * 132 + r] = v.w;
    }
  }

  float m_run[8], l_run[8];
  unsigned long long o2[8][2];
#pragma unroll
  for (int i = 0; i < 8; i++) {
    m_run[i] = -1e30f; l_run[i] = 0.f;
    o2[i][0] = 0ull; o2[i][1] = 0ull;
  }

  const int rr = tid >> 2;
  const int sg = (tid & 3) * 16;

#pragma unroll 1
  for (int kt = 0; kt < PL / 64; kt++) {
    __syncthreads();
    {
      const float* ksrc = g_kt + ((size_t)bh * PDH + rr) * PL + kt * 64 + sg;
      const float* vsrc = g_v + ((size_t)bh * PL + kt * 64 + rr) * PDH + sg;
      const uint32_t kdst = sptr(&Ks[rr * 68 + sg]);
      const uint32_t vdst = sptr(&Vs[rr * 68 + sg]);
#pragma unroll
      for (int j = 0; j < 4; j++) CP16(kdst + j * 16, ksrc + j * 4);
#pragma unroll
      for (int j = 0; j < 4; j++) CP16(vdst + j * 16, vsrc + j * 4);
      CP_COMMIT();
      CP_WAIT0();
    }
    __syncthreads();

    // S = Q.K^T via f32x2 (pairs over rows)
    unsigned long long s2[4][4];
#pragma unroll
    for (int p = 0; p < 4; p++)
#pragma unroll
      for (int j = 0; j < 4; j++) s2[p][j] = 0ull;
#pragma unroll 8
    for (int d = 0; d < 64; d++) {
      ulonglong2 ap0 = *(const ulonglong2*)&Qs[d * 132 + ty * 4];
      ulonglong2 ap1 = *(const ulonglong2*)&Qs[d * 132 + 64 + ty * 4];
      float4 bv = *(const float4*)&Ks[d * 68 + tx * 4];
      unsigned long long b0 = pk2(bv.x, bv.x), b1 = pk2(bv.y, bv.y);
      unsigned long long b2 = pk2(bv.z, bv.z), b3 = pk2(bv.w, bv.w);
      s2[0][0] = fma2(ap0.x, b0, s2[0][0]);
      s2[0][1] = fma2(ap0.x, b1, s2[0][1]);
      s2[0][2] = fma2(ap0.x, b2, s2[0][2]);
      s2[0][3] = fma2(ap0.x, b3, s2[0][3]);
      s2[1][0] = fma2(ap0.y, b0, s2[1][0]);
      s2[1][1] = fma2(ap0.y, b1, s2[1][1]);
      s2[1][2] = fma2(ap0.y, b2, s2[1][2]);
      s2[1][3] = fma2(ap0.y, b3, s2[1][3]);
      s2[2][0] = fma2(ap1.x, b0, s2[2][0]);
      s2[2][1] = fma2(ap1.x, b1, s2[2][1]);
      s2[2][2] = fma2(ap1.x, b2, s2[2][2]);
      s2[2][3] = fma2(ap1.x, b3, s2[2][3]);
      s2[3][0] = fma2(ap1.y, b0, s2[3][0]);
      s2[3][1] = fma2(ap1.y, b1, s2[3][1]);
      s2[3][2] = fma2(ap1.y, b2, s2[3][2]);
      s2[3][3] = fma2(ap1.y, b3, s2[3][3]);
    }
    float s[8][4];
#pragma unroll
    for (int p = 0; p < 4; p++)
#pragma unroll
      for (int j = 0; j < 4; j++)
        upk2(s2[p][j], s[2 * p][j], s[2 * p + 1][j]);

    // online softmax (unchanged order)
#pragma unroll
    for (int i = 0; i < 8; i++) {
      float tm = fmaxf(fmaxf(s[i][0], s[i][1]), fmaxf(s[i][2], s[i][3])) * scale;
#pragma unroll
      for (int off = 8; off; off >>= 1)
        tm = fmaxf(tm, __shfl_xor_sync(0xffffffffu, tm, off));
      const float mn = fmaxf(m_run[i], tm);
      const float alpha = __expf(m_run[i] - mn);
      m_run[i] = mn;
      float ts = 0.f;
#pragma unroll
      for (int j = 0; j < 4; j++) {
        const float pv = __expf(s[i][j] * scale - mn);
        s[i][j] = pv;
        ts += pv;
      }
#pragma unroll
      for (int off = 8; off; off >>= 1)
        ts += __shfl_xor_sync(0xffffffffu, ts, off);
      l_run[i] = l_run[i] * alpha + ts;
      const unsigned long long ad = pk2(alpha, alpha);
      o2[i][0] = mul2(o2[i][0], ad);
      o2[i][1] = mul2(o2[i][1], ad);
    }

#pragma unroll
    for (int i = 0; i < 8; i++) {
      const int ri = ty * 4 + (i & 3) + ((i >> 2) << 6);
      float4 pv = {s[i][0], s[i][1], s[i][2], s[i][3]};
      *(float4*)&Ps[ri * 68 + tx * 4] = pv;
    }
    __syncthreads();

    // O += P @ V via f32x2 (pairs over d-cols)
#pragma unroll 4
    for (int k4 = 0; k4 < 64; k4 += 4) {
      ulonglong2 w0 = *(const ulonglong2*)&Vs[(k4 + 0) * 68 + tx * 4];
      ulonglong2 w1 = *(const ulonglong2*)&Vs[(k4 + 1) * 68 + tx * 4];
      ulonglong2 w2 = *(const ulonglong2*)&Vs[(k4 + 2) * 68 + tx * 4];
      ulonglong2 w3 = *(const ulonglong2*)&Vs[(k4 + 3) * 68 + tx * 4];
#pragma unroll
      for (int i = 0; i < 8; i++) {
        const int ri = ty * 4 + (i & 3) + ((i >> 2) << 6);
        float4 pk = *(const float4*)&Ps[ri * 68 + k4];
        const unsigned long long p0 = pk2(pk.x, pk.x);
        const unsigned long long p1 = pk2(pk.y, pk.y);
        const unsigned long long p2 = pk2(pk.z, pk.z);
        const unsigned long long p3 = pk2(pk.w, pk.w);
        o2[i][0] = fma2(p0, w0.x, o2[i][0]);
        o2[i][1] = fma2(p0, w0.y, o2[i][1]);
        o2[i][0] = fma2(p1, w1.x, o2[i][0]);
        o2[i][1] = fma2(p1, w1.y, o2[i][1]);
        o2[i][0] = fma2(p2, w2.x, o2[i][0]);
        o2[i][1] = fma2(p2, w2.y, o2[i][1]);
        o2[i][0] = fma2(p3, w3.x, o2[i][0]);
        o2[i][1] = fma2(p3, w3.y, o2[i][1]);
      }
    }
  }

  const int b = bh >> 4, h = bh & 15;
#pragma unroll
  for (int i = 0; i < 8; i++) {
    const int ri = ty * 4 + (i & 3) + ((i >> 2) << 6);
    const int src = qidx[ri];
    if (src >= 0) {
      const float inv = 1.0f / l_run[i];
      float o0, o1, o2v, o3;
      upk2(o2[i][0], o0, o1);
      upk2(o2[i][1], o2v, o3);
      float4 ov = {o0 * inv, o1 * inv, o2v * inv, o3 * inv};
      *(float4*)&g_attn[((size_t)b * PL + src) * PD + h * PDH + tx * 4] = ov;
    }
  }
}

// ============================================================
// host launcher
// ============================================================
extern "C" void kernel_launch(void* const* d_in, const int* in_sizes, int n_in,
                              void* d_out, int out_size) {
  (void)in_sizes; (void)n_in; (void)out_size;
  const float* x  = (const float*)d_in[0];
  const float* Wq = (const float*)d_in[1];
  const float* bq = (const float*)d_in[2];
  const float* Wk = (const float*)d_in[3];
  const float* bk = (const float*)d_in[4];
  const float* Wv = (const float*)d_in[5];
  const float* bv = (const float*)d_in[6];
  const float* Wo = (const float*)d_in[7];
  const float* bo = (const float*)d_in[8];
  float* out = (float*)d_out;

  float *pq, *pk, *pv, *pkt, *pqtf, *pattn;
  uint32_t *pkthi, *pktlo, *pqthi, *pqtlo, *pwhi, *pwlo;
  uint32_t *pxthi, *pxtlo, *pathi, *patlo;
  cudaGetSymbolAddress((void**)&pq, g_q);
  cudaGetSymbolAddress((void**)&pk, g_k);
  cudaGetSymbolAddress((void**)&pv, g_v);
  cudaGetSymbolAddress((void**)&pkt, g_kt);
  cudaGetSymbolAddress((void**)&pqtf, g_qtf);
  cudaGetSymbolAddress((void**)&pkthi, g_kthi);
  cudaGetSymbolAddress((void**)&pktlo, g_ktlo);
  cudaGetSymbolAddress((void**)&pqthi, g_qthi);
  cudaGetSymbolAddress((void**)&pqtlo, g_qtlo);
  cudaGetSymbolAddress((void**)&pwhi, g_whi);
  cudaGetSymbolAddress((void**)&pwlo, g_wlo);
  cudaGetSymbolAddress((void**)&pxthi, g_xthi);
  cudaGetSymbolAddress((void**)&pxtlo, g_xtlo);
  cudaGetSymbolAddress((void**)&pathi, g_athi);
  cudaGetSymbolAddress((void**)&patlo, g_atlo);
  cudaGetSymbolAddress((void**)&pattn, g_attn);

  cudaFuncSetAttribute(gemm_v3<0>, cudaFuncAttributeMaxDynamicSharedMemorySize, GEMM_SMEM);
  cudaFuncSetAttribute(gemm_v3<1>, cudaFuncAttributeMaxDynamicSharedMemorySize, GEMM_SMEM);
  cudaFuncSetAttribute(sparsity_v6, cudaFuncAttributeMaxDynamicSharedMemorySize, SP_SMEM);
  cudaFuncSetAttribute(flash_v4, cudaFuncAttributeMaxDynamicSharedMemorySize, FL_SMEM);

  // pre-split weights (row-major) and x (transposed to K-major)
  const size_t WN = (size_t)PD * PD;
  const int n4 = (int)(WN / 4);
  split_kernel<<<(n4 + 255) / 256, 256>>>(Wq, pwhi + 0 * WN, pwlo + 0 * WN, n4);
  split_kernel<<<(n4 + 255) / 256, 256>>>(Wk, pwhi + 1 * WN, pwlo + 1 * WN, n4);
  split_kernel<<<(n4 + 255) / 256, 256>>>(Wv, pwhi + 2 * WN, pwlo + 2 * WN, n4);
  split_kernel<<<(n4 + 255) / 256, 256>>>(Wo, pwhi + 3 * WN, pwlo + 3 * WN, n4);
  transpose_split<<<dim3(PM / 32, PD / 32), 256>>>(x, pxthi, pxtlo, PM, PD);

  const dim3 gGemm(PD / 128, PM / 128);  // (8, 32)

  // Q/K/V projections (pure LDS+MMA mainloops)
  gemm_v3<1><<<gGemm, 256, GEMM_SMEM>>>(pxthi, pxtlo, pwhi + 0 * WN, pwlo + 0 * WN, bq, pq, PM, PD, PD);
  gemm_v3<1><<<gGemm, 256, GEMM_SMEM>>>(pxthi, pxtlo, pwhi + 1 * WN, pwlo + 1 * WN, bk, pk, PM, PD, PD);
  gemm_v3<1><<<gGemm, 256, GEMM_SMEM>>>(pxthi, pxtlo, pwhi + 2 * WN, pwlo + 2 * WN, bv, pv, PM, PD, PD);

  // head transposes + tf32 splits (K for sparsity+flash, Q for sparsity)
  const dim3 gT(PL / 32, PDH / 32, PBH);
  transpose_head_split<<<gT, 256>>>(pk, pkt, pkthi, pktlo);
  transpose_head_split<<<gT, 256>>>(pq, pqtf, pqthi, pqtlo);

  // sparsity heuristic
  sparsity_v6<<<dim3(PL / 128, PBH), 256, SP_SMEM>>>();

  // exact per-(b,h) top-U selection
  topk_radix<<<PBH, 256>>>();

  // zero scatter buffer, attention on selected rows
  zero_attn_kernel<<<(PB * PL * PD / 4) / 256, 256>>>();
  flash_v4<<<dim3((PU + 127) / 128, PBH), 256, FL_SMEM>>>();

  // transpose-split attn, then output projection
  transpose_split<<<dim3(PM / 32, PD / 32), 256>>>(pattn, pathi, patlo, PM, PD);
  gemm_v3<0><<<gGemm, 256, GEMM_SMEM>>>(pathi, patlo, pwhi + 3 * WN, pwlo + 3 * WN, bo, out, PM, PD, PD);
}

// round 10
// speedup vs baseline: 1.5862x; 1.1015x over previous
#include <cuda_runtime.h>
#include <cuda_bf16.h>
#include <cstdint>

// ---------------- problem constants ----------------
#define PB 2
#define PL 2048
#define PD 1024
#define PH 16
#define PDH 64
#define PU 1228          // int(0.6 * 2048)
#define PBH (PB * PH)    // 32
#define PM (PB * PL)     // 4096 rows

// ---------------- device scratch (no allocation allowed) ----------------
__device__ float g_q [(size_t)PBH * PL * PDH];   // [b,h,l,dh]
__device__ float g_k [(size_t)PBH * PL * PDH];
__device__ float g_v [(size_t)PBH * PL * PDH];
__device__ float g_kt[(size_t)PBH * PDH * PL];   // [b,h,dh,l] fp32 (flash)
__device__ float g_qtf[(size_t)PBH * PDH * PL];  // scratch fp32 (unused)
__device__ uint32_t g_kthi[(size_t)PBH * PDH * PL];
__device__ uint32_t g_ktlo[(size_t)PBH * PDH * PL];
__device__ uint32_t g_qthi[(size_t)PBH * PDH * PL];
__device__ uint32_t g_qtlo[(size_t)PBH * PDH * PL];
__device__ uint32_t g_whi[(size_t)2 * PD * PD];  // Wq,Wk tf32 pre-split
__device__ uint32_t g_wlo[(size_t)2 * PD * PD];
__device__ uint32_t g_xthi[(size_t)PD * PM];     // x^T K-major tf32
__device__ uint32_t g_xtlo[(size_t)PD * PM];
// bf16 operands for V / Wo path
__device__ __nv_bfloat16 g_xbh[(size_t)PM * PD];   // x row-major bf16 hi
__device__ __nv_bfloat16 g_xbl[(size_t)PM * PD];
__device__ __nv_bfloat16 g_abh[(size_t)PM * PD];   // attn row-major bf16 hi
__device__ __nv_bfloat16 g_abl[(size_t)PM * PD];
__device__ __nv_bfloat16 g_wvth[(size_t)PD * PD];  // Wv^T [N][K] bf16
__device__ __nv_bfloat16 g_wvtl[(size_t)PD * PD];
__device__ __nv_bfloat16 g_woth[(size_t)PD * PD];  // Wo^T [N][K] bf16
__device__ __nv_bfloat16 g_wotl[(size_t)PD * PD];
__device__ float g_spars[(size_t)PBH * PL];
__device__ int   g_topidx[(size_t)PBH * PU];
__device__ float g_attn[(size_t)PB * PL * PD];   // pre-output-proj, [b,l,d]

// ---------------- cp.async helpers ----------------
#define CP16(dst_u32, src_ptr) \
  asm volatile("cp.async.cg.shared.global [%0], [%1], 16;\n" :: "r"(dst_u32), "l"(src_ptr))
#define CP_COMMIT() asm volatile("cp.async.commit_group;\n" ::)
#define CP_WAIT0()  asm volatile("cp.async.wait_group 0;\n" ::)
#define CP_WAIT1()  asm volatile("cp.async.wait_group 1;\n" ::)

static __device__ __forceinline__ uint32_t sptr(const void* p) {
  return (uint32_t)__cvta_generic_to_shared(p);
}

// ---------------- tf32 / bf16 / f32x2 helpers ----------------
static __device__ __forceinline__ void split_tf32(float x, uint32_t& hi, uint32_t& lo) {
  uint32_t h;
  asm("cvt.rna.tf32.f32 %0, %1;" : "=r"(h) : "f"(x));
  float r = x - __uint_as_float(h);
  uint32_t l;
  asm("cvt.rna.tf32.f32 %0, %1;" : "=r"(l) : "f"(x - __uint_as_float(h)));
  (void)r;
  hi = h; lo = l;
}

static __device__ __forceinline__ void split_bf16(float x, __nv_bfloat16& h, __nv_bfloat16& l) {
  h = __float2bfloat16(x);
  l = __float2bfloat16(x - __bfloat162float(h));
}

static __device__ __forceinline__ void mma_tf32(
    float* c, uint32_t a0, uint32_t a1, uint32_t a2, uint32_t a3,
    uint32_t b0, uint32_t b1) {
  asm volatile(
      "mma.sync.aligned.m16n8k8.row.col.f32.tf32.tf32.f32 "
      "{%0,%1,%2,%3}, {%4,%5,%6,%7}, {%8,%9}, {%0,%1,%2,%3};"
      : "+f"(c[0]), "+f"(c[1]), "+f"(c[2]), "+f"(c[3])
      : "r"(a0), "r"(a1), "r"(a2), "r"(a3), "r"(b0), "r"(b1));
}

static __device__ __forceinline__ void mma_bf16(
    float* c, uint32_t a0, uint32_t a1, uint32_t a2, uint32_t a3,
    uint32_t b0, uint32_t b1) {
  asm volatile(
      "mma.sync.aligned.m16n8k16.row.col.f32.bf16.bf16.f32 "
      "{%0,%1,%2,%3}, {%4,%5,%6,%7}, {%8,%9}, {%0,%1,%2,%3};"
      : "+f"(c[0]), "+f"(c[1]), "+f"(c[2]), "+f"(c[3])
      : "r"(a0), "r"(a1), "r"(a2), "r"(a3), "r"(b0), "r"(b1));
}

static __device__ __forceinline__ unsigned long long pk2(float lo, float hi) {
  unsigned long long r;
  asm("mov.b64 %0, {%1, %2};" : "=l"(r) : "f"(lo), "f"(hi));
  return r;
}
static __device__ __forceinline__ void upk2(unsigned long long v, float& lo, float& hi) {
  asm("mov.b64 {%0, %1}, %2;" : "=f"(lo), "=f"(hi) : "l"(v));
}
static __device__ __forceinline__ unsigned long long fma2(
    unsigned long long a, unsigned long long b, unsigned long long c) {
  unsigned long long d;
  asm("fma.rn.f32x2 %0, %1, %2, %3;" : "=l"(d) : "l"(a), "l"(b), "l"(c));
  return d;
}
static __device__ __forceinline__ unsigned long long mul2(
    unsigned long long a, unsigned long long b) {
  unsigned long long d;
  asm("mul.rn.f32x2 %0, %1, %2;" : "=l"(d) : "l"(a), "l"(b));
  return d;
}

// ============================================================
// Elementwise splits.
// ============================================================
__global__ __launch_bounds__(256) void split_kernel(
    const float* __restrict__ in, uint32_t* __restrict__ hi,
    uint32_t* __restrict__ lo, int n4) {
  const int i = blockIdx.x * 256 + threadIdx.x;
  if (i >= n4) return;
  float4 v = ((const float4*)in)[i];
  uint4 h, l;
  split_tf32(v.x, h.x, l.x);
  split_tf32(v.y, h.y, l.y);
  split_tf32(v.z, h.z, l.z);
  split_tf32(v.w, h.w, l.w);
  ((uint4*)hi)[i] = h;
  ((uint4*)lo)[i] = l;
}

__global__ __launch_bounds__(256) void split_bf16_kernel(
    const float* __restrict__ in, __nv_bfloat16* __restrict__ hi,
    __nv_bfloat16* __restrict__ lo, int n4) {
  const int i = blockIdx.x * 256 + threadIdx.x;
  if (i >= n4) return;
  float4 v = ((const float4*)in)[i];
  __nv_bfloat16 h[4], l[4];
  split_bf16(v.x, h[0], l[0]);
  split_bf16(v.y, h[1], l[1]);
  split_bf16(v.z, h[2], l[2]);
  split_bf16(v.w, h[3], l[3]);
  uint2 hp, lp;
  hp.x = ((uint32_t)__bfloat16_as_ushort(h[0])) | ((uint32_t)__bfloat16_as_ushort(h[1]) << 16);
  hp.y = ((uint32_t)__bfloat16_as_ushort(h[2])) | ((uint32_t)__bfloat16_as_ushort(h[3]) << 16);
  lp.x = ((uint32_t)__bfloat16_as_ushort(l[0])) | ((uint32_t)__bfloat16_as_ushort(l[1]) << 16);
  lp.y = ((uint32_t)__bfloat16_as_ushort(l[2])) | ((uint32_t)__bfloat16_as_ushort(l[3]) << 16);
  ((uint2*)hi)[i] = hp;
  ((uint2*)lo)[i] = lp;
}

// ============================================================
// Transpose + tf32 split: in[M][N] fp32 -> [N][M] tf32 hi/lo.
// ============================================================
__global__ __launch_bounds__(256) void transpose_split(
    const float* __restrict__ in, uint32_t* __restrict__ ohi,
    uint32_t* __restrict__ olo, int M, int N) {
  __shared__ float t[32][33];
  const int m0 = blockIdx.x * 32, n0 = blockIdx.y * 32;
  const int x = threadIdx.x & 31, y = threadIdx.x >> 5;
#pragma unroll
  for (int k = 0; k < 4; k++)
    t[y + 8 * k][x] = in[(size_t)(m0 + y + 8 * k) * N + n0 + x];
  __syncthreads();
#pragma unroll
  for (int k = 0; k < 4; k++) {
    const float v = t[x][y + 8 * k];
    uint32_t h, l;
    split_tf32(v, h, l);
    const size_t idx = (size_t)(n0 + y + 8 * k) * M + m0 + x;
    ohi[idx] = h;
    olo[idx] = l;
  }
}

// ============================================================
// Transpose + bf16 split: in[M][N] fp32 -> [N][M] bf16 hi/lo.
// ============================================================
__global__ __launch_bounds__(256) void transpose_split_bf16(
    const float* __restrict__ in, __nv_bfloat16* __restrict__ ohi,
    __nv_bfloat16* __restrict__ olo, int M, int N) {
  __shared__ float t[32][33];
  const int m0 = blockIdx.x * 32, n0 = blockIdx.y * 32;
  const int x = threadIdx.x & 31, y = threadIdx.x >> 5;
#pragma unroll
  for (int k = 0; k < 4; k++)
    t[y + 8 * k][x] = in[(size_t)(m0 + y + 8 * k) * N + n0 + x];
  __syncthreads();
#pragma unroll
  for (int k = 0; k < 4; k++) {
    const float v = t[x][y + 8 * k];
    __nv_bfloat16 h, l;
    split_bf16(v, h, l);
    const size_t idx = (size_t)(n0 + y + 8 * k) * M + m0 + x;
    ohi[idx] = h;
    olo[idx] = l;
  }
}

// ============================================================
// Head transpose + tf32 split: [bh][l][dh] -> [bh][dh][l].
// ============================================================
__global__ __launch_bounds__(256) void transpose_head_split(
    const float* __restrict__ in, float* __restrict__ out,
    uint32_t* __restrict__ ohi, uint32_t* __restrict__ olo) {
  __shared__ float t[32][33];
  const int bh = blockIdx.z;
  const int l0 = blockIdx.x * 32, d0 = blockIdx.y * 32;
  const int x = threadIdx.x & 31, y = threadIdx.x >> 5;
  const float* ip = in + (size_t)bh * PL * PDH;
#pragma unroll
  for (int k = 0; k < 4; k++)
    t[y + 8 * k][x] = ip[(size_t)(l0 + y + 8 * k) * PDH + d0 + x];
  __syncthreads();
  const size_t base = (size_t)bh * PDH * PL;
#pragma unroll
  for (int k = 0; k < 4; k++) {
    const float v = t[x][y + 8 * k];
    const size_t idx = base + (size_t)(d0 + y + 8 * k) * PL + l0 + x;
    out[idx] = v;
    uint32_t h, l;
    split_tf32(v, h, l);
    ohi[idx] = h;
    olo[idx] = l;
  }
}

// ============================================================
// Fused Q+K projection (tf32x3, selection-critical precision).
// Identical math to gemm_v3<1>; block picks Wq or Wk half.
// grid ((PD/128)*2, PM/128).
// ============================================================
#define GS 136
#define GEMM_SMEM (4 * 2 * 16 * GS * 4)

__global__ __launch_bounds__(256, 2) void gemm_qk(
    const uint32_t* __restrict__ Ahi, const uint32_t* __restrict__ Alo,
    const uint32_t* __restrict__ WhiQ, const uint32_t* __restrict__ WloQ,
    const uint32_t* __restrict__ WhiK, const uint32_t* __restrict__ WloK,
    const float* __restrict__ biasQ, const float* __restrict__ biasK,
    float* __restrict__ CQ, float* __restrict__ CK) {
  extern __shared__ uint32_t smg[];
  uint32_t* Ah = smg;
  uint32_t* Al = Ah + 2 * 16 * GS;
  uint32_t* Bh = Al + 2 * 16 * GS;
  uint32_t* Bl = Bh + 2 * 16 * GS;

  const int HB = PD / 128;  // 8
  const bool isK = (blockIdx.x >= HB);
  const uint32_t* Whi = isK ? WhiK : WhiQ;
  const uint32_t* Wlo = isK ? WloK : WloQ;
  const float* bias = isK ? biasK : biasQ;
  float* C = isK ? CK : CQ;
  const int bn = (isK ? blockIdx.x - HB : blockIdx.x) * 128;

  const int M = PM, N = PD, K = PD;
  const int tid = threadIdx.x;
  const int warp = tid >> 5, lane = tid & 31;
  const int gid = lane >> 2, tig = lane & 3;
  const int wm = warp >> 1, wn = warp & 1;
  const int bm = blockIdx.y * 128;

  const int lr = tid >> 4;
  const int lc = (tid & 15) * 8;

  float c[2][8][4];
#pragma unroll
  for (int mb = 0; mb < 2; mb++)
#pragma unroll
    for (int nb = 0; nb < 8; nb++)
#pragma unroll
      for (int j = 0; j < 4; j++) c[mb][nb][j] = 0.f;

  const int NP = K >> 4;

  auto issue = [&](int p, int bf) {
    const size_t arow = (size_t)(p * 16 + lr) * M + bm + lc;
    const size_t brow = (size_t)(p * 16 + lr) * N + bn + lc;
    const uint32_t so = bf * 16 * GS + lr * GS + lc;
    CP16(sptr(&Ah[so]), Ahi + arow); CP16(sptr(&Ah[so]) + 16, Ahi + arow + 4);
    CP16(sptr(&Al[so]), Alo + arow); CP16(sptr(&Al[so]) + 16, Alo + arow + 4);
    CP16(sptr(&Bh[so]), Whi + brow); CP16(sptr(&Bh[so]) + 16, Whi + brow + 4);
    CP16(sptr(&Bl[so]), Wlo + brow); CP16(sptr(&Bl[so]) + 16, Wlo + brow + 4);
    CP_COMMIT();
  };

  issue(0, 0);

#pragma unroll 1
  for (int p = 0; p < NP; p++) {
    const int buf = p & 1;
    if (p + 1 < NP) { issue(p + 1, buf ^ 1); CP_WAIT1(); }
    else            { CP_WAIT0(); }
    __syncthreads();

    const uint32_t* ah = Ah + buf * 16 * GS;
    const uint32_t* al = Al + buf * 16 * GS;
    const uint32_t* bhp = Bh + buf * 16 * GS;
    const uint32_t* blp = Bl + buf * 16 * GS;

#pragma unroll
    for (int ks = 0; ks < 2; ks++) {
      const int k0 = ks * 8;
      uint32_t ahi[2][4], alo[2][4];
#pragma unroll
      for (int mb = 0; mb < 2; mb++) {
        const int r = wm * 32 + mb * 16;
        ahi[mb][0] = ah[(k0 + tig)     * GS + r + gid];
        ahi[mb][1] = ah[(k0 + tig)     * GS + r + gid + 8];
        ahi[mb][2] = ah[(k0 + tig + 4) * GS + r + gid];
        ahi[mb][3] = ah[(k0 + tig + 4) * GS + r + gid + 8];
        alo[mb][0] = al[(k0 + tig)     * GS + r + gid];
        alo[mb][1] = al[(k0 + tig)     * GS + r + gid + 8];
        alo[mb][2] = al[(k0 + tig + 4) * GS + r + gid];
        alo[mb][3] = al[(k0 + tig + 4) * GS + r + gid + 8];
      }
#pragma unroll
      for (int nb = 0; nb < 8; nb++) {
        const int n = wn * 64 + nb * 8 + gid;
        const uint32_t bh0 = bhp[(k0 + tig)     * GS + n];
        const uint32_t bh1 = bhp[(k0 + tig + 4) * GS + n];
        const uint32_t bl0 = blp[(k0 + tig)     * GS + n];
        const uint32_t bl1 = blp[(k0 + tig + 4) * GS + n];
#pragma unroll
        for (int mb = 0; mb < 2; mb++) {
          mma_tf32(c[mb][nb], ahi[mb][0], ahi[mb][1], ahi[mb][2], ahi[mb][3], bh0, bh1);
          mma_tf32(c[mb][nb], ahi[mb][0], ahi[mb][1], ahi[mb][2], ahi[mb][3], bl0, bl1);
          mma_tf32(c[mb][nb], alo[mb][0], alo[mb][1], alo[mb][2], alo[mb][3], bh0, bh1);
        }
      }
    }
    __syncthreads();
  }

#pragma unroll
  for (int mb = 0; mb < 2; mb++) {
#pragma unroll
    for (int nb = 0; nb < 8; nb++) {
      const int m0 = bm + wm * 32 + mb * 16 + gid;
      const int n0 = bn + wn * 64 + nb * 8 + tig * 2;
      const float bx = bias[n0], by = bias[n0 + 1];
      float2 v0 = {c[mb][nb][0] + bx, c[mb][nb][1] + by};
      float2 v1 = {c[mb][nb][2] + bx, c[mb][nb][3] + by};
      const int h = n0 >> 6, dh = n0 & 63;
      const int b0i = m0 >> 11, l0 = m0 & (PL - 1);
      const int b1i = (m0 + 8) >> 11, l1 = (m0 + 8) & (PL - 1);
      *(float2*)&C[(((size_t)b0i * PH + h) * PL + l0) * PDH + dh] = v0;
      *(float2*)&C[(((size_t)b1i * PH + h) * PL + l1) * PDH + dh] = v1;
    }
  }
}

// ============================================================
// bf16x2 3-term GEMM: C = A @ Wt^T + bias.
// A [M][K] bf16 hi/lo row-major; Wt [N][K] bf16 hi/lo (W transposed).
// 128x128x32 tiles, m16n8k16, cp.async double-buffered.
// MODE 0: row-major C.  MODE 1: [b,h,l,dh] head layout.
// ============================================================
#define GB_S 20   // u32 row stride for a [*][32 bf16] tile row
#define GBF_SMEM (4 * 2 * 128 * GB_S * 4)   // Ah,Al,Bh,Bl x 2buf

template<int MODE>
__global__ __launch_bounds__(256, 2) void gemm_bf16(
    const __nv_bfloat16* __restrict__ Agh, const __nv_bfloat16* __restrict__ Agl,
    const __nv_bfloat16* __restrict__ Bgh, const __nv_bfloat16* __restrict__ Bgl,
    const float* __restrict__ bias, float* __restrict__ C,
    int M, int N, int K) {
  extern __shared__ uint32_t smb[];
  uint32_t* Ah = smb;                      // [2][128][GB_S]
  uint32_t* Al = Ah + 2 * 128 * GB_S;
  uint32_t* Bh = Al + 2 * 128 * GB_S;
  uint32_t* Bl = Bh + 2 * 128 * GB_S;

  const int tid = threadIdx.x;
  const int warp = tid >> 5, lane = tid & 31;
  const int gid = lane >> 2, tig = lane & 3;
  const int wm = warp >> 1, wn = warp & 1;
  const int bm = blockIdx.y * 128, bn = blockIdx.x * 128;

  const int lr = tid >> 1;            // 0..127 (tile row)
  const int lh = (tid & 1) * 16;      // bf16 element offset 0 or 16

  float c[2][8][4];
#pragma unroll
  for (int mb = 0; mb < 2; mb++)
#pragma unroll
    for (int nb = 0; nb < 8; nb++)
#pragma unroll
      for (int j = 0; j < 4; j++) c[mb][nb][j] = 0.f;

  const int NP = K >> 5;   // 32-k panels

  auto issue = [&](int p, int bf) {
    const __nv_bfloat16* asrc = Agh + (size_t)(bm + lr) * K + p * 32 + lh;
    const __nv_bfloat16* asrl = Agl + (size_t)(bm + lr) * K + p * 32 + lh;
    const __nv_bfloat16* bsrc = Bgh + (size_t)(bn + lr) * K + p * 32 + lh;
    const __nv_bfloat16* bsrl = Bgl + (size_t)(bn + lr) * K + p * 32 + lh;
    const uint32_t so = (bf * 128 + lr) * GB_S * 4 + lh * 2;  // byte offset
    CP16(sptr(Ah) + so, asrc); CP16(sptr(Ah) + so + 16, asrc + 8);
    CP16(sptr(Al) + so, asrl); CP16(sptr(Al) + so + 16, asrl + 8);
    CP16(sptr(Bh) + so, bsrc); CP16(sptr(Bh) + so + 16, bsrc + 8);
    CP16(sptr(Bl) + so, bsrl); CP16(sptr(Bl) + so + 16, bsrl + 8);
    CP_COMMIT();
  };

  issue(0, 0);

#pragma unroll 1
  for (int p = 0; p < NP; p++) {
    const int buf = p & 1;
    if (p + 1 < NP) { issue(p + 1, buf ^ 1); CP_WAIT1(); }
    else            { CP_WAIT0(); }
    __syncthreads();

    const uint32_t* ah = Ah + buf * 128 * GB_S;
    const uint32_t* al = Al + buf * 128 * GB_S;
    const uint32_t* bhp = Bh + buf * 128 * GB_S;
    const uint32_t* blp = Bl + buf * 128 * GB_S;

#pragma unroll
    for (int kb = 0; kb < 2; kb++) {     // two k16 blocks per panel
      const int ko = kb * 8;             // u32 offset
      uint32_t ahi[2][4], alo[2][4];
#pragma unroll
      for (int mb = 0; mb < 2; mb++) {
        const int r = wm * 32 + mb * 16;
        ahi[mb][0] = ah[(r + gid)     * GB_S + ko + tig];
        ahi[mb][1] = ah[(r + gid + 8) * GB_S + ko + tig];
        ahi[mb][2] = ah[(r + gid)     * GB_S + ko + tig + 4];
        ahi[mb][3] = ah[(r + gid + 8) * GB_S + ko + tig + 4];
        alo[mb][0] = al[(r + gid)     * GB_S + ko + tig];
        alo[mb][1] = al[(r + gid + 8) * GB_S + ko + tig];
        alo[mb][2] = al[(r + gid)     * GB_S + ko + tig + 4];
        alo[mb][3] = al[(r + gid + 8) * GB_S + ko + tig + 4];
      }
#pragma unroll
      for (int nb = 0; nb < 8; nb++) {
        const int n = wn * 64 + nb * 8 + gid;
        const uint32_t bh0 = bhp[n * GB_S + ko + tig];
        const uint32_t bh1 = bhp[n * GB_S + ko + tig + 4];
        const uint32_t bl0 = blp[n * GB_S + ko + tig];
        const uint32_t bl1 = blp[n * GB_S + ko + tig + 4];
#pragma unroll
        for (int mb = 0; mb < 2; mb++) {
          mma_bf16(c[mb][nb], ahi[mb][0], ahi[mb][1], ahi[mb][2], ahi[mb][3], bh0, bh1);
          mma_bf16(c[mb][nb], ahi[mb][0], ahi[mb][1], ahi[mb][2], ahi[mb][3], bl0, bl1);
          mma_bf16(c[mb][nb], alo[mb][0], alo[mb][1], alo[mb][2], alo[mb][3], bh0, bh1);
        }
      }
    }
    __syncthreads();
  }

#pragma unroll
  for (int mb = 0; mb < 2; mb++) {
#pragma unroll
    for (int nb = 0; nb < 8; nb++) {
      const int m0 = bm + wm * 32 + mb * 16 + gid;
      const int n0 = bn + wn * 64 + nb * 8 + tig * 2;
      const float bx = bias[n0], by = bias[n0 + 1];
      float2 v0 = {c[mb][nb][0] + bx, c[mb][nb][1] + by};
      float2 v1 = {c[mb][nb][2] + bx, c[mb][nb][3] + by};
      if (MODE == 0) {
        *(float2*)&C[(size_t)m0 * N + n0] = v0;
        *(float2*)&C[(size_t)(m0 + 8) * N + n0] = v1;
      } else {
        const int h = n0 >> 6, dh = n0 & 63;
        const int b0i = m0 >> 11, l0 = m0 & (PL - 1);
        const int b1i = (m0 + 8) >> 11, l1 = (m0 + 8) & (PL - 1);
        *(float2*)&C[(((size_t)b0i * PH + h) * PL + l0) * PDH + dh] = v0;
        *(float2*)&C[(((size_t)b1i * PH + h) * PL + l1) * PDH + dh] = v1;
      }
    }
  }
}

// ============================================================
// Sparsity v6 (unchanged, tf32x3 selection-grade).
// ============================================================
#define SPA_S 136
#define SPK_S 40
#define SP_SMEM ((2 * 64 * SPA_S + 2 * 2 * 64 * SPK_S) * 4)

__global__ __launch_bounds__(256, 2) void sparsity_v6() {
  extern __shared__ uint32_t sm[];
  uint32_t* Qh = sm;
  uint32_t* Ql = Qh + 64 * SPA_S;
  uint32_t* Kh = Ql + 64 * SPA_S;
  uint32_t* Kl = Kh + 2 * 64 * SPK_S;

  const int bh = blockIdx.y;
  const int q0 = blockIdx.x * 128;
  const int tid = threadIdx.x;
  const int warp = tid >> 5, lane = tid & 31;
  const int gid = lane >> 2, tig = lane & 3;

  const int dr = tid >> 2;

  {
    const int qc = (tid & 3) * 32;
    const size_t off = ((size_t)bh * PDH + dr) * PL + q0 + qc;
    const uint32_t hd = sptr(&Qh[dr * SPA_S + qc]);
    const uint32_t ld = sptr(&Ql[dr * SPA_S + qc]);
#pragma unroll
    for (int j = 0; j < 8; j++) CP16(hd + j * 16, g_qthi + off + j * 4);
#pragma unroll
    for (int j = 0; j < 8; j++) CP16(ld + j * 16, g_qtlo + off + j * 4);
  }
  const int kc = (tid & 3) * 8;
  auto issueK = [&](int kt, int bf) {
    const size_t off = ((size_t)bh * PDH + dr) * PL + kt * 32 + kc;
    const uint32_t so = bf * 64 * SPK_S + dr * SPK_S + kc;
    CP16(sptr(&Kh[so]), g_kthi + off); CP16(sptr(&Kh[so]) + 16, g_kthi + off + 4);
    CP16(sptr(&Kl[so]), g_ktlo + off); CP16(sptr(&Kl[so]) + 16, g_ktlo + off + 4);
    CP_COMMIT();
  };
  issueK(0, 0);

  float rmax0 = -1e30f, rsum0 = 0.f, rmax1 = -1e30f, rsum1 = 0.f;
  const int rbase = warp * 16;

#pragma unroll 1
  for (int kt = 0; kt < PL / 32; kt++) {
    const int buf = kt & 1;
    if (kt + 1 < PL / 32) { issueK(kt + 1, buf ^ 1); CP_WAIT1(); }
    else                  { CP_WAIT0(); }
    __syncthreads();

    const uint32_t* kh = Kh + buf * 64 * SPK_S;
    const uint32_t* kl = Kl + buf * 64 * SPK_S;

    float c[4][4];
#pragma unroll
    for (int nb = 0; nb < 4; nb++)
#pragma unroll
      for (int j = 0; j < 4; j++) c[nb][j] = 0.f;

#pragma unroll
    for (int ks = 0; ks < 8; ks++) {
      const int k0 = ks * 8;
      uint32_t ahi[4], alo[4];
      ahi[0] = Qh[(k0 + tig)     * SPA_S + rbase + gid];
      ahi[1] = Qh[(k0 + tig)     * SPA_S + rbase + gid + 8];
      ahi[2] = Qh[(k0 + tig + 4) * SPA_S + rbase + gid];
      ahi[3] = Qh[(k0 + tig + 4) * SPA_S + rbase + gid + 8];
      alo[0] = Ql[(k0 + tig)     * SPA_S + rbase + gid];
      alo[1] = Ql[(k0 + tig)     * SPA_S + rbase + gid + 8];
      alo[2] = Ql[(k0 + tig + 4) * SPA_S + rbase + gid];
      alo[3] = Ql[(k0 + tig + 4) * SPA_S + rbase + gid + 8];
#pragma unroll
      for (int nb = 0; nb < 4; nb++) {
        const int n = nb * 8 + gid;
        const uint32_t bh0 = kh[(k0 + tig)     * SPK_S + n];
        const uint32_t bh1 = kh[(k0 + tig + 4) * SPK_S + n];
        const uint32_t bl0 = kl[(k0 + tig)     * SPK_S + n];
        const uint32_t bl1 = kl[(k0 + tig + 4) * SPK_S + n];
        mma_tf32(c[nb], ahi[0], ahi[1], ahi[2], ahi[3], bh0, bh1);
        mma_tf32(c[nb], ahi[0], ahi[1], ahi[2], ahi[3], bl0, bl1);
        mma_tf32(c[nb], alo[0], alo[1], alo[2], alo[3], bh0, bh1);
      }
    }

    float mx0 = -1e30f, sm0 = 0.f, mx1 = -1e30f, sm1 = 0.f;
#pragma unroll
    for (int nb = 0; nb < 4; nb++) {
      mx0 = fmaxf(mx0, fmaxf(c[nb][0], c[nb][1]));
      sm0 += c[nb][0] + c[nb][1];
      mx1 = fmaxf(mx1, fmaxf(c[nb][2], c[nb][3]));
      sm1 += c[nb][2] + c[nb][3];
    }
    rmax0 = fmaxf(rmax0, mx0); rsum0 += sm0;
    rmax1 = fmaxf(rmax1, mx1); rsum1 += sm1;
    __syncthreads();
  }

#pragma unroll
  for (int off = 1; off <= 2; off <<= 1) {
    rmax0 = fmaxf(rmax0, __shfl_xor_sync(0xffffffffu, rmax0, off));
    rsum0 += __shfl_xor_sync(0xffffffffu, rsum0, off);
    rmax1 = fmaxf(rmax1, __shfl_xor_sync(0xffffffffu, rmax1, off));
    rsum1 += __shfl_xor_sync(0xffffffffu, rsum1, off);
  }
  const float scale = 0.125f;
  if (tig == 0) {
    const int r0 = q0 + warp * 16 + gid;
    g_spars[(size_t)bh * PL + r0]     = scale * rmax0 - scale * rsum0 * (1.0f / PL);
    g_spars[(size_t)bh * PL + r0 + 8] = scale * rmax1 - scale * rsum1 * (1.0f / PL);
  }
}

// ============================================================
// Exact top-U via radix select (unchanged).
// ============================================================
__global__ __launch_bounds__(256) void topk_radix() {
  __shared__ unsigned su[2048];
  __shared__ int hist[256];
  __shared__ unsigned s_pref;
  __shared__ int s_rem;
  __shared__ unsigned eqm[64];
  __shared__ int wpfx[64];
  __shared__ int outcnt;

  const int bh = blockIdx.x;
  const int tid = threadIdx.x;

  for (int t = tid; t < 2048; t += 256) {
    unsigned b = __float_as_uint(g_spars[(size_t)bh * PL + t]);
    su[t] = (b & 0x80000000u) ? ~b : (b | 0x80000000u);
  }
  if (tid == 0) { s_pref = 0u; s_rem = PU; outcnt = 0; }
  if (tid < 64) eqm[tid] = 0u;
  __syncthreads();

  for (int shift = 24; shift >= 0; shift -= 8) {
    hist[tid & 255] = 0;
    __syncthreads();
    const unsigned pref = s_pref;
    for (int t = tid; t < 2048; t += 256) {
      const unsigned u = su[t];
      if (shift == 24 || (u >> (shift + 8)) == pref)
        atomicAdd(&hist[(u >> shift) & 255], 1);
    }
    __syncthreads();
    if (tid == 0) {
      int rem = s_rem, acc = 0;
      for (int b = 255; b >= 0; b--) {
        if (acc + hist[b] >= rem) {
          s_rem = rem - acc;
          s_pref = (s_pref << 8) | (unsigned)b;
          break;
        }
        acc += hist[b];
      }
    }
    __syncthreads();
  }

  const unsigned T = s_pref;
  const int e = s_rem;

  for (int t = tid; t < 2048; t += 256)
    if (su[t] == T) atomicOr(&eqm[t >> 5], 1u << (t & 31));
  __syncthreads();
  if (tid == 0) {
    int a = 0;
    for (int w = 0; w < 64; w++) { wpfx[w] = a; a += __popc(eqm[w]); }
  }
  __syncthreads();

  for (int t = tid; t < 2048; t += 256) {
    const unsigned u = su[t];
    bool sel = (u > T);
    if (u == T) {
      const int rank = wpfx[t >> 5] + __popc(eqm[t >> 5] & ((1u << (t & 31)) - 1u));
      sel = (rank < e);
    }
    if (sel) {
      const int slot = atomicAdd(&outcnt, 1);
      g_topidx[(size_t)bh * PU + slot] = t;
    }
  }
}

// ============================================================
// Zero the scatter buffer.
// ============================================================
__global__ void zero_attn_kernel() {
  const size_t i = (size_t)blockIdx.x * blockDim.x + threadIdx.x;
  float4 z = {0.f, 0.f, 0.f, 0.f};
  ((float4*)g_attn)[i] = z;
}

// ============================================================
// Flash v4 (unchanged from R8).
// ============================================================
#define FL_KOFF (64 * 132)
#define FL_VOFF (64 * 132 + 64 * 68)
#define FL_POFF (64 * 132 + 2 * 64 * 68)
#define FL_SMEM ((64 * 132 + 2 * 64 * 68 + 128 * 68) * (int)sizeof(float))

__global__ __launch_bounds__(256, 2) void flash_v4() {
  extern __shared__ float sm_fl[];
  float* Qs = sm_fl;
  float* Ks = sm_fl + FL_KOFF;
  float* Vs = sm_fl + FL_VOFF;
  float* Ps = sm_fl + FL_POFF;
  __shared__ int qidx[128];

  const int bh = blockIdx.y;
  const int qt = blockIdx.x;
  const int tid = threadIdx.x;
  const int tx = tid & 15, ty = tid >> 4;
  const float scale = 0.125f;

  if (tid < 128) {
    const int u = qt * 128 + tid;
    qidx[tid] = (u < PU) ? g_topidx[(size_t)bh * PU + u] : -1;
  }
  __syncthreads();

  {
    const int r = tid >> 1, c0 = (tid & 1) * 32;
    int src = qidx[r];
    if (src < 0) src = 0;
    const float* qrow = g_q + ((size_t)bh * PL + src) * PDH + c0;
#pragma unroll
    for (int c = 0; c < 32; c += 4) {
      float4 v = *(const float4*)(qrow + c);
      Qs[(c0 + c + 0) * 132 + r] = v.x;
      Qs[(c0 + c + 1) * 132 + r] = v.y;
      Qs[(c0 + c + 2) * 132 + r] = v.z;
      Qs[(c0 + c + 3) * 132 + r] = v.w;
    }
  }

  float m_run[8], l_run[8];
  unsigned long long o2[8][2];
#pragma unroll
  for (int i = 0; i < 8; i++) {
    m_run[i] = -1e30f; l_run[i] = 0.f;
    o2[i][0] = 0ull; o2[i][1] = 0ull;
  }

  const int rr = tid >> 2;
  const int sg = (tid & 3) * 16;

#pragma unroll 1
  for (int kt = 0; kt < PL / 64; kt++) {
    __syncthreads();
    {
      const float* ksrc = g_kt + ((size_t)bh * PDH + rr) * PL + kt * 64 + sg;
      const float* vsrc = g_v + ((size_t)bh * PL + kt * 64 + rr) * PDH + sg;
      const uint32_t kdst = sptr(&Ks[rr * 68 + sg]);
      const uint32_t vdst = sptr(&Vs[rr * 68 + sg]);
#pragma unroll
      for (int j = 0; j < 4; j++) CP16(kdst + j * 16, ksrc + j * 4);
#pragma unroll
      for (int j = 0; j < 4; j++) CP16(vdst + j * 16, vsrc + j * 4);
      CP_COMMIT();
      CP_WAIT0();
    }
    __syncthreads();

    unsigned long long s2[4][4];
#pragma unroll
    for (int p = 0; p < 4; p++)
#pragma unroll
      for (int j = 0; j < 4; j++) s2[p][j] = 0ull;
#pragma unroll 8
    for (int d = 0; d < 64; d++) {
      ulonglong2 ap0 = *(const ulonglong2*)&Qs[d * 132 + ty * 4];
      ulonglong2 ap1 = *(const ulonglong2*)&Qs[d * 132 + 64 + ty * 4];
      float4 bv = *(const float4*)&Ks[d * 68 + tx * 4];
      unsigned long long b0 = pk2(bv.x, bv.x), b1 = pk2(bv.y, bv.y);
      unsigned long long b2 = pk2(bv.z, bv.z), b3 = pk2(bv.w, bv.w);
      s2[0][0] = fma2(ap0.x, b0, s2[0][0]);
      s2[0][1] = fma2(ap0.x, b1, s2[0][1]);
      s2[0][2] = fma2(ap0.x, b2, s2[0][2]);
      s2[0][3] = fma2(ap0.x, b3, s2[0][3]);
      s2[1][0] = fma2(ap0.y, b0, s2[1][0]);
      s2[1][1] = fma2(ap0.y, b1, s2[1][1]);
      s2[1][2] = fma2(ap0.y, b2, s2[1][2]);
      s2[1][3] = fma2(ap0.y, b3, s2[1][3]);
      s2[2][0] = fma2(ap1.x, b0, s2[2][0]);
      s2[2][1] = fma2(ap1.x, b1, s2[2][1]);
      s2[2][2] = fma2(ap1.x, b2, s2[2][2]);
      s2[2][3] = fma2(ap1.x, b3, s2[2][3]);
      s2[3][0] = fma2(ap1.y, b0, s2[3][0]);
      s2[3][1] = fma2(ap1.y, b1, s2[3][1]);
      s2[3][2] = fma2(ap1.y, b2, s2[3][2]);
      s2[3][3] = fma2(ap1.y, b3, s2[3][3]);
    }
    float s[8][4];
#pragma unroll
    for (int p = 0; p < 4; p++)
#pragma unroll
      for (int j = 0; j < 4; j++)
        upk2(s2[p][j], s[2 * p][j], s[2 * p + 1][j]);

#pragma unroll
    for (int i = 0; i < 8; i++) {
      float tm = fmaxf(fmaxf(s[i][0], s[i][1]), fmaxf(s[i][2], s[i][3])) * scale;
#pragma unroll
      for (int off = 8; off; off >>= 1)
        tm = fmaxf(tm, __shfl_xor_sync(0xffffffffu, tm, off));
      const float mn = fmaxf(m_run[i], tm);
      const float alpha = __expf(m_run[i] - mn);
      m_run[i] = mn;
      float ts = 0.f;
#pragma unroll
      for (int j = 0; j < 4; j++) {
        const float pv = __expf(s[i][j] * scale - mn);
        s[i][j] = pv;
        ts += pv;
      }
#pragma unroll
      for (int off = 8; off; off >>= 1)
        ts += __shfl_xor_sync(0xffffffffu, ts, off);
      l_run[i] = l_run[i] * alpha + ts;
      const unsigned long long ad = pk2(alpha, alpha);
      o2[i][0] = mul2(o2[i][0], ad);
      o2[i][1] = mul2(o2[i][1], ad);
    }

#pragma unroll
    for (int i = 0; i < 8; i++) {
      const int ri = ty * 4 + (i & 3) + ((i >> 2) << 6);
      float4 pv = {s[i][0], s[i][1], s[i][2], s[i][3]};
      *(float4*)&Ps[ri * 68 + tx * 4] = pv;
    }
    __syncthreads();

#pragma unroll 4
    for (int k4 = 0; k4 < 64; k4 += 4) {
      ulonglong2 w0 = *(const ulonglong2*)&Vs[(k4 + 0) * 68 + tx * 4];
      ulonglong2 w1 = *(const ulonglong2*)&Vs[(k4 + 1) * 68 + tx * 4];
      ulonglong2 w2 = *(const ulonglong2*)&Vs[(k4 + 2) * 68 + tx * 4];
      ulonglong2 w3 = *(const ulonglong2*)&Vs[(k4 + 3) * 68 + tx * 4];
#pragma unroll
      for (int i = 0; i < 8; i++) {
        const int ri = ty * 4 + (i & 3) + ((i >> 2) << 6);
        float4 pk = *(const float4*)&Ps[ri * 68 + k4];
        const unsigned long long p0 = pk2(pk.x, pk.x);
        const unsigned long long p1 = pk2(pk.y, pk.y);
        const unsigned long long p2 = pk2(pk.z, pk.z);
        const unsigned long long p3 = pk2(pk.w, pk.w);
        o2[i][0] = fma2(p0, w0.x, o2[i][0]);
        o2[i][1] = fma2(p0, w0.y, o2[i][1]);
        o2[i][0] = fma2(p1, w1.x, o2[i][0]);
        o2[i][1] = fma2(p1, w1.y, o2[i][1]);
        o2[i][0] = fma2(p2, w2.x, o2[i][0]);
        o2[i][1] = fma2(p2, w2.y, o2[i][1]);
        o2[i][0] = fma2(p3, w3.x, o2[i][0]);
        o2[i][1] = fma2(p3, w3.y, o2[i][1]);
      }
    }
  }

  const int b = bh >> 4, h = bh & 15;
#pragma unroll
  for (int i = 0; i < 8; i++) {
    const int ri = ty * 4 + (i & 3) + ((i >> 2) << 6);
    const int src = qidx[ri];
    if (src >= 0) {
      const float inv = 1.0f / l_run[i];
      float o0, o1, o2v, o3;
      upk2(o2[i][0], o0, o1);
      upk2(o2[i][1], o2v, o3);
      float4 ov = {o0 * inv, o1 * inv, o2v * inv, o3 * inv};
      *(float4*)&g_attn[((size_t)b * PL + src) * PD + h * PDH + tx * 4] = ov;
    }
  }
}

// ============================================================
// host launcher
// ============================================================
extern "C" void kernel_launch(void* const* d_in, const int* in_sizes, int n_in,
                              void* d_out, int out_size) {
  (void)in_sizes; (void)n_in; (void)out_size;
  const float* x  = (const float*)d_in[0];
  const float* Wq = (const float*)d_in[1];
  const float* bq = (const float*)d_in[2];
  const float* Wk = (const float*)d_in[3];
  const float* bk = (const float*)d_in[4];
  const float* Wv = (const float*)d_in[5];
  const float* bv = (const float*)d_in[6];
  const float* Wo = (const float*)d_in[7];
  const float* bo = (const float*)d_in[8];
  float* out = (float*)d_out;

  float *pq, *pk, *pv, *pkt, *pqtf, *pattn;
  uint32_t *pkthi, *pktlo, *pqthi, *pqtlo, *pwhi, *pwlo, *pxthi, *pxtlo;
  __nv_bfloat16 *pxbh, *pxbl, *pabh, *pabl, *pwvth, *pwvtl, *pwoth, *pwotl;
  cudaGetSymbolAddress((void**)&pq, g_q);
  cudaGetSymbolAddress((void**)&pk, g_k);
  cudaGetSymbolAddress((void**)&pv, g_v);
  cudaGetSymbolAddress((void**)&pkt, g_kt);
  cudaGetSymbolAddress((void**)&pqtf, g_qtf);
  cudaGetSymbolAddress((void**)&pkthi, g_kthi);
  cudaGetSymbolAddress((void**)&pktlo, g_ktlo);
  cudaGetSymbolAddress((void**)&pqthi, g_qthi);
  cudaGetSymbolAddress((void**)&pqtlo, g_qtlo);
  cudaGetSymbolAddress((void**)&pwhi, g_whi);
  cudaGetSymbolAddress((void**)&pwlo, g_wlo);
  cudaGetSymbolAddress((void**)&pxthi, g_xthi);
  cudaGetSymbolAddress((void**)&pxtlo, g_xtlo);
  cudaGetSymbolAddress((void**)&pxbh, g_xbh);
  cudaGetSymbolAddress((void**)&pxbl, g_xbl);
  cudaGetSymbolAddress((void**)&pabh, g_abh);
  cudaGetSymbolAddress((void**)&pabl, g_abl);
  cudaGetSymbolAddress((void**)&pwvth, g_wvth);
  cudaGetSymbolAddress((void**)&pwvtl, g_wvtl);
  cudaGetSymbolAddress((void**)&pwoth, g_woth);
  cudaGetSymbolAddress((void**)&pwotl, g_wotl);
  cudaGetSymbolAddress((void**)&pattn, g_attn);

  cudaFuncSetAttribute(gemm_qk, cudaFuncAttributeMaxDynamicSharedMemorySize, GEMM_SMEM);
  cudaFuncSetAttribute(gemm_bf16<0>, cudaFuncAttributeMaxDynamicSharedMemorySize, GBF_SMEM);
  cudaFuncSetAttribute(gemm_bf16<1>, cudaFuncAttributeMaxDynamicSharedMemorySize, GBF_SMEM);
  cudaFuncSetAttribute(sparsity_v6, cudaFuncAttributeMaxDynamicSharedMemorySize, SP_SMEM);
  cudaFuncSetAttribute(flash_v4, cudaFuncAttributeMaxDynamicSharedMemorySize, FL_SMEM);

  const size_t WN = (size_t)PD * PD;
  const int n4w = (int)(WN / 4);
  const int n4x = (int)((size_t)PM * PD / 4);

  // tf32 pre-splits for selection-critical path (Q/K)
  split_kernel<<<(n4w + 255) / 256, 256>>>(Wq, pwhi + 0 * WN, pwlo + 0 * WN, n4w);
  split_kernel<<<(n4w + 255) / 256, 256>>>(Wk, pwhi + 1 * WN, pwlo + 1 * WN, n4w);
  transpose_split<<<dim3(PM / 32, PD / 32), 256>>>(x, pxthi, pxtlo, PM, PD);

  // bf16 pre-splits for value path (V / Wo)
  split_bf16_kernel<<<(n4x + 255) / 256, 256>>>(x, pxbh, pxbl, n4x);
  transpose_split_bf16<<<dim3(PD / 32, PD / 32), 256>>>(Wv, pwvth, pwvtl, PD, PD);
  transpose_split_bf16<<<dim3(PD / 32, PD / 32), 256>>>(Wo, pwoth, pwotl, PD, PD);

  // fused Q+K projection (tf32x3) and V projection (bf16x2 3-term)
  gemm_qk<<<dim3(2 * PD / 128, PM / 128), 256, GEMM_SMEM>>>(
      pxthi, pxtlo, pwhi + 0 * WN, pwlo + 0 * WN, pwhi + 1 * WN, pwlo + 1 * WN,
      bq, bk, pq, pk);
  gemm_bf16<1><<<dim3(PD / 128, PM / 128), 256, GBF_SMEM>>>(
      pxbh, pxbl, pwvth, pwvtl, bv, pv, PM, PD, PD);

  // head transposes + tf32 splits
  const dim3 gT(PL / 32, PDH / 32, PBH);
  transpose_head_split<<<gT, 256>>>(pk, pkt, pkthi, pktlo);
  transpose_head_split<<<gT, 256>>>(pq, pqtf, pqthi, pqtlo);

  // sparsity + selection
  sparsity_v6<<<dim3(PL / 128, PBH), 256, SP_SMEM>>>();
  topk_radix<<<PBH, 256>>>();

  // attention on selected rows
  zero_attn_kernel<<<(PB * PL * PD / 4) / 256, 256>>>();
  flash_v4<<<dim3((PU + 127) / 128, PBH), 256, FL_SMEM>>>();

  // output projection (bf16x2 3-term)
  split_bf16_kernel<<<(n4x + 255) / 256, 256>>>(pattn, pabh, pabl, n4x);
  gemm_bf16<0><<<dim3(PD / 128, PM / 128), 256, GBF_SMEM>>>(
      pabh, pabl, pwoth, pwotl, bo, out, PM, PD, PD);
}

// round 11
// speedup vs baseline: 2.0739x; 1.3075x over previous
#include <cuda_runtime.h>
#include <cuda_bf16.h>
#include <cstdint>

// ---------------- problem constants ----------------
#define PB 2
#define PL 2048
#define PD 1024
#define PH 16
#define PDH 64
#define PU 1228          // int(0.6 * 2048)
#define PBH (PB * PH)    // 32
#define PM (PB * PL)     // 4096 rows

// ---------------- device scratch (no allocation allowed) ----------------
__device__ float g_q [(size_t)PBH * PL * PDH];   // [b,h,l,dh]
__device__ float g_k [(size_t)PBH * PL * PDH];
__device__ float g_v [(size_t)PBH * PL * PDH];
__device__ float g_kt[(size_t)PBH * PDH * PL];   // [b,h,dh,l] fp32 (legacy)
__device__ float g_qtf[(size_t)PBH * PDH * PL];  // scratch fp32 (unused)
__device__ uint32_t g_kthi[(size_t)PBH * PDH * PL];
__device__ uint32_t g_ktlo[(size_t)PBH * PDH * PL];
__device__ uint32_t g_qthi[(size_t)PBH * PDH * PL];
__device__ uint32_t g_qtlo[(size_t)PBH * PDH * PL];
__device__ uint32_t g_whi[(size_t)2 * PD * PD];  // Wq,Wk tf32 pre-split
__device__ uint32_t g_wlo[(size_t)2 * PD * PD];
__device__ uint32_t g_xthi[(size_t)PD * PM];     // x^T K-major tf32
__device__ uint32_t g_xtlo[(size_t)PD * PM];
// bf16 operands
__device__ __nv_bfloat16 g_xbh[(size_t)PM * PD];   // x row-major bf16 hi
__device__ __nv_bfloat16 g_xbl[(size_t)PM * PD];
__device__ __nv_bfloat16 g_abh[(size_t)PM * PD];   // attn row-major bf16 hi
__device__ __nv_bfloat16 g_abl[(size_t)PM * PD];
__device__ __nv_bfloat16 g_wvth[(size_t)PD * PD];  // Wv^T [N][K] bf16
__device__ __nv_bfloat16 g_wvtl[(size_t)PD * PD];
__device__ __nv_bfloat16 g_woth[(size_t)PD * PD];  // Wo^T [N][K] bf16
__device__ __nv_bfloat16 g_wotl[(size_t)PD * PD];
__device__ __nv_bfloat16 g_kbh[(size_t)PBH * PL * PDH];  // K row-major bf16 hi
__device__ __nv_bfloat16 g_kbl[(size_t)PBH * PL * PDH];
__device__ __nv_bfloat16 g_vth[(size_t)PBH * PDH * PL];  // V^T [bh][dh][l] bf16 hi
__device__ __nv_bfloat16 g_vtl[(size_t)PBH * PDH * PL];
__device__ float g_spars[(size_t)PBH * PL];
__device__ int   g_topidx[(size_t)PBH * PU];
__device__ float g_attn[(size_t)PB * PL * PD];   // pre-output-proj, [b,l,d]

// ---------------- cp.async helpers ----------------
#define CP16(dst_u32, src_ptr) \
  asm volatile("cp.async.cg.shared.global [%0], [%1], 16;\n" :: "r"(dst_u32), "l"(src_ptr))
#define CP_COMMIT() asm volatile("cp.async.commit_group;\n" ::)
#define CP_WAIT0()  asm volatile("cp.async.wait_group 0;\n" ::)
#define CP_WAIT1()  asm volatile("cp.async.wait_group 1;\n" ::)

static __device__ __forceinline__ uint32_t sptr(const void* p) {
  return (uint32_t)__cvta_generic_to_shared(p);
}

// ---------------- tf32 / bf16 helpers ----------------
static __device__ __forceinline__ void split_tf32(float x, uint32_t& hi, uint32_t& lo) {
  uint32_t h;
  asm("cvt.rna.tf32.f32 %0, %1;" : "=r"(h) : "f"(x));
  uint32_t l;
  asm("cvt.rna.tf32.f32 %0, %1;" : "=r"(l) : "f"(x - __uint_as_float(h)));
  hi = h; lo = l;
}

static __device__ __forceinline__ void split_bf16(float x, __nv_bfloat16& h, __nv_bfloat16& l) {
  h = __float2bfloat16(x);
  l = __float2bfloat16(x - __bfloat162float(h));
}

static __device__ __forceinline__ uint32_t pack_bf16(__nv_bfloat16 a, __nv_bfloat16 b) {
  return (uint32_t)__bfloat16_as_ushort(a) | ((uint32_t)__bfloat16_as_ushort(b) << 16);
}

static __device__ __forceinline__ void mma_tf32(
    float* c, uint32_t a0, uint32_t a1, uint32_t a2, uint32_t a3,
    uint32_t b0, uint32_t b1) {
  asm volatile(
      "mma.sync.aligned.m16n8k8.row.col.f32.tf32.tf32.f32 "
      "{%0,%1,%2,%3}, {%4,%5,%6,%7}, {%8,%9}, {%0,%1,%2,%3};"
      : "+f"(c[0]), "+f"(c[1]), "+f"(c[2]), "+f"(c[3])
      : "r"(a0), "r"(a1), "r"(a2), "r"(a3), "r"(b0), "r"(b1));
}

static __device__ __forceinline__ void mma_bf16(
    float* c, uint32_t a0, uint32_t a1, uint32_t a2, uint32_t a3,
    uint32_t b0, uint32_t b1) {
  asm volatile(
      "mma.sync.aligned.m16n8k16.row.col.f32.bf16.bf16.f32 "
      "{%0,%1,%2,%3}, {%4,%5,%6,%7}, {%8,%9}, {%0,%1,%2,%3};"
      : "+f"(c[0]), "+f"(c[1]), "+f"(c[2]), "+f"(c[3])
      : "r"(a0), "r"(a1), "r"(a2), "r"(a3), "r"(b0), "r"(b1));
}

// ============================================================
// Elementwise splits.
// ============================================================
__global__ __launch_bounds__(256) void split_kernel(
    const float* __restrict__ in, uint32_t* __restrict__ hi,
    uint32_t* __restrict__ lo, int n4) {
  const int i = blockIdx.x * 256 + threadIdx.x;
  if (i >= n4) return;
  float4 v = ((const float4*)in)[i];
  uint4 h, l;
  split_tf32(v.x, h.x, l.x);
  split_tf32(v.y, h.y, l.y);
  split_tf32(v.z, h.z, l.z);
  split_tf32(v.w, h.w, l.w);
  ((uint4*)hi)[i] = h;
  ((uint4*)lo)[i] = l;
}

__global__ __launch_bounds__(256) void split_bf16_kernel(
    const float* __restrict__ in, __nv_bfloat16* __restrict__ hi,
    __nv_bfloat16* __restrict__ lo, int n4) {
  const int i = blockIdx.x * 256 + threadIdx.x;
  if (i >= n4) return;
  float4 v = ((const float4*)in)[i];
  __nv_bfloat16 h[4], l[4];
  split_bf16(v.x, h[0], l[0]);
  split_bf16(v.y, h[1], l[1]);
  split_bf16(v.z, h[2], l[2]);
  split_bf16(v.w, h[3], l[3]);
  uint2 hp, lp;
  hp.x = pack_bf16(h[0], h[1]);
  hp.y = pack_bf16(h[2], h[3]);
  lp.x = pack_bf16(l[0], l[1]);
  lp.y = pack_bf16(l[2], l[3]);
  ((uint2*)hi)[i] = hp;
  ((uint2*)lo)[i] = lp;
}

// ============================================================
// Transpose + tf32 split: in[M][N] fp32 -> [N][M] tf32 hi/lo.
// ============================================================
__global__ __launch_bounds__(256) void transpose_split(
    const float* __restrict__ in, uint32_t* __restrict__ ohi,
    uint32_t* __restrict__ olo, int M, int N) {
  __shared__ float t[32][33];
  const int m0 = blockIdx.x * 32, n0 = blockIdx.y * 32;
  const int x = threadIdx.x & 31, y = threadIdx.x >> 5;
#pragma unroll
  for (int k = 0; k < 4; k++)
    t[y + 8 * k][x] = in[(size_t)(m0 + y + 8 * k) * N + n0 + x];
  __syncthreads();
#pragma unroll
  for (int k = 0; k < 4; k++) {
    const float v = t[x][y + 8 * k];
    uint32_t h, l;
    split_tf32(v, h, l);
    const size_t idx = (size_t)(n0 + y + 8 * k) * M + m0 + x;
    ohi[idx] = h;
    olo[idx] = l;
  }
}

// ============================================================
// Transpose + bf16 split: in[M][N] fp32 -> [N][M] bf16 hi/lo.
// ============================================================
__global__ __launch_bounds__(256) void transpose_split_bf16(
    const float* __restrict__ in, __nv_bfloat16* __restrict__ ohi,
    __nv_bfloat16* __restrict__ olo, int M, int N) {
  __shared__ float t[32][33];
  const int m0 = blockIdx.x * 32, n0 = blockIdx.y * 32;
  const int x = threadIdx.x & 31, y = threadIdx.x >> 5;
#pragma unroll
  for (int k = 0; k < 4; k++)
    t[y + 8 * k][x] = in[(size_t)(m0 + y + 8 * k) * N + n0 + x];
  __syncthreads();
#pragma unroll
  for (int k = 0; k < 4; k++) {
    const float v = t[x][y + 8 * k];
    __nv_bfloat16 h, l;
    split_bf16(v, h, l);
    const size_t idx = (size_t)(n0 + y + 8 * k) * M + m0 + x;
    ohi[idx] = h;
    olo[idx] = l;
  }
}

// ============================================================
// Head transpose + tf32 split: [bh][l][dh] -> [bh][dh][l].
// ============================================================
__global__ __launch_bounds__(256) void transpose_head_split(
    const float* __restrict__ in, float* __restrict__ out,
    uint32_t* __restrict__ ohi, uint32_t* __restrict__ olo) {
  __shared__ float t[32][33];
  const int bh = blockIdx.z;
  const int l0 = blockIdx.x * 32, d0 = blockIdx.y * 32;
  const int x = threadIdx.x & 31, y = threadIdx.x >> 5;
  const float* ip = in + (size_t)bh * PL * PDH;
#pragma unroll
  for (int k = 0; k < 4; k++)
    t[y + 8 * k][x] = ip[(size_t)(l0 + y + 8 * k) * PDH + d0 + x];
  __syncthreads();
  const size_t base = (size_t)bh * PDH * PL;
#pragma unroll
  for (int k = 0; k < 4; k++) {
    const float v = t[x][y + 8 * k];
    const size_t idx = base + (size_t)(d0 + y + 8 * k) * PL + l0 + x;
    out[idx] = v;
    uint32_t h, l;
    split_tf32(v, h, l);
    ohi[idx] = h;
    olo[idx] = l;
  }
}

// ============================================================
// Head transpose + bf16 split: [bh][l][dh] -> [bh][dh][l] bf16.
// ============================================================
__global__ __launch_bounds__(256) void transpose_head_bf16(
    const float* __restrict__ in, __nv_bfloat16* __restrict__ ohi,
    __nv_bfloat16* __restrict__ olo) {
  __shared__ float t[32][33];
  const int bh = blockIdx.z;
  const int l0 = blockIdx.x * 32, d0 = blockIdx.y * 32;
  const int x = threadIdx.x & 31, y = threadIdx.x >> 5;
  const float* ip = in + (size_t)bh * PL * PDH;
#pragma unroll
  for (int k = 0; k < 4; k++)
    t[y + 8 * k][x] = ip[(size_t)(l0 + y + 8 * k) * PDH + d0 + x];
  __syncthreads();
  const size_t base = (size_t)bh * PDH * PL;
#pragma unroll
  for (int k = 0; k < 4; k++) {
    const float v = t[x][y + 8 * k];
    __nv_bfloat16 h, l;
    split_bf16(v, h, l);
    const size_t idx = base + (size_t)(d0 + y + 8 * k) * PL + l0 + x;
    ohi[idx] = h;
    olo[idx] = l;
  }
}

// ============================================================
// Fused Q+K projection (tf32x3, selection-critical; unchanged).
// ============================================================
#define GS 136
#define GEMM_SMEM (4 * 2 * 16 * GS * 4)

__global__ __launch_bounds__(256, 2) void gemm_qk(
    const uint32_t* __restrict__ Ahi, const uint32_t* __restrict__ Alo,
    const uint32_t* __restrict__ WhiQ, const uint32_t* __restrict__ WloQ,
    const uint32_t* __restrict__ WhiK, const uint32_t* __restrict__ WloK,
    const float* __restrict__ biasQ, const float* __restrict__ biasK,
    float* __restrict__ CQ, float* __restrict__ CK) {
  extern __shared__ uint32_t smg[];
  uint32_t* Ah = smg;
  uint32_t* Al = Ah + 2 * 16 * GS;
  uint32_t* Bh = Al + 2 * 16 * GS;
  uint32_t* Bl = Bh + 2 * 16 * GS;

  const int HB = PD / 128;
  const bool isK = (blockIdx.x >= HB);
  const uint32_t* Whi = isK ? WhiK : WhiQ;
  const uint32_t* Wlo = isK ? WloK : WloQ;
  const float* bias = isK ? biasK : biasQ;
  float* C = isK ? CK : CQ;
  const int bn = (isK ? blockIdx.x - HB : blockIdx.x) * 128;

  const int M = PM, N = PD, K = PD;
  const int tid = threadIdx.x;
  const int warp = tid >> 5, lane = tid & 31;
  const int gid = lane >> 2, tig = lane & 3;
  const int wm = warp >> 1, wn = warp & 1;
  const int bm = blockIdx.y * 128;

  const int lr = tid >> 4;
  const int lc = (tid & 15) * 8;

  float c[2][8][4];
#pragma unroll
  for (int mb = 0; mb < 2; mb++)
#pragma unroll
    for (int nb = 0; nb < 8; nb++)
#pragma unroll
      for (int j = 0; j < 4; j++) c[mb][nb][j] = 0.f;

  const int NP = K >> 4;

  auto issue = [&](int p, int bf) {
    const size_t arow = (size_t)(p * 16 + lr) * M + bm + lc;
    const size_t brow = (size_t)(p * 16 + lr) * N + bn + lc;
    const uint32_t so = bf * 16 * GS + lr * GS + lc;
    CP16(sptr(&Ah[so]), Ahi + arow); CP16(sptr(&Ah[so]) + 16, Ahi + arow + 4);
    CP16(sptr(&Al[so]), Alo + arow); CP16(sptr(&Al[so]) + 16, Alo + arow + 4);
    CP16(sptr(&Bh[so]), Whi + brow); CP16(sptr(&Bh[so]) + 16, Whi + brow + 4);
    CP16(sptr(&Bl[so]), Wlo + brow); CP16(sptr(&Bl[so]) + 16, Wlo + brow + 4);
    CP_COMMIT();
  };

  issue(0, 0);

#pragma unroll 1
  for (int p = 0; p < NP; p++) {
    const int buf = p & 1;
    if (p + 1 < NP) { issue(p + 1, buf ^ 1); CP_WAIT1(); }
    else            { CP_WAIT0(); }
    __syncthreads();

    const uint32_t* ah = Ah + buf * 16 * GS;
    const uint32_t* al = Al + buf * 16 * GS;
    const uint32_t* bhp = Bh + buf * 16 * GS;
    const uint32_t* blp = Bl + buf * 16 * GS;

#pragma unroll
    for (int ks = 0; ks < 2; ks++) {
      const int k0 = ks * 8;
      uint32_t ahi[2][4], alo[2][4];
#pragma unroll
      for (int mb = 0; mb < 2; mb++) {
        const int r = wm * 32 + mb * 16;
        ahi[mb][0] = ah[(k0 + tig)     * GS + r + gid];
        ahi[mb][1] = ah[(k0 + tig)     * GS + r + gid + 8];
        ahi[mb][2] = ah[(k0 + tig + 4) * GS + r + gid];
        ahi[mb][3] = ah[(k0 + tig + 4) * GS + r + gid + 8];
        alo[mb][0] = al[(k0 + tig)     * GS + r + gid];
        alo[mb][1] = al[(k0 + tig)     * GS + r + gid + 8];
        alo[mb][2] = al[(k0 + tig + 4) * GS + r + gid];
        alo[mb][3] = al[(k0 + tig + 4) * GS + r + gid + 8];
      }
#pragma unroll
      for (int nb = 0; nb < 8; nb++) {
        const int n = wn * 64 + nb * 8 + gid;
        const uint32_t bh0 = bhp[(k0 + tig)     * GS + n];
        const uint32_t bh1 = bhp[(k0 + tig + 4) * GS + n];
        const uint32_t bl0 = blp[(k0 + tig)     * GS + n];
        const uint32_t bl1 = blp[(k0 + tig + 4) * GS + n];
#pragma unroll
        for (int mb = 0; mb < 2; mb++) {
          mma_tf32(c[mb][nb], ahi[mb][0], ahi[mb][1], ahi[mb][2], ahi[mb][3], bh0, bh1);
          mma_tf32(c[mb][nb], ahi[mb][0], ahi[mb][1], ahi[mb][2], ahi[mb][3], bl0, bl1);
          mma_tf32(c[mb][nb], alo[mb][0], alo[mb][1], alo[mb][2], alo[mb][3], bh0, bh1);
        }
      }
    }
    __syncthreads();
  }

#pragma unroll
  for (int mb = 0; mb < 2; mb++) {
#pragma unroll
    for (int nb = 0; nb < 8; nb++) {
      const int m0 = bm + wm * 32 + mb * 16 + gid;
      const int n0 = bn + wn * 64 + nb * 8 + tig * 2;
      const float bx = bias[n0], by = bias[n0 + 1];
      float2 v0 = {c[mb][nb][0] + bx, c[mb][nb][1] + by};
      float2 v1 = {c[mb][nb][2] + bx, c[mb][nb][3] + by};
      const int h = n0 >> 6, dh = n0 & 63;
      const int b0i = m0 >> 11, l0 = m0 & (PL - 1);
      const int b1i = (m0 + 8) >> 11, l1 = (m0 + 8) & (PL - 1);
      *(float2*)&C[(((size_t)b0i * PH + h) * PL + l0) * PDH + dh] = v0;
      *(float2*)&C[(((size_t)b1i * PH + h) * PL + l1) * PDH + dh] = v1;
    }
  }
}

// ============================================================
// bf16x2 3-term GEMM (unchanged from R9).
// ============================================================
#define GB_S 20
#define GBF_SMEM (4 * 2 * 128 * GB_S * 4)

template<int MODE>
__global__ __launch_bounds__(256, 2) void gemm_bf16(
    const __nv_bfloat16* __restrict__ Agh, const __nv_bfloat16* __restrict__ Agl,
    const __nv_bfloat16* __restrict__ Bgh, const __nv_bfloat16* __restrict__ Bgl,
    const float* __restrict__ bias, float* __restrict__ C,
    int M, int N, int K) {
  extern __shared__ uint32_t smb[];
  uint32_t* Ah = smb;
  uint32_t* Al = Ah + 2 * 128 * GB_S;
  uint32_t* Bh = Al + 2 * 128 * GB_S;
  uint32_t* Bl = Bh + 2 * 128 * GB_S;

  const int tid = threadIdx.x;
  const int warp = tid >> 5, lane = tid & 31;
  const int gid = lane >> 2, tig = lane & 3;
  const int wm = warp >> 1, wn = warp & 1;
  const int bm = blockIdx.y * 128, bn = blockIdx.x * 128;

  const int lr = tid >> 1;
  const int lh = (tid & 1) * 16;

  float c[2][8][4];
#pragma unroll
  for (int mb = 0; mb < 2; mb++)
#pragma unroll
    for (int nb = 0; nb < 8; nb++)
#pragma unroll
      for (int j = 0; j < 4; j++) c[mb][nb][j] = 0.f;

  const int NP = K >> 5;

  auto issue = [&](int p, int bf) {
    const __nv_bfloat16* asrc = Agh + (size_t)(bm + lr) * K + p * 32 + lh;
    const __nv_bfloat16* asrl = Agl + (size_t)(bm + lr) * K + p * 32 + lh;
    const __nv_bfloat16* bsrc = Bgh + (size_t)(bn + lr) * K + p * 32 + lh;
    const __nv_bfloat16* bsrl = Bgl + (size_t)(bn + lr) * K + p * 32 + lh;
    const uint32_t so = (bf * 128 + lr) * GB_S * 4 + lh * 2;
    CP16(sptr(Ah) + so, asrc); CP16(sptr(Ah) + so + 16, asrc + 8);
    CP16(sptr(Al) + so, asrl); CP16(sptr(Al) + so + 16, asrl + 8);
    CP16(sptr(Bh) + so, bsrc); CP16(sptr(Bh) + so + 16, bsrc + 8);
    CP16(sptr(Bl) + so, bsrl); CP16(sptr(Bl) + so + 16, bsrl + 8);
    CP_COMMIT();
  };

  issue(0, 0);

#pragma unroll 1
  for (int p = 0; p < NP; p++) {
    const int buf = p & 1;
    if (p + 1 < NP) { issue(p + 1, buf ^ 1); CP_WAIT1(); }
    else            { CP_WAIT0(); }
    __syncthreads();

    const uint32_t* ah = Ah + buf * 128 * GB_S;
    const uint32_t* al = Al + buf * 128 * GB_S;
    const uint32_t* bhp = Bh + buf * 128 * GB_S;
    const uint32_t* blp = Bl + buf * 128 * GB_S;

#pragma unroll
    for (int kb = 0; kb < 2; kb++) {
      const int ko = kb * 8;
      uint32_t ahi[2][4], alo[2][4];
#pragma unroll
      for (int mb = 0; mb < 2; mb++) {
        const int r = wm * 32 + mb * 16;
        ahi[mb][0] = ah[(r + gid)     * GB_S + ko + tig];
        ahi[mb][1] = ah[(r + gid + 8) * GB_S + ko + tig];
        ahi[mb][2] = ah[(r + gid)     * GB_S + ko + tig + 4];
        ahi[mb][3] = ah[(r + gid + 8) * GB_S + ko + tig + 4];
        alo[mb][0] = al[(r + gid)     * GB_S + ko + tig];
        alo[mb][1] = al[(r + gid + 8) * GB_S + ko + tig];
        alo[mb][2] = al[(r + gid)     * GB_S + ko + tig + 4];
        alo[mb][3] = al[(r + gid + 8) * GB_S + ko + tig + 4];
      }
#pragma unroll
      for (int nb = 0; nb < 8; nb++) {
        const int n = wn * 64 + nb * 8 + gid;
        const uint32_t bh0 = bhp[n * GB_S + ko + tig];
        const uint32_t bh1 = bhp[n * GB_S + ko + tig + 4];
        const uint32_t bl0 = blp[n * GB_S + ko + tig];
        const uint32_t bl1 = blp[n * GB_S + ko + tig + 4];
#pragma unroll
        for (int mb = 0; mb < 2; mb++) {
          mma_bf16(c[mb][nb], ahi[mb][0], ahi[mb][1], ahi[mb][2], ahi[mb][3], bh0, bh1);
          mma_bf16(c[mb][nb], ahi[mb][0], ahi[mb][1], ahi[mb][2], ahi[mb][3], bl0, bl1);
          mma_bf16(c[mb][nb], alo[mb][0], alo[mb][1], alo[mb][2], alo[mb][3], bh0, bh1);
        }
      }
    }
    __syncthreads();
  }

#pragma unroll
  for (int mb = 0; mb < 2; mb++) {
#pragma unroll
    for (int nb = 0; nb < 8; nb++) {
      const int m0 = bm + wm * 32 + mb * 16 + gid;
      const int n0 = bn + wn * 64 + nb * 8 + tig * 2;
      const float bx = bias[n0], by = bias[n0 + 1];
      float2 v0 = {c[mb][nb][0] + bx, c[mb][nb][1] + by};
      float2 v1 = {c[mb][nb][2] + bx, c[mb][nb][3] + by};
      if (MODE == 0) {
        *(float2*)&C[(size_t)m0 * N + n0] = v0;
        *(float2*)&C[(size_t)(m0 + 8) * N + n0] = v1;
      } else {
        const int h = n0 >> 6, dh = n0 & 63;
        const int b0i = m0 >> 11, l0 = m0 & (PL - 1);
        const int b1i = (m0 + 8) >> 11, l1 = (m0 + 8) & (PL - 1);
        *(float2*)&C[(((size_t)b0i * PH + h) * PL + l0) * PDH + dh] = v0;
        *(float2*)&C[(((size_t)b1i * PH + h) * PL + l1) * PDH + dh] = v1;
      }
    }
  }
}

// ============================================================
// Sparsity v6 (unchanged, tf32x3 selection-grade).
// ============================================================
#define SPA_S 136
#define SPK_S 40
#define SP_SMEM ((2 * 64 * SPA_S + 2 * 2 * 64 * SPK_S) * 4)

__global__ __launch_bounds__(256, 2) void sparsity_v6() {
  extern __shared__ uint32_t sm[];
  uint32_t* Qh = sm;
  uint32_t* Ql = Qh + 64 * SPA_S;
  uint32_t* Kh = Ql + 64 * SPA_S;
  uint32_t* Kl = Kh + 2 * 64 * SPK_S;

  const int bh = blockIdx.y;
  const int q0 = blockIdx.x * 128;
  const int tid = threadIdx.x;
  const int warp = tid >> 5, lane = tid & 31;
  const int gid = lane >> 2, tig = lane & 3;

  const int dr = tid >> 2;

  {
    const int qc = (tid & 3) * 32;
    const size_t off = ((size_t)bh * PDH + dr) * PL + q0 + qc;
    const uint32_t hd = sptr(&Qh[dr * SPA_S + qc]);
    const uint32_t ld = sptr(&Ql[dr * SPA_S + qc]);
#pragma unroll
    for (int j = 0; j < 8; j++) CP16(hd + j * 16, g_qthi + off + j * 4);
#pragma unroll
    for (int j = 0; j < 8; j++) CP16(ld + j * 16, g_qtlo + off + j * 4);
  }
  const int kc = (tid & 3) * 8;
  auto issueK = [&](int kt, int bf) {
    const size_t off = ((size_t)bh * PDH + dr) * PL + kt * 32 + kc;
    const uint32_t so = bf * 64 * SPK_S + dr * SPK_S + kc;
    CP16(sptr(&Kh[so]), g_kthi + off); CP16(sptr(&Kh[so]) + 16, g_kthi + off + 4);
    CP16(sptr(&Kl[so]), g_ktlo + off); CP16(sptr(&Kl[so]) + 16, g_ktlo + off + 4);
    CP_COMMIT();
  };
  issueK(0, 0);

  float rmax0 = -1e30f, rsum0 = 0.f, rmax1 = -1e30f, rsum1 = 0.f;
  const int rbase = warp * 16;

#pragma unroll 1
  for (int kt = 0; kt < PL / 32; kt++) {
    const int buf = kt & 1;
    if (kt + 1 < PL / 32) { issueK(kt + 1, buf ^ 1); CP_WAIT1(); }
    else                  { CP_WAIT0(); }
    __syncthreads();

    const uint32_t* kh = Kh + buf * 64 * SPK_S;
    const uint32_t* kl = Kl + buf * 64 * SPK_S;

    float c[4][4];
#pragma unroll
    for (int nb = 0; nb < 4; nb++)
#pragma unroll
      for (int j = 0; j < 4; j++) c[nb][j] = 0.f;

#pragma unroll
    for (int ks = 0; ks < 8; ks++) {
      const int k0 = ks * 8;
      uint32_t ahi[4], alo[4];
      ahi[0] = Qh[(k0 + tig)     * SPA_S + rbase + gid];
      ahi[1] = Qh[(k0 + tig)     * SPA_S + rbase + gid + 8];
      ahi[2] = Qh[(k0 + tig + 4) * SPA_S + rbase + gid];
      ahi[3] = Qh[(k0 + tig + 4) * SPA_S + rbase + gid + 8];
      alo[0] = Ql[(k0 + tig)     * SPA_S + rbase + gid];
      alo[1] = Ql[(k0 + tig)     * SPA_S + rbase + gid + 8];
      alo[2] = Ql[(k0 + tig + 4) * SPA_S + rbase + gid];
      alo[3] = Ql[(k0 + tig + 4) * SPA_S + rbase + gid + 8];
#pragma unroll
      for (int nb = 0; nb < 4; nb++) {
        const int n = nb * 8 + gid;
        const uint32_t bh0 = kh[(k0 + tig)     * SPK_S + n];
        const uint32_t bh1 = kh[(k0 + tig + 4) * SPK_S + n];
        const uint32_t bl0 = kl[(k0 + tig)     * SPK_S + n];
        const uint32_t bl1 = kl[(k0 + tig + 4) * SPK_S + n];
        mma_tf32(c[nb], ahi[0], ahi[1], ahi[2], ahi[3], bh0, bh1);
        mma_tf32(c[nb], ahi[0], ahi[1], ahi[2], ahi[3], bl0, bl1);
        mma_tf32(c[nb], alo[0], alo[1], alo[2], alo[3], bh0, bh1);
      }
    }

    float mx0 = -1e30f, sm0 = 0.f, mx1 = -1e30f, sm1 = 0.f;
#pragma unroll
    for (int nb = 0; nb < 4; nb++) {
      mx0 = fmaxf(mx0, fmaxf(c[nb][0], c[nb][1]));
      sm0 += c[nb][0] + c[nb][1];
      mx1 = fmaxf(mx1, fmaxf(c[nb][2], c[nb][3]));
      sm1 += c[nb][2] + c[nb][3];
    }
    rmax0 = fmaxf(rmax0, mx0); rsum0 += sm0;
    rmax1 = fmaxf(rmax1, mx1); rsum1 += sm1;
    __syncthreads();
  }

#pragma unroll
  for (int off = 1; off <= 2; off <<= 1) {
    rmax0 = fmaxf(rmax0, __shfl_xor_sync(0xffffffffu, rmax0, off));
    rsum0 += __shfl_xor_sync(0xffffffffu, rsum0, off);
    rmax1 = fmaxf(rmax1, __shfl_xor_sync(0xffffffffu, rmax1, off));
    rsum1 += __shfl_xor_sync(0xffffffffu, rsum1, off);
  }
  const float scale = 0.125f;
  if (tig == 0) {
    const int r0 = q0 + warp * 16 + gid;
    g_spars[(size_t)bh * PL + r0]     = scale * rmax0 - scale * rsum0 * (1.0f / PL);
    g_spars[(size_t)bh * PL + r0 + 8] = scale * rmax1 - scale * rsum1 * (1.0f / PL);
  }
}

// ============================================================
// Exact top-U via radix select (unchanged).
// ============================================================
__global__ __launch_bounds__(256) void topk_radix() {
  __shared__ unsigned su[2048];
  __shared__ int hist[256];
  __shared__ unsigned s_pref;
  __shared__ int s_rem;
  __shared__ unsigned eqm[64];
  __shared__ int wpfx[64];
  __shared__ int outcnt;

  const int bh = blockIdx.x;
  const int tid = threadIdx.x;

  for (int t = tid; t < 2048; t += 256) {
    unsigned b = __float_as_uint(g_spars[(size_t)bh * PL + t]);
    su[t] = (b & 0x80000000u) ? ~b : (b | 0x80000000u);
  }
  if (tid == 0) { s_pref = 0u; s_rem = PU; outcnt = 0; }
  if (tid < 64) eqm[tid] = 0u;
  __syncthreads();

  for (int shift = 24; shift >= 0; shift -= 8) {
    hist[tid & 255] = 0;
    __syncthreads();
    const unsigned pref = s_pref;
    for (int t = tid; t < 2048; t += 256) {
      const unsigned u = su[t];
      if (shift == 24 || (u >> (shift + 8)) == pref)
        atomicAdd(&hist[(u >> shift) & 255], 1);
    }
    __syncthreads();
    if (tid == 0) {
      int rem = s_rem, acc = 0;
      for (int b = 255; b >= 0; b--) {
        if (acc + hist[b] >= rem) {
          s_rem = rem - acc;
          s_pref = (s_pref << 8) | (unsigned)b;
          break;
        }
        acc += hist[b];
      }
    }
    __syncthreads();
  }

  const unsigned T = s_pref;
  const int e = s_rem;

  for (int t = tid; t < 2048; t += 256)
    if (su[t] == T) atomicOr(&eqm[t >> 5], 1u << (t & 31));
  __syncthreads();
  if (tid == 0) {
    int a = 0;
    for (int w = 0; w < 64; w++) { wpfx[w] = a; a += __popc(eqm[w]); }
  }
  __syncthreads();

  for (int t = tid; t < 2048; t += 256) {
    const unsigned u = su[t];
    bool sel = (u > T);
    if (u == T) {
      const int rank = wpfx[t >> 5] + __popc(eqm[t >> 5] & ((1u << (t & 31)) - 1u));
      sel = (rank < e);
    }
    if (sel) {
      const int slot = atomicAdd(&outcnt, 1);
      g_topidx[(size_t)bh * PU + slot] = t;
    }
  }
}

// ============================================================
// Zero the scatter buffer.
// ============================================================
__global__ void zero_attn_kernel() {
  const size_t i = (size_t)blockIdx.x * blockDim.x + threadIdx.x;
  float4 z = {0.f, 0.f, 0.f, 0.f};
  ((float4*)g_attn)[i] = z;
}

// ============================================================
// Flash v5: tensor-core attention on selected rows.
// 128 sel q x one bh per CTA; 64-key tiles; m16n8k16 bf16 3-term
// for both S=QK^T and O+=PV. S C-fragments feed PV A-fragments
// directly in registers (no P smem). Online softmax per row via
// quad shfls. cp.async double-buffered K/V.
// smem: Qh/Ql[128][36] + Kh/Kl[2][64][36] + Vh/Vl[2][64][36] u32
//     = 108KB -> 2 CTAs/SM.
// ============================================================
#define FQ_S 36
#define FK_S 36
#define FL_SMEM ((2 * 128 * FQ_S + 4 * 2 * 64 * FK_S) * 4)

__global__ __launch_bounds__(256, 2) void flash_v5() {
  extern __shared__ uint32_t smf[];
  uint32_t* Qh = smf;                      // [128][36]
  uint32_t* Ql = Qh + 128 * FQ_S;
  uint32_t* Kh = Ql + 128 * FQ_S;          // [2][64][36]
  uint32_t* Kl = Kh + 2 * 64 * FK_S;
  uint32_t* Vh = Kl + 2 * 64 * FK_S;       // [2][64][36]
  uint32_t* Vl = Vh + 2 * 64 * FK_S;
  __shared__ int qidx[128];

  const int bh = blockIdx.y, qt = blockIdx.x;
  const int tid = threadIdx.x;
  const int warp = tid >> 5, lane = tid & 31;
  const int gid = lane >> 2, tig = lane & 3;
  const int rbase = warp * 16;
  const float scale = 0.125f;

  if (tid < 128) {
    const int u = qt * 128 + tid;
    qidx[tid] = (u < PU) ? g_topidx[(size_t)bh * PU + u] : -1;
  }
  __syncthreads();

  {  // gather Q rows, split to bf16 hi/lo pairs in smem (row-major dh)
    const int r = tid >> 1, c0 = (tid & 1) * 32;
    int src = qidx[r];
    if (src < 0) src = 0;
    const float* qrow = g_q + ((size_t)bh * PL + src) * PDH + c0;
#pragma unroll
    for (int c = 0; c < 32; c += 2) {
      float2 v = *(const float2*)(qrow + c);
      __nv_bfloat16 h0, l0, h1, l1;
      split_bf16(v.x, h0, l0);
      split_bf16(v.y, h1, l1);
      Qh[r * FQ_S + (c0 + c) / 2] = pack_bf16(h0, h1);
      Ql[r * FQ_S + (c0 + c) / 2] = pack_bf16(l0, l1);
    }
  }

  // cp.async K/V tile loader: 64 keys x 64 dh bf16 hi/lo (+ V^T)
  const int krow = tid >> 2;           // K: key row; V: dh row
  const int sg8 = (tid & 3) * 8;       // u32 segment
  auto issueKV = [&](int kt, int bf) {
    const __nv_bfloat16* ksh = g_kbh + ((size_t)bh * PL + kt * 64 + krow) * PDH + sg8 * 2;
    const __nv_bfloat16* ksl = g_kbl + ((size_t)bh * PL + kt * 64 + krow) * PDH + sg8 * 2;
    const __nv_bfloat16* vsh = g_vth + ((size_t)bh * PDH + krow) * PL + kt * 64 + sg8 * 2;
    const __nv_bfloat16* vsl = g_vtl + ((size_t)bh * PDH + krow) * PL + kt * 64 + sg8 * 2;
    const uint32_t so = ((bf * 64 + krow) * FK_S + sg8) * 4;
    CP16(sptr(Kh) + so, ksh); CP16(sptr(Kh) + so + 16, ksh + 8);
    CP16(sptr(Kl) + so, ksl); CP16(sptr(Kl) + so + 16, ksl + 8);
    CP16(sptr(Vh) + so, vsh); CP16(sptr(Vh) + so + 16, vsh + 8);
    CP16(sptr(Vl) + so, vsl); CP16(sptr(Vl) + so + 16, vsl + 8);
    CP_COMMIT();
  };
  issueKV(0, 0);

  float co[8][4];
#pragma unroll
  for (int nb = 0; nb < 8; nb++)
#pragma unroll
    for (int j = 0; j < 4; j++) co[nb][j] = 0.f;
  float m0 = -1e30f, m1 = -1e30f, lr0 = 0.f, lr1 = 0.f;

#pragma unroll 1
  for (int kt = 0; kt < PL / 64; kt++) {
    const int buf = kt & 1;
    if (kt + 1 < PL / 64) { issueKV(kt + 1, buf ^ 1); CP_WAIT1(); }
    else                  { CP_WAIT0(); }
    __syncthreads();

    const uint32_t* kh = Kh + buf * 64 * FK_S;
    const uint32_t* kl = Kl + buf * 64 * FK_S;
    const uint32_t* vh = Vh + buf * 64 * FK_S;
    const uint32_t* vl = Vl + buf * 64 * FK_S;

    // ---- S = Q . K^T (bf16 3-term) ----
    float cs[8][4];
#pragma unroll
    for (int nb = 0; nb < 8; nb++)
#pragma unroll
      for (int j = 0; j < 4; j++) cs[nb][j] = 0.f;

#pragma unroll
    for (int ks = 0; ks < 4; ks++) {
      const int ko = ks * 8;
      const uint32_t qh0 = Qh[(rbase + gid)     * FQ_S + ko + tig];
      const uint32_t qh1 = Qh[(rbase + gid + 8) * FQ_S + ko + tig];
      const uint32_t qh2 = Qh[(rbase + gid)     * FQ_S + ko + tig + 4];
      const uint32_t qh3 = Qh[(rbase + gid + 8) * FQ_S + ko + tig + 4];
      const uint32_t ql0 = Ql[(rbase + gid)     * FQ_S + ko + tig];
      const uint32_t ql1 = Ql[(rbase + gid + 8) * FQ_S + ko + tig];
      const uint32_t ql2 = Ql[(rbase + gid)     * FQ_S + ko + tig + 4];
      const uint32_t ql3 = Ql[(rbase + gid + 8) * FQ_S + ko + tig + 4];
#pragma unroll
      for (int nb = 0; nb < 8; nb++) {
        const int n = nb * 8 + gid;
        const uint32_t b0 = kh[n * FK_S + ko + tig];
        const uint32_t b1 = kh[n * FK_S + ko + tig + 4];
        const uint32_t c0 = kl[n * FK_S + ko + tig];
        const uint32_t c1 = kl[n * FK_S + ko + tig + 4];
        mma_bf16(cs[nb], qh0, qh1, qh2, qh3, b0, b1);
        mma_bf16(cs[nb], qh0, qh1, qh2, qh3, c0, c1);
        mma_bf16(cs[nb], ql0, ql1, ql2, ql3, b0, b1);
      }
    }

    // ---- online softmax (rows rbase+gid and rbase+gid+8) ----
    float tm0 = -1e30f, tm1 = -1e30f;
#pragma unroll
    for (int nb = 0; nb < 8; nb++) {
      tm0 = fmaxf(tm0, fmaxf(cs[nb][0], cs[nb][1]));
      tm1 = fmaxf(tm1, fmaxf(cs[nb][2], cs[nb][3]));
    }
    tm0 *= scale; tm1 *= scale;
#pragma unroll
    for (int off = 1; off <= 2; off <<= 1) {
      tm0 = fmaxf(tm0, __shfl_xor_sync(0xffffffffu, tm0, off));
      tm1 = fmaxf(tm1, __shfl_xor_sync(0xffffffffu, tm1, off));
    }
    const float mn0 = fmaxf(m0, tm0), mn1 = fmaxf(m1, tm1);
    const float al0 = __expf(m0 - mn0), al1 = __expf(m1 - mn1);
    m0 = mn0; m1 = mn1;

    float ts0 = 0.f, ts1 = 0.f;
#pragma unroll
    for (int nb = 0; nb < 8; nb++) {
      cs[nb][0] = __expf(cs[nb][0] * scale - mn0);
      cs[nb][1] = __expf(cs[nb][1] * scale - mn0);
      cs[nb][2] = __expf(cs[nb][2] * scale - mn1);
      cs[nb][3] = __expf(cs[nb][3] * scale - mn1);
      ts0 += cs[nb][0] + cs[nb][1];
      ts1 += cs[nb][2] + cs[nb][3];
    }
#pragma unroll
    for (int off = 1; off <= 2; off <<= 1) {
      ts0 += __shfl_xor_sync(0xffffffffu, ts0, off);
      ts1 += __shfl_xor_sync(0xffffffffu, ts1, off);
    }
    lr0 = lr0 * al0 + ts0;
    lr1 = lr1 * al1 + ts1;

    // rescale running O
#pragma unroll
    for (int nb = 0; nb < 8; nb++) {
      co[nb][0] *= al0; co[nb][1] *= al0;
      co[nb][2] *= al1; co[nb][3] *= al1;
    }

    // ---- O += P . V (bf16 3-term; P packed from cs in registers) ----
#pragma unroll
    for (int kq = 0; kq < 4; kq++) {
      const int s0 = 2 * kq, s1 = 2 * kq + 1;
      __nv_bfloat16 h, l;
      uint32_t pa0, pa1, pa2, pa3, la0, la1, la2, la3;
      {
        __nv_bfloat16 h2, l2;
        split_bf16(cs[s0][0], h, l); split_bf16(cs[s0][1], h2, l2);
        pa0 = pack_bf16(h, h2); la0 = pack_bf16(l, l2);
        split_bf16(cs[s0][2], h, l); split_bf16(cs[s0][3], h2, l2);
        pa1 = pack_bf16(h, h2); la1 = pack_bf16(l, l2);
        split_bf16(cs[s1][0], h, l); split_bf16(cs[s1][1], h2, l2);
        pa2 = pack_bf16(h, h2); la2 = pack_bf16(l, l2);
        split_bf16(cs[s1][2], h, l); split_bf16(cs[s1][3], h2, l2);
        pa3 = pack_bf16(h, h2); la3 = pack_bf16(l, l2);
      }
      const int ko = kq * 8;
#pragma unroll
      for (int nb = 0; nb < 8; nb++) {
        const int n = nb * 8 + gid;
        const uint32_t b0 = vh[n * FK_S + ko + tig];
        const uint32_t b1 = vh[n * FK_S + ko + tig + 4];
        const uint32_t c0 = vl[n * FK_S + ko + tig];
        const uint32_t c1 = vl[n * FK_S + ko + tig + 4];
        mma_bf16(co[nb], pa0, pa1, pa2, pa3, b0, b1);
        mma_bf16(co[nb], pa0, pa1, pa2, pa3, c0, c1);
        mma_bf16(co[nb], la0, la1, la2, la3, b0, b1);
      }
    }
    __syncthreads();   // tile fully consumed before its buffer is re-filled
  }

  // ---- epilogue: scatter O / l into g_attn ----
  const int b = bh >> 4, h = bh & 15;
  const int r0 = rbase + gid, r1 = rbase + gid + 8;
  const int s0 = qidx[r0], s1 = qidx[r1];
  const float inv0 = 1.0f / lr0, inv1 = 1.0f / lr1;
#pragma unroll
  for (int nb = 0; nb < 8; nb++) {
    const int col = h * PDH + nb * 8 + tig * 2;
    if (s0 >= 0) {
      float2 o = {co[nb][0] * inv0, co[nb][1] * inv0};
      *(float2*)&g_attn[((size_t)b * PL + s0) * PD + col] = o;
    }
    if (s1 >= 0) {
      float2 o = {co[nb][2] * inv1, co[nb][3] * inv1};
      *(float2*)&g_attn[((size_t)b * PL + s1) * PD + col] = o;
    }
  }
}

// ============================================================
// host launcher
// ============================================================
extern "C" void kernel_launch(void* const* d_in, const int* in_sizes, int n_in,
                              void* d_out, int out_size) {
  (void)in_sizes; (void)n_in; (void)out_size;
  const float* x  = (const float*)d_in[0];
  const float* Wq = (const float*)d_in[1];
  const float* bq = (const float*)d_in[2];
  const float* Wk = (const float*)d_in[3];
  const float* bk = (const float*)d_in[4];
  const float* Wv = (const float*)d_in[5];
  const float* bv = (const float*)d_in[6];
  const float* Wo = (const float*)d_in[7];
  const float* bo = (const float*)d_in[8];
  float* out = (float*)d_out;

  float *pq, *pk, *pv, *pkt, *pqtf, *pattn;
  uint32_t *pkthi, *pktlo, *pqthi, *pqtlo, *pwhi, *pwlo, *pxthi, *pxtlo;
  __nv_bfloat16 *pxbh, *pxbl, *pabh, *pabl, *pwvth, *pwvtl, *pwoth, *pwotl;
  __nv_bfloat16 *pkbh, *pkbl, *pvth, *pvtl;
  cudaGetSymbolAddress((void**)&pq, g_q);
  cudaGetSymbolAddress((void**)&pk, g_k);
  cudaGetSymbolAddress((void**)&pv, g_v);
  cudaGetSymbolAddress((void**)&pkt, g_kt);
  cudaGetSymbolAddress((void**)&pqtf, g_qtf);
  cudaGetSymbolAddress((void**)&pkthi, g_kthi);
  cudaGetSymbolAddress((void**)&pktlo, g_ktlo);
  cudaGetSymbolAddress((void**)&pqthi, g_qthi);
  cudaGetSymbolAddress((void**)&pqtlo, g_qtlo);
  cudaGetSymbolAddress((void**)&pwhi, g_whi);
  cudaGetSymbolAddress((void**)&pwlo, g_wlo);
  cudaGetSymbolAddress((void**)&pxthi, g_xthi);
  cudaGetSymbolAddress((void**)&pxtlo, g_xtlo);
  cudaGetSymbolAddress((void**)&pxbh, g_xbh);
  cudaGetSymbolAddress((void**)&pxbl, g_xbl);
  cudaGetSymbolAddress((void**)&pabh, g_abh);
  cudaGetSymbolAddress((void**)&pabl, g_abl);
  cudaGetSymbolAddress((void**)&pwvth, g_wvth);
  cudaGetSymbolAddress((void**)&pwvtl, g_wvtl);
  cudaGetSymbolAddress((void**)&pwoth, g_woth);
  cudaGetSymbolAddress((void**)&pwotl, g_wotl);
  cudaGetSymbolAddress((void**)&pkbh, g_kbh);
  cudaGetSymbolAddress((void**)&pkbl, g_kbl);
  cudaGetSymbolAddress((void**)&pvth, g_vth);
  cudaGetSymbolAddress((void**)&pvtl, g_vtl);
  cudaGetSymbolAddress((void**)&pattn, g_attn);

  cudaFuncSetAttribute(gemm_qk, cudaFuncAttributeMaxDynamicSharedMemorySize, GEMM_SMEM);
  cudaFuncSetAttribute(gemm_bf16<0>, cudaFuncAttributeMaxDynamicSharedMemorySize, GBF_SMEM);
  cudaFuncSetAttribute(gemm_bf16<1>, cudaFuncAttributeMaxDynamicSharedMemorySize, GBF_SMEM);
  cudaFuncSetAttribute(sparsity_v6, cudaFuncAttributeMaxDynamicSharedMemorySize, SP_SMEM);
  cudaFuncSetAttribute(flash_v5, cudaFuncAttributeMaxDynamicSharedMemorySize, FL_SMEM);

  const size_t WN = (size_t)PD * PD;
  const int n4w = (int)(WN / 4);
  const int n4x = (int)((size_t)PM * PD / 4);

  // tf32 pre-splits for selection-critical path (Q/K)
  split_kernel<<<(n4w + 255) / 256, 256>>>(Wq, pwhi + 0 * WN, pwlo + 0 * WN, n4w);
  split_kernel<<<(n4w + 255) / 256, 256>>>(Wk, pwhi + 1 * WN, pwlo + 1 * WN, n4w);
  transpose_split<<<dim3(PM / 32, PD / 32), 256>>>(x, pxthi, pxtlo, PM, PD);

  // bf16 pre-splits for value path (V / Wo)
  split_bf16_kernel<<<(n4x + 255) / 256, 256>>>(x, pxbh, pxbl, n4x);
  transpose_split_bf16<<<dim3(PD / 32, PD / 32), 256>>>(Wv, pwvth, pwvtl, PD, PD);
  transpose_split_bf16<<<dim3(PD / 32, PD / 32), 256>>>(Wo, pwoth, pwotl, PD, PD);

  // fused Q+K projection (tf32x3) and V projection (bf16x2 3-term)
  gemm_qk<<<dim3(2 * PD / 128, PM / 128), 256, GEMM_SMEM>>>(
      pxthi, pxtlo, pwhi + 0 * WN, pwlo + 0 * WN, pwhi + 1 * WN, pwlo + 1 * WN,
      bq, bk, pq, pk);
  gemm_bf16<1><<<dim3(PD / 128, PM / 128), 256, GBF_SMEM>>>(
      pxbh, pxbl, pwvth, pwvtl, bv, pv, PM, PD, PD);

  // head transposes + tf32 splits (selection path)
  const dim3 gT(PL / 32, PDH / 32, PBH);
  transpose_head_split<<<gT, 256>>>(pk, pkt, pkthi, pktlo);
  transpose_head_split<<<gT, 256>>>(pq, pqtf, pqthi, pqtlo);

  // bf16 operands for flash: K row-major split, V^T transposed split
  split_bf16_kernel<<<((PBH * PL * PDH / 4) + 255) / 256, 256>>>(
      pk, pkbh, pkbl, PBH * PL * PDH / 4);
  transpose_head_bf16<<<gT, 256>>>(pv, pvth, pvtl);

  // sparsity + selection
  sparsity_v6<<<dim3(PL / 128, PBH), 256, SP_SMEM>>>();
  topk_radix<<<PBH, 256>>>();

  // attention on selected rows (tensor cores)
  zero_attn_kernel<<<(PB * PL * PD / 4) / 256, 256>>>();
  flash_v5<<<dim3((PU + 127) / 128, PBH), 256, FL_SMEM>>>();

  // output projection (bf16x2 3-term)
  split_bf16_kernel<<<(n4x + 255) / 256, 256>>>(pattn, pabh, pabl, n4x);
  gemm_bf16<0><<<dim3(PD / 128, PM / 128), 256, GBF_SMEM>>>(
      pabh, pabl, pwoth, pwotl, bo, out, PM, PD, PD);
}

// round 12
// speedup vs baseline: 2.4248x; 1.1692x over previous
#include <cuda_runtime.h>
#include <cuda_bf16.h>
#include <cstdint>

// ---------------- problem constants ----------------
#define PB 2
#define PL 2048
#define PD 1024
#define PH 16
#define PDH 64
#define PU 1228          // int(0.6 * 2048)
#define PBH (PB * PH)    // 32
#define PM (PB * PL)     // 4096 rows

// ---------------- device scratch (no allocation allowed) ----------------
__device__ float g_q [(size_t)PBH * PL * PDH];   // [b,h,l,dh] fp32 (refine)
__device__ float g_k [(size_t)PBH * PL * PDH];   // [b,h,l,dh] fp32 (refine/kbar)
__device__ float g_v [(size_t)PBH * PL * PDH];   // [b,h,l,dh] fp32
__device__ uint32_t g_whi[(size_t)2 * PD * PD];  // Wq,Wk tf32 pre-split
__device__ uint32_t g_wlo[(size_t)2 * PD * PD];
__device__ uint32_t g_xthi[(size_t)PD * PM];     // x^T K-major tf32
__device__ uint32_t g_xtlo[(size_t)PD * PM];
// bf16 pair-packed (u32 = 2 bf16) operands
__device__ uint32_t g_qbh[(size_t)PBH * PL * PDH / 2];  // Q row-major bf16 hi
__device__ uint32_t g_qbl[(size_t)PBH * PL * PDH / 2];
__device__ uint32_t g_kbh[(size_t)PBH * PL * PDH / 2];  // K row-major bf16 hi
__device__ uint32_t g_kbl[(size_t)PBH * PL * PDH / 2];
__device__ uint32_t g_abh[(size_t)PM * PD / 2];         // attn row-major bf16 hi
__device__ uint32_t g_abl[(size_t)PM * PD / 2];
__device__ __nv_bfloat16 g_xbh[(size_t)PM * PD];   // x row-major bf16 hi
__device__ __nv_bfloat16 g_xbl[(size_t)PM * PD];
__device__ __nv_bfloat16 g_wvth[(size_t)PD * PD];  // Wv^T [N][K] bf16
__device__ __nv_bfloat16 g_wvtl[(size_t)PD * PD];
__device__ __nv_bfloat16 g_woth[(size_t)PD * PD];  // Wo^T [N][K] bf16
__device__ __nv_bfloat16 g_wotl[(size_t)PD * PD];
__device__ __nv_bfloat16 g_vth[(size_t)PBH * PDH * PL];  // V^T [bh][dh][l] bf16 hi
__device__ __nv_bfloat16 g_vtl[(size_t)PBH * PDH * PL];
__device__ float g_kbar[PBH * PDH];              // per-head mean K row
__device__ int   g_amax[(size_t)PBH * PL];       // per-row argmax key
__device__ float g_spars[(size_t)PBH * PL];
__device__ int   g_topidx[(size_t)PBH * PU];

// ---------------- cp.async helpers ----------------
#define CP16(dst_u32, src_ptr) \
  asm volatile("cp.async.cg.shared.global [%0], [%1], 16;\n" :: "r"(dst_u32), "l"(src_ptr))
#define CP_COMMIT() asm volatile("cp.async.commit_group;\n" ::)
#define CP_WAIT0()  asm volatile("cp.async.wait_group 0;\n" ::)
#define CP_WAIT1()  asm volatile("cp.async.wait_group 1;\n" ::)

static __device__ __forceinline__ uint32_t sptr(const void* p) {
  return (uint32_t)__cvta_generic_to_shared(p);
}

// ---------------- tf32 / bf16 helpers ----------------
static __device__ __forceinline__ void split_tf32(float x, uint32_t& hi, uint32_t& lo) {
  uint32_t h;
  asm("cvt.rna.tf32.f32 %0, %1;" : "=r"(h) : "f"(x));
  uint32_t l;
  asm("cvt.rna.tf32.f32 %0, %1;" : "=r"(l) : "f"(x - __uint_as_float(h)));
  hi = h; lo = l;
}

static __device__ __forceinline__ void split_bf16(float x, __nv_bfloat16& h, __nv_bfloat16& l) {
  h = __float2bfloat16(x);
  l = __float2bfloat16(x - __bfloat162float(h));
}

static __device__ __forceinline__ uint32_t pack_bf16(__nv_bfloat16 a, __nv_bfloat16 b) {
  return (uint32_t)__bfloat16_as_ushort(a) | ((uint32_t)__bfloat16_as_ushort(b) << 16);
}

static __device__ __forceinline__ void mma_tf32(
    float* c, uint32_t a0, uint32_t a1, uint32_t a2, uint32_t a3,
    uint32_t b0, uint32_t b1) {
  asm volatile(
      "mma.sync.aligned.m16n8k8.row.col.f32.tf32.tf32.f32 "
      "{%0,%1,%2,%3}, {%4,%5,%6,%7}, {%8,%9}, {%0,%1,%2,%3};"
      : "+f"(c[0]), "+f"(c[1]), "+f"(c[2]), "+f"(c[3])
      : "r"(a0), "r"(a1), "r"(a2), "r"(a3), "r"(b0), "r"(b1));
}

static __device__ __forceinline__ void mma_bf16(
    float* c, uint32_t a0, uint32_t a1, uint32_t a2, uint32_t a3,
    uint32_t b0, uint32_t b1) {
  asm volatile(
      "mma.sync.aligned.m16n8k16.row.col.f32.bf16.bf16.f32 "
      "{%0,%1,%2,%3}, {%4,%5,%6,%7}, {%8,%9}, {%0,%1,%2,%3};"
      : "+f"(c[0]), "+f"(c[1]), "+f"(c[2]), "+f"(c[3])
      : "r"(a0), "r"(a1), "r"(a2), "r"(a3), "r"(b0), "r"(b1));
}

// ============================================================
// Elementwise / transpose splits.
// ============================================================
__global__ __launch_bounds__(256) void split_kernel(
    const float* __restrict__ in, uint32_t* __restrict__ hi,
    uint32_t* __restrict__ lo, int n4) {
  const int i = blockIdx.x * 256 + threadIdx.x;
  if (i >= n4) return;
  float4 v = ((const float4*)in)[i];
  uint4 h, l;
  split_tf32(v.x, h.x, l.x);
  split_tf32(v.y, h.y, l.y);
  split_tf32(v.z, h.z, l.z);
  split_tf32(v.w, h.w, l.w);
  ((uint4*)hi)[i] = h;
  ((uint4*)lo)[i] = l;
}

__global__ __launch_bounds__(256) void split_bf16_kernel(
    const float* __restrict__ in, __nv_bfloat16* __restrict__ hi,
    __nv_bfloat16* __restrict__ lo, int n4) {
  const int i = blockIdx.x * 256 + threadIdx.x;
  if (i >= n4) return;
  float4 v = ((const float4*)in)[i];
  __nv_bfloat16 h[4], l[4];
  split_bf16(v.x, h[0], l[0]);
  split_bf16(v.y, h[1], l[1]);
  split_bf16(v.z, h[2], l[2]);
  split_bf16(v.w, h[3], l[3]);
  uint2 hp, lp;
  hp.x = pack_bf16(h[0], h[1]);
  hp.y = pack_bf16(h[2], h[3]);
  lp.x = pack_bf16(l[0], l[1]);
  lp.y = pack_bf16(l[2], l[3]);
  ((uint2*)hi)[i] = hp;
  ((uint2*)lo)[i] = lp;
}

__global__ __launch_bounds__(256) void transpose_split(
    const float* __restrict__ in, uint32_t* __restrict__ ohi,
    uint32_t* __restrict__ olo, int M, int N) {
  __shared__ float t[32][33];
  const int m0 = blockIdx.x * 32, n0 = blockIdx.y * 32;
  const int x = threadIdx.x & 31, y = threadIdx.x >> 5;
#pragma unroll
  for (int k = 0; k < 4; k++)
    t[y + 8 * k][x] = in[(size_t)(m0 + y + 8 * k) * N + n0 + x];
  __syncthreads();
#pragma unroll
  for (int k = 0; k < 4; k++) {
    const float v = t[x][y + 8 * k];
    uint32_t h, l;
    split_tf32(v, h, l);
    const size_t idx = (size_t)(n0 + y + 8 * k) * M + m0 + x;
    ohi[idx] = h;
    olo[idx] = l;
  }
}

__global__ __launch_bounds__(256) void transpose_split_bf16(
    const float* __restrict__ in, __nv_bfloat16* __restrict__ ohi,
    __nv_bfloat16* __restrict__ olo, int M, int N) {
  __shared__ float t[32][33];
  const int m0 = blockIdx.x * 32, n0 = blockIdx.y * 32;
  const int x = threadIdx.x & 31, y = threadIdx.x >> 5;
#pragma unroll
  for (int k = 0; k < 4; k++)
    t[y + 8 * k][x] = in[(size_t)(m0 + y + 8 * k) * N + n0 + x];
  __syncthreads();
#pragma unroll
  for (int k = 0; k < 4; k++) {
    const float v = t[x][y + 8 * k];
    __nv_bfloat16 h, l;
    split_bf16(v, h, l);
    const size_t idx = (size_t)(n0 + y + 8 * k) * M + m0 + x;
    ohi[idx] = h;
    olo[idx] = l;
  }
}

// Head transpose + bf16 split: [bh][l][dh] -> [bh][dh][l] bf16 (for V^T).
__global__ __launch_bounds__(256) void transpose_head_bf16(
    const float* __restrict__ in, __nv_bfloat16* __restrict__ ohi,
    __nv_bfloat16* __restrict__ olo) {
  __shared__ float t[32][33];
  const int bh = blockIdx.z;
  const int l0 = blockIdx.x * 32, d0 = blockIdx.y * 32;
  const int x = threadIdx.x & 31, y = threadIdx.x >> 5;
  const float* ip = in + (size_t)bh * PL * PDH;
#pragma unroll
  for (int k = 0; k < 4; k++)
    t[y + 8 * k][x] = ip[(size_t)(l0 + y + 8 * k) * PDH + d0 + x];
  __syncthreads();
  const size_t base = (size_t)bh * PDH * PL;
#pragma unroll
  for (int k = 0; k < 4; k++) {
    const float v = t[x][y + 8 * k];
    __nv_bfloat16 h, l;
    split_bf16(v, h, l);
    const size_t idx = base + (size_t)(d0 + y + 8 * k) * PL + l0 + x;
    ohi[idx] = h;
    olo[idx] = l;
  }
}

// ============================================================
// Fused Q+K projection (tf32x3). Epilogue emits fp32 head layout
// AND pair-packed bf16 hi/lo row-major (for sparsity+flash).
// ============================================================
#define GS 136
#define GEMM_SMEM (4 * 2 * 16 * GS * 4)

__global__ __launch_bounds__(256, 2) void gemm_qk(
    const uint32_t* __restrict__ Ahi, const uint32_t* __restrict__ Alo,
    const uint32_t* __restrict__ WhiQ, const uint32_t* __restrict__ WloQ,
    const uint32_t* __restrict__ WhiK, const uint32_t* __restrict__ WloK,
    const float* __restrict__ biasQ, const float* __restrict__ biasK,
    float* __restrict__ CQ, float* __restrict__ CK) {
  extern __shared__ uint32_t smg[];
  uint32_t* Ah = smg;
  uint32_t* Al = Ah + 2 * 16 * GS;
  uint32_t* Bh = Al + 2 * 16 * GS;
  uint32_t* Bl = Bh + 2 * 16 * GS;

  const int HB = PD / 128;
  const bool isK = (blockIdx.x >= HB);
  const uint32_t* Whi = isK ? WhiK : WhiQ;
  const uint32_t* Wlo = isK ? WloK : WloQ;
  const float* bias = isK ? biasK : biasQ;
  float* C = isK ? CK : CQ;
  uint32_t* BH = isK ? g_kbh : g_qbh;
  uint32_t* BL = isK ? g_kbl : g_qbl;
  const int bn = (isK ? blockIdx.x - HB : blockIdx.x) * 128;

  const int M = PM, N = PD, K = PD;
  const int tid = threadIdx.x;
  const int warp = tid >> 5, lane = tid & 31;
  const int gid = lane >> 2, tig = lane & 3;
  const int wm = warp >> 1, wn = warp & 1;
  const int bm = blockIdx.y * 128;

  const int lr = tid >> 4;
  const int lc = (tid & 15) * 8;

  float c[2][8][4];
#pragma unroll
  for (int mb = 0; mb < 2; mb++)
#pragma unroll
    for (int nb = 0; nb < 8; nb++)
#pragma unroll
      for (int j = 0; j < 4; j++) c[mb][nb][j] = 0.f;

  const int NP = K >> 4;

  auto issue = [&](int p, int bf) {
    const size_t arow = (size_t)(p * 16 + lr) * M + bm + lc;
    const size_t brow = (size_t)(p * 16 + lr) * N + bn + lc;
    const uint32_t so = bf * 16 * GS + lr * GS + lc;
    CP16(sptr(&Ah[so]), Ahi + arow); CP16(sptr(&Ah[so]) + 16, Ahi + arow + 4);
    CP16(sptr(&Al[so]), Alo + arow); CP16(sptr(&Al[so]) + 16, Alo + arow + 4);
    CP16(sptr(&Bh[so]), Whi + brow); CP16(sptr(&Bh[so]) + 16, Whi + brow + 4);
    CP16(sptr(&Bl[so]), Wlo + brow); CP16(sptr(&Bl[so]) + 16, Wlo + brow + 4);
    CP_COMMIT();
  };

  issue(0, 0);

#pragma unroll 1
  for (int p = 0; p < NP; p++) {
    const int buf = p & 1;
    if (p + 1 < NP) { issue(p + 1, buf ^ 1); CP_WAIT1(); }
    else            { CP_WAIT0(); }
    __syncthreads();

    const uint32_t* ah = Ah + buf * 16 * GS;
    const uint32_t* al = Al + buf * 16 * GS;
    const uint32_t* bhp = Bh + buf * 16 * GS;
    const uint32_t* blp = Bl + buf * 16 * GS;

#pragma unroll
    for (int ks = 0; ks < 2; ks++) {
      const int k0 = ks * 8;
      uint32_t ahi[2][4], alo[2][4];
#pragma unroll
      for (int mb = 0; mb < 2; mb++) {
        const int r = wm * 32 + mb * 16;
        ahi[mb][0] = ah[(k0 + tig)     * GS + r + gid];
        ahi[mb][1] = ah[(k0 + tig)     * GS + r + gid + 8];
        ahi[mb][2] = ah[(k0 + tig + 4) * GS + r + gid];
        ahi[mb][3] = ah[(k0 + tig + 4) * GS + r + gid + 8];
        alo[mb][0] = al[(k0 + tig)     * GS + r + gid];
        alo[mb][1] = al[(k0 + tig)     * GS + r + gid + 8];
        alo[mb][2] = al[(k0 + tig + 4) * GS + r + gid];
        alo[mb][3] = al[(k0 + tig + 4) * GS + r + gid + 8];
      }
#pragma unroll
      for (int nb = 0; nb < 8; nb++) {
        const int n = wn * 64 + nb * 8 + gid;
        const uint32_t bh0 = bhp[(k0 + tig)     * GS + n];
        const uint32_t bh1 = bhp[(k0 + tig + 4) * GS + n];
        const uint32_t bl0 = blp[(k0 + tig)     * GS + n];
        const uint32_t bl1 = blp[(k0 + tig + 4) * GS + n];
#pragma unroll
        for (int mb = 0; mb < 2; mb++) {
          mma_tf32(c[mb][nb], ahi[mb][0], ahi[mb][1], ahi[mb][2], ahi[mb][3], bh0, bh1);
          mma_tf32(c[mb][nb], ahi[mb][0], ahi[mb][1], ahi[mb][2], ahi[mb][3], bl0, bl1);
          mma_tf32(c[mb][nb], alo[mb][0], alo[mb][1], alo[mb][2], alo[mb][3], bh0, bh1);
        }
      }
    }
    __syncthreads();
  }

#pragma unroll
  for (int mb = 0; mb < 2; mb++) {
#pragma unroll
    for (int nb = 0; nb < 8; nb++) {
      const int m0 = bm + wm * 32 + mb * 16 + gid;
      const int n0 = bn + wn * 64 + nb * 8 + tig * 2;
      const float bx = bias[n0], by = bias[n0 + 1];
      float2 v0 = {c[mb][nb][0] + bx, c[mb][nb][1] + by};
      float2 v1 = {c[mb][nb][2] + bx, c[mb][nb][3] + by};
      const int h = n0 >> 6, dh = n0 & 63;
      const int b0i = m0 >> 11, l0 = m0 & (PL - 1);
      const int b1i = (m0 + 8) >> 11, l1 = (m0 + 8) & (PL - 1);
      const size_t i0 = (((size_t)b0i * PH + h) * PL + l0) * PDH + dh;
      const size_t i1 = (((size_t)b1i * PH + h) * PL + l1) * PDH + dh;
      *(float2*)&C[i0] = v0;
      *(float2*)&C[i1] = v1;
      __nv_bfloat16 h0, l0b, h1, l1b;
      split_bf16(v0.x, h0, l0b); split_bf16(v0.y, h1, l1b);
      BH[i0 / 2] = pack_bf16(h0, h1);
      BL[i0 / 2] = pack_bf16(l0b, l1b);
      split_bf16(v1.x, h0, l0b); split_bf16(v1.y, h1, l1b);
      BH[i1 / 2] = pack_bf16(h0, h1);
      BL[i1 / 2] = pack_bf16(l0b, l1b);
    }
  }
}

// ============================================================
// bf16x2 3-term GEMM (unchanged).
// ============================================================
#define GB_S 20
#define GBF_SMEM (4 * 2 * 128 * GB_S * 4)

template<int MODE>
__global__ __launch_bounds__(256, 2) void gemm_bf16(
    const __nv_bfloat16* __restrict__ Agh, const __nv_bfloat16* __restrict__ Agl,
    const __nv_bfloat16* __restrict__ Bgh, const __nv_bfloat16* __restrict__ Bgl,
    const float* __restrict__ bias, float* __restrict__ C,
    int M, int N, int K) {
  extern __shared__ uint32_t smb[];
  uint32_t* Ah = smb;
  uint32_t* Al = Ah + 2 * 128 * GB_S;
  uint32_t* Bh = Al + 2 * 128 * GB_S;
  uint32_t* Bl = Bh + 2 * 128 * GB_S;

  const int tid = threadIdx.x;
  const int warp = tid >> 5, lane = tid & 31;
  const int gid = lane >> 2, tig = lane & 3;
  const int wm = warp >> 1, wn = warp & 1;
  const int bm = blockIdx.y * 128, bn = blockIdx.x * 128;

  const int lr = tid >> 1;
  const int lh = (tid & 1) * 16;

  float c[2][8][4];
#pragma unroll
  for (int mb = 0; mb < 2; mb++)
#pragma unroll
    for (int nb = 0; nb < 8; nb++)
#pragma unroll
      for (int j = 0; j < 4; j++) c[mb][nb][j] = 0.f;

  const int NP = K >> 5;

  auto issue = [&](int p, int bf) {
    const __nv_bfloat16* asrc = Agh + (size_t)(bm + lr) * K + p * 32 + lh;
    const __nv_bfloat16* asrl = Agl + (size_t)(bm + lr) * K + p * 32 + lh;
    const __nv_bfloat16* bsrc = Bgh + (size_t)(bn + lr) * K + p * 32 + lh;
    const __nv_bfloat16* bsrl = Bgl + (size_t)(bn + lr) * K + p * 32 + lh;
    const uint32_t so = (bf * 128 + lr) * GB_S * 4 + lh * 2;
    CP16(sptr(Ah) + so, asrc); CP16(sptr(Ah) + so + 16, asrc + 8);
    CP16(sptr(Al) + so, asrl); CP16(sptr(Al) + so + 16, asrl + 8);
    CP16(sptr(Bh) + so, bsrc); CP16(sptr(Bh) + so + 16, bsrc + 8);
    CP16(sptr(Bl) + so, bsrl); CP16(sptr(Bl) + so + 16, bsrl + 8);
    CP_COMMIT();
  };

  issue(0, 0);

#pragma unroll 1
  for (int p = 0; p < NP; p++) {
    const int buf = p & 1;
    if (p + 1 < NP) { issue(p + 1, buf ^ 1); CP_WAIT1(); }
    else            { CP_WAIT0(); }
    __syncthreads();

    const uint32_t* ah = Ah + buf * 128 * GB_S;
    const uint32_t* al = Al + buf * 128 * GB_S;
    const uint32_t* bhp = Bh + buf * 128 * GB_S;
    const uint32_t* blp = Bl + buf * 128 * GB_S;

#pragma unroll
    for (int kb = 0; kb < 2; kb++) {
      const int ko = kb * 8;
      uint32_t ahi[2][4], alo[2][4];
#pragma unroll
      for (int mb = 0; mb < 2; mb++) {
        const int r = wm * 32 + mb * 16;
        ahi[mb][0] = ah[(r + gid)     * GB_S + ko + tig];
        ahi[mb][1] = ah[(r + gid + 8) * GB_S + ko + tig];
        ahi[mb][2] = ah[(r + gid)     * GB_S + ko + tig + 4];
        ahi[mb][3] = ah[(r + gid + 8) * GB_S + ko + tig + 4];
        alo[mb][0] = al[(r + gid)     * GB_S + ko + tig];
        alo[mb][1] = al[(r + gid + 8) * GB_S + ko + tig];
        alo[mb][2] = al[(r + gid)     * GB_S + ko + tig + 4];
        alo[mb][3] = al[(r + gid + 8) * GB_S + ko + tig + 4];
      }
#pragma unroll
      for (int nb = 0; nb < 8; nb++) {
        const int n = wn * 64 + nb * 8 + gid;
        const uint32_t bh0 = bhp[n * GB_S + ko + tig];
        const uint32_t bh1 = bhp[n * GB_S + ko + tig + 4];
        const uint32_t bl0 = blp[n * GB_S + ko + tig];
        const uint32_t bl1 = blp[n * GB_S + ko + tig + 4];
#pragma unroll
        for (int mb = 0; mb < 2; mb++) {
          mma_bf16(c[mb][nb], ahi[mb][0], ahi[mb][1], ahi[mb][2], ahi[mb][3], bh0, bh1);
          mma_bf16(c[mb][nb], ahi[mb][0], ahi[mb][1], ahi[mb][2], ahi[mb][3], bl0, bl1);
          mma_bf16(c[mb][nb], alo[mb][0], alo[mb][1], alo[mb][2], alo[mb][3], bh0, bh1);
        }
      }
    }
    __syncthreads();
  }

#pragma unroll
  for (int mb = 0; mb < 2; mb++) {
#pragma unroll
    for (int nb = 0; nb < 8; nb++) {
      const int m0 = bm + wm * 32 + mb * 16 + gid;
      const int n0 = bn + wn * 64 + nb * 8 + tig * 2;
      const float bx = bias[n0], by = bias[n0 + 1];
      float2 v0 = {c[mb][nb][0] + bx, c[mb][nb][1] + by};
      float2 v1 = {c[mb][nb][2] + bx, c[mb][nb][3] + by};
      if (MODE == 0) {
        *(float2*)&C[(size_t)m0 * N + n0] = v0;
        *(float2*)&C[(size_t)(m0 + 8) * N + n0] = v1;
      } else {
        const int h = n0 >> 6, dh = n0 & 63;
        const int b0i = m0 >> 11, l0 = m0 & (PL - 1);
        const int b1i = (m0 + 8) >> 11, l1 = (m0 + 8) & (PL - 1);
        *(float2*)&C[(((size_t)b0i * PH + h) * PL + l0) * PDH + dh] = v0;
        *(float2*)&C[(((size_t)b1i * PH + h) * PL + l1) * PDH + dh] = v1;
      }
    }
  }
}

// ============================================================
// kbar: per-head mean K row (exact fp32).
// ============================================================
__global__ __launch_bounds__(1024) void kbar_kernel() {
  __shared__ float acc[16][64];
  const int bh = blockIdx.x, tid = threadIdx.x;
  const int dh = tid & 63, grp = tid >> 6;
  float s = 0.f;
  for (int r = grp; r < PL; r += 16)
    s += g_k[((size_t)bh * PL + r) * PDH + dh];
  acc[grp][dh] = s;
  __syncthreads();
  if (tid < 64) {
    float t = 0.f;
#pragma unroll
    for (int g2 = 0; g2 < 16; g2++) t += acc[g2][tid];
    g_kbar[bh * PDH + tid] = t * (1.0f / PL);
  }
}

// ============================================================
// Sparsity v7: bf16 3-term QK^T, per-row MAX + ARGMAX only.
// CTA = 128 q-rows x one bh; 64-key tiles; m16n8k16.
// smem: Qh/Ql[128][36] + Kh/Kl[2][64][36] u32 = 72KB.
// Emits g_amax; exact values come from refine_kernel.
// ============================================================
#define SQ_S 36
#define SK_S 36
#define SP7_SMEM ((2 * 128 * SQ_S + 4 * 64 * SK_S) * 4)

__global__ __launch_bounds__(256, 2) void sparsity_v7() {
  extern __shared__ uint32_t sm7[];
  uint32_t* Qh = sm7;                  // [128][36]
  uint32_t* Ql = Qh + 128 * SQ_S;
  uint32_t* Kh = Ql + 128 * SQ_S;      // [2][64][36]
  uint32_t* Kl = Kh + 2 * 64 * SK_S;

  const int bh = blockIdx.y, q0 = blockIdx.x * 128;
  const int tid = threadIdx.x;
  const int warp = tid >> 5, lane = tid & 31;
  const int gid = lane >> 2, tig = lane & 3;
  const int rbase = warp * 16;

  {  // Q tile: 128 rows x 32 u32 (bf16 pairs), resident
    const int r = tid >> 1, c0 = (tid & 1) * 16;
    const uint32_t* qh = g_qbh + (size_t)(bh * PL + q0 + r) * 32 + c0;
    const uint32_t* ql = g_qbl + (size_t)(bh * PL + q0 + r) * 32 + c0;
    const uint32_t hd = sptr(&Qh[r * SQ_S + c0]);
    const uint32_t ld = sptr(&Ql[r * SQ_S + c0]);
#pragma unroll
    for (int j = 0; j < 4; j++) CP16(hd + j * 16, qh + j * 4);
#pragma unroll
    for (int j = 0; j < 4; j++) CP16(ld + j * 16, ql + j * 4);
  }
  const int krow = tid >> 2;
  const int seg = (tid & 3) * 8;
  auto issueK = [&](int kt, int bf) {
    const uint32_t* kh = g_kbh + (size_t)(bh * PL + kt * 64 + krow) * 32 + seg;
    const uint32_t* kl = g_kbl + (size_t)(bh * PL + kt * 64 + krow) * 32 + seg;
    const uint32_t so = ((bf * 64 + krow) * SK_S + seg) * 4;
    CP16(sptr(Kh) + so, kh); CP16(sptr(Kh) + so + 16, kh + 4);
    CP16(sptr(Kl) + so, kl); CP16(sptr(Kl) + so + 16, kl + 4);
    CP_COMMIT();
  };
  issueK(0, 0);

  float mx0 = -1e30f, mx1 = -1e30f;
  int ix0 = 0, ix1 = 0;

#pragma unroll 1
  for (int kt = 0; kt < PL / 64; kt++) {
    const int buf = kt & 1;
    if (kt + 1 < PL / 64) { issueK(kt + 1, buf ^ 1); CP_WAIT1(); }
    else                  { CP_WAIT0(); }
    __syncthreads();

    const uint32_t* kh = Kh + buf * 64 * SK_S;
    const uint32_t* kl = Kl + buf * 64 * SK_S;

    float cs[8][4];
#pragma unroll
    for (int nb = 0; nb < 8; nb++)
#pragma unroll
      for (int j = 0; j < 4; j++) cs[nb][j] = 0.f;

#pragma unroll
    for (int ks = 0; ks < 4; ks++) {
      const int ko = ks * 8;
      const uint32_t qh0 = Qh[(rbase + gid)     * SQ_S + ko + tig];
      const uint32_t qh1 = Qh[(rbase + gid + 8) * SQ_S + ko + tig];
      const uint32_t qh2 = Qh[(rbase + gid)     * SQ_S + ko + tig + 4];
      const uint32_t qh3 = Qh[(rbase + gid + 8) * SQ_S + ko + tig + 4];
      const uint32_t ql0 = Ql[(rbase + gid)     * SQ_S + ko + tig];
      const uint32_t ql1 = Ql[(rbase + gid + 8) * SQ_S + ko + tig];
      const uint32_t ql2 = Ql[(rbase + gid)     * SQ_S + ko + tig + 4];
      const uint32_t ql3 = Ql[(rbase + gid + 8) * SQ_S + ko + tig + 4];
#pragma unroll
      for (int nb = 0; nb < 8; nb++) {
        const int n = nb * 8 + gid;
        const uint32_t b0 = kh[n * SK_S + ko + tig];
        const uint32_t b1 = kh[n * SK_S + ko + tig + 4];
        const uint32_t c0 = kl[n * SK_S + ko + tig];
        const uint32_t c1 = kl[n * SK_S + ko + tig + 4];
        mma_bf16(cs[nb], qh0, qh1, qh2, qh3, b0, b1);
        mma_bf16(cs[nb], qh0, qh1, qh2, qh3, c0, c1);
        mma_bf16(cs[nb], ql0, ql1, ql2, ql3, b0, b1);
      }
    }

    // running max + argmax (cols: key = kt*64 + nb*8 + tig*2 + {0,1})
#pragma unroll
    for (int nb = 0; nb < 8; nb++) {
      const int kb = kt * 64 + nb * 8 + tig * 2;
      if (cs[nb][0] > mx0) { mx0 = cs[nb][0]; ix0 = kb; }
      if (cs[nb][1] > mx0) { mx0 = cs[nb][1]; ix0 = kb + 1; }
      if (cs[nb][2] > mx1) { mx1 = cs[nb][2]; ix1 = kb; }
      if (cs[nb][3] > mx1) { mx1 = cs[nb][3]; ix1 = kb + 1; }
    }
    __syncthreads();
  }

  // quad reduce (lanes tig 0..3 share the same rows)
#pragma unroll
  for (int off = 1; off <= 2; off <<= 1) {
    const float o0 = __shfl_xor_sync(0xffffffffu, mx0, off);
    const int oi0 = __shfl_xor_sync(0xffffffffu, ix0, off);
    if (o0 > mx0) { mx0 = o0; ix0 = oi0; }
    const float o1 = __shfl_xor_sync(0xffffffffu, mx1, off);
    const int oi1 = __shfl_xor_sync(0xffffffffu, ix1, off);
    if (o1 > mx1) { mx1 = o1; ix1 = oi1; }
  }
  if (tig == 0) {
    g_amax[(size_t)bh * PL + q0 + rbase + gid] = ix0;
    g_amax[(size_t)bh * PL + q0 + rbase + gid + 8] = ix1;
  }
}

// ============================================================
// Refine: exact fp32 sparsity score per row:
//   spars = scale * (q . k_argmax)  -  scale * (q . kbar)
// One warp per row.
// ============================================================
__global__ __launch_bounds__(256) void refine_kernel() {
  const int tid = threadIdx.x;
  const int warp = tid >> 5, lane = tid & 31;
  const int g = blockIdx.x * 8 + warp;   // global row id, PBH*PL total
  const int bh = g >> 11;                // / PL
  const int l = g & (PL - 1);
  const float* q = g_q + ((size_t)bh * PL + l) * PDH;
  const int am = g_amax[(size_t)bh * PL + l];
  const float* ka = g_k + ((size_t)bh * PL + am) * PDH;
  const float* kb = g_kbar + bh * PDH;
  const float2 qv = ((const float2*)q)[lane];
  const float2 kav = ((const float2*)ka)[lane];
  const float2 kbv = ((const float2*)kb)[lane];
  float dmax = qv.x * kav.x + qv.y * kav.y;
  float dmean = qv.x * kbv.x + qv.y * kbv.y;
#pragma unroll
  for (int off = 16; off; off >>= 1) {
    dmax += __shfl_xor_sync(0xffffffffu, dmax, off);
    dmean += __shfl_xor_sync(0xffffffffu, dmean, off);
  }
  if (lane == 0)
    g_spars[(size_t)bh * PL + l] = 0.125f * dmax - 0.125f * dmean;
}

// ============================================================
// Exact top-U via radix select (unchanged).
// ============================================================
__global__ __launch_bounds__(256) void topk_radix() {
  __shared__ unsigned su[2048];
  __shared__ int hist[256];
  __shared__ unsigned s_pref;
  __shared__ int s_rem;
  __shared__ unsigned eqm[64];
  __shared__ int wpfx[64];
  __shared__ int outcnt;

  const int bh = blockIdx.x;
  const int tid = threadIdx.x;

  for (int t = tid; t < 2048; t += 256) {
    unsigned b = __float_as_uint(g_spars[(size_t)bh * PL + t]);
    su[t] = (b & 0x80000000u) ? ~b : (b | 0x80000000u);
  }
  if (tid == 0) { s_pref = 0u; s_rem = PU; outcnt = 0; }
  if (tid < 64) eqm[tid] = 0u;
  __syncthreads();

  for (int shift = 24; shift >= 0; shift -= 8) {
    hist[tid & 255] = 0;
    __syncthreads();
    const unsigned pref = s_pref;
    for (int t = tid; t < 2048; t += 256) {
      const unsigned u = su[t];
      if (shift == 24 || (u >> (shift + 8)) == pref)
        atomicAdd(&hist[(u >> shift) & 255], 1);
    }
    __syncthreads();
    if (tid == 0) {
      int rem = s_rem, acc = 0;
      for (int b = 255; b >= 0; b--) {
        if (acc + hist[b] >= rem) {
          s_rem = rem - acc;
          s_pref = (s_pref << 8) | (unsigned)b;
          break;
        }
        acc += hist[b];
      }
    }
    __syncthreads();
  }

  const unsigned T = s_pref;
  const int e = s_rem;

  for (int t = tid; t < 2048; t += 256)
    if (su[t] == T) atomicOr(&eqm[t >> 5], 1u << (t & 31));
  __syncthreads();
  if (tid == 0) {
    int a = 0;
    for (int w = 0; w < 64; w++) { wpfx[w] = a; a += __popc(eqm[w]); }
  }
  __syncthreads();

  for (int t = tid; t < 2048; t += 256) {
    const unsigned u = su[t];
    bool sel = (u > T);
    if (u == T) {
      const int rank = wpfx[t >> 5] + __popc(eqm[t >> 5] & ((1u << (t & 31)) - 1u));
      sel = (rank < e);
    }
    if (sel) {
      const int slot = atomicAdd(&outcnt, 1);
      g_topidx[(size_t)bh * PU + slot] = t;
    }
  }
}

// ============================================================
// Zero the bf16 attn scatter buffers.
// ============================================================
__global__ void zero_ab() {
  const size_t i = (size_t)blockIdx.x * blockDim.x + threadIdx.x;
  const size_t N = (size_t)PM * PD / 8;   // uint4 count per array
  uint4 z = {0u, 0u, 0u, 0u};
  if (i < N) ((uint4*)g_abh)[i] = z;
  else       ((uint4*)g_abl)[i - N] = z;
}

// ============================================================
// Flash v5b: tensor-core attention, Q from pre-split bf16,
// epilogue writes bf16 hi/lo attn directly.
// ============================================================
#define FQ_S 36
#define FK_S 36
#define FL_SMEM ((2 * 128 * FQ_S + 4 * 2 * 64 * FK_S) * 4)

__global__ __launch_bounds__(256, 2) void flash_v5() {
  extern __shared__ uint32_t smf[];
  uint32_t* Qh = smf;                      // [128][36]
  uint32_t* Ql = Qh + 128 * FQ_S;
  uint32_t* Kh = Ql + 128 * FQ_S;          // [2][64][36]
  uint32_t* Kl = Kh + 2 * 64 * FK_S;
  uint32_t* Vh = Kl + 2 * 64 * FK_S;       // [2][64][36]
  uint32_t* Vl = Vh + 2 * 64 * FK_S;
  __shared__ int qidx[128];

  const int bh = blockIdx.y, qt = blockIdx.x;
  const int tid = threadIdx.x;
  const int warp = tid >> 5, lane = tid & 31;
  const int gid = lane >> 2, tig = lane & 3;
  const int rbase = warp * 16;
  const float scale = 0.125f;

  if (tid < 128) {
    const int u = qt * 128 + tid;
    qidx[tid] = (u < PU) ? g_topidx[(size_t)bh * PU + u] : -1;
  }
  __syncthreads();

  {  // gather pre-split Q rows (u32 pairs)
    const int r = tid >> 1, c0 = (tid & 1) * 16;
    int src = qidx[r];
    if (src < 0) src = 0;
    const uint32_t* qh = g_qbh + (size_t)(bh * PL + src) * 32 + c0;
    const uint32_t* ql = g_qbl + (size_t)(bh * PL + src) * 32 + c0;
#pragma unroll
    for (int j = 0; j < 4; j++) {
      *(uint4*)&Qh[r * FQ_S + c0 + j * 4] = *(const uint4*)(qh + j * 4);
      *(uint4*)&Ql[r * FQ_S + c0 + j * 4] = *(const uint4*)(ql + j * 4);
    }
  }

  const int krow = tid >> 2;
  const int seg = (tid & 3) * 8;
  auto issueKV = [&](int kt, int bf) {
    const uint32_t* ksh = g_kbh + (size_t)(bh * PL + kt * 64 + krow) * 32 + seg;
    const uint32_t* ksl = g_kbl + (size_t)(bh * PL + kt * 64 + krow) * 32 + seg;
    const uint32_t* vsh = (const uint32_t*)g_vth + (size_t)(bh * PDH + krow) * (PL / 2) + kt * 32 + seg;
    const uint32_t* vsl = (const uint32_t*)g_vtl + (size_t)(bh * PDH + krow) * (PL / 2) + kt * 32 + seg;
    const uint32_t so = ((bf * 64 + krow) * FK_S + seg) * 4;
    CP16(sptr(Kh) + so, ksh); CP16(sptr(Kh) + so + 16, ksh + 4);
    CP16(sptr(Kl) + so, ksl); CP16(sptr(Kl) + so + 16, ksl + 4);
    CP16(sptr(Vh) + so, vsh); CP16(sptr(Vh) + so + 16, vsh + 4);
    CP16(sptr(Vl) + so, vsl); CP16(sptr(Vl) + so + 16, vsl + 4);
    CP_COMMIT();
  };
  issueKV(0, 0);

  float co[8][4];
#pragma unroll
  for (int nb = 0; nb < 8; nb++)
#pragma unroll
    for (int j = 0; j < 4; j++) co[nb][j] = 0.f;
  float m0 = -1e30f, m1 = -1e30f, lr0 = 0.f, lr1 = 0.f;

#pragma unroll 1
  for (int kt = 0; kt < PL / 64; kt++) {
    const int buf = kt & 1;
    if (kt + 1 < PL / 64) { issueKV(kt + 1, buf ^ 1); CP_WAIT1(); }
    else                  { CP_WAIT0(); }
    __syncthreads();

    const uint32_t* kh = Kh + buf * 64 * FK_S;
    const uint32_t* kl = Kl + buf * 64 * FK_S;
    const uint32_t* vh = Vh + buf * 64 * FK_S;
    const uint32_t* vl = Vl + buf * 64 * FK_S;

    float cs[8][4];
#pragma unroll
    for (int nb = 0; nb < 8; nb++)
#pragma unroll
      for (int j = 0; j < 4; j++) cs[nb][j] = 0.f;

#pragma unroll
    for (int ks = 0; ks < 4; ks++) {
      const int ko = ks * 8;
      const uint32_t qh0 = Qh[(rbase + gid)     * FQ_S + ko + tig];
      const uint32_t qh1 = Qh[(rbase + gid + 8) * FQ_S + ko + tig];
      const uint32_t qh2 = Qh[(rbase + gid)     * FQ_S + ko + tig + 4];
      const uint32_t qh3 = Qh[(rbase + gid + 8) * FQ_S + ko + tig + 4];
      const uint32_t ql0 = Ql[(rbase + gid)     * FQ_S + ko + tig];
      const uint32_t ql1 = Ql[(rbase + gid + 8) * FQ_S + ko + tig];
      const uint32_t ql2 = Ql[(rbase + gid)     * FQ_S + ko + tig + 4];
      const uint32_t ql3 = Ql[(rbase + gid + 8) * FQ_S + ko + tig + 4];
#pragma unroll
      for (int nb = 0; nb < 8; nb++) {
        const int n = nb * 8 + gid;
        const uint32_t b0 = kh[n * FK_S + ko + tig];
        const uint32_t b1 = kh[n * FK_S + ko + tig + 4];
        const uint32_t c0 = kl[n * FK_S + ko + tig];
        const uint32_t c1 = kl[n * FK_S + ko + tig + 4];
        mma_bf16(cs[nb], qh0, qh1, qh2, qh3, b0, b1);
        mma_bf16(cs[nb], qh0, qh1, qh2, qh3, c0, c1);
        mma_bf16(cs[nb], ql0, ql1, ql2, ql3, b0, b1);
      }
    }

    // online softmax
    float tm0 = -1e30f, tm1 = -1e30f;
#pragma unroll
    for (int nb = 0; nb < 8; nb++) {
      tm0 = fmaxf(tm0, fmaxf(cs[nb][0], cs[nb][1]));
      tm1 = fmaxf(tm1, fmaxf(cs[nb][2], cs[nb][3]));
    }
    tm0 *= scale; tm1 *= scale;
#pragma unroll
    for (int off = 1; off <= 2; off <<= 1) {
      tm0 = fmaxf(tm0, __shfl_xor_sync(0xffffffffu, tm0, off));
      tm1 = fmaxf(tm1, __shfl_xor_sync(0xffffffffu, tm1, off));
    }
    const float mn0 = fmaxf(m0, tm0), mn1 = fmaxf(m1, tm1);
    const float al0 = __expf(m0 - mn0), al1 = __expf(m1 - mn1);
    m0 = mn0; m1 = mn1;

    float ts0 = 0.f, ts1 = 0.f;
#pragma unroll
    for (int nb = 0; nb < 8; nb++) {
      cs[nb][0] = __expf(cs[nb][0] * scale - mn0);
      cs[nb][1] = __expf(cs[nb][1] * scale - mn0);
      cs[nb][2] = __expf(cs[nb][2] * scale - mn1);
      cs[nb][3] = __expf(cs[nb][3] * scale - mn1);
      ts0 += cs[nb][0] + cs[nb][1];
      ts1 += cs[nb][2] + cs[nb][3];
    }
#pragma unroll
    for (int off = 1; off <= 2; off <<= 1) {
      ts0 += __shfl_xor_sync(0xffffffffu, ts0, off);
      ts1 += __shfl_xor_sync(0xffffffffu, ts1, off);
    }
    lr0 = lr0 * al0 + ts0;
    lr1 = lr1 * al1 + ts1;

#pragma unroll
    for (int nb = 0; nb < 8; nb++) {
      co[nb][0] *= al0; co[nb][1] *= al0;
      co[nb][2] *= al1; co[nb][3] *= al1;
    }

    // O += P . V (P packed in registers)
#pragma unroll
    for (int kq = 0; kq < 4; kq++) {
      const int s0 = 2 * kq, s1 = 2 * kq + 1;
      __nv_bfloat16 h, l;
      uint32_t pa0, pa1, pa2, pa3, la0, la1, la2, la3;
      {
        __nv_bfloat16 h2, l2;
        split_bf16(cs[s0][0], h, l); split_bf16(cs[s0][1], h2, l2);
        pa0 = pack_bf16(h, h2); la0 = pack_bf16(l, l2);
        split_bf16(cs[s0][2], h, l); split_bf16(cs[s0][3], h2, l2);
        pa1 = pack_bf16(h, h2); la1 = pack_bf16(l, l2);
        split_bf16(cs[s1][0], h, l); split_bf16(cs[s1][1], h2, l2);
        pa2 = pack_bf16(h, h2); la2 = pack_bf16(l, l2);
        split_bf16(cs[s1][2], h, l); split_bf16(cs[s1][3], h2, l2);
        pa3 = pack_bf16(h, h2); la3 = pack_bf16(l, l2);
      }
      const int ko = kq * 8;
#pragma unroll
      for (int nb = 0; nb < 8; nb++) {
        const int n = nb * 8 + gid;
        const uint32_t b0 = vh[n * FK_S + ko + tig];
        const uint32_t b1 = vh[n * FK_S + ko + tig + 4];
        const uint32_t c0 = vl[n * FK_S + ko + tig];
        const uint32_t c1 = vl[n * FK_S + ko + tig + 4];
        mma_bf16(co[nb], pa0, pa1, pa2, pa3, b0, b1);
        mma_bf16(co[nb], pa0, pa1, pa2, pa3, c0, c1);
        mma_bf16(co[nb], la0, la1, la2, la3, b0, b1);
      }
    }
    __syncthreads();
  }

  // epilogue: scatter O / l as bf16 hi/lo pairs
  const int b = bh >> 4, h = bh & 15;
  const int r0 = rbase + gid, r1 = r0 + 8;
  const int s0 = qidx[r0], s1 = qidx[r1];
  const float inv0 = 1.0f / lr0, inv1 = 1.0f / lr1;
#pragma unroll
  for (int nb = 0; nb < 8; nb++) {
    const int col = h * PDH + nb * 8 + tig * 2;
    if (s0 >= 0) {
      __nv_bfloat16 h0, l0, h1, l1;
      split_bf16(co[nb][0] * inv0, h0, l0);
      split_bf16(co[nb][1] * inv0, h1, l1);
      const size_t ui = ((size_t)(b * PL + s0) * PD + col) / 2;
      g_abh[ui] = pack_bf16(h0, h1);
      g_abl[ui] = pack_bf16(l0, l1);
    }
    if (s1 >= 0) {
      __nv_bfloat16 h0, l0, h1, l1;
      split_bf16(co[nb][2] * inv1, h0, l0);
      split_bf16(co[nb][3] * inv1, h1, l1);
      const size_t ui = ((size_t)(b * PL + s1) * PD + col) / 2;
      g_abh[ui] = pack_bf16(h0, h1);
      g_abl[ui] = pack_bf16(l0, l1);
    }
  }
}

// ============================================================
// host launcher
// ============================================================
extern "C" void kernel_launch(void* const* d_in, const int* in_sizes, int n_in,
                              void* d_out, int out_size) {
  (void)in_sizes; (void)n_in; (void)out_size;
  const float* x  = (const float*)d_in[0];
  const float* Wq = (const float*)d_in[1];
  const float* bq = (const float*)d_in[2];
  const float* Wk = (const float*)d_in[3];
  const float* bk = (const float*)d_in[4];
  const float* Wv = (const float*)d_in[5];
  const float* bv = (const float*)d_in[6];
  const float* Wo = (const float*)d_in[7];
  const float* bo = (const float*)d_in[8];
  float* out = (float*)d_out;

  float *pq, *pk, *pv;
  uint32_t *pwhi, *pwlo, *pxthi, *pxtlo, *pabh, *pabl;
  __nv_bfloat16 *pxbh, *pxbl, *pwvth, *pwvtl, *pwoth, *pwotl, *pvth, *pvtl;
  cudaGetSymbolAddress((void**)&pq, g_q);
  cudaGetSymbolAddress((void**)&pk, g_k);
  cudaGetSymbolAddress((void**)&pv, g_v);
  cudaGetSymbolAddress((void**)&pwhi, g_whi);
  cudaGetSymbolAddress((void**)&pwlo, g_wlo);
  cudaGetSymbolAddress((void**)&pxthi, g_xthi);
  cudaGetSymbolAddress((void**)&pxtlo, g_xtlo);
  cudaGetSymbolAddress((void**)&pxbh, g_xbh);
  cudaGetSymbolAddress((void**)&pxbl, g_xbl);
  cudaGetSymbolAddress((void**)&pwvth, g_wvth);
  cudaGetSymbolAddress((void**)&pwvtl, g_wvtl);
  cudaGetSymbolAddress((void**)&pwoth, g_woth);
  cudaGetSymbolAddress((void**)&pwotl, g_wotl);
  cudaGetSymbolAddress((void**)&pvth, g_vth);
  cudaGetSymbolAddress((void**)&pvtl, g_vtl);
  cudaGetSymbolAddress((void**)&pabh, g_abh);
  cudaGetSymbolAddress((void**)&pabl, g_abl);

  cudaFuncSetAttribute(gemm_qk, cudaFuncAttributeMaxDynamicSharedMemorySize, GEMM_SMEM);
  cudaFuncSetAttribute(gemm_bf16<0>, cudaFuncAttributeMaxDynamicSharedMemorySize, GBF_SMEM);
  cudaFuncSetAttribute(gemm_bf16<1>, cudaFuncAttributeMaxDynamicSharedMemorySize, GBF_SMEM);
  cudaFuncSetAttribute(sparsity_v7, cudaFuncAttributeMaxDynamicSharedMemorySize, SP7_SMEM);
  cudaFuncSetAttribute(flash_v5, cudaFuncAttributeMaxDynamicSharedMemorySize, FL_SMEM);

  const size_t WN = (size_t)PD * PD;
  const int n4w = (int)(WN / 4);
  const int n4x = (int)((size_t)PM * PD / 4);

  // pre-splits
  split_kernel<<<(n4w + 255) / 256, 256>>>(Wq, pwhi + 0 * WN, pwlo + 0 * WN, n4w);
  split_kernel<<<(n4w + 255) / 256, 256>>>(Wk, pwhi + 1 * WN, pwlo + 1 * WN, n4w);
  transpose_split<<<dim3(PM / 32, PD / 32), 256>>>(x, pxthi, pxtlo, PM, PD);
  split_bf16_kernel<<<(n4x + 255) / 256, 256>>>(x, pxbh, pxbl, n4x);
  transpose_split_bf16<<<dim3(PD / 32, PD / 32), 256>>>(Wv, pwvth, pwvtl, PD, PD);
  transpose_split_bf16<<<dim3(PD / 32, PD / 32), 256>>>(Wo, pwoth, pwotl, PD, PD);

  // projections
  gemm_qk<<<dim3(2 * PD / 128, PM / 128), 256, GEMM_SMEM>>>(
      pxthi, pxtlo, pwhi + 0 * WN, pwlo + 0 * WN, pwhi + 1 * WN, pwlo + 1 * WN,
      bq, bk, pq, pk);
  gemm_bf16<1><<<dim3(PD / 128, PM / 128), 256, GBF_SMEM>>>(
      pxbh, pxbl, pwvth, pwvtl, bv, pv, PM, PD, PD);

  // V^T bf16 split for flash
  const dim3 gT(PL / 32, PDH / 32, PBH);
  transpose_head_bf16<<<gT, 256>>>(pv, pvth, pvtl);

  // selection: kbar (exact mean vector), bf16 argmax pass, exact refine, top-k
  kbar_kernel<<<PBH, 1024>>>();
  sparsity_v7<<<dim3(PL / 128, PBH), 256, SP7_SMEM>>>();
  refine_kernel<<<PBH * PL / 8, 256>>>();
  topk_radix<<<PBH, 256>>>();

  // attention on selected rows
  zero_ab<<<(int)(2 * ((size_t)PM * PD / 8) / 256), 256>>>();
  flash_v5<<<dim3((PU + 127) / 128, PBH), 256, FL_SMEM>>>();

  // output projection
  gemm_bf16<0><<<dim3(PD / 128, PM / 128), 256, GBF_SMEM>>>(
      (const __nv_bfloat16*)pabh, (const __nv_bfloat16*)pabl,
      pwoth, pwotl, bo, out, PM, PD, PD);
}

// round 14
// speedup vs baseline: 2.5831x; 1.0653x over previous
#include <cuda_runtime.h>
#include <cuda_bf16.h>
#include <cstdint>

// ---------------- problem constants ----------------
#define PB 2
#define PL 2048
#define PD 1024
#define PH 16
#define PDH 64
#define PU 1228          // int(0.6 * 2048)
#define PBH (PB * PH)    // 32
#define PM (PB * PL)     // 4096 rows

// ---------------- device scratch (no allocation allowed) ----------------
__device__ float g_q [(size_t)PBH * PL * PDH];   // [b,h,l,dh] fp32 (refine)
__device__ float g_k [(size_t)PBH * PL * PDH];   // [b,h,l,dh] fp32 (refine/kbar)
__device__ float g_v [(size_t)PBH * PL * PDH];   // [b,h,l,dh] fp32
// 3-way bf16 split of x (h+m+l ~ 24 mantissa bits)
__device__ __nv_bfloat16 g_x3h[(size_t)PM * PD];
__device__ __nv_bfloat16 g_x3m[(size_t)PM * PD];
__device__ __nv_bfloat16 g_x3l[(size_t)PM * PD];
// 2-way bf16 splits of W^T ([N][K])
__device__ __nv_bfloat16 g_wqth[(size_t)PD * PD];
__device__ __nv_bfloat16 g_wqtl[(size_t)PD * PD];
__device__ __nv_bfloat16 g_wkth[(size_t)PD * PD];
__device__ __nv_bfloat16 g_wktl[(size_t)PD * PD];
__device__ __nv_bfloat16 g_wvth[(size_t)PD * PD];
__device__ __nv_bfloat16 g_wvtl[(size_t)PD * PD];
__device__ __nv_bfloat16 g_woth[(size_t)PD * PD];
__device__ __nv_bfloat16 g_wotl[(size_t)PD * PD];
// bf16 pair-packed (u32 = 2 bf16) operands
__device__ uint32_t g_qbh[(size_t)PBH * PL * PDH / 2];  // Q row-major bf16 hi
__device__ uint32_t g_qbl[(size_t)PBH * PL * PDH / 2];
__device__ uint32_t g_kbh[(size_t)PBH * PL * PDH / 2];  // K row-major bf16 hi
__device__ uint32_t g_kbl[(size_t)PBH * PL * PDH / 2];
__device__ uint32_t g_abh[(size_t)PM * PD / 2];         // attn row-major bf16 hi
__device__ uint32_t g_abl[(size_t)PM * PD / 2];
__device__ __nv_bfloat16 g_vth[(size_t)PBH * PDH * PL];  // V^T [bh][dh][l] bf16 hi
__device__ __nv_bfloat16 g_vtl[(size_t)PBH * PDH * PL];
__device__ float g_kbar[PBH * PDH];              // per-head mean K row
__device__ int   g_amax[(size_t)PBH * PL];       // per-row argmax key
__device__ float g_spars[(size_t)PBH * PL];
__device__ int   g_topidx[(size_t)PBH * PU];

// ---------------- cp.async helpers ----------------
#define CP16(dst_u32, src_ptr) \
  asm volatile("cp.async.cg.shared.global [%0], [%1], 16;\n" :: "r"(dst_u32), "l"(src_ptr))
#define CP_COMMIT() asm volatile("cp.async.commit_group;\n" ::)
#define CP_WAIT0()  asm volatile("cp.async.wait_group 0;\n" ::)
#define CP_WAIT1()  asm volatile("cp.async.wait_group 1;\n" ::)

static __device__ __forceinline__ uint32_t sptr(const void* p) {
  return (uint32_t)__cvta_generic_to_shared(p);
}

// ---------------- bf16 helpers ----------------
static __device__ __forceinline__ void split_bf16(float x, __nv_bfloat16& h, __nv_bfloat16& l) {
  h = __float2bfloat16(x);
  l = __float2bfloat16(x - __bfloat162float(h));
}

static __device__ __forceinline__ uint32_t pack_bf16(__nv_bfloat16 a, __nv_bfloat16 b) {
  return (uint32_t)__bfloat16_as_ushort(a) | ((uint32_t)__bfloat16_as_ushort(b) << 16);
}

static __device__ __forceinline__ void mma_bf16(
    float* c, uint32_t a0, uint32_t a1, uint32_t a2, uint32_t a3,
    uint32_t b0, uint32_t b1) {
  asm volatile(
      "mma.sync.aligned.m16n8k16.row.col.f32.bf16.bf16.f32 "
      "{%0,%1,%2,%3}, {%4,%5,%6,%7}, {%8,%9}, {%0,%1,%2,%3};"
      : "+f"(c[0]), "+f"(c[1]), "+f"(c[2]), "+f"(c[3])
      : "r"(a0), "r"(a1), "r"(a2), "r"(a3), "r"(b0), "r"(b1));
}

// ============================================================
// Elementwise / transpose splits.
// ============================================================
// 3-way split: x = h + m + l (bf16 each)
__global__ __launch_bounds__(256) void split3_bf16_kernel(
    const float* __restrict__ in, __nv_bfloat16* __restrict__ oh,
    __nv_bfloat16* __restrict__ om, __nv_bfloat16* __restrict__ ol, int n4) {
  const int i = blockIdx.x * 256 + threadIdx.x;
  if (i >= n4) return;
  float4 v = ((const float4*)in)[i];
  float a[4] = {v.x, v.y, v.z, v.w};
  __nv_bfloat16 h[4], m[4], l[4];
#pragma unroll
  for (int j = 0; j < 4; j++) {
    h[j] = __float2bfloat16(a[j]);
    float r = a[j] - __bfloat162float(h[j]);
    m[j] = __float2bfloat16(r);
    r -= __bfloat162float(m[j]);
    l[j] = __float2bfloat16(r);
  }
  uint2 hp = {pack_bf16(h[0], h[1]), pack_bf16(h[2], h[3])};
  uint2 mp = {pack_bf16(m[0], m[1]), pack_bf16(m[2], m[3])};
  uint2 lp = {pack_bf16(l[0], l[1]), pack_bf16(l[2], l[3])};
  ((uint2*)oh)[i] = hp;
  ((uint2*)om)[i] = mp;
  ((uint2*)ol)[i] = lp;
}

__global__ __launch_bounds__(256) void transpose_split_bf16(
    const float* __restrict__ in, __nv_bfloat16* __restrict__ ohi,
    __nv_bfloat16* __restrict__ olo, int M, int N) {
  __shared__ float t[32][33];
  const int m0 = blockIdx.x * 32, n0 = blockIdx.y * 32;
  const int x = threadIdx.x & 31, y = threadIdx.x >> 5;
#pragma unroll
  for (int k = 0; k < 4; k++)
    t[y + 8 * k][x] = in[(size_t)(m0 + y + 8 * k) * N + n0 + x];
  __syncthreads();
#pragma unroll
  for (int k = 0; k < 4; k++) {
    const float v = t[x][y + 8 * k];
    __nv_bfloat16 h, l;
    split_bf16(v, h, l);
    const size_t idx = (size_t)(n0 + y + 8 * k) * M + m0 + x;
    ohi[idx] = h;
    olo[idx] = l;
  }
}

// Head transpose + bf16 split: [bh][l][dh] -> [bh][dh][l] bf16 (for V^T).
__global__ __launch_bounds__(256) void transpose_head_bf16(
    const float* __restrict__ in, __nv_bfloat16* __restrict__ ohi,
    __nv_bfloat16* __restrict__ olo) {
  __shared__ float t[32][33];
  const int bh = blockIdx.z;
  const int l0 = blockIdx.x * 32, d0 = blockIdx.y * 32;
  const int x = threadIdx.x & 31, y = threadIdx.x >> 5;
  const float* ip = in + (size_t)bh * PL * PDH;
#pragma unroll
  for (int k = 0; k < 4; k++)
    t[y + 8 * k][x] = ip[(size_t)(l0 + y + 8 * k) * PDH + d0 + x];
  __syncthreads();
  const size_t base = (size_t)bh * PDH * PL;
#pragma unroll
  for (int k = 0; k < 4; k++) {
    const float v = t[x][y + 8 * k];
    __nv_bfloat16 h, l;
    split_bf16(v, h, l);
    const size_t idx = base + (size_t)(d0 + y + 8 * k) * PL + l0 + x;
    ohi[idx] = h;
    olo[idx] = l;
  }
}

// ============================================================
// gemm_qk5: fused Q+K projection, bf16 5-term (fp32-grade).
// A = x split 3-way (h/m/l) row-major; B = W^T split 2-way [N][K].
// Terms: Ah·Bh + Ah·Bl + Am·Bh + Am·Bl + Al·Bh (drop Al·Bl ~ 2^-26).
// 128x128x32 tiles, m16n8k16, cp.async double-buffered.
// Epilogue: fp32 head layout + packed bf16 hi/lo pairs.
// grid (16, 32): x<8 -> Q, else K.
// ============================================================
#define GB_S 20
#define QK5_SMEM (5 * 2 * 128 * GB_S * 4)   // 102,400 B

__global__ __launch_bounds__(256, 2) void gemm_qk5(
    const float* __restrict__ biasQ, const float* __restrict__ biasK) {
  extern __shared__ uint32_t smq[];
  uint32_t* Ah = smq;                       // [2][128][GB_S] each
  uint32_t* Am = Ah + 2 * 128 * GB_S;
  uint32_t* Al = Am + 2 * 128 * GB_S;
  uint32_t* Bh = Al + 2 * 128 * GB_S;
  uint32_t* Bl = Bh + 2 * 128 * GB_S;

  const bool isK = (blockIdx.x >= PD / 128);
  const __nv_bfloat16* BgH = isK ? g_wkth : g_wqth;
  const __nv_bfloat16* BgL = isK ? g_wktl : g_wqtl;
  const float* bias = isK ? biasK : biasQ;
  float* C = isK ? g_k : g_q;
  uint32_t* OH = isK ? g_kbh : g_qbh;
  uint32_t* OL = isK ? g_kbl : g_qbl;
  const int bn = (isK ? blockIdx.x - PD / 128 : blockIdx.x) * 128;
  const int bm = blockIdx.y * 128;
  const int K = PD;

  const int tid = threadIdx.x;
  const int warp = tid >> 5, lane = tid & 31;
  const int gid = lane >> 2, tig = lane & 3;
  const int wm = warp >> 1, wn = warp & 1;

  const int lr = tid >> 1;            // tile row 0..127
  const int lh = (tid & 1) * 16;      // bf16 element offset 0 or 16

  float c[2][8][4];
#pragma unroll
  for (int mb = 0; mb < 2; mb++)
#pragma unroll
    for (int nb = 0; nb < 8; nb++)
#pragma unroll
      for (int j = 0; j < 4; j++) c[mb][nb][j] = 0.f;

  const int NP = K >> 5;   // 32-K panels

  auto issue = [&](int p, int bf) {
    const __nv_bfloat16* ah = g_x3h + (size_t)(bm + lr) * K + p * 32 + lh;
    const __nv_bfloat16* am = g_x3m + (size_t)(bm + lr) * K + p * 32 + lh;
    const __nv_bfloat16* al = g_x3l + (size_t)(bm + lr) * K + p * 32 + lh;
    const __nv_bfloat16* bhh = BgH + (size_t)(bn + lr) * K + p * 32 + lh;
    const __nv_bfloat16* bll = BgL + (size_t)(bn + lr) * K + p * 32 + lh;
    const uint32_t so = (bf * 128 + lr) * GB_S * 4 + lh * 2;  // byte offset
    CP16(sptr(Ah) + so, ah);  CP16(sptr(Ah) + so + 16, ah + 8);
    CP16(sptr(Am) + so, am);  CP16(sptr(Am) + so + 16, am + 8);
    CP16(sptr(Al) + so, al);  CP16(sptr(Al) + so + 16, al + 8);
    CP16(sptr(Bh) + so, bhh); CP16(sptr(Bh) + so + 16, bhh + 8);
    CP16(sptr(Bl) + so, bll); CP16(sptr(Bl) + so + 16, bll + 8);
    CP_COMMIT();
  };

  issue(0, 0);

#pragma unroll 1
  for (int p = 0; p < NP; p++) {
    const int buf = p & 1;
    if (p + 1 < NP) { issue(p + 1, buf ^ 1); CP_WAIT1(); }
    else            { CP_WAIT0(); }
    __syncthreads();

    const uint32_t* ah = Ah + buf * 128 * GB_S;
    const uint32_t* am = Am + buf * 128 * GB_S;
    const uint32_t* al = Al + buf * 128 * GB_S;
    const uint32_t* bhp = Bh + buf * 128 * GB_S;
    const uint32_t* blp = Bl + buf * 128 * GB_S;

#pragma unroll
    for (int kb = 0; kb < 2; kb++) {
      const int ko = kb * 8;
      uint32_t fh[2][4], fm[2][4], fl[2][4];
#pragma unroll
      for (int mb = 0; mb < 2; mb++) {
        const int r = wm * 32 + mb * 16;
        fh[mb][0] = ah[(r + gid)     * GB_S + ko + tig];
        fh[mb][1] = ah[(r + gid + 8) * GB_S + ko + tig];
        fh[mb][2] = ah[(r + gid)     * GB_S + ko + tig + 4];
        fh[mb][3] = ah[(r + gid + 8) * GB_S + ko + tig + 4];
        fm[mb][0] = am[(r + gid)     * GB_S + ko + tig];
        fm[mb][1] = am[(r + gid + 8) * GB_S + ko + tig];
        fm[mb][2] = am[(r + gid)     * GB_S + ko + tig + 4];
        fm[mb][3] = am[(r + gid + 8) * GB_S + ko + tig + 4];
        fl[mb][0] = al[(r + gid)     * GB_S + ko + tig];
        fl[mb][1] = al[(r + gid + 8) * GB_S + ko + tig];
        fl[mb][2] = al[(r + gid)     * GB_S + ko + tig + 4];
        fl[mb][3] = al[(r + gid + 8) * GB_S + ko + tig + 4];
      }
#pragma unroll
      for (int nb = 0; nb < 8; nb++) {
        const int n = wn * 64 + nb * 8 + gid;
        const uint32_t bh0 = bhp[n * GB_S + ko + tig];
        const uint32_t bh1 = bhp[n * GB_S + ko + tig + 4];
        const uint32_t bl0 = blp[n * GB_S + ko + tig];
        const uint32_t bl1 = blp[n * GB_S + ko + tig + 4];
#pragma unroll
        for (int mb = 0; mb < 2; mb++) {
          mma_bf16(c[mb][nb], fh[mb][0], fh[mb][1], fh[mb][2], fh[mb][3], bh0, bh1);
          mma_bf16(c[mb][nb], fh[mb][0], fh[mb][1], fh[mb][2], fh[mb][3], bl0, bl1);
          mma_bf16(c[mb][nb], fm[mb][0], fm[mb][1], fm[mb][2], fm[mb][3], bh0, bh1);
          mma_bf16(c[mb][nb], fm[mb][0], fm[mb][1], fm[mb][2], fm[mb][3], bl0, bl1);
          mma_bf16(c[mb][nb], fl[mb][0], fl[mb][1], fl[mb][2], fl[mb][3], bh0, bh1);
        }
      }
    }
    __syncthreads();
  }

  // epilogue: fp32 head layout + packed bf16 hi/lo pairs
#pragma unroll
  for (int mb = 0; mb < 2; mb++) {
#pragma unroll
    for (int nb = 0; nb < 8; nb++) {
      const int m0 = bm + wm * 32 + mb * 16 + gid;
      const int n0 = bn + wn * 64 + nb * 8 + tig * 2;
      const float bx = bias[n0], by = bias[n0 + 1];
      float2 v0 = {c[mb][nb][0] + bx, c[mb][nb][1] + by};
      float2 v1 = {c[mb][nb][2] + bx, c[mb][nb][3] + by};
      const int h = n0 >> 6, dh = n0 & 63;
      const int b0i = m0 >> 11, l0 = m0 & (PL - 1);
      const int b1i = (m0 + 8) >> 11, l1 = (m0 + 8) & (PL - 1);
      const size_t i0 = (((size_t)b0i * PH + h) * PL + l0) * PDH + dh;
      const size_t i1 = (((size_t)b1i * PH + h) * PL + l1) * PDH + dh;
      *(float2*)&C[i0] = v0;
      *(float2*)&C[i1] = v1;
      __nv_bfloat16 h0, l0b, h1, l1b;
      split_bf16(v0.x, h0, l0b); split_bf16(v0.y, h1, l1b);
      OH[i0 / 2] = pack_bf16(h0, h1);
      OL[i0 / 2] = pack_bf16(l0b, l1b);
      split_bf16(v1.x, h0, l0b); split_bf16(v1.y, h1, l1b);
      OH[i1 / 2] = pack_bf16(h0, h1);
      OL[i1 / 2] = pack_bf16(l0b, l1b);
    }
  }
}

// ============================================================
// bf16x2 3-term GEMM (unchanged): V and Wo paths.
// ============================================================
#define GBF_SMEM (4 * 2 * 128 * GB_S * 4)

template<int MODE>
__global__ __launch_bounds__(256, 2) void gemm_bf16(
    const __nv_bfloat16* __restrict__ Agh, const __nv_bfloat16* __restrict__ Agl,
    const __nv_bfloat16* __restrict__ Bgh, const __nv_bfloat16* __restrict__ Bgl,
    const float* __restrict__ bias, float* __restrict__ C,
    int M, int N, int K) {
  extern __shared__ uint32_t smb[];
  uint32_t* Ah = smb;
  uint32_t* Al = Ah + 2 * 128 * GB_S;
  uint32_t* Bh = Al + 2 * 128 * GB_S;
  uint32_t* Bl = Bh + 2 * 128 * GB_S;

  const int tid = threadIdx.x;
  const int warp = tid >> 5, lane = tid & 31;
  const int gid = lane >> 2, tig = lane & 3;
  const int wm = warp >> 1, wn = warp & 1;
  const int bm = blockIdx.y * 128, bn = blockIdx.x * 128;

  const int lr = tid >> 1;
  const int lh = (tid & 1) * 16;

  float c[2][8][4];
#pragma unroll
  for (int mb = 0; mb < 2; mb++)
#pragma unroll
    for (int nb = 0; nb < 8; nb++)
#pragma unroll
      for (int j = 0; j < 4; j++) c[mb][nb][j] = 0.f;

  const int NP = K >> 5;

  auto issue = [&](int p, int bf) {
    const __nv_bfloat16* asrc = Agh + (size_t)(bm + lr) * K + p * 32 + lh;
    const __nv_bfloat16* asrl = Agl + (size_t)(bm + lr) * K + p * 32 + lh;
    const __nv_bfloat16* bsrc = Bgh + (size_t)(bn + lr) * K + p * 32 + lh;
    const __nv_bfloat16* bsrl = Bgl + (size_t)(bn + lr) * K + p * 32 + lh;
    const uint32_t so = (bf * 128 + lr) * GB_S * 4 + lh * 2;
    CP16(sptr(Ah) + so, asrc); CP16(sptr(Ah) + so + 16, asrc + 8);
    CP16(sptr(Al) + so, asrl); CP16(sptr(Al) + so + 16, asrl + 8);
    CP16(sptr(Bh) + so, bsrc); CP16(sptr(Bh) + so + 16, bsrc + 8);
    CP16(sptr(Bl) + so, bsrl); CP16(sptr(Bl) + so + 16, bsrl + 8);
    CP_COMMIT();
  };

  issue(0, 0);

#pragma unroll 1
  for (int p = 0; p < NP; p++) {
    const int buf = p & 1;
    if (p + 1 < NP) { issue(p + 1, buf ^ 1); CP_WAIT1(); }
    else            { CP_WAIT0(); }
    __syncthreads();

    const uint32_t* ah = Ah + buf * 128 * GB_S;
    const uint32_t* al = Al + buf * 128 * GB_S;
    const uint32_t* bhp = Bh + buf * 128 * GB_S;
    const uint32_t* blp = Bl + buf * 128 * GB_S;

#pragma unroll
    for (int kb = 0; kb < 2; kb++) {
      const int ko = kb * 8;
      uint32_t ahi[2][4], alo[2][4];
#pragma unroll
      for (int mb = 0; mb < 2; mb++) {
        const int r = wm * 32 + mb * 16;
        ahi[mb][0] = ah[(r + gid)     * GB_S + ko + tig];
        ahi[mb][1] = ah[(r + gid + 8) * GB_S + ko + tig];
        ahi[mb][2] = ah[(r + gid)     * GB_S + ko + tig + 4];
        ahi[mb][3] = ah[(r + gid + 8) * GB_S + ko + tig + 4];
        alo[mb][0] = al[(r + gid)     * GB_S + ko + tig];
        alo[mb][1] = al[(r + gid + 8) * GB_S + ko + tig];
        alo[mb][2] = al[(r + gid)     * GB_S + ko + tig + 4];
        alo[mb][3] = al[(r + gid + 8) * GB_S + ko + tig + 4];
      }
#pragma unroll
      for (int nb = 0; nb < 8; nb++) {
        const int n = wn * 64 + nb * 8 + gid;
        const uint32_t bh0 = bhp[n * GB_S + ko + tig];
        const uint32_t bh1 = bhp[n * GB_S + ko + tig + 4];
        const uint32_t bl0 = blp[n * GB_S + ko + tig];
        const uint32_t bl1 = blp[n * GB_S + ko + tig + 4];
#pragma unroll
        for (int mb = 0; mb < 2; mb++) {
          mma_bf16(c[mb][nb], ahi[mb][0], ahi[mb][1], ahi[mb][2], ahi[mb][3], bh0, bh1);
          mma_bf16(c[mb][nb], ahi[mb][0], ahi[mb][1], ahi[mb][2], ahi[mb][3], bl0, bl1);
          mma_bf16(c[mb][nb], alo[mb][0], alo[mb][1], alo[mb][2], alo[mb][3], bh0, bh1);
        }
      }
    }
    __syncthreads();
  }

#pragma unroll
  for (int mb = 0; mb < 2; mb++) {
#pragma unroll
    for (int nb = 0; nb < 8; nb++) {
      const int m0 = bm + wm * 32 + mb * 16 + gid;
      const int n0 = bn + wn * 64 + nb * 8 + tig * 2;
      const float bx = bias[n0], by = bias[n0 + 1];
      float2 v0 = {c[mb][nb][0] + bx, c[mb][nb][1] + by};
      float2 v1 = {c[mb][nb][2] + bx, c[mb][nb][3] + by};
      if (MODE == 0) {
        *(float2*)&C[(size_t)m0 * N + n0] = v0;
        *(float2*)&C[(size_t)(m0 + 8) * N + n0] = v1;
      } else {
        const int h = n0 >> 6, dh = n0 & 63;
        const int b0i = m0 >> 11, l0 = m0 & (PL - 1);
        const int b1i = (m0 + 8) >> 11, l1 = (m0 + 8) & (PL - 1);
        *(float2*)&C[(((size_t)b0i * PH + h) * PL + l0) * PDH + dh] = v0;
        *(float2*)&C[(((size_t)b1i * PH + h) * PL + l1) * PDH + dh] = v1;
      }
    }
  }
}

// ============================================================
// kbar: per-head mean K row (exact fp32).
// ============================================================
__global__ __launch_bounds__(1024) void kbar_kernel() {
  __shared__ float acc[16][64];
  const int bh = blockIdx.x, tid = threadIdx.x;
  const int dh = tid & 63, grp = tid >> 6;
  float s = 0.f;
  for (int r = grp; r < PL; r += 16)
    s += g_k[((size_t)bh * PL + r) * PDH + dh];
  acc[grp][dh] = s;
  __syncthreads();
  if (tid < 64) {
    float t = 0.f;
#pragma unroll
    for (int g2 = 0; g2 < 16; g2++) t += acc[g2][tid];
    g_kbar[bh * PDH + tid] = t * (1.0f / PL);
  }
}

// ============================================================
// Sparsity v7 (unchanged): bf16 3-term QK^T argmax pass.
// ============================================================
#define SQ_S 36
#define SK_S 36
#define SP7_SMEM ((2 * 128 * SQ_S + 4 * 64 * SK_S) * 4)

__global__ __launch_bounds__(256, 2) void sparsity_v7() {
  extern __shared__ uint32_t sm7[];
  uint32_t* Qh = sm7;
  uint32_t* Ql = Qh + 128 * SQ_S;
  uint32_t* Kh = Ql + 128 * SQ_S;
  uint32_t* Kl = Kh + 2 * 64 * SK_S;

  const int bh = blockIdx.y, q0 = blockIdx.x * 128;
  const int tid = threadIdx.x;
  const int warp = tid >> 5, lane = tid & 31;
  const int gid = lane >> 2, tig = lane & 3;
  const int rbase = warp * 16;

  {
    const int r = tid >> 1, c0 = (tid & 1) * 16;
    const uint32_t* qh = g_qbh + (size_t)(bh * PL + q0 + r) * 32 + c0;
    const uint32_t* ql = g_qbl + (size_t)(bh * PL + q0 + r) * 32 + c0;
    const uint32_t hd = sptr(&Qh[r * SQ_S + c0]);
    const uint32_t ld = sptr(&Ql[r * SQ_S + c0]);
#pragma unroll
    for (int j = 0; j < 4; j++) CP16(hd + j * 16, qh + j * 4);
#pragma unroll
    for (int j = 0; j < 4; j++) CP16(ld + j * 16, ql + j * 4);
  }
  const int krow = tid >> 2;
  const int seg = (tid & 3) * 8;
  auto issueK = [&](int kt, int bf) {
    const uint32_t* kh = g_kbh + (size_t)(bh * PL + kt * 64 + krow) * 32 + seg;
    const uint32_t* kl = g_kbl + (size_t)(bh * PL + kt * 64 + krow) * 32 + seg;
    const uint32_t so = ((bf * 64 + krow) * SK_S + seg) * 4;
    CP16(sptr(Kh) + so, kh); CP16(sptr(Kh) + so + 16, kh + 4);
    CP16(sptr(Kl) + so, kl); CP16(sptr(Kl) + so + 16, kl + 4);
    CP_COMMIT();
  };
  issueK(0, 0);

  float mx0 = -1e30f, mx1 = -1e30f;
  int ix0 = 0, ix1 = 0;

#pragma unroll 1
  for (int kt = 0; kt < PL / 64; kt++) {
    const int buf = kt & 1;
    if (kt + 1 < PL / 64) { issueK(kt + 1, buf ^ 1); CP_WAIT1(); }
    else                  { CP_WAIT0(); }
    __syncthreads();

    const uint32_t* kh = Kh + buf * 64 * SK_S;
    const uint32_t* kl = Kl + buf * 64 * SK_S;

    float cs[8][4];
#pragma unroll
    for (int nb = 0; nb < 8; nb++)
#pragma unroll
      for (int j = 0; j < 4; j++) cs[nb][j] = 0.f;

#pragma unroll
    for (int ks = 0; ks < 4; ks++) {
      const int ko = ks * 8;
      const uint32_t qh0 = Qh[(rbase + gid)     * SQ_S + ko + tig];
      const uint32_t qh1 = Qh[(rbase + gid + 8) * SQ_S + ko + tig];
      const uint32_t qh2 = Qh[(rbase + gid)     * SQ_S + ko + tig + 4];
      const uint32_t qh3 = Qh[(rbase + gid + 8) * SQ_S + ko + tig + 4];
      const uint32_t ql0 = Ql[(rbase + gid)     * SQ_S + ko + tig];
      const uint32_t ql1 = Ql[(rbase + gid + 8) * SQ_S + ko + tig];
      const uint32_t ql2 = Ql[(rbase + gid)     * SQ_S + ko + tig + 4];
      const uint32_t ql3 = Ql[(rbase + gid + 8) * SQ_S + ko + tig + 4];
#pragma unroll
      for (int nb = 0; nb < 8; nb++) {
        const int n = nb * 8 + gid;
        const uint32_t b0 = kh[n * SK_S + ko + tig];
        const uint32_t b1 = kh[n * SK_S + ko + tig + 4];
        const uint32_t c0 = kl[n * SK_S + ko + tig];
        const uint32_t c1 = kl[n * SK_S + ko + tig + 4];
        mma_bf16(cs[nb], qh0, qh1, qh2, qh3, b0, b1);
        mma_bf16(cs[nb], qh0, qh1, qh2, qh3, c0, c1);
        mma_bf16(cs[nb], ql0, ql1, ql2, ql3, b0, b1);
      }
    }

#pragma unroll
    for (int nb = 0; nb < 8; nb++) {
      const int kb = kt * 64 + nb * 8 + tig * 2;
      if (cs[nb][0] > mx0) { mx0 = cs[nb][0]; ix0 = kb; }
      if (cs[nb][1] > mx0) { mx0 = cs[nb][1]; ix0 = kb + 1; }
      if (cs[nb][2] > mx1) { mx1 = cs[nb][2]; ix1 = kb; }
      if (cs[nb][3] > mx1) { mx1 = cs[nb][3]; ix1 = kb + 1; }
    }
    __syncthreads();
  }

#pragma unroll
  for (int off = 1; off <= 2; off <<= 1) {
    const float o0 = __shfl_xor_sync(0xffffffffu, mx0, off);
    const int oi0 = __shfl_xor_sync(0xffffffffu, ix0, off);
    if (o0 > mx0) { mx0 = o0; ix0 = oi0; }
    const float o1 = __shfl_xor_sync(0xffffffffu, mx1, off);
    const int oi1 = __shfl_xor_sync(0xffffffffu, ix1, off);
    if (o1 > mx1) { mx1 = o1; ix1 = oi1; }
  }
  if (tig == 0) {
    g_amax[(size_t)bh * PL + q0 + rbase + gid] = ix0;
    g_amax[(size_t)bh * PL + q0 + rbase + gid + 8] = ix1;
  }
}

// ============================================================
// Refine: exact fp32 sparsity score per row (unchanged).
// ============================================================
__global__ __launch_bounds__(256) void refine_kernel() {
  const int tid = threadIdx.x;
  const int warp = tid >> 5, lane = tid & 31;
  const int g = blockIdx.x * 8 + warp;
  const int bh = g >> 11;
  const int l = g & (PL - 1);
  const float* q = g_q + ((size_t)bh * PL + l) * PDH;
  const int am = g_amax[(size_t)bh * PL + l];
  const float* ka = g_k + ((size_t)bh * PL + am) * PDH;
  const float* kb = g_kbar + bh * PDH;
  const float2 qv = ((const float2*)q)[lane];
  const float2 kav = ((const float2*)ka)[lane];
  const float2 kbv = ((const float2*)kb)[lane];
  float dmax = qv.x * kav.x + qv.y * kav.y;
  float dmean = qv.x * kbv.x + qv.y * kbv.y;
#pragma unroll
  for (int off = 16; off; off >>= 1) {
    dmax += __shfl_xor_sync(0xffffffffu, dmax, off);
    dmean += __shfl_xor_sync(0xffffffffu, dmean, off);
  }
  if (lane == 0)
    g_spars[(size_t)bh * PL + l] = 0.125f * dmax - 0.125f * dmean;
}

// ============================================================
// Exact top-U via radix select (unchanged).
// ============================================================
__global__ __launch_bounds__(256) void topk_radix() {
  __shared__ unsigned su[2048];
  __shared__ int hist[256];
  __shared__ unsigned s_pref;
  __shared__ int s_rem;
  __shared__ unsigned eqm[64];
  __shared__ int wpfx[64];
  __shared__ int outcnt;

  const int bh = blockIdx.x;
  const int tid = threadIdx.x;

  for (int t = tid; t < 2048; t += 256) {
    unsigned b = __float_as_uint(g_spars[(size_t)bh * PL + t]);
    su[t] = (b & 0x80000000u) ? ~b : (b | 0x80000000u);
  }
  if (tid == 0) { s_pref = 0u; s_rem = PU; outcnt = 0; }
  if (tid < 64) eqm[tid] = 0u;
  __syncthreads();

  for (int shift = 24; shift >= 0; shift -= 8) {
    hist[tid & 255] = 0;
    __syncthreads();
    const unsigned pref = s_pref;
    for (int t = tid; t < 2048; t += 256) {
      const unsigned u = su[t];
      if (shift == 24 || (u >> (shift + 8)) == pref)
        atomicAdd(&hist[(u >> shift) & 255], 1);
    }
    __syncthreads();
    if (tid == 0) {
      int rem = s_rem, acc = 0;
      for (int b = 255; b >= 0; b--) {
        if (acc + hist[b] >= rem) {
          s_rem = rem - acc;
          s_pref = (s_pref << 8) | (unsigned)b;
          break;
        }
        acc += hist[b];
      }
    }
    __syncthreads();
  }

  const unsigned T = s_pref;
  const int e = s_rem;

  for (int t = tid; t < 2048; t += 256)
    if (su[t] == T) atomicOr(&eqm[t >> 5], 1u << (t & 31));
  __syncthreads();
  if (tid == 0) {
    int a = 0;
    for (int w = 0; w < 64; w++) { wpfx[w] = a; a += __popc(eqm[w]); }
  }
  __syncthreads();

  for (int t = tid; t < 2048; t += 256) {
    const unsigned u = su[t];
    bool sel = (u > T);
    if (u == T) {
      const int rank = wpfx[t >> 5] + __popc(eqm[t >> 5] & ((1u << (t & 31)) - 1u));
      sel = (rank < e);
    }
    if (sel) {
      const int slot = atomicAdd(&outcnt, 1);
      g_topidx[(size_t)bh * PU + slot] = t;
    }
  }
}

// ============================================================
// Zero the bf16 attn scatter buffers.
// ============================================================
__global__ void zero_ab() {
  const size_t i = (size_t)blockIdx.x * blockDim.x + threadIdx.x;
  const size_t N = (size_t)PM * PD / 8;
  uint4 z = {0u, 0u, 0u, 0u};
  if (i < N) ((uint4*)g_abh)[i] = z;
  else       ((uint4*)g_abl)[i - N] = z;
}

// ============================================================
// Flash v5 (unchanged): legacy bf16 MMA attention on selected rows.
// ============================================================
#define FQ_S 36
#define FK_S 36
#define FL_SMEM ((2 * 128 * FQ_S + 4 * 2 * 64 * FK_S) * 4)

__global__ __launch_bounds__(256, 2) void flash_v5() {
  extern __shared__ uint32_t smf[];
  uint32_t* Qh = smf;
  uint32_t* Ql = Qh + 128 * FQ_S;
  uint32_t* Kh = Ql + 128 * FQ_S;
  uint32_t* Kl = Kh + 2 * 64 * FK_S;
  uint32_t* Vh = Kl + 2 * 64 * FK_S;
  uint32_t* Vl = Vh + 2 * 64 * FK_S;
  __shared__ int qidx[128];

  const int bh = blockIdx.y, qt = blockIdx.x;
  const int tid = threadIdx.x;
  const int warp = tid >> 5, lane = tid & 31;
  const int gid = lane >> 2, tig = lane & 3;
  const int rbase = warp * 16;
  const float scale = 0.125f;

  if (tid < 128) {
    const int u = qt * 128 + tid;
    qidx[tid] = (u < PU) ? g_topidx[(size_t)bh * PU + u] : -1;
  }
  __syncthreads();

  {
    const int r = tid >> 1, c0 = (tid & 1) * 16;
    int src = qidx[r];
    if (src < 0) src = 0;
    const uint32_t* qh = g_qbh + (size_t)(bh * PL + src) * 32 + c0;
    const uint32_t* ql = g_qbl + (size_t)(bh * PL + src) * 32 + c0;
#pragma unroll
    for (int j = 0; j < 4; j++) {
      *(uint4*)&Qh[r * FQ_S + c0 + j * 4] = *(const uint4*)(qh + j * 4);
      *(uint4*)&Ql[r * FQ_S + c0 + j * 4] = *(const uint4*)(ql + j * 4);
    }
  }

  const int krow = tid >> 2;
  const int seg = (tid & 3) * 8;
  auto issueKV = [&](int kt, int bf) {
    const uint32_t* ksh = g_kbh + (size_t)(bh * PL + kt * 64 + krow) * 32 + seg;
    const uint32_t* ksl = g_kbl + (size_t)(bh * PL + kt * 64 + krow) * 32 + seg;
    const uint32_t* vsh = (const uint32_t*)g_vth + (size_t)(bh * PDH + krow) * (PL / 2) + kt * 32 + seg;
    const uint32_t* vsl = (const uint32_t*)g_vtl + (size_t)(bh * PDH + krow) * (PL / 2) + kt * 32 + seg;
    const uint32_t so = ((bf * 64 + krow) * FK_S + seg) * 4;
    CP16(sptr(Kh) + so, ksh); CP16(sptr(Kh) + so + 16, ksh + 4);
    CP16(sptr(Kl) + so, ksl); CP16(sptr(Kl) + so + 16, ksl + 4);
    CP16(sptr(Vh) + so, vsh); CP16(sptr(Vh) + so + 16, vsh + 4);
    CP16(sptr(Vl) + so, vsl); CP16(sptr(Vl) + so + 16, vsl + 4);
    CP_COMMIT();
  };
  issueKV(0, 0);

  float co[8][4];
#pragma unroll
  for (int nb = 0; nb < 8; nb++)
#pragma unroll
    for (int j = 0; j < 4; j++) co[nb][j] = 0.f;
  float m0 = -1e30f, m1 = -1e30f, lr0 = 0.f, lr1 = 0.f;

#pragma unroll 1
  for (int kt = 0; kt < PL / 64; kt++) {
    const int buf = kt & 1;
    if (kt + 1 < PL / 64) { issueKV(kt + 1, buf ^ 1); CP_WAIT1(); }
    else                  { CP_WAIT0(); }
    __syncthreads();

    const uint32_t* kh = Kh + buf * 64 * FK_S;
    const uint32_t* kl = Kl + buf * 64 * FK_S;
    const uint32_t* vh = Vh + buf * 64 * FK_S;
    const uint32_t* vl = Vl + buf * 64 * FK_S;

    float cs[8][4];
#pragma unroll
    for (int nb = 0; nb < 8; nb++)
#pragma unroll
      for (int j = 0; j < 4; j++) cs[nb][j] = 0.f;

#pragma unroll
    for (int ks = 0; ks < 4; ks++) {
      const int ko = ks * 8;
      const uint32_t qh0 = Qh[(rbase + gid)     * FQ_S + ko + tig];
      const uint32_t qh1 = Qh[(rbase + gid + 8) * FQ_S + ko + tig];
      const uint32_t qh2 = Qh[(rbase + gid)     * FQ_S + ko + tig + 4];
      const uint32_t qh3 = Qh[(rbase + gid + 8) * FQ_S + ko + tig + 4];
      const uint32_t ql0 = Ql[(rbase + gid)     * FQ_S + ko + tig];
      const uint32_t ql1 = Ql[(rbase + gid + 8) * FQ_S + ko + tig];
      const uint32_t ql2 = Ql[(rbase + gid)     * FQ_S + ko + tig + 4];
      const uint32_t ql3 = Ql[(rbase + gid + 8) * FQ_S + ko + tig + 4];
#pragma unroll
      for (int nb = 0; nb < 8; nb++) {
        const int n = nb * 8 + gid;
        const uint32_t b0 = kh[n * FK_S + ko + tig];
        const uint32_t b1 = kh[n * FK_S + ko + tig + 4];
        const uint32_t c0 = kl[n * FK_S + ko + tig];
        const uint32_t c1 = kl[n * FK_S + ko + tig + 4];
        mma_bf16(cs[nb], qh0, qh1, qh2, qh3, b0, b1);
        mma_bf16(cs[nb], qh0, qh1, qh2, qh3, c0, c1);
        mma_bf16(cs[nb], ql0, ql1, ql2, ql3, b0, b1);
      }
    }

    float tm0 = -1e30f, tm1 = -1e30f;
#pragma unroll
    for (int nb = 0; nb < 8; nb++) {
      tm0 = fmaxf(tm0, fmaxf(cs[nb][0], cs[nb][1]));
      tm1 = fmaxf(tm1, fmaxf(cs[nb][2], cs[nb][3]));
    }
    tm0 *= scale; tm1 *= scale;
#pragma unroll
    for (int off = 1; off <= 2; off <<= 1) {
      tm0 = fmaxf(tm0, __shfl_xor_sync(0xffffffffu, tm0, off));
      tm1 = fmaxf(tm1, __shfl_xor_sync(0xffffffffu, tm1, off));
    }
    const float mn0 = fmaxf(m0, tm0), mn1 = fmaxf(m1, tm1);
    const float al0 = __expf(m0 - mn0), al1 = __expf(m1 - mn1);
    m0 = mn0; m1 = mn1;

    float ts0 = 0.f, ts1 = 0.f;
#pragma unroll
    for (int nb = 0; nb < 8; nb++) {
      cs[nb][0] = __expf(cs[nb][0] * scale - mn0);
      cs[nb][1] = __expf(cs[nb][1] * scale - mn0);
      cs[nb][2] = __expf(cs[nb][2] * scale - mn1);
      cs[nb][3] = __expf(cs[nb][3] * scale - mn1);
      ts0 += cs[nb][0] + cs[nb][1];
      ts1 += cs[nb][2] + cs[nb][3];
    }
#pragma unroll
    for (int off = 1; off <= 2; off <<= 1) {
      ts0 += __shfl_xor_sync(0xffffffffu, ts0, off);
      ts1 += __shfl_xor_sync(0xffffffffu, ts1, off);
    }
    lr0 = lr0 * al0 + ts0;
    lr1 = lr1 * al1 + ts1;

#pragma unroll
    for (int nb = 0; nb < 8; nb++) {
      co[nb][0] *= al0; co[nb][1] *= al0;
      co[nb][2] *= al1; co[nb][3] *= al1;
    }

#pragma unroll
    for (int kq = 0; kq < 4; kq++) {
      const int s0 = 2 * kq, s1 = 2 * kq + 1;
      __nv_bfloat16 h, l;
      uint32_t pa0, pa1, pa2, pa3, la0, la1, la2, la3;
      {
        __nv_bfloat16 h2, l2;
        split_bf16(cs[s0][0], h, l); split_bf16(cs[s0][1], h2, l2);
        pa0 = pack_bf16(h, h2); la0 = pack_bf16(l, l2);
        split_bf16(cs[s0][2], h, l); split_bf16(cs[s0][3], h2, l2);
        pa1 = pack_bf16(h, h2); la1 = pack_bf16(l, l2);
        split_bf16(cs[s1][0], h, l); split_bf16(cs[s1][1], h2, l2);
        pa2 = pack_bf16(h, h2); la2 = pack_bf16(l, l2);
        split_bf16(cs[s1][2], h, l); split_bf16(cs[s1][3], h2, l2);
        pa3 = pack_bf16(h, h2); la3 = pack_bf16(l, l2);
      }
      const int ko = kq * 8;
#pragma unroll
      for (int nb = 0; nb < 8; nb++) {
        const int n = nb * 8 + gid;
        const uint32_t b0 = vh[n * FK_S + ko + tig];
        const uint32_t b1 = vh[n * FK_S + ko + tig + 4];
        const uint32_t c0 = vl[n * FK_S + ko + tig];
        const uint32_t c1 = vl[n * FK_S + ko + tig + 4];
        mma_bf16(co[nb], pa0, pa1, pa2, pa3, b0, b1);
        mma_bf16(co[nb], pa0, pa1, pa2, pa3, c0, c1);
        mma_bf16(co[nb], la0, la1, la2, la3, b0, b1);
      }
    }
    __syncthreads();
  }

  const int b = bh >> 4, h = bh & 15;
  const int r0 = rbase + gid, r1 = r0 + 8;
  const int s0 = qidx[r0], s1 = qidx[r1];
  const float inv0 = 1.0f / lr0, inv1 = 1.0f / lr1;
#pragma unroll
  for (int nb = 0; nb < 8; nb++) {
    const int col = h * PDH + nb * 8 + tig * 2;
    if (s0 >= 0) {
      __nv_bfloat16 h0, l0, h1, l1;
      split_bf16(co[nb][0] * inv0, h0, l0);
      split_bf16(co[nb][1] * inv0, h1, l1);
      const size_t ui = ((size_t)(b * PL + s0) * PD + col) / 2;
      g_abh[ui] = pack_bf16(h0, h1);
      g_abl[ui] = pack_bf16(l0, l1);
    }
    if (s1 >= 0) {
      __nv_bfloat16 h0, l0, h1, l1;
      split_bf16(co[nb][2] * inv1, h0, l0);
      split_bf16(co[nb][3] * inv1, h1, l1);
      const size_t ui = ((size_t)(b * PL + s1) * PD + col) / 2;
      g_abh[ui] = pack_bf16(h0, h1);
      g_abl[ui] = pack_bf16(l0, l1);
    }
  }
}

// ============================================================
// host launcher
// ============================================================
extern "C" void kernel_launch(void* const* d_in, const int* in_sizes, int n_in,
                              void* d_out, int out_size) {
  (void)in_sizes; (void)n_in; (void)out_size;
  const float* x  = (const float*)d_in[0];
  const float* Wq = (const float*)d_in[1];
  const float* bq = (const float*)d_in[2];
  const float* Wk = (const float*)d_in[3];
  const float* bk = (const float*)d_in[4];
  const float* Wv = (const float*)d_in[5];
  const float* bv = (const float*)d_in[6];
  const float* Wo = (const float*)d_in[7];
  const float* bo = (const float*)d_in[8];
  float* out = (float*)d_out;

  float *pv;
  uint32_t *pabh, *pabl;
  __nv_bfloat16 *px3h, *px3m, *px3l;
  __nv_bfloat16 *pwqth, *pwqtl, *pwkth, *pwktl;
  __nv_bfloat16 *pwvth, *pwvtl, *pwoth, *pwotl, *pvth, *pvtl;
  cudaGetSymbolAddress((void**)&pv, g_v);
  cudaGetSymbolAddress((void**)&px3h, g_x3h);
  cudaGetSymbolAddress((void**)&px3m, g_x3m);
  cudaGetSymbolAddress((void**)&px3l, g_x3l);
  cudaGetSymbolAddress((void**)&pwqth, g_wqth);
  cudaGetSymbolAddress((void**)&pwqtl, g_wqtl);
  cudaGetSymbolAddress((void**)&pwkth, g_wkth);
  cudaGetSymbolAddress((void**)&pwktl, g_wktl);
  cudaGetSymbolAddress((void**)&pwvth, g_wvth);
  cudaGetSymbolAddress((void**)&pwvtl, g_wvtl);
  cudaGetSymbolAddress((void**)&pwoth, g_woth);
  cudaGetSymbolAddress((void**)&pwotl, g_wotl);
  cudaGetSymbolAddress((void**)&pvth, g_vth);
  cudaGetSymbolAddress((void**)&pvtl, g_vtl);
  cudaGetSymbolAddress((void**)&pabh, g_abh);
  cudaGetSymbolAddress((void**)&pabl, g_abl);

  cudaFuncSetAttribute(gemm_qk5, cudaFuncAttributeMaxDynamicSharedMemorySize, QK5_SMEM);
  cudaFuncSetAttribute(gemm_bf16<0>, cudaFuncAttributeMaxDynamicSharedMemorySize, GBF_SMEM);
  cudaFuncSetAttribute(gemm_bf16<1>, cudaFuncAttributeMaxDynamicSharedMemorySize, GBF_SMEM);
  cudaFuncSetAttribute(sparsity_v7, cudaFuncAttributeMaxDynamicSharedMemorySize, SP7_SMEM);
  cudaFuncSetAttribute(flash_v5, cudaFuncAttributeMaxDynamicSharedMemorySize, FL_SMEM);

  const int n4x = (int)((size_t)PM * PD / 4);

  // pre-splits: x 3-way row-major; W^T 2-way bf16 for all four weights
  split3_bf16_kernel<<<(n4x + 255) / 256, 256>>>(x, px3h, px3m, px3l, n4x);
  transpose_split_bf16<<<dim3(PD / 32, PD / 32), 256>>>(Wq, pwqth, pwqtl, PD, PD);
  transpose_split_bf16<<<dim3(PD / 32, PD / 32), 256>>>(Wk, pwkth, pwktl, PD, PD);
  transpose_split_bf16<<<dim3(PD / 32, PD / 32), 256>>>(Wv, pwvth, pwvtl, PD, PD);
  transpose_split_bf16<<<dim3(PD / 32, PD / 32), 256>>>(Wo, pwoth, pwotl, PD, PD);

  // fused Q+K projection (bf16 5-term); V projection (bf16 3-term,
  // A operands = (x3h, x3m) == the 2-way split, bit-identical)
  gemm_qk5<<<dim3(2 * PD / 128, PM / 128), 256, QK5_SMEM>>>(bq, bk);
  gemm_bf16<1><<<dim3(PD / 128, PM / 128), 256, GBF_SMEM>>>(
      px3h, px3m, pwvth, pwvtl, bv, pv, PM, PD, PD);

  // V^T bf16 split for flash
  const dim3 gT(PL / 32, PDH / 32, PBH);
  transpose_head_bf16<<<gT, 256>>>(pv, pvth, pvtl);

  // selection: kbar, bf16 argmax pass, exact refine, top-k
  kbar_kernel<<<PBH, 1024>>>();
  sparsity_v7<<<dim3(PL / 128, PBH), 256, SP7_SMEM>>>();
  refine_kernel<<<PBH * PL / 8, 256>>>();
  topk_radix<<<PBH, 256>>>();

  // attention on selected rows
  zero_ab<<<(int)(2 * ((size_t)PM * PD / 8) / 256), 256>>>();
  flash_v5<<<dim3((PU + 127) / 128, PBH), 256, FL_SMEM>>>();

  // output projection
  gemm_bf16<0><<<dim3(PD / 128, PM / 128), 256, GBF_SMEM>>>(
      (const __nv_bfloat16*)pabh, (const __nv_bfloat16*)pabl,
      pwoth, pwotl, bo, out, PM, PD, PD);
}

// round 15
// speedup vs baseline: 2.6438x; 1.0235x over previous
#include <cuda_runtime.h>
#include <cuda_bf16.h>
#include <cstdint>

// ---------------- problem constants ----------------
#define PB 2
#define PL 2048
#define PD 1024
#define PH 16
#define PDH 64
#define PU 1228          // int(0.6 * 2048)
#define PBH (PB * PH)    // 32
#define PM (PB * PL)     // 4096 rows

// ---------------- device scratch (no allocation allowed) ----------------
__device__ float g_q [(size_t)PBH * PL * PDH];   // [b,h,l,dh] fp32 (refine)
__device__ float g_k [(size_t)PBH * PL * PDH];   // [b,h,l,dh] fp32 (refine/kbar)
__device__ float g_v [(size_t)PBH * PL * PDH];   // [b,h,l,dh] fp32
// 3-way bf16 split of x (h+m+l ~ 24 mantissa bits)
__device__ __nv_bfloat16 g_x3h[(size_t)PM * PD];
__device__ __nv_bfloat16 g_x3m[(size_t)PM * PD];
__device__ __nv_bfloat16 g_x3l[(size_t)PM * PD];
// 2-way bf16 splits of W^T ([N][K])
__device__ __nv_bfloat16 g_wqth[(size_t)PD * PD];
__device__ __nv_bfloat16 g_wqtl[(size_t)PD * PD];
__device__ __nv_bfloat16 g_wkth[(size_t)PD * PD];
__device__ __nv_bfloat16 g_wktl[(size_t)PD * PD];
__device__ __nv_bfloat16 g_wvth[(size_t)PD * PD];
__device__ __nv_bfloat16 g_wvtl[(size_t)PD * PD];
__device__ __nv_bfloat16 g_woth[(size_t)PD * PD];
__device__ __nv_bfloat16 g_wotl[(size_t)PD * PD];
// bf16 pair-packed (u32 = 2 bf16) operands
__device__ uint32_t g_qbh[(size_t)PBH * PL * PDH / 2];  // Q row-major bf16 hi
__device__ uint32_t g_qbl[(size_t)PBH * PL * PDH / 2];
__device__ uint32_t g_kbh[(size_t)PBH * PL * PDH / 2];  // K row-major bf16 hi
__device__ uint32_t g_kbl[(size_t)PBH * PL * PDH / 2];
__device__ uint32_t g_abh[(size_t)PM * PD / 2];         // attn row-major bf16 hi
__device__ uint32_t g_abl[(size_t)PM * PD / 2];
__device__ __nv_bfloat16 g_vth[(size_t)PBH * PDH * PL];  // V^T [bh][dh][l] bf16 hi
__device__ __nv_bfloat16 g_vtl[(size_t)PBH * PDH * PL];
__device__ float g_kbar[PBH * PDH];              // per-head mean K row
__device__ int   g_amax[(size_t)PBH * PL];       // per-row argmax key
__device__ float g_spars[(size_t)PBH * PL];
__device__ int   g_topidx[(size_t)PBH * PU];

// ---------------- cp.async helpers ----------------
#define CP16(dst_u32, src_ptr) \
  asm volatile("cp.async.cg.shared.global [%0], [%1], 16;\n" :: "r"(dst_u32), "l"(src_ptr))
#define CP_COMMIT() asm volatile("cp.async.commit_group;\n" ::)
#define CP_WAIT0()  asm volatile("cp.async.wait_group 0;\n" ::)
#define CP_WAIT1()  asm volatile("cp.async.wait_group 1;\n" ::)

static __device__ __forceinline__ uint32_t sptr(const void* p) {
  return (uint32_t)__cvta_generic_to_shared(p);
}

// ---------------- bf16 helpers ----------------
static __device__ __forceinline__ void split_bf16(float x, __nv_bfloat16& h, __nv_bfloat16& l) {
  h = __float2bfloat16(x);
  l = __float2bfloat16(x - __bfloat162float(h));
}

static __device__ __forceinline__ uint32_t pack_bf16(__nv_bfloat16 a, __nv_bfloat16 b) {
  return (uint32_t)__bfloat16_as_ushort(a) | ((uint32_t)__bfloat16_as_ushort(b) << 16);
}

static __device__ __forceinline__ void mma_bf16(
    float* c, uint32_t a0, uint32_t a1, uint32_t a2, uint32_t a3,
    uint32_t b0, uint32_t b1) {
  asm volatile(
      "mma.sync.aligned.m16n8k16.row.col.f32.bf16.bf16.f32 "
      "{%0,%1,%2,%3}, {%4,%5,%6,%7}, {%8,%9}, {%0,%1,%2,%3};"
      : "+f"(c[0]), "+f"(c[1]), "+f"(c[2]), "+f"(c[3])
      : "r"(a0), "r"(a1), "r"(a2), "r"(a3), "r"(b0), "r"(b1));
}

// ============================================================
// Elementwise / transpose splits.
// ============================================================
// 3-way split: x = h + m + l (bf16 each)
__global__ __launch_bounds__(256) void split3_bf16_kernel(
    const float* __restrict__ in, __nv_bfloat16* __restrict__ oh,
    __nv_bfloat16* __restrict__ om, __nv_bfloat16* __restrict__ ol, int n4) {
  const int i = blockIdx.x * 256 + threadIdx.x;
  if (i >= n4) return;
  float4 v = ((const float4*)in)[i];
  float a[4] = {v.x, v.y, v.z, v.w};
  __nv_bfloat16 h[4], m[4], l[4];
#pragma unroll
  for (int j = 0; j < 4; j++) {
    h[j] = __float2bfloat16(a[j]);
    float r = a[j] - __bfloat162float(h[j]);
    m[j] = __float2bfloat16(r);
    r -= __bfloat162float(m[j]);
    l[j] = __float2bfloat16(r);
  }
  uint2 hp = {pack_bf16(h[0], h[1]), pack_bf16(h[2], h[3])};
  uint2 mp = {pack_bf16(m[0], m[1]), pack_bf16(m[2], m[3])};
  uint2 lp = {pack_bf16(l[0], l[1]), pack_bf16(l[2], l[3])};
  ((uint2*)oh)[i] = hp;
  ((uint2*)om)[i] = mp;
  ((uint2*)ol)[i] = lp;
}

__global__ __launch_bounds__(256) void transpose_split_bf16(
    const float* __restrict__ in, __nv_bfloat16* __restrict__ ohi,
    __nv_bfloat16* __restrict__ olo, int M, int N) {
  __shared__ float t[32][33];
  const int m0 = blockIdx.x * 32, n0 = blockIdx.y * 32;
  const int x = threadIdx.x & 31, y = threadIdx.x >> 5;
#pragma unroll
  for (int k = 0; k < 4; k++)
    t[y + 8 * k][x] = in[(size_t)(m0 + y + 8 * k) * N + n0 + x];
  __syncthreads();
#pragma unroll
  for (int k = 0; k < 4; k++) {
    const float v = t[x][y + 8 * k];
    __nv_bfloat16 h, l;
    split_bf16(v, h, l);
    const size_t idx = (size_t)(n0 + y + 8 * k) * M + m0 + x;
    ohi[idx] = h;
    olo[idx] = l;
  }
}

// Head transpose + bf16 split: [bh][l][dh] -> [bh][dh][l] bf16 (for V^T).
__global__ __launch_bounds__(256) void transpose_head_bf16(
    const float* __restrict__ in, __nv_bfloat16* __restrict__ ohi,
    __nv_bfloat16* __restrict__ olo) {
  __shared__ float t[32][33];
  const int bh = blockIdx.z;
  const int l0 = blockIdx.x * 32, d0 = blockIdx.y * 32;
  const int x = threadIdx.x & 31, y = threadIdx.x >> 5;
  const float* ip = in + (size_t)bh * PL * PDH;
#pragma unroll
  for (int k = 0; k < 4; k++)
    t[y + 8 * k][x] = ip[(size_t)(l0 + y + 8 * k) * PDH + d0 + x];
  __syncthreads();
  const size_t base = (size_t)bh * PDH * PL;
#pragma unroll
  for (int k = 0; k < 4; k++) {
    const float v = t[x][y + 8 * k];
    __nv_bfloat16 h, l;
    split_bf16(v, h, l);
    const size_t idx = base + (size_t)(d0 + y + 8 * k) * PL + l0 + x;
    ohi[idx] = h;
    olo[idx] = l;
  }
}

// ============================================================
// gemm_qk5: fused Q+K projection, bf16 5-term (fp32-grade).
// ============================================================
#define GB_S 20
#define QK5_SMEM (5 * 2 * 128 * GB_S * 4)   // 102,400 B

__global__ __launch_bounds__(256, 2) void gemm_qk5(
    const float* __restrict__ biasQ, const float* __restrict__ biasK) {
  extern __shared__ uint32_t smq[];
  uint32_t* Ah = smq;                       // [2][128][GB_S] each
  uint32_t* Am = Ah + 2 * 128 * GB_S;
  uint32_t* Al = Am + 2 * 128 * GB_S;
  uint32_t* Bh = Al + 2 * 128 * GB_S;
  uint32_t* Bl = Bh + 2 * 128 * GB_S;

  const bool isK = (blockIdx.x >= PD / 128);
  const __nv_bfloat16* BgH = isK ? g_wkth : g_wqth;
  const __nv_bfloat16* BgL = isK ? g_wktl : g_wqtl;
  const float* bias = isK ? biasK : biasQ;
  float* C = isK ? g_k : g_q;
  uint32_t* OH = isK ? g_kbh : g_qbh;
  uint32_t* OL = isK ? g_kbl : g_qbl;
  const int bn = (isK ? blockIdx.x - PD / 128 : blockIdx.x) * 128;
  const int bm = blockIdx.y * 128;
  const int K = PD;

  const int tid = threadIdx.x;
  const int warp = tid >> 5, lane = tid & 31;
  const int gid = lane >> 2, tig = lane & 3;
  const int wm = warp >> 1, wn = warp & 1;

  const int lr = tid >> 1;            // tile row 0..127
  const int lh = (tid & 1) * 16;      // bf16 element offset 0 or 16

  float c[2][8][4];
#pragma unroll
  for (int mb = 0; mb < 2; mb++)
#pragma unroll
    for (int nb = 0; nb < 8; nb++)
#pragma unroll
      for (int j = 0; j < 4; j++) c[mb][nb][j] = 0.f;

  const int NP = K >> 5;   // 32-K panels

  auto issue = [&](int p, int bf) {
    const __nv_bfloat16* ah = g_x3h + (size_t)(bm + lr) * K + p * 32 + lh;
    const __nv_bfloat16* am = g_x3m + (size_t)(bm + lr) * K + p * 32 + lh;
    const __nv_bfloat16* al = g_x3l + (size_t)(bm + lr) * K + p * 32 + lh;
    const __nv_bfloat16* bhh = BgH + (size_t)(bn + lr) * K + p * 32 + lh;
    const __nv_bfloat16* bll = BgL + (size_t)(bn + lr) * K + p * 32 + lh;
    const uint32_t so = (bf * 128 + lr) * GB_S * 4 + lh * 2;  // byte offset
    CP16(sptr(Ah) + so, ah);  CP16(sptr(Ah) + so + 16, ah + 8);
    CP16(sptr(Am) + so, am);  CP16(sptr(Am) + so + 16, am + 8);
    CP16(sptr(Al) + so, al);  CP16(sptr(Al) + so + 16, al + 8);
    CP16(sptr(Bh) + so, bhh); CP16(sptr(Bh) + so + 16, bhh + 8);
    CP16(sptr(Bl) + so, bll); CP16(sptr(Bl) + so + 16, bll + 8);
    CP_COMMIT();
  };

  issue(0, 0);

#pragma unroll 1
  for (int p = 0; p < NP; p++) {
    const int buf = p & 1;
    if (p + 1 < NP) { issue(p + 1, buf ^ 1); CP_WAIT1(); }
    else            { CP_WAIT0(); }
    __syncthreads();

    const uint32_t* ah = Ah + buf * 128 * GB_S;
    const uint32_t* am = Am + buf * 128 * GB_S;
    const uint32_t* al = Al + buf * 128 * GB_S;
    const uint32_t* bhp = Bh + buf * 128 * GB_S;
    const uint32_t* blp = Bl + buf * 128 * GB_S;

#pragma unroll
    for (int kb = 0; kb < 2; kb++) {
      const int ko = kb * 8;
      uint32_t fh[2][4], fm[2][4], fl[2][4];
#pragma unroll
      for (int mb = 0; mb < 2; mb++) {
        const int r = wm * 32 + mb * 16;
        fh[mb][0] = ah[(r + gid)     * GB_S + ko + tig];
        fh[mb][1] = ah[(r + gid + 8) * GB_S + ko + tig];
        fh[mb][2] = ah[(r + gid)     * GB_S + ko + tig + 4];
        fh[mb][3] = ah[(r + gid + 8) * GB_S + ko + tig + 4];
        fm[mb][0] = am[(r + gid)     * GB_S + ko + tig];
        fm[mb][1] = am[(r + gid + 8) * GB_S + ko + tig];
        fm[mb][2] = am[(r + gid)     * GB_S + ko + tig + 4];
        fm[mb][3] = am[(r + gid + 8) * GB_S + ko + tig + 4];
        fl[mb][0] = al[(r + gid)     * GB_S + ko + tig];
        fl[mb][1] = al[(r + gid + 8) * GB_S + ko + tig];
        fl[mb][2] = al[(r + gid)     * GB_S + ko + tig + 4];
        fl[mb][3] = al[(r + gid + 8) * GB_S + ko + tig + 4];
      }
#pragma unroll
      for (int nb = 0; nb < 8; nb++) {
        const int n = wn * 64 + nb * 8 + gid;
        const uint32_t bh0 = bhp[n * GB_S + ko + tig];
        const uint32_t bh1 = bhp[n * GB_S + ko + tig + 4];
        const uint32_t bl0 = blp[n * GB_S + ko + tig];
        const uint32_t bl1 = blp[n * GB_S + ko + tig + 4];
#pragma unroll
        for (int mb = 0; mb < 2; mb++) {
          mma_bf16(c[mb][nb], fh[mb][0], fh[mb][1], fh[mb][2], fh[mb][3], bh0, bh1);
          mma_bf16(c[mb][nb], fh[mb][0], fh[mb][1], fh[mb][2], fh[mb][3], bl0, bl1);
          mma_bf16(c[mb][nb], fm[mb][0], fm[mb][1], fm[mb][2], fm[mb][3], bh0, bh1);
          mma_bf16(c[mb][nb], fm[mb][0], fm[mb][1], fm[mb][2], fm[mb][3], bl0, bl1);
          mma_bf16(c[mb][nb], fl[mb][0], fl[mb][1], fl[mb][2], fl[mb][3], bh0, bh1);
        }
      }
    }
    __syncthreads();
  }

#pragma unroll
  for (int mb = 0; mb < 2; mb++) {
#pragma unroll
    for (int nb = 0; nb < 8; nb++) {
      const int m0 = bm + wm * 32 + mb * 16 + gid;
      const int n0 = bn + wn * 64 + nb * 8 + tig * 2;
      const float bx = bias[n0], by = bias[n0 + 1];
      float2 v0 = {c[mb][nb][0] + bx, c[mb][nb][1] + by};
      float2 v1 = {c[mb][nb][2] + bx, c[mb][nb][3] + by};
      const int h = n0 >> 6, dh = n0 & 63;
      const int b0i = m0 >> 11, l0 = m0 & (PL - 1);
      const int b1i = (m0 + 8) >> 11, l1 = (m0 + 8) & (PL - 1);
      const size_t i0 = (((size_t)b0i * PH + h) * PL + l0) * PDH + dh;
      const size_t i1 = (((size_t)b1i * PH + h) * PL + l1) * PDH + dh;
      *(float2*)&C[i0] = v0;
      *(float2*)&C[i1] = v1;
      __nv_bfloat16 h0, l0b, h1, l1b;
      split_bf16(v0.x, h0, l0b); split_bf16(v0.y, h1, l1b);
      OH[i0 / 2] = pack_bf16(h0, h1);
      OL[i0 / 2] = pack_bf16(l0b, l1b);
      split_bf16(v1.x, h0, l0b); split_bf16(v1.y, h1, l1b);
      OH[i1 / 2] = pack_bf16(h0, h1);
      OL[i1 / 2] = pack_bf16(l0b, l1b);
    }
  }
}

// ============================================================
// bf16x2 3-term GEMM (unchanged): V and Wo paths.
// ============================================================
#define GBF_SMEM (4 * 2 * 128 * GB_S * 4)

template<int MODE>
__global__ __launch_bounds__(256, 2) void gemm_bf16(
    const __nv_bfloat16* __restrict__ Agh, const __nv_bfloat16* __restrict__ Agl,
    const __nv_bfloat16* __restrict__ Bgh, const __nv_bfloat16* __restrict__ Bgl,
    const float* __restrict__ bias, float* __restrict__ C,
    int M, int N, int K) {
  extern __shared__ uint32_t smb[];
  uint32_t* Ah = smb;
  uint32_t* Al = Ah + 2 * 128 * GB_S;
  uint32_t* Bh = Al + 2 * 128 * GB_S;
  uint32_t* Bl = Bh + 2 * 128 * GB_S;

  const int tid = threadIdx.x;
  const int warp = tid >> 5, lane = tid & 31;
  const int gid = lane >> 2, tig = lane & 3;
  const int wm = warp >> 1, wn = warp & 1;
  const int bm = blockIdx.y * 128, bn = blockIdx.x * 128;

  const int lr = tid >> 1;
  const int lh = (tid & 1) * 16;

  float c[2][8][4];
#pragma unroll
  for (int mb = 0; mb < 2; mb++)
#pragma unroll
    for (int nb = 0; nb < 8; nb++)
#pragma unroll
      for (int j = 0; j < 4; j++) c[mb][nb][j] = 0.f;

  const int NP = K >> 5;

  auto issue = [&](int p, int bf) {
    const __nv_bfloat16* asrc = Agh + (size_t)(bm + lr) * K + p * 32 + lh;
    const __nv_bfloat16* asrl = Agl + (size_t)(bm + lr) * K + p * 32 + lh;
    const __nv_bfloat16* bsrc = Bgh + (size_t)(bn + lr) * K + p * 32 + lh;
    const __nv_bfloat16* bsrl = Bgl + (size_t)(bn + lr) * K + p * 32 + lh;
    const uint32_t so = (bf * 128 + lr) * GB_S * 4 + lh * 2;
    CP16(sptr(Ah) + so, asrc); CP16(sptr(Ah) + so + 16, asrc + 8);
    CP16(sptr(Al) + so, asrl); CP16(sptr(Al) + so + 16, asrl + 8);
    CP16(sptr(Bh) + so, bsrc); CP16(sptr(Bh) + so + 16, bsrc + 8);
    CP16(sptr(Bl) + so, bsrl); CP16(sptr(Bl) + so + 16, bsrl + 8);
    CP_COMMIT();
  };

  issue(0, 0);

#pragma unroll 1
  for (int p = 0; p < NP; p++) {
    const int buf = p & 1;
    if (p + 1 < NP) { issue(p + 1, buf ^ 1); CP_WAIT1(); }
    else            { CP_WAIT0(); }
    __syncthreads();

    const uint32_t* ah = Ah + buf * 128 * GB_S;
    const uint32_t* al = Al + buf * 128 * GB_S;
    const uint32_t* bhp = Bh + buf * 128 * GB_S;
    const uint32_t* blp = Bl + buf * 128 * GB_S;

#pragma unroll
    for (int kb = 0; kb < 2; kb++) {
      const int ko = kb * 8;
      uint32_t ahi[2][4], alo[2][4];
#pragma unroll
      for (int mb = 0; mb < 2; mb++) {
        const int r = wm * 32 + mb * 16;
        ahi[mb][0] = ah[(r + gid)     * GB_S + ko + tig];
        ahi[mb][1] = ah[(r + gid + 8) * GB_S + ko + tig];
        ahi[mb][2] = ah[(r + gid)     * GB_S + ko + tig + 4];
        ahi[mb][3] = ah[(r + gid + 8) * GB_S + ko + tig + 4];
        alo[mb][0] = al[(r + gid)     * GB_S + ko + tig];
        alo[mb][1] = al[(r + gid + 8) * GB_S + ko + tig];
        alo[mb][2] = al[(r + gid)     * GB_S + ko + tig + 4];
        alo[mb][3] = al[(r + gid + 8) * GB_S + ko + tig + 4];
      }
#pragma unroll
      for (int nb = 0; nb < 8; nb++) {
        const int n = wn * 64 + nb * 8 + gid;
        const uint32_t bh0 = bhp[n * GB_S + ko + tig];
        const uint32_t bh1 = bhp[n * GB_S + ko + tig + 4];
        const uint32_t bl0 = blp[n * GB_S + ko + tig];
        const uint32_t bl1 = blp[n * GB_S + ko + tig + 4];
#pragma unroll
        for (int mb = 0; mb < 2; mb++) {
          mma_bf16(c[mb][nb], ahi[mb][0], ahi[mb][1], ahi[mb][2], ahi[mb][3], bh0, bh1);
          mma_bf16(c[mb][nb], ahi[mb][0], ahi[mb][1], ahi[mb][2], ahi[mb][3], bl0, bl1);
          mma_bf16(c[mb][nb], alo[mb][0], alo[mb][1], alo[mb][2], alo[mb][3], bh0, bh1);
        }
      }
    }
    __syncthreads();
  }

#pragma unroll
  for (int mb = 0; mb < 2; mb++) {
#pragma unroll
    for (int nb = 0; nb < 8; nb++) {
      const int m0 = bm + wm * 32 + mb * 16 + gid;
      const int n0 = bn + wn * 64 + nb * 8 + tig * 2;
      const float bx = bias[n0], by = bias[n0 + 1];
      float2 v0 = {c[mb][nb][0] + bx, c[mb][nb][1] + by};
      float2 v1 = {c[mb][nb][2] + bx, c[mb][nb][3] + by};
      if (MODE == 0) {
        *(float2*)&C[(size_t)m0 * N + n0] = v0;
        *(float2*)&C[(size_t)(m0 + 8) * N + n0] = v1;
      } else {
        const int h = n0 >> 6, dh = n0 & 63;
        const int b0i = m0 >> 11, l0 = m0 & (PL - 1);
        const int b1i = (m0 + 8) >> 11, l1 = (m0 + 8) & (PL - 1);
        *(float2*)&C[(((size_t)b0i * PH + h) * PL + l0) * PDH + dh] = v0;
        *(float2*)&C[(((size_t)b1i * PH + h) * PL + l1) * PDH + dh] = v1;
      }
    }
  }
}

// ============================================================
// kbar: per-head mean K row (exact fp32).
// ============================================================
__global__ __launch_bounds__(1024) void kbar_kernel() {
  __shared__ float acc[16][64];
  const int bh = blockIdx.x, tid = threadIdx.x;
  const int dh = tid & 63, grp = tid >> 6;
  float s = 0.f;
  for (int r = grp; r < PL; r += 16)
    s += g_k[((size_t)bh * PL + r) * PDH + dh];
  acc[grp][dh] = s;
  __syncthreads();
  if (tid < 64) {
    float t = 0.f;
#pragma unroll
    for (int g2 = 0; g2 < 16; g2++) t += acc[g2][tid];
    g_kbar[bh * PDH + tid] = t * (1.0f / PL);
  }
}

// ============================================================
// Sparsity v7 (unchanged): bf16 3-term QK^T argmax pass.
// ============================================================
#define SQ_S 36
#define SK_S 36
#define SP7_SMEM ((2 * 128 * SQ_S + 4 * 64 * SK_S) * 4)

__global__ __launch_bounds__(256, 2) void sparsity_v7() {
  extern __shared__ uint32_t sm7[];
  uint32_t* Qh = sm7;
  uint32_t* Ql = Qh + 128 * SQ_S;
  uint32_t* Kh = Ql + 128 * SQ_S;
  uint32_t* Kl = Kh + 2 * 64 * SK_S;

  const int bh = blockIdx.y, q0 = blockIdx.x * 128;
  const int tid = threadIdx.x;
  const int warp = tid >> 5, lane = tid & 31;
  const int gid = lane >> 2, tig = lane & 3;
  const int rbase = warp * 16;

  {
    const int r = tid >> 1, c0 = (tid & 1) * 16;
    const uint32_t* qh = g_qbh + (size_t)(bh * PL + q0 + r) * 32 + c0;
    const uint32_t* ql = g_qbl + (size_t)(bh * PL + q0 + r) * 32 + c0;
    const uint32_t hd = sptr(&Qh[r * SQ_S + c0]);
    const uint32_t ld = sptr(&Ql[r * SQ_S + c0]);
#pragma unroll
    for (int j = 0; j < 4; j++) CP16(hd + j * 16, qh + j * 4);
#pragma unroll
    for (int j = 0; j < 4; j++) CP16(ld + j * 16, ql + j * 4);
  }
  const int krow = tid >> 2;
  const int seg = (tid & 3) * 8;
  auto issueK = [&](int kt, int bf) {
    const uint32_t* kh = g_kbh + (size_t)(bh * PL + kt * 64 + krow) * 32 + seg;
    const uint32_t* kl = g_kbl + (size_t)(bh * PL + kt * 64 + krow) * 32 + seg;
    const uint32_t so = ((bf * 64 + krow) * SK_S + seg) * 4;
    CP16(sptr(Kh) + so, kh); CP16(sptr(Kh) + so + 16, kh + 4);
    CP16(sptr(Kl) + so, kl); CP16(sptr(Kl) + so + 16, kl + 4);
    CP_COMMIT();
  };
  issueK(0, 0);

  float mx0 = -1e30f, mx1 = -1e30f;
  int ix0 = 0, ix1 = 0;

#pragma unroll 1
  for (int kt = 0; kt < PL / 64; kt++) {
    const int buf = kt & 1;
    if (kt + 1 < PL / 64) { issueK(kt + 1, buf ^ 1); CP_WAIT1(); }
    else                  { CP_WAIT0(); }
    __syncthreads();

    const uint32_t* kh = Kh + buf * 64 * SK_S;
    const uint32_t* kl = Kl + buf * 64 * SK_S;

    float cs[8][4];
#pragma unroll
    for (int nb = 0; nb < 8; nb++)
#pragma unroll
      for (int j = 0; j < 4; j++) cs[nb][j] = 0.f;

#pragma unroll
    for (int ks = 0; ks < 4; ks++) {
      const int ko = ks * 8;
      const uint32_t qh0 = Qh[(rbase + gid)     * SQ_S + ko + tig];
      const uint32_t qh1 = Qh[(rbase + gid + 8) * SQ_S + ko + tig];
      const uint32_t qh2 = Qh[(rbase + gid)     * SQ_S + ko + tig + 4];
      const uint32_t qh3 = Qh[(rbase + gid + 8) * SQ_S + ko + tig + 4];
      const uint32_t ql0 = Ql[(rbase + gid)     * SQ_S + ko + tig];
      const uint32_t ql1 = Ql[(rbase + gid + 8) * SQ_S + ko + tig];
      const uint32_t ql2 = Ql[(rbase + gid)     * SQ_S + ko + tig + 4];
      const uint32_t ql3 = Ql[(rbase + gid + 8) * SQ_S + ko + tig + 4];
#pragma unroll
      for (int nb = 0; nb < 8; nb++) {
        const int n = nb * 8 + gid;
        const uint32_t b0 = kh[n * SK_S + ko + tig];
        const uint32_t b1 = kh[n * SK_S + ko + tig + 4];
        const uint32_t c0 = kl[n * SK_S + ko + tig];
        const uint32_t c1 = kl[n * SK_S + ko + tig + 4];
        mma_bf16(cs[nb], qh0, qh1, qh2, qh3, b0, b1);
        mma_bf16(cs[nb], qh0, qh1, qh2, qh3, c0, c1);
        mma_bf16(cs[nb], ql0, ql1, ql2, ql3, b0, b1);
      }
    }

#pragma unroll
    for (int nb = 0; nb < 8; nb++) {
      const int kb = kt * 64 + nb * 8 + tig * 2;
      if (cs[nb][0] > mx0) { mx0 = cs[nb][0]; ix0 = kb; }
      if (cs[nb][1] > mx0) { mx0 = cs[nb][1]; ix0 = kb + 1; }
      if (cs[nb][2] > mx1) { mx1 = cs[nb][2]; ix1 = kb; }
      if (cs[nb][3] > mx1) { mx1 = cs[nb][3]; ix1 = kb + 1; }
    }
    __syncthreads();
  }

#pragma unroll
  for (int off = 1; off <= 2; off <<= 1) {
    const float o0 = __shfl_xor_sync(0xffffffffu, mx0, off);
    const int oi0 = __shfl_xor_sync(0xffffffffu, ix0, off);
    if (o0 > mx0) { mx0 = o0; ix0 = oi0; }
    const float o1 = __shfl_xor_sync(0xffffffffu, mx1, off);
    const int oi1 = __shfl_xor_sync(0xffffffffu, ix1, off);
    if (o1 > mx1) { mx1 = o1; ix1 = oi1; }
  }
  if (tig == 0) {
    g_amax[(size_t)bh * PL + q0 + rbase + gid] = ix0;
    g_amax[(size_t)bh * PL + q0 + rbase + gid + 8] = ix1;
  }
}

// ============================================================
// Refine: exact fp32 sparsity score per row (unchanged).
// ============================================================
__global__ __launch_bounds__(256) void refine_kernel() {
  const int tid = threadIdx.x;
  const int warp = tid >> 5, lane = tid & 31;
  const int g = blockIdx.x * 8 + warp;
  const int bh = g >> 11;
  const int l = g & (PL - 1);
  const float* q = g_q + ((size_t)bh * PL + l) * PDH;
  const int am = g_amax[(size_t)bh * PL + l];
  const float* ka = g_k + ((size_t)bh * PL + am) * PDH;
  const float* kb = g_kbar + bh * PDH;
  const float2 qv = ((const float2*)q)[lane];
  const float2 kav = ((const float2*)ka)[lane];
  const float2 kbv = ((const float2*)kb)[lane];
  float dmax = qv.x * kav.x + qv.y * kav.y;
  float dmean = qv.x * kbv.x + qv.y * kbv.y;
#pragma unroll
  for (int off = 16; off; off >>= 1) {
    dmax += __shfl_xor_sync(0xffffffffu, dmax, off);
    dmean += __shfl_xor_sync(0xffffffffu, dmean, off);
  }
  if (lane == 0)
    g_spars[(size_t)bh * PL + l] = 0.125f * dmax - 0.125f * dmean;
}

// ============================================================
// Exact top-U via radix select (512 threads).
// ============================================================
__global__ __launch_bounds__(512) void topk_radix() {
  __shared__ unsigned su[2048];
  __shared__ int hist[256];
  __shared__ unsigned s_pref;
  __shared__ int s_rem;
  __shared__ unsigned eqm[64];
  __shared__ int wpfx[64];
  __shared__ int outcnt;

  const int bh = blockIdx.x;
  const int tid = threadIdx.x;

  for (int t = tid; t < 2048; t += 512) {
    unsigned b = __float_as_uint(g_spars[(size_t)bh * PL + t]);
    su[t] = (b & 0x80000000u) ? ~b : (b | 0x80000000u);
  }
  if (tid == 0) { s_pref = 0u; s_rem = PU; outcnt = 0; }
  if (tid < 64) eqm[tid] = 0u;
  __syncthreads();

  for (int shift = 24; shift >= 0; shift -= 8) {
    if (tid < 256) hist[tid] = 0;
    __syncthreads();
    const unsigned pref = s_pref;
    for (int t = tid; t < 2048; t += 512) {
      const unsigned u = su[t];
      if (shift == 24 || (u >> (shift + 8)) == pref)
        atomicAdd(&hist[(u >> shift) & 255], 1);
    }
    __syncthreads();
    if (tid == 0) {
      int rem = s_rem, acc = 0;
      for (int b = 255; b >= 0; b--) {
        if (acc + hist[b] >= rem) {
          s_rem = rem - acc;
          s_pref = (s_pref << 8) | (unsigned)b;
          break;
        }
        acc += hist[b];
      }
    }
    __syncthreads();
  }

  const unsigned T = s_pref;
  const int e = s_rem;

  for (int t = tid; t < 2048; t += 512)
    if (su[t] == T) atomicOr(&eqm[t >> 5], 1u << (t & 31));
  __syncthreads();
  if (tid == 0) {
    int a = 0;
    for (int w = 0; w < 64; w++) { wpfx[w] = a; a += __popc(eqm[w]); }
  }
  __syncthreads();

  for (int t = tid; t < 2048; t += 512) {
    const unsigned u = su[t];
    bool sel = (u > T);
    if (u == T) {
      const int rank = wpfx[t >> 5] + __popc(eqm[t >> 5] & ((1u << (t & 31)) - 1u));
      sel = (rank < e);
    }
    if (sel) {
      const int slot = atomicAdd(&outcnt, 1);
      g_topidx[(size_t)bh * PU + slot] = t;
    }
  }
}

// ============================================================
// Zero the bf16 attn scatter buffers.
// ============================================================
__global__ void zero_ab() {
  const size_t i = (size_t)blockIdx.x * blockDim.x + threadIdx.x;
  const size_t N = (size_t)PM * PD / 8;
  uint4 z = {0u, 0u, 0u, 0u};
  if (i < N) ((uint4*)g_abh)[i] = z;
  else       ((uint4*)g_abl)[i - N] = z;
}

// ============================================================
// Flash v5 (unchanged): legacy bf16 MMA attention on selected rows.
// ============================================================
#define FQ_S 36
#define FK_S 36
#define FL_SMEM ((2 * 128 * FQ_S + 4 * 2 * 64 * FK_S) * 4)

__global__ __launch_bounds__(256, 2) void flash_v5() {
  extern __shared__ uint32_t smf[];
  uint32_t* Qh = smf;
  uint32_t* Ql = Qh + 128 * FQ_S;
  uint32_t* Kh = Ql + 128 * FQ_S;
  uint32_t* Kl = Kh + 2 * 64 * FK_S;
  uint32_t* Vh = Kl + 2 * 64 * FK_S;
  uint32_t* Vl = Vh + 2 * 64 * FK_S;
  __shared__ int qidx[128];

  const int bh = blockIdx.y, qt = blockIdx.x;
  const int tid = threadIdx.x;
  const int warp = tid >> 5, lane = tid & 31;
  const int gid = lane >> 2, tig = lane & 3;
  const int rbase = warp * 16;
  const float scale = 0.125f;

  if (tid < 128) {
    const int u = qt * 128 + tid;
    qidx[tid] = (u < PU) ? g_topidx[(size_t)bh * PU + u] : -1;
  }
  __syncthreads();

  {
    const int r = tid >> 1, c0 = (tid & 1) * 16;
    int src = qidx[r];
    if (src < 0) src = 0;
    const uint32_t* qh = g_qbh + (size_t)(bh * PL + src) * 32 + c0;
    const uint32_t* ql = g_qbl + (size_t)(bh * PL + src) * 32 + c0;
#pragma unroll
    for (int j = 0; j < 4; j++) {
      *(uint4*)&Qh[r * FQ_S + c0 + j * 4] = *(const uint4*)(qh + j * 4);
      *(uint4*)&Ql[r * FQ_S + c0 + j * 4] = *(const uint4*)(ql + j * 4);
    }
  }

  const int krow = tid >> 2;
  const int seg = (tid & 3) * 8;
  auto issueKV = [&](int kt, int bf) {
    const uint32_t* ksh = g_kbh + (size_t)(bh * PL + kt * 64 + krow) * 32 + seg;
    const uint32_t* ksl = g_kbl + (size_t)(bh * PL + kt * 64 + krow) * 32 + seg;
    const uint32_t* vsh = (const uint32_t*)g_vth + (size_t)(bh * PDH + krow) * (PL / 2) + kt * 32 + seg;
    const uint32_t* vsl = (const uint32_t*)g_vtl + (size_t)(bh * PDH + krow) * (PL / 2) + kt * 32 + seg;
    const uint32_t so = ((bf * 64 + krow) * FK_S + seg) * 4;
    CP16(sptr(Kh) + so, ksh); CP16(sptr(Kh) + so + 16, ksh + 4);
    CP16(sptr(Kl) + so, ksl); CP16(sptr(Kl) + so + 16, ksl + 4);
    CP16(sptr(Vh) + so, vsh); CP16(sptr(Vh) + so + 16, vsh + 4);
    CP16(sptr(Vl) + so, vsl); CP16(sptr(Vl) + so + 16, vsl + 4);
    CP_COMMIT();
  };
  issueKV(0, 0);

  float co[8][4];
#pragma unroll
  for (int nb = 0; nb < 8; nb++)
#pragma unroll
    for (int j = 0; j < 4; j++) co[nb][j] = 0.f;
  float m0 = -1e30f, m1 = -1e30f, lr0 = 0.f, lr1 = 0.f;

#pragma unroll 1
  for (int kt = 0; kt < PL / 64; kt++) {
    const int buf = kt & 1;
    if (kt + 1 < PL / 64) { issueKV(kt + 1, buf ^ 1); CP_WAIT1(); }
    else                  { CP_WAIT0(); }
    __syncthreads();

    const uint32_t* kh = Kh + buf * 64 * FK_S;
    const uint32_t* kl = Kl + buf * 64 * FK_S;
    const uint32_t* vh = Vh + buf * 64 * FK_S;
    const uint32_t* vl = Vl + buf * 64 * FK_S;

    float cs[8][4];
#pragma unroll
    for (int nb = 0; nb < 8; nb++)
#pragma unroll
      for (int j = 0; j < 4; j++) cs[nb][j] = 0.f;

#pragma unroll
    for (int ks = 0; ks < 4; ks++) {
      const int ko = ks * 8;
      const uint32_t qh0 = Qh[(rbase + gid)     * FQ_S + ko + tig];
      const uint32_t qh1 = Qh[(rbase + gid + 8) * FQ_S + ko + tig];
      const uint32_t qh2 = Qh[(rbase + gid)     * FQ_S + ko + tig + 4];
      const uint32_t qh3 = Qh[(rbase + gid + 8) * FQ_S + ko + tig + 4];
      const uint32_t ql0 = Ql[(rbase + gid)     * FQ_S + ko + tig];
      const uint32_t ql1 = Ql[(rbase + gid + 8) * FQ_S + ko + tig];
      const uint32_t ql2 = Ql[(rbase + gid)     * FQ_S + ko + tig + 4];
      const uint32_t ql3 = Ql[(rbase + gid + 8) * FQ_S + ko + tig + 4];
#pragma unroll
      for (int nb = 0; nb < 8; nb++) {
        const int n = nb * 8 + gid;
        const uint32_t b0 = kh[n * FK_S + ko + tig];
        const uint32_t b1 = kh[n * FK_S + ko + tig + 4];
        const uint32_t c0 = kl[n * FK_S + ko + tig];
        const uint32_t c1 = kl[n * FK_S + ko + tig + 4];
        mma_bf16(cs[nb], qh0, qh1, qh2, qh3, b0, b1);
        mma_bf16(cs[nb], qh0, qh1, qh2, qh3, c0, c1);
        mma_bf16(cs[nb], ql0, ql1, ql2, ql3, b0, b1);
      }
    }

    float tm0 = -1e30f, tm1 = -1e30f;
#pragma unroll
    for (int nb = 0; nb < 8; nb++) {
      tm0 = fmaxf(tm0, fmaxf(cs[nb][0], cs[nb][1]));
      tm1 = fmaxf(tm1, fmaxf(cs[nb][2], cs[nb][3]));
    }
    tm0 *= scale; tm1 *= scale;
#pragma unroll
    for (int off = 1; off <= 2; off <<= 1) {
      tm0 = fmaxf(tm0, __shfl_xor_sync(0xffffffffu, tm0, off));
      tm1 = fmaxf(tm1, __shfl_xor_sync(0xffffffffu, tm1, off));
    }
    const float mn0 = fmaxf(m0, tm0), mn1 = fmaxf(m1, tm1);
    const float al0 = __expf(m0 - mn0), al1 = __expf(m1 - mn1);
    m0 = mn0; m1 = mn1;

    float ts0 = 0.f, ts1 = 0.f;
#pragma unroll
    for (int nb = 0; nb < 8; nb++) {
      cs[nb][0] = __expf(cs[nb][0] * scale - mn0);
      cs[nb][1] = __expf(cs[nb][1] * scale - mn0);
      cs[nb][2] = __expf(cs[nb][2] * scale - mn1);
      cs[nb][3] = __expf(cs[nb][3] * scale - mn1);
      ts0 += cs[nb][0] + cs[nb][1];
      ts1 += cs[nb][2] + cs[nb][3];
    }
#pragma unroll
    for (int off = 1; off <= 2; off <<= 1) {
      ts0 += __shfl_xor_sync(0xffffffffu, ts0, off);
      ts1 += __shfl_xor_sync(0xffffffffu, ts1, off);
    }
    lr0 = lr0 * al0 + ts0;
    lr1 = lr1 * al1 + ts1;

#pragma unroll
    for (int nb = 0; nb < 8; nb++) {
      co[nb][0] *= al0; co[nb][1] *= al0;
      co[nb][2] *= al1; co[nb][3] *= al1;
    }

#pragma unroll
    for (int kq = 0; kq < 4; kq++) {
      const int s0 = 2 * kq, s1 = 2 * kq + 1;
      __nv_bfloat16 h, l;
      uint32_t pa0, pa1, pa2, pa3, la0, la1, la2, la3;
      {
        __nv_bfloat16 h2, l2;
        split_bf16(cs[s0][0], h, l); split_bf16(cs[s0][1], h2, l2);
        pa0 = pack_bf16(h, h2); la0 = pack_bf16(l, l2);
        split_bf16(cs[s0][2], h, l); split_bf16(cs[s0][3], h2, l2);
        pa1 = pack_bf16(h, h2); la1 = pack_bf16(l, l2);
        split_bf16(cs[s1][0], h, l); split_bf16(cs[s1][1], h2, l2);
        pa2 = pack_bf16(h, h2); la2 = pack_bf16(l, l2);
        split_bf16(cs[s1][2], h, l); split_bf16(cs[s1][3], h2, l2);
        pa3 = pack_bf16(h, h2); la3 = pack_bf16(l, l2);
      }
      const int ko = kq * 8;
#pragma unroll
      for (int nb = 0; nb < 8; nb++) {
        const int n = nb * 8 + gid;
        const uint32_t b0 = vh[n * FK_S + ko + tig];
        const uint32_t b1 = vh[n * FK_S + ko + tig + 4];
        const uint32_t c0 = vl[n * FK_S + ko + tig];
        const uint32_t c1 = vl[n * FK_S + ko + tig + 4];
        mma_bf16(co[nb], pa0, pa1, pa2, pa3, b0, b1);
        mma_bf16(co[nb], pa0, pa1, pa2, pa3, c0, c1);
        mma_bf16(co[nb], la0, la1, la2, la3, b0, b1);
      }
    }
    __syncthreads();
  }

  const int b = bh >> 4, h = bh & 15;
  const int r0 = rbase + gid, r1 = r0 + 8;
  const int s0 = qidx[r0], s1 = qidx[r1];
  const float inv0 = 1.0f / lr0, inv1 = 1.0f / lr1;
#pragma unroll
  for (int nb = 0; nb < 8; nb++) {
    const int col = h * PDH + nb * 8 + tig * 2;
    if (s0 >= 0) {
      __nv_bfloat16 h0, l0, h1, l1;
      split_bf16(co[nb][0] * inv0, h0, l0);
      split_bf16(co[nb][1] * inv0, h1, l1);
      const size_t ui = ((size_t)(b * PL + s0) * PD + col) / 2;
      g_abh[ui] = pack_bf16(h0, h1);
      g_abl[ui] = pack_bf16(l0, l1);
    }
    if (s1 >= 0) {
      __nv_bfloat16 h0, l0, h1, l1;
      split_bf16(co[nb][2] * inv1, h0, l0);
      split_bf16(co[nb][3] * inv1, h1, l1);
      const size_t ui = ((size_t)(b * PL + s1) * PD + col) / 2;
      g_abh[ui] = pack_bf16(h0, h1);
      g_abl[ui] = pack_bf16(l0, l1);
    }
  }
}

// ============================================================
// one-time stream/event setup (static ctor: before harness baseline)
// ============================================================
struct HxStreams {
  cudaStream_t s2;
  cudaEvent_t evS, evX, evB;
  HxStreams() {
    cudaStreamCreateWithFlags(&s2, cudaStreamNonBlocking);
    cudaEventCreateWithFlags(&evS, cudaEventDisableTiming);
    cudaEventCreateWithFlags(&evX, cudaEventDisableTiming);
    cudaEventCreateWithFlags(&evB, cudaEventDisableTiming);
  }
};
static HxStreams g_hx;

// ============================================================
// host launcher
// ============================================================
extern "C" void kernel_launch(void* const* d_in, const int* in_sizes, int n_in,
                              void* d_out, int out_size) {
  (void)in_sizes; (void)n_in; (void)out_size;
  const float* x  = (const float*)d_in[0];
  const float* Wq = (const float*)d_in[1];
  const float* bq = (const float*)d_in[2];
  const float* Wk = (const float*)d_in[3];
  const float* bk = (const float*)d_in[4];
  const float* Wv = (const float*)d_in[5];
  const float* bv = (const float*)d_in[6];
  const float* Wo = (const float*)d_in[7];
  const float* bo = (const float*)d_in[8];
  float* out = (float*)d_out;

  float *pv;
  uint32_t *pabh, *pabl;
  __nv_bfloat16 *px3h, *px3m, *px3l;
  __nv_bfloat16 *pwqth, *pwqtl, *pwkth, *pwktl;
  __nv_bfloat16 *pwvth, *pwvtl, *pwoth, *pwotl, *pvth, *pvtl;
  cudaGetSymbolAddress((void**)&pv, g_v);
  cudaGetSymbolAddress((void**)&px3h, g_x3h);
  cudaGetSymbolAddress((void**)&px3m, g_x3m);
  cudaGetSymbolAddress((void**)&px3l, g_x3l);
  cudaGetSymbolAddress((void**)&pwqth, g_wqth);
  cudaGetSymbolAddress((void**)&pwqtl, g_wqtl);
  cudaGetSymbolAddress((void**)&pwkth, g_wkth);
  cudaGetSymbolAddress((void**)&pwktl, g_wktl);
  cudaGetSymbolAddress((void**)&pwvth, g_wvth);
  cudaGetSymbolAddress((void**)&pwvtl, g_wvtl);
  cudaGetSymbolAddress((void**)&pwoth, g_woth);
  cudaGetSymbolAddress((void**)&pwotl, g_wotl);
  cudaGetSymbolAddress((void**)&pvth, g_vth);
  cudaGetSymbolAddress((void**)&pvtl, g_vtl);
  cudaGetSymbolAddress((void**)&pabh, g_abh);
  cudaGetSymbolAddress((void**)&pabl, g_abl);

  cudaFuncSetAttribute(gemm_qk5, cudaFuncAttributeMaxDynamicSharedMemorySize, QK5_SMEM);
  cudaFuncSetAttribute(gemm_bf16<0>, cudaFuncAttributeMaxDynamicSharedMemorySize, GBF_SMEM);
  cudaFuncSetAttribute(gemm_bf16<1>, cudaFuncAttributeMaxDynamicSharedMemorySize, GBF_SMEM);
  cudaFuncSetAttribute(sparsity_v7, cudaFuncAttributeMaxDynamicSharedMemorySize, SP7_SMEM);
  cudaFuncSetAttribute(flash_v5, cudaFuncAttributeMaxDynamicSharedMemorySize, FL_SMEM);

  const int n4x = (int)((size_t)PM * PD / 4);
  const dim3 gW(PD / 32, PD / 32);
  cudaStream_t s2 = g_hx.s2;

  // ---- fork: stream B handles the V/Wo prep chain ----
  cudaEventRecord(g_hx.evS, 0);
  cudaStreamWaitEvent(s2, g_hx.evS, 0);

  // s2: weight transposes not needed by the QK critical path
  transpose_split_bf16<<<gW, 256, 0, s2>>>(Wv, pwvth, pwvtl, PD, PD);
  transpose_split_bf16<<<gW, 256, 0, s2>>>(Wo, pwoth, pwotl, PD, PD);

  // s0 (critical path): x split, QK weight transposes, QK gemm, selection
  split3_bf16_kernel<<<(n4x + 255) / 256, 256>>>(x, px3h, px3m, px3l, n4x);
  cudaEventRecord(g_hx.evX, 0);   // x3 ready -> V gemm may start on s2
  transpose_split_bf16<<<gW, 256>>>(Wq, pwqth, pwqtl, PD, PD);
  transpose_split_bf16<<<gW, 256>>>(Wk, pwkth, pwktl, PD, PD);
  gemm_qk5<<<dim3(2 * PD / 128, PM / 128), 256, QK5_SMEM>>>(bq, bk);
  kbar_kernel<<<PBH, 1024>>>();
  sparsity_v7<<<dim3(PL / 128, PBH), 256, SP7_SMEM>>>();
  refine_kernel<<<PBH * PL / 8, 256>>>();
  topk_radix<<<PBH, 512>>>();

  // s2: V projection + V^T split + zero of attn buffers (overlaps selection)
  cudaStreamWaitEvent(s2, g_hx.evX, 0);
  gemm_bf16<1><<<dim3(PD / 128, PM / 128), 256, GBF_SMEM, s2>>>(
      px3h, px3m, pwvth, pwvtl, bv, pv, PM, PD, PD);
  transpose_head_bf16<<<dim3(PL / 32, PDH / 32, PBH), 256, 0, s2>>>(pv, pvth, pvtl);
  zero_ab<<<(int)(2 * ((size_t)PM * PD / 8) / 256), 256, 0, s2>>>();
  cudaEventRecord(g_hx.evB, s2);

  // ---- join: flash needs topk (s0) + V^T/zero (s2) ----
  cudaStreamWaitEvent(0, g_hx.evB, 0);
  flash_v5<<<dim3((PU + 127) / 128, PBH), 256, FL_SMEM>>>();

  // output projection (Wo^T ready on s2 before evB)
  gemm_bf16<0><<<dim3(PD / 128, PM / 128), 256, GBF_SMEM>>>(
      (const __nv_bfloat16*)pabh, (const __nv_bfloat16*)pabl,
      pwoth, pwotl, bo, out, PM, PD, PD);
}